// round 2
// baseline (speedup 1.0000x reference)
#include <cuda_runtime.h>
#include <cstdint>

#define B_  256
#define N_  4096
#define M_  64
#define C_  512
#define EPSV 1e-8f

// ---------------- device scratch (no allocations allowed) ----------------
__device__ __align__(16) float g_mem[(size_t)B_ * N_ * M_];      // 256 MiB working memory
__device__ __align__(16) float g_x[B_ * 320];
__device__ __align__(16) float g_gates[B_ * 2048];
__device__ __align__(16) float g_c[B_ * C_];
__device__ __align__(16) float g_h[B_ * C_];
__device__ __align__(16) float g_pall[B_ * 560];
__device__ __align__(16) float g_eaall[B_ * 512];
__device__ __align__(16) float g_k[7 * B_ * M_];
__device__ float g_knorm[7 * B_];
__device__ float g_beta[7 * B_];
__device__ float g_gate[7 * B_];
__device__ float g_s[7 * B_ * 3];
__device__ float g_gamma[7 * B_];
__device__ __align__(16) float g_e[3 * B_ * M_];
__device__ __align__(16) float g_a[3 * B_ * M_];
__device__ __align__(16) float g_dot0[(size_t)B_ * N_];
__device__ __align__(16) float g_dot1[(size_t)B_ * N_];
__device__ __align__(16) float g_nrm[(size_t)B_ * N_];
__device__ __align__(16) float g_w[2 * (size_t)B_ * N_];         // slot0 = read-head w, slot1 = write-head w
__device__ __align__(16) float g_rpart[4 * B_ * 16 * M_];        // per-block partial reads
__device__ __align__(16) float g_state[B_ * 768];

// ---------------- helpers ----------------
__device__ __forceinline__ float sigf(float x) { return 1.f / (1.f + expf(-x)); }
__device__ __forceinline__ float softplusf(float x) { return x > 20.f ? x : log1pf(expf(x)); }

// ---------------- build x = [in_data | prev_reads 0..3] ----------------
__global__ void build_x_kernel(const float* __restrict__ in_data,
                               const float* __restrict__ prev_reads) {
    int idx = blockIdx.x * blockDim.x + threadIdx.x;
    if (idx >= B_ * 320) return;
    int b = idx / 320, j = idx % 320;
    float v;
    if (j < 64) v = in_data[b * 64 + j];
    else { int i = (j - 64) >> 6, m = (j - 64) & 63; v = prev_reads[((size_t)i * B_ + b) * 64 + m]; }
    g_x[idx] = v;
}

// ---------------- generic SGEMM: C[MM,NN] (+)= A[MM,K] * B[NN,K]^T + bias ----------------
template<bool ACC, bool SIG>
__global__ void sgemm_kernel(const float* __restrict__ A, const float* __restrict__ Bw,
                             const float* __restrict__ bias, float* __restrict__ C,
                             int NN, int K) {
    __shared__ __align__(16) float As[16][64];
    __shared__ __align__(16) float Bs[16][64];
    int tid = threadIdx.x;                   // 256 threads
    int m0 = blockIdx.y * 64, n0 = blockIdx.x * 64;
    int ty = tid >> 4, tx = tid & 15;
    int la_r = tid >> 2;                     // 0..63
    int la_k = (tid & 3) << 2;               // 0,4,8,12
    float acc[4][4];
#pragma unroll
    for (int i = 0; i < 4; i++)
#pragma unroll
        for (int j = 0; j < 4; j++) acc[i][j] = 0.f;

    for (int k0 = 0; k0 < K; k0 += 16) {
        float4 av = *(const float4*)(A + (size_t)(m0 + la_r) * K + k0 + la_k);
        float4 bv = make_float4(0.f, 0.f, 0.f, 0.f);
        int br = n0 + la_r;
        if (br < NN) bv = *(const float4*)(Bw + (size_t)br * K + k0 + la_k);
        __syncthreads();
        As[la_k + 0][la_r] = av.x; As[la_k + 1][la_r] = av.y;
        As[la_k + 2][la_r] = av.z; As[la_k + 3][la_r] = av.w;
        Bs[la_k + 0][la_r] = bv.x; Bs[la_k + 1][la_r] = bv.y;
        Bs[la_k + 2][la_r] = bv.z; Bs[la_k + 3][la_r] = bv.w;
        __syncthreads();
#pragma unroll
        for (int kk = 0; kk < 16; kk++) {
            float4 a = *(const float4*)&As[kk][ty << 2];
            float4 b = *(const float4*)&Bs[kk][tx << 2];
            acc[0][0] += a.x * b.x; acc[0][1] += a.x * b.y; acc[0][2] += a.x * b.z; acc[0][3] += a.x * b.w;
            acc[1][0] += a.y * b.x; acc[1][1] += a.y * b.y; acc[1][2] += a.y * b.z; acc[1][3] += a.y * b.w;
            acc[2][0] += a.z * b.x; acc[2][1] += a.z * b.y; acc[2][2] += a.z * b.z; acc[2][3] += a.z * b.w;
            acc[3][0] += a.w * b.x; acc[3][1] += a.w * b.y; acc[3][2] += a.w * b.z; acc[3][3] += a.w * b.w;
        }
    }
#pragma unroll
    for (int i = 0; i < 4; i++) {
        int m = m0 + (ty << 2) + i;
#pragma unroll
        for (int j = 0; j < 4; j++) {
            int n = n0 + (tx << 2) + j;
            if (n < NN) {
                float v = acc[i][j];
                if (bias) v += bias[n];
                size_t ci = (size_t)m * NN + n;
                if (ACC) v += C[ci];
                if (SIG) v = sigf(v);
                C[ci] = v;
            }
        }
    }
}

// ---------------- LSTM pointwise ----------------
__global__ void lstm_kernel(const float* __restrict__ c0) {
    int idx = blockIdx.x * blockDim.x + threadIdx.x;
    if (idx >= B_ * C_) return;
    int b = idx / C_, j = idx % C_;
    const float* gr = g_gates + (size_t)b * 2048;
    float ig = gr[j], fg = gr[512 + j], gg = gr[1024 + j], og = gr[1536 + j];
    float c = sigf(fg) * c0[idx] + sigf(ig) * tanhf(gg);
    g_c[idx] = c;
    g_h[idx] = sigf(og) * tanhf(c);
}

// ---------------- head activations (k, beta, gate, s, gamma, e, a) ----------------
__global__ void head_act_kernel() {
    int b = blockIdx.x;
    int lane = threadIdx.x;   // 32 threads
    for (int hd = 0; hd < 7; ++hd) {
        const float* p = g_pall + (size_t)b * 560 + hd * 70;
        float ssq = 0.f;
        for (int j = lane; j < 64; j += 32) {
            float kv = tanhf(p[j]);
            g_k[((size_t)hd * B_ + b) * 64 + j] = kv;
            ssq += kv * kv;
        }
#pragma unroll
        for (int o = 16; o; o >>= 1) ssq += __shfl_xor_sync(0xffffffffu, ssq, o);
        if (lane == 0) {
            int hb = hd * B_ + b;
            g_knorm[hb] = sqrtf(ssq);
            g_beta[hb] = softplusf(p[64]);
            g_gate[hb] = sigf(p[65]);
            float s0 = p[66], s1 = p[67], s2 = p[68];
            float mx = fmaxf(s0, fmaxf(s1, s2));
            float e0 = expf(s0 - mx), e1 = expf(s1 - mx), e2 = expf(s2 - mx);
            float inv = 1.f / (e0 + e1 + e2);
            g_s[hb * 3 + 0] = e0 * inv; g_s[hb * 3 + 1] = e1 * inv; g_s[hb * 3 + 2] = e2 * inv;
            g_gamma[hb] = 1.f + softplusf(p[69]);
        }
    }
    for (int wh = 0; wh < 3; ++wh) {
        const float* ea = g_eaall + (size_t)b * 512 + wh * 128;
        for (int j = lane; j < 64; j += 32) {
            g_e[((size_t)wh * B_ + b) * 64 + j] = sigf(ea[j]);
            g_a[((size_t)wh * B_ + b) * 64 + j] = tanhf(ea[64 + j]);
        }
    }
}

// ---------------- big memory pass ----------------
// One block: (b, chunk of 256 rows). 256 threads; 16 lanes per row, 2 rows per warp.
template<int NDOT, bool READS, bool UPDATE, bool NORMS>
__global__ void pass_kernel(const float* __restrict__ memExt, int inSel,
                            int k0Idx, int k1Idx, int eaIdx, int rSlot) {
    __shared__ __align__(16) float sk0[64], sk1[64], se[64], sa[64];
    __shared__ float4 sred[8][16];
    int b = blockIdx.y, chunk = blockIdx.x;
    int tid = threadIdx.x;
    if (tid < 64) {
        if (NDOT >= 1) sk0[tid] = g_k[((size_t)k0Idx * B_ + b) * 64 + tid];
        if (NDOT >= 2) sk1[tid] = g_k[((size_t)k1Idx * B_ + b) * 64 + tid];
        if (UPDATE) {
            se[tid] = g_e[((size_t)eaIdx * B_ + b) * 64 + tid];
            sa[tid] = g_a[((size_t)eaIdx * B_ + b) * 64 + tid];
        }
    }
    __syncthreads();
    const float* mi = inSel ? g_mem : memExt;
    int lane = tid & 31, warp = tid >> 5;
    int rg = lane >> 4, g = lane & 15;
    float4 k0v = make_float4(0,0,0,0), k1v = make_float4(0,0,0,0);
    float4 ev = make_float4(0,0,0,0), av = make_float4(0,0,0,0);
    if (NDOT >= 1) k0v = ((const float4*)sk0)[g];
    if (NDOT >= 2) k1v = ((const float4*)sk1)[g];
    if (UPDATE) { ev = ((const float4*)se)[g]; av = ((const float4*)sa)[g]; }
    float4 acc = make_float4(0,0,0,0);
    size_t rowBase = (size_t)b * N_ + (size_t)chunk * 256;
    const float* wR = g_w;
    const float* wW = g_w + (size_t)B_ * N_;

#pragma unroll 4
    for (int it = 0; it < 16; ++it) {
        int r = it * 16 + warp * 2 + rg;
        size_t n = rowBase + r;
        size_t off = n * 64 + (size_t)g * 4;
        float4 v = *(const float4*)(mi + off);
        if (READS) {
            float wr = wR[n];
            acc.x += wr * v.x; acc.y += wr * v.y; acc.z += wr * v.z; acc.w += wr * v.w;
        }
        if (UPDATE) {
            float ww = wW[n];
            v.x = v.x * (1.f - ww * ev.x) + ww * av.x;
            v.y = v.y * (1.f - ww * ev.y) + ww * av.y;
            v.z = v.z * (1.f - ww * ev.z) + ww * av.z;
            v.w = v.w * (1.f - ww * ev.w) + ww * av.w;
            *(float4*)(g_mem + off) = v;
        }
        float pd0 = 0.f, pd1 = 0.f, pn = 0.f;
        if (NDOT >= 1) pd0 = v.x * k0v.x + v.y * k0v.y + v.z * k0v.z + v.w * k0v.w;
        if (NDOT >= 2) pd1 = v.x * k1v.x + v.y * k1v.y + v.z * k1v.z + v.w * k1v.w;
        if (NORMS)     pn  = v.x * v.x + v.y * v.y + v.z * v.z + v.w * v.w;
        if (NDOT >= 1 || NORMS) {
#pragma unroll
            for (int o = 8; o; o >>= 1) {
                if (NDOT >= 1) pd0 += __shfl_xor_sync(0xffffffffu, pd0, o);
                if (NDOT >= 2) pd1 += __shfl_xor_sync(0xffffffffu, pd1, o);
                if (NORMS)     pn  += __shfl_xor_sync(0xffffffffu, pn, o);
            }
            if (g == 0) {
                if (NDOT >= 1) g_dot0[n] = pd0;
                if (NDOT >= 2) g_dot1[n] = pd1;
                if (NORMS)     g_nrm[n]  = pn;
            }
        }
    }

    if (READS) {
        acc.x += __shfl_xor_sync(0xffffffffu, acc.x, 16);
        acc.y += __shfl_xor_sync(0xffffffffu, acc.y, 16);
        acc.z += __shfl_xor_sync(0xffffffffu, acc.z, 16);
        acc.w += __shfl_xor_sync(0xffffffffu, acc.w, 16);
        if (lane < 16) sred[warp][g] = acc;
        __syncthreads();
        if (tid < 16) {
            float4 s = sred[0][tid];
#pragma unroll
            for (int wv = 1; wv < 8; ++wv) {
                float4 t = sred[wv][tid];
                s.x += t.x; s.y += t.y; s.z += t.z; s.w += t.w;
            }
            *(float4*)(g_rpart + (size_t)rSlot * B_ * 16 * 64 +
                       ((size_t)b * 16 + chunk) * 64 + tid * 4) = s;
        }
    }
}

// ---------------- finalize: dot/norm -> addressing weight w ----------------
__device__ __forceinline__ float block_reduce_max(float v, float* sbuf) {
#pragma unroll
    for (int o = 16; o; o >>= 1) v = fmaxf(v, __shfl_xor_sync(0xffffffffu, v, o));
    int lane = threadIdx.x & 31, w = threadIdx.x >> 5;
    if (lane == 0) sbuf[w] = v;
    __syncthreads();
    if (threadIdx.x < 32) {
        float vv = (threadIdx.x < 8) ? sbuf[threadIdx.x] : -3.4e38f;
#pragma unroll
        for (int o = 4; o; o >>= 1) vv = fmaxf(vv, __shfl_xor_sync(0xffffffffu, vv, o));
        if (threadIdx.x == 0) sbuf[0] = vv;
    }
    __syncthreads();
    v = sbuf[0];
    __syncthreads();
    return v;
}
__device__ __forceinline__ float block_reduce_sum(float v, float* sbuf) {
#pragma unroll
    for (int o = 16; o; o >>= 1) v += __shfl_xor_sync(0xffffffffu, v, o);
    int lane = threadIdx.x & 31, w = threadIdx.x >> 5;
    if (lane == 0) sbuf[w] = v;
    __syncthreads();
    if (threadIdx.x < 32) {
        float vv = (threadIdx.x < 8) ? sbuf[threadIdx.x] : 0.f;
#pragma unroll
        for (int o = 4; o; o >>= 1) vv += __shfl_xor_sync(0xffffffffu, vv, o);
        if (threadIdx.x == 0) sbuf[0] = vv;
    }
    __syncthreads();
    v = sbuf[0];
    __syncthreads();
    return v;
}

__global__ void fin_kernel(int head0, int nheads, const float* __restrict__ prevW) {
    __shared__ float swg[N_];
    __shared__ float sbuf[8];
    int b = blockIdx.x;
    int tid = threadIdx.x;   // 256
    for (int hh = 0; hh < nheads; ++hh) {
        int hd = head0 + hh;
        const float* dot = (hh == 0) ? g_dot0 : g_dot1;
        int hb = hd * B_ + b;
        float knorm = g_knorm[hb], beta = g_beta[hb], gate = g_gate[hb], gamma = g_gamma[hb];
        float s0 = g_s[hb * 3 + 0], s1 = g_s[hb * 3 + 1], s2 = g_s[hb * 3 + 2];
        const float* pw = prevW + ((size_t)hd * B_ + b) * N_;
        const size_t base = (size_t)b * N_;

        float sc[16];
        float lmax = -3.4e38f;
#pragma unroll
        for (int t = 0; t < 16; ++t) {
            int idx = tid + t * 256;
            float d = dot[base + idx];
            float nr = g_nrm[base + idx];
            float v = beta * d / (sqrtf(nr) * knorm + EPSV);
            sc[t] = v;
            lmax = fmaxf(lmax, v);
        }
        float bmax = block_reduce_max(lmax, sbuf);
        float lsum = 0.f;
#pragma unroll
        for (int t = 0; t < 16; ++t) { float e = __expf(sc[t] - bmax); sc[t] = e; lsum += e; }
        float bsum = block_reduce_sum(lsum, sbuf);
        float inv = 1.f / bsum;
#pragma unroll
        for (int t = 0; t < 16; ++t) {
            int idx = tid + t * 256;
            swg[idx] = gate * sc[t] * inv + (1.f - gate) * pw[idx];
        }
        __syncthreads();
        float wp[16];
        float lps = 0.f;
#pragma unroll
        for (int t = 0; t < 16; ++t) {
            int idx = tid + t * 256;
            float ws = s0 * swg[(idx + N_ - 1) & (N_ - 1)] + s1 * swg[idx]
                     + s2 * swg[(idx + 1) & (N_ - 1)];
            float p = __powf(ws, gamma);
            wp[t] = p; lps += p;
        }
        float psum = block_reduce_sum(lps, sbuf);
        float invp = 1.f / (psum + EPSV);
        float* wout = g_w + (size_t)(hd & 1) * B_ * N_;
#pragma unroll
        for (int t = 0; t < 16; ++t) {
            int idx = tid + t * 256;
            wout[base + idx] = wp[t] * invp;
        }
        __syncthreads();
    }
}

// ---------------- build state = [h | reads0 | reads2 | reads4 | reads6] ----------------
__global__ void build_state_kernel() {
    int b = blockIdx.x;
    for (int j = threadIdx.x; j < 768; j += blockDim.x) {
        float v;
        if (j < 512) v = g_h[(size_t)b * C_ + j];
        else {
            int ri = (j - 512) >> 6, m = (j - 512) & 63;
            float s = 0.f;
            const float* rp = g_rpart + (size_t)ri * B_ * 16 * 64 + (size_t)b * 16 * 64 + m;
#pragma unroll
            for (int c = 0; c < 16; ++c) s += rp[c * 64];
            v = s;
        }
        g_state[(size_t)b * 768 + j] = v;
    }
}

// ---------------- host ----------------
extern "C" void kernel_launch(void* const* d_in, const int* in_sizes, int n_in,
                              void* d_out, int out_size) {
    const float* in_data      = (const float*)d_in[0];
    const float* memory       = (const float*)d_in[1];
    const float* h0           = (const float*)d_in[2];
    const float* c0           = (const float*)d_in[3];
    const float* prev_weights = (const float*)d_in[4];
    const float* prev_reads   = (const float*)d_in[5];
    const float* W_ih         = (const float*)d_in[6];
    const float* b_ih         = (const float*)d_in[7];
    const float* W_hh         = (const float*)d_in[8];
    const float* b_hh         = (const float*)d_in[9];
    const float* W_out        = (const float*)d_in[10];
    const float* b_out        = (const float*)d_in[11];
    const float* W_addr       = (const float*)d_in[12];
    const float* b_addr       = (const float*)d_in[13];
    const float* W_ea         = (const float*)d_in[14];
    const float* b_ea         = (const float*)d_in[15];
    float* outp = (float*)d_out;

    float *p_x, *p_gates, *p_c, *p_pall, *p_ea, *p_state;
    cudaGetSymbolAddress((void**)&p_x,     g_x);
    cudaGetSymbolAddress((void**)&p_gates, g_gates);
    cudaGetSymbolAddress((void**)&p_c,     g_c);
    cudaGetSymbolAddress((void**)&p_pall,  g_pall);
    cudaGetSymbolAddress((void**)&p_ea,    g_eaall);
    cudaGetSymbolAddress((void**)&p_state, g_state);

    // controller
    build_x_kernel<<<(B_ * 320 + 255) / 256, 256>>>(in_data, prev_reads);
    sgemm_kernel<false, false><<<dim3(2048 / 64, B_ / 64), 256>>>(p_x, W_ih, b_ih, p_gates, 2048, 320);
    sgemm_kernel<true,  false><<<dim3(2048 / 64, B_ / 64), 256>>>(h0,  W_hh, b_hh, p_gates, 2048, 512);
    lstm_kernel<<<(B_ * C_ + 255) / 256, 256>>>(c0);

    // all head parameters up front (head 7 is dead code: its write is never observed)
    sgemm_kernel<false, false><<<dim3((560 + 63) / 64, B_ / 64), 256>>>(p_c, W_addr, b_addr, p_pall, 560, 512);
    sgemm_kernel<false, false><<<dim3(512 / 64, B_ / 64), 256>>>(p_c, W_ea, b_ea, p_ea, 512, 512);
    head_act_kernel<<<B_, 32>>>();

    dim3 pg(16, B_);
    // Pass A: dot0,dot1,norms on v0
    pass_kernel<2, false, false, true><<<pg, 256>>>(memory, 0, 0, 1, 0, 0);
    fin_kernel<<<B_, 256>>>(0, 2, prev_weights);
    // Pass B: reads0 + update(w1) -> v1, dot2,dot3,norms
    pass_kernel<2, true, true, true><<<pg, 256>>>(memory, 0, 2, 3, 0, 0);
    fin_kernel<<<B_, 256>>>(2, 2, prev_weights);
    // Pass C: reads2 + update(w3) -> v2, dot4,dot5,norms
    pass_kernel<2, true, true, true><<<pg, 256>>>(memory, 1, 4, 5, 1, 1);
    fin_kernel<<<B_, 256>>>(4, 2, prev_weights);
    // Pass D: reads4 + update(w5) -> v3, dot6,norms
    pass_kernel<1, true, true, true><<<pg, 256>>>(memory, 1, 6, 6, 2, 2);
    fin_kernel<<<B_, 256>>>(6, 1, prev_weights);
    // Pass E: reads6 on v3
    pass_kernel<0, true, false, false><<<pg, 256>>>(memory, 1, 0, 0, 0, 3);

    // output
    build_state_kernel<<<B_, 256>>>();
    sgemm_kernel<false, true><<<dim3(1, B_ / 64), 256>>>(p_state, W_out, b_out, outp, 64, 768);
}

// round 3
// speedup vs baseline: 1.2117x; 1.2117x over previous
#include <cuda_runtime.h>
#include <cstdint>

#define B_  256
#define N_  4096
#define M_  64
#define C_  512
#define EPSV 1e-8f

// ---------------- packed f32x2 helpers (sm_103a FFMA2) ----------------
struct px2 { unsigned long long u; };
__device__ __forceinline__ px2 pk(float x, float y) {
    px2 r; asm("mov.b64 %0,{%1,%2};" : "=l"(r.u) : "f"(x), "f"(y)); return r;
}
__device__ __forceinline__ float2 up(px2 a) {
    float2 f; asm("mov.b64 {%0,%1},%2;" : "=f"(f.x), "=f"(f.y) : "l"(a.u)); return f;
}
__device__ __forceinline__ px2 fma2(px2 a, px2 b, px2 c) {
    px2 r; asm("fma.rn.f32x2 %0,%1,%2,%3;" : "=l"(r.u) : "l"(a.u), "l"(b.u), "l"(c.u)); return r;
}

// ---------------- device scratch (no allocations allowed) ----------------
__device__ __align__(16) float g_mem[(size_t)B_ * N_ * M_];      // 256 MiB working memory
__device__ __align__(16) float g_x[B_ * 320];
__device__ __align__(16) float g_gates[B_ * 2048];
__device__ __align__(16) float g_c[B_ * C_];
__device__ __align__(16) float g_h[B_ * C_];
__device__ __align__(16) float g_pall[B_ * 560];
__device__ __align__(16) float g_eaall[B_ * 512];
__device__ __align__(16) float g_k[7 * B_ * M_];
__device__ float g_knorm[7 * B_];
__device__ float g_beta[7 * B_];
__device__ float g_gate[7 * B_];
__device__ float g_s[7 * B_ * 3];
__device__ float g_gamma[7 * B_];
__device__ __align__(16) float g_e[3 * B_ * M_];
__device__ __align__(16) float g_a[3 * B_ * M_];
__device__ __align__(16) float g_dot0[(size_t)B_ * N_];
__device__ __align__(16) float g_dot1[(size_t)B_ * N_];
__device__ __align__(16) float g_nrm[(size_t)B_ * N_];
__device__ __align__(16) float g_w[2 * (size_t)B_ * N_];         // slot0 = read-head w, slot1 = write-head w
__device__ __align__(16) float g_rpart[4 * B_ * 16 * M_];        // per-block partial reads
__device__ __align__(16) float g_state[B_ * 768];

// ---------------- helpers ----------------
__device__ __forceinline__ float sigf(float x) { return 1.f / (1.f + expf(-x)); }
__device__ __forceinline__ float softplusf(float x) { return x > 20.f ? x : log1pf(expf(x)); }

// ---------------- build x = [in_data | prev_reads 0..3] ----------------
__global__ void build_x_kernel(const float* __restrict__ in_data,
                               const float* __restrict__ prev_reads) {
    int idx = blockIdx.x * blockDim.x + threadIdx.x;
    if (idx >= B_ * 320) return;
    int b = idx / 320, j = idx % 320;
    float v;
    if (j < 64) v = in_data[b * 64 + j];
    else { int i = (j - 64) >> 6, m = (j - 64) & 63; v = prev_reads[((size_t)i * B_ + b) * 64 + m]; }
    g_x[idx] = v;
}

// ---------------- generic SGEMM: C[MM,NN] (+)= A[MM,K] * B[NN,K]^T + bias ----------------
template<bool ACC, bool SIG>
__global__ void sgemm_kernel(const float* __restrict__ A, const float* __restrict__ Bw,
                             const float* __restrict__ bias, float* __restrict__ C,
                             int NN, int K) {
    __shared__ __align__(16) float As[16][64];
    __shared__ __align__(16) float Bs[16][64];
    int tid = threadIdx.x;                   // 256 threads
    int m0 = blockIdx.y * 64, n0 = blockIdx.x * 64;
    int ty = tid >> 4, tx = tid & 15;
    int la_r = tid >> 2;                     // 0..63
    int la_k = (tid & 3) << 2;               // 0,4,8,12
    float acc[4][4];
#pragma unroll
    for (int i = 0; i < 4; i++)
#pragma unroll
        for (int j = 0; j < 4; j++) acc[i][j] = 0.f;

    for (int k0 = 0; k0 < K; k0 += 16) {
        float4 av = *(const float4*)(A + (size_t)(m0 + la_r) * K + k0 + la_k);
        float4 bv = make_float4(0.f, 0.f, 0.f, 0.f);
        int br = n0 + la_r;
        if (br < NN) bv = *(const float4*)(Bw + (size_t)br * K + k0 + la_k);
        __syncthreads();
        As[la_k + 0][la_r] = av.x; As[la_k + 1][la_r] = av.y;
        As[la_k + 2][la_r] = av.z; As[la_k + 3][la_r] = av.w;
        Bs[la_k + 0][la_r] = bv.x; Bs[la_k + 1][la_r] = bv.y;
        Bs[la_k + 2][la_r] = bv.z; Bs[la_k + 3][la_r] = bv.w;
        __syncthreads();
#pragma unroll
        for (int kk = 0; kk < 16; kk++) {
            float4 a = *(const float4*)&As[kk][ty << 2];
            float4 b = *(const float4*)&Bs[kk][tx << 2];
            acc[0][0] += a.x * b.x; acc[0][1] += a.x * b.y; acc[0][2] += a.x * b.z; acc[0][3] += a.x * b.w;
            acc[1][0] += a.y * b.x; acc[1][1] += a.y * b.y; acc[1][2] += a.y * b.z; acc[1][3] += a.y * b.w;
            acc[2][0] += a.z * b.x; acc[2][1] += a.z * b.y; acc[2][2] += a.z * b.z; acc[2][3] += a.z * b.w;
            acc[3][0] += a.w * b.x; acc[3][1] += a.w * b.y; acc[3][2] += a.w * b.z; acc[3][3] += a.w * b.w;
        }
    }
#pragma unroll
    for (int i = 0; i < 4; i++) {
        int m = m0 + (ty << 2) + i;
#pragma unroll
        for (int j = 0; j < 4; j++) {
            int n = n0 + (tx << 2) + j;
            if (n < NN) {
                float v = acc[i][j];
                if (bias) v += bias[n];
                size_t ci = (size_t)m * NN + n;
                if (ACC) v += C[ci];
                if (SIG) v = sigf(v);
                C[ci] = v;
            }
        }
    }
}

// ---------------- LSTM pointwise ----------------
__global__ void lstm_kernel(const float* __restrict__ c0) {
    int idx = blockIdx.x * blockDim.x + threadIdx.x;
    if (idx >= B_ * C_) return;
    int b = idx / C_, j = idx % C_;
    const float* gr = g_gates + (size_t)b * 2048;
    float ig = gr[j], fg = gr[512 + j], gg = gr[1024 + j], og = gr[1536 + j];
    float c = sigf(fg) * c0[idx] + sigf(ig) * tanhf(gg);
    g_c[idx] = c;
    g_h[idx] = sigf(og) * tanhf(c);
}

// ---------------- head activations (k, beta, gate, s, gamma, e, a) ----------------
__global__ void head_act_kernel() {
    int b = blockIdx.x;
    int lane = threadIdx.x;   // 32 threads
    for (int hd = 0; hd < 7; ++hd) {
        const float* p = g_pall + (size_t)b * 560 + hd * 70;
        float ssq = 0.f;
        for (int j = lane; j < 64; j += 32) {
            float kv = tanhf(p[j]);
            g_k[((size_t)hd * B_ + b) * 64 + j] = kv;
            ssq += kv * kv;
        }
#pragma unroll
        for (int o = 16; o; o >>= 1) ssq += __shfl_xor_sync(0xffffffffu, ssq, o);
        if (lane == 0) {
            int hb = hd * B_ + b;
            g_knorm[hb] = sqrtf(ssq);
            g_beta[hb] = softplusf(p[64]);
            g_gate[hb] = sigf(p[65]);
            float s0 = p[66], s1 = p[67], s2 = p[68];
            float mx = fmaxf(s0, fmaxf(s1, s2));
            float e0 = expf(s0 - mx), e1 = expf(s1 - mx), e2 = expf(s2 - mx);
            float inv = 1.f / (e0 + e1 + e2);
            g_s[hb * 3 + 0] = e0 * inv; g_s[hb * 3 + 1] = e1 * inv; g_s[hb * 3 + 2] = e2 * inv;
            g_gamma[hb] = 1.f + softplusf(p[69]);
        }
    }
    for (int wh = 0; wh < 3; ++wh) {
        const float* ea = g_eaall + (size_t)b * 512 + wh * 128;
        for (int j = lane; j < 64; j += 32) {
            g_e[((size_t)wh * B_ + b) * 64 + j] = sigf(ea[j]);
            g_a[((size_t)wh * B_ + b) * 64 + j] = tanhf(ea[64 + j]);
        }
    }
}

// ---------------- big memory pass (4 lanes/row, f32x2 math) ----------------
// Block: (chunk of 256 rows, b). 256 threads = 8 warps; warp handles 8 rows/iter,
// lane owns 16 columns of one row (cols j*16 + c*4 + {0..3}, j=0..3).
template<int NDOT, bool READS, bool UPDATE, bool NORMS>
__global__ __launch_bounds__(256, 2)
void pass_kernel(const float* __restrict__ memExt, int inSel,
                 int k0Idx, int k1Idx, int eaIdx, int rSlot) {
    __shared__ __align__(16) float sk0[64], sk1[64], se[64], sa[64];
    __shared__ float sred[8][64];
    int b = blockIdx.y, chunk = blockIdx.x;
    int tid = threadIdx.x;
    if (tid < 64) {
        if (NDOT >= 1) sk0[tid] = g_k[((size_t)k0Idx * B_ + b) * 64 + tid];
        if (NDOT >= 2) sk1[tid] = g_k[((size_t)k1Idx * B_ + b) * 64 + tid];
        if (UPDATE) {
            se[tid] = g_e[((size_t)eaIdx * B_ + b) * 64 + tid];
            sa[tid] = g_a[((size_t)eaIdx * B_ + b) * 64 + tid];
        }
    }
    __syncthreads();

    int lane = tid & 31, warp = tid >> 5;
    int c = lane & 3;          // column group 0..3
    int rg = lane >> 2;        // row-in-group 0..7

    px2 k0r[8], k1r[8], ner[8], ar[8], acc[8];
#pragma unroll
    for (int j = 0; j < 4; ++j)
#pragma unroll
        for (int p = 0; p < 2; ++p) {
            int col = j * 16 + c * 4 + p * 2;
            int i = j * 2 + p;
            if (NDOT >= 1) k0r[i] = pk(sk0[col], sk0[col + 1]);
            if (NDOT >= 2) k1r[i] = pk(sk1[col], sk1[col + 1]);
            if (UPDATE) { ner[i] = pk(-se[col], -se[col + 1]); ar[i] = pk(sa[col], sa[col + 1]); }
            if (READS)  acc[i] = pk(0.f, 0.f);
        }

    const float* mi = inSel ? g_mem : memExt;
    const float* wR = g_w;
    const float* wW = g_w + (size_t)B_ * N_;
    size_t rowBase = (size_t)b * N_ + (size_t)chunk * 256;

#pragma unroll
    for (int it = 0; it < 4; ++it) {
        size_t n = rowBase + it * 64 + warp * 8 + rg;
        const float* pr = mi + n * 64 + c * 4;
        float4 v0 = *(const float4*)(pr);
        float4 v1 = *(const float4*)(pr + 16);
        float4 v2 = *(const float4*)(pr + 32);
        float4 v3 = *(const float4*)(pr + 48);
        float wrv = 0.f, wwv = 0.f;
        if (READS)  wrv = wR[n];
        if (UPDATE) wwv = wW[n];

        px2 vv[8];
        vv[0] = pk(v0.x, v0.y); vv[1] = pk(v0.z, v0.w);
        vv[2] = pk(v1.x, v1.y); vv[3] = pk(v1.z, v1.w);
        vv[4] = pk(v2.x, v2.y); vv[5] = pk(v2.z, v2.w);
        vv[6] = pk(v3.x, v3.y); vv[7] = pk(v3.z, v3.w);

        if (READS) {               // reads use PRE-update memory
            px2 wr2 = pk(wrv, wrv);
#pragma unroll
            for (int i = 0; i < 8; ++i) acc[i] = fma2(wr2, vv[i], acc[i]);
        }
        if (UPDATE) {              // update, then dots/norms on POST-update memory
            px2 ww2 = pk(wwv, wwv);
#pragma unroll
            for (int i = 0; i < 8; ++i) {
                px2 t = fma2(ner[i], vv[i], ar[i]);
                vv[i] = fma2(ww2, t, vv[i]);
            }
            float* po = g_mem + n * 64 + c * 4;
            float2 f0 = up(vv[0]), f1 = up(vv[1]);
            *(float4*)(po)      = make_float4(f0.x, f0.y, f1.x, f1.y);
            float2 f2 = up(vv[2]), f3 = up(vv[3]);
            *(float4*)(po + 16) = make_float4(f2.x, f2.y, f3.x, f3.y);
            float2 f4 = up(vv[4]), f5 = up(vv[5]);
            *(float4*)(po + 32) = make_float4(f4.x, f4.y, f5.x, f5.y);
            float2 f6 = up(vv[6]), f7 = up(vv[7]);
            *(float4*)(po + 48) = make_float4(f6.x, f6.y, f7.x, f7.y);
        }
        if (NDOT >= 1 || NORMS) {
            px2 d0 = pk(0.f, 0.f), d1 = pk(0.f, 0.f), nr = pk(0.f, 0.f);
#pragma unroll
            for (int i = 0; i < 8; ++i) {
                if (NDOT >= 1) d0 = fma2(vv[i], k0r[i], d0);
                if (NDOT >= 2) d1 = fma2(vv[i], k1r[i], d1);
                if (NORMS)     nr = fma2(vv[i], vv[i], nr);
            }
            float s0 = 0.f, s1 = 0.f, sn = 0.f;
            if (NDOT >= 1) {
                float2 f = up(d0); s0 = f.x + f.y;
                s0 += __shfl_xor_sync(0xffffffffu, s0, 1);
                s0 += __shfl_xor_sync(0xffffffffu, s0, 2);
            }
            if (NDOT >= 2) {
                float2 f = up(d1); s1 = f.x + f.y;
                s1 += __shfl_xor_sync(0xffffffffu, s1, 1);
                s1 += __shfl_xor_sync(0xffffffffu, s1, 2);
            }
            if (NORMS) {
                float2 f = up(nr); sn = f.x + f.y;
                sn += __shfl_xor_sync(0xffffffffu, sn, 1);
                sn += __shfl_xor_sync(0xffffffffu, sn, 2);
            }
            if (c == 0) {
                if (NDOT >= 1) g_dot0[n] = s0;
                if (NDOT >= 2) g_dot1[n] = s1;
                if (NORMS)     g_nrm[n]  = sn;
            }
        }
    }

    if (READS) {
        float vals[16];
#pragma unroll
        for (int i = 0; i < 8; ++i) { float2 f = up(acc[i]); vals[2 * i] = f.x; vals[2 * i + 1] = f.y; }
#pragma unroll
        for (int o = 4; o <= 16; o <<= 1)
#pragma unroll
            for (int t = 0; t < 16; ++t) vals[t] += __shfl_xor_sync(0xffffffffu, vals[t], o);
        if (rg == 0) {
#pragma unroll
            for (int idx = 0; idx < 16; ++idx) {
                int j = idx >> 2, rem = idx & 3;
                sred[warp][j * 16 + c * 4 + rem] = vals[idx];
            }
        }
        __syncthreads();
        if (tid < 64) {
            float s = 0.f;
#pragma unroll
            for (int wv = 0; wv < 8; ++wv) s += sred[wv][tid];
            g_rpart[(size_t)rSlot * B_ * 16 * 64 + ((size_t)b * 16 + chunk) * 64 + tid] = s;
        }
    }
}

// ---------------- finalize: dot/norm -> addressing weight w (one block per (b, head)) --------
__device__ __forceinline__ float block_reduce_max(float v, float* sbuf) {
#pragma unroll
    for (int o = 16; o; o >>= 1) v = fmaxf(v, __shfl_xor_sync(0xffffffffu, v, o));
    int lane = threadIdx.x & 31, w = threadIdx.x >> 5;
    if (lane == 0) sbuf[w] = v;
    __syncthreads();
    if (threadIdx.x < 32) {
        float vv = (threadIdx.x < 8) ? sbuf[threadIdx.x] : -3.4e38f;
#pragma unroll
        for (int o = 4; o; o >>= 1) vv = fmaxf(vv, __shfl_xor_sync(0xffffffffu, vv, o));
        if (threadIdx.x == 0) sbuf[0] = vv;
    }
    __syncthreads();
    v = sbuf[0];
    __syncthreads();
    return v;
}
__device__ __forceinline__ float block_reduce_sum(float v, float* sbuf) {
#pragma unroll
    for (int o = 16; o; o >>= 1) v += __shfl_xor_sync(0xffffffffu, v, o);
    int lane = threadIdx.x & 31, w = threadIdx.x >> 5;
    if (lane == 0) sbuf[w] = v;
    __syncthreads();
    if (threadIdx.x < 32) {
        float vv = (threadIdx.x < 8) ? sbuf[threadIdx.x] : 0.f;
#pragma unroll
        for (int o = 4; o; o >>= 1) vv += __shfl_xor_sync(0xffffffffu, vv, o);
        if (threadIdx.x == 0) sbuf[0] = vv;
    }
    __syncthreads();
    v = sbuf[0];
    __syncthreads();
    return v;
}

__global__ void fin_kernel(int head0, const float* __restrict__ prevW) {
    __shared__ float swg[N_];
    __shared__ float sbuf[8];
    int b = blockIdx.x;
    int hh = blockIdx.y;
    int hd = head0 + hh;
    int tid = threadIdx.x;   // 256
    const float* dot = hh ? g_dot1 : g_dot0;
    int hb = hd * B_ + b;
    float knorm = g_knorm[hb], beta = g_beta[hb], gate = g_gate[hb], gamma = g_gamma[hb];
    float s0 = g_s[hb * 3 + 0], s1 = g_s[hb * 3 + 1], s2 = g_s[hb * 3 + 2];
    const float* pw = prevW + ((size_t)hd * B_ + b) * N_;
    const size_t base = (size_t)b * N_;

    float sc[16];
    float lmax = -3.4e38f;
#pragma unroll
    for (int t = 0; t < 16; ++t) {
        int idx = tid + t * 256;
        float d = dot[base + idx];
        float nr = g_nrm[base + idx];
        float v = beta * d / (sqrtf(nr) * knorm + EPSV);
        sc[t] = v;
        lmax = fmaxf(lmax, v);
    }
    float bmax = block_reduce_max(lmax, sbuf);
    float lsum = 0.f;
#pragma unroll
    for (int t = 0; t < 16; ++t) { float e = __expf(sc[t] - bmax); sc[t] = e; lsum += e; }
    float bsum = block_reduce_sum(lsum, sbuf);
    float inv = 1.f / bsum;
#pragma unroll
    for (int t = 0; t < 16; ++t) {
        int idx = tid + t * 256;
        swg[idx] = gate * sc[t] * inv + (1.f - gate) * pw[idx];
    }
    __syncthreads();
    float wp[16];
    float lps = 0.f;
#pragma unroll
    for (int t = 0; t < 16; ++t) {
        int idx = tid + t * 256;
        float ws = s0 * swg[(idx + N_ - 1) & (N_ - 1)] + s1 * swg[idx]
                 + s2 * swg[(idx + 1) & (N_ - 1)];
        float p = __powf(ws, gamma);
        wp[t] = p; lps += p;
    }
    float psum = block_reduce_sum(lps, sbuf);
    float invp = 1.f / (psum + EPSV);
    float* wout = g_w + (size_t)(hd & 1) * B_ * N_;
#pragma unroll
    for (int t = 0; t < 16; ++t) {
        int idx = tid + t * 256;
        wout[base + idx] = wp[t] * invp;
    }
}

// ---------------- build state = [h | reads0 | reads2 | reads4 | reads6] ----------------
__global__ void build_state_kernel() {
    int b = blockIdx.x;
    for (int j = threadIdx.x; j < 768; j += blockDim.x) {
        float v;
        if (j < 512) v = g_h[(size_t)b * C_ + j];
        else {
            int ri = (j - 512) >> 6, m = (j - 512) & 63;
            float s = 0.f;
            const float* rp = g_rpart + (size_t)ri * B_ * 16 * 64 + (size_t)b * 16 * 64 + m;
#pragma unroll
            for (int c = 0; c < 16; ++c) s += rp[c * 64];
            v = s;
        }
        g_state[(size_t)b * 768 + j] = v;
    }
}

// ---------------- host ----------------
extern "C" void kernel_launch(void* const* d_in, const int* in_sizes, int n_in,
                              void* d_out, int out_size) {
    const float* in_data      = (const float*)d_in[0];
    const float* memory       = (const float*)d_in[1];
    const float* h0           = (const float*)d_in[2];
    const float* c0           = (const float*)d_in[3];
    const float* prev_weights = (const float*)d_in[4];
    const float* prev_reads   = (const float*)d_in[5];
    const float* W_ih         = (const float*)d_in[6];
    const float* b_ih         = (const float*)d_in[7];
    const float* W_hh         = (const float*)d_in[8];
    const float* b_hh         = (const float*)d_in[9];
    const float* W_out        = (const float*)d_in[10];
    const float* b_out        = (const float*)d_in[11];
    const float* W_addr       = (const float*)d_in[12];
    const float* b_addr       = (const float*)d_in[13];
    const float* W_ea         = (const float*)d_in[14];
    const float* b_ea         = (const float*)d_in[15];
    float* outp = (float*)d_out;

    float *p_x, *p_gates, *p_c, *p_pall, *p_ea, *p_state;
    cudaGetSymbolAddress((void**)&p_x,     g_x);
    cudaGetSymbolAddress((void**)&p_gates, g_gates);
    cudaGetSymbolAddress((void**)&p_c,     g_c);
    cudaGetSymbolAddress((void**)&p_pall,  g_pall);
    cudaGetSymbolAddress((void**)&p_ea,    g_eaall);
    cudaGetSymbolAddress((void**)&p_state, g_state);

    // controller
    build_x_kernel<<<(B_ * 320 + 255) / 256, 256>>>(in_data, prev_reads);
    sgemm_kernel<false, false><<<dim3(2048 / 64, B_ / 64), 256>>>(p_x, W_ih, b_ih, p_gates, 2048, 320);
    sgemm_kernel<true,  false><<<dim3(2048 / 64, B_ / 64), 256>>>(h0,  W_hh, b_hh, p_gates, 2048, 512);
    lstm_kernel<<<(B_ * C_ + 255) / 256, 256>>>(c0);

    // all head parameters up front (head 7 is dead code: its write is never observed)
    sgemm_kernel<false, false><<<dim3((560 + 63) / 64, B_ / 64), 256>>>(p_c, W_addr, b_addr, p_pall, 560, 512);
    sgemm_kernel<false, false><<<dim3(512 / 64, B_ / 64), 256>>>(p_c, W_ea, b_ea, p_ea, 512, 512);
    head_act_kernel<<<B_, 32>>>();

    dim3 pg(16, B_);
    // Pass A: dot0,dot1,norms on v0
    pass_kernel<2, false, false, true><<<pg, 256>>>(memory, 0, 0, 1, 0, 0);
    fin_kernel<<<dim3(B_, 2), 256>>>(0, prev_weights);
    // Pass B: reads0 + update(w1) -> v1, dot2,dot3,norms
    pass_kernel<2, true, true, true><<<pg, 256>>>(memory, 0, 2, 3, 0, 0);
    fin_kernel<<<dim3(B_, 2), 256>>>(2, prev_weights);
    // Pass C: reads2 + update(w3) -> v2, dot4,dot5,norms
    pass_kernel<2, true, true, true><<<pg, 256>>>(memory, 1, 4, 5, 1, 1);
    fin_kernel<<<dim3(B_, 2), 256>>>(4, prev_weights);
    // Pass D: reads4 + update(w5) -> v3, dot6,norms
    pass_kernel<1, true, true, true><<<pg, 256>>>(memory, 1, 6, 6, 2, 2);
    fin_kernel<<<dim3(B_, 1), 256>>>(6, prev_weights);
    // Pass E: reads6 on v3
    pass_kernel<0, true, false, false><<<pg, 256>>>(memory, 1, 0, 0, 0, 3);

    // output
    build_state_kernel<<<B_, 256>>>();
    sgemm_kernel<false, true><<<dim3(1, B_ / 64), 256>>>(p_state, W_out, b_out, outp, 64, 768);
}

// round 5
// speedup vs baseline: 1.3517x; 1.1155x over previous
#include <cuda_runtime.h>
#include <cstdint>

#define B_  256
#define N_  4096
#define M_  64
#define C_  512
#define EPSV 1e-8f

// ---------------- packed f32x2 helpers (sm_103a FFMA2) ----------------
struct px2 { unsigned long long u; };
__device__ __forceinline__ px2 pk(float x, float y) {
    px2 r; asm("mov.b64 %0,{%1,%2};" : "=l"(r.u) : "f"(x), "f"(y)); return r;
}
__device__ __forceinline__ float2 up(px2 a) {
    float2 f; asm("mov.b64 {%0,%1},%2;" : "=f"(f.x), "=f"(f.y) : "l"(a.u)); return f;
}
__device__ __forceinline__ px2 fma2(px2 a, px2 b, px2 c) {
    px2 r; asm("fma.rn.f32x2 %0,%1,%2,%3;" : "=l"(r.u) : "l"(a.u), "l"(b.u), "l"(c.u)); return r;
}

// ---------------- device scratch ----------------
__device__ __align__(16) float g_mem[(size_t)B_ * N_ * M_];      // v2 working memory (written once, pass C)
__device__ __align__(16) float g_x[B_ * 320];
__device__ __align__(16) float g_gates[B_ * 2048];
__device__ __align__(16) float g_c[B_ * C_];
__device__ __align__(16) float g_h[B_ * C_];
__device__ __align__(16) float g_pall[B_ * 560];
__device__ __align__(16) float g_eaall[B_ * 512];
__device__ __align__(16) float g_k[7 * B_ * M_];
__device__ float g_knorm[7 * B_];
__device__ float g_beta[7 * B_];
__device__ float g_gate[7 * B_];
__device__ float g_s[7 * B_ * 3];
__device__ float g_gamma[7 * B_];
__device__ __align__(16) float g_e[3 * B_ * M_];
__device__ __align__(16) float g_a[3 * B_ * M_];
__device__ __align__(16) float g_dot0[(size_t)B_ * N_];
__device__ __align__(16) float g_dot1[(size_t)B_ * N_];
__device__ __align__(16) float g_nrm[(size_t)B_ * N_];
__device__ __align__(16) float g_r1[(size_t)B_ * N_];
__device__ __align__(16) float g_r2[(size_t)B_ * N_];
__device__ __align__(16) float g_r3[(size_t)B_ * N_];
__device__ __align__(16) float g_r4[(size_t)B_ * N_];
__device__ __align__(16) float g_w[7 * (size_t)B_ * N_];         // per-head weights, slot = head index
__device__ __align__(16) float g_rpart[5 * B_ * 16 * M_];        // colsum partials: reads0,2,4, Sa, Sb
__device__ float g_ak[B_];    // a5 . k6
__device__ float g_aa[B_];    // |a5|^2
__device__ float g_T[B_];     // sum_n w6 w5
__device__ __align__(16) float g_state[B_ * 768];

// ---------------- helpers ----------------
__device__ __forceinline__ float sigf(float x) { return 1.f / (1.f + expf(-x)); }
__device__ __forceinline__ float softplusf(float x) { return x > 20.f ? x : log1pf(expf(x)); }

// ---------------- build x = [in_data | prev_reads 0..3] ----------------
__global__ void build_x_kernel(const float* __restrict__ in_data,
                               const float* __restrict__ prev_reads) {
    int idx = blockIdx.x * blockDim.x + threadIdx.x;
    if (idx >= B_ * 320) return;
    int b = idx / 320, j = idx % 320;
    float v;
    if (j < 64) v = in_data[b * 64 + j];
    else { int i = (j - 64) >> 6, m = (j - 64) & 63; v = prev_reads[((size_t)i * B_ + b) * 64 + m]; }
    g_x[idx] = v;
}

// ---------------- generic SGEMM: C[MM,NN] (+)= A[MM,K] * B[NN,K]^T + bias ----------------
template<bool ACC, bool SIG>
__global__ void sgemm_kernel(const float* __restrict__ A, const float* __restrict__ Bw,
                             const float* __restrict__ bias, float* __restrict__ C,
                             int NN, int K) {
    __shared__ __align__(16) float As[16][64];
    __shared__ __align__(16) float Bs[16][64];
    int tid = threadIdx.x;
    int m0 = blockIdx.y * 64, n0 = blockIdx.x * 64;
    int ty = tid >> 4, tx = tid & 15;
    int la_r = tid >> 2;
    int la_k = (tid & 3) << 2;
    float acc[4][4];
#pragma unroll
    for (int i = 0; i < 4; i++)
#pragma unroll
        for (int j = 0; j < 4; j++) acc[i][j] = 0.f;

    for (int k0 = 0; k0 < K; k0 += 16) {
        float4 av = *(const float4*)(A + (size_t)(m0 + la_r) * K + k0 + la_k);
        float4 bv = make_float4(0.f, 0.f, 0.f, 0.f);
        int br = n0 + la_r;
        if (br < NN) bv = *(const float4*)(Bw + (size_t)br * K + k0 + la_k);
        __syncthreads();
        As[la_k + 0][la_r] = av.x; As[la_k + 1][la_r] = av.y;
        As[la_k + 2][la_r] = av.z; As[la_k + 3][la_r] = av.w;
        Bs[la_k + 0][la_r] = bv.x; Bs[la_k + 1][la_r] = bv.y;
        Bs[la_k + 2][la_r] = bv.z; Bs[la_k + 3][la_r] = bv.w;
        __syncthreads();
#pragma unroll
        for (int kk = 0; kk < 16; kk++) {
            float4 a = *(const float4*)&As[kk][ty << 2];
            float4 b = *(const float4*)&Bs[kk][tx << 2];
            acc[0][0] += a.x * b.x; acc[0][1] += a.x * b.y; acc[0][2] += a.x * b.z; acc[0][3] += a.x * b.w;
            acc[1][0] += a.y * b.x; acc[1][1] += a.y * b.y; acc[1][2] += a.y * b.z; acc[1][3] += a.y * b.w;
            acc[2][0] += a.z * b.x; acc[2][1] += a.z * b.y; acc[2][2] += a.z * b.z; acc[2][3] += a.z * b.w;
            acc[3][0] += a.w * b.x; acc[3][1] += a.w * b.y; acc[3][2] += a.w * b.z; acc[3][3] += a.w * b.w;
        }
    }
#pragma unroll
    for (int i = 0; i < 4; i++) {
        int m = m0 + (ty << 2) + i;
#pragma unroll
        for (int j = 0; j < 4; j++) {
            int n = n0 + (tx << 2) + j;
            if (n < NN) {
                float v = acc[i][j];
                if (bias) v += bias[n];
                size_t ci = (size_t)m * NN + n;
                if (ACC) v += C[ci];
                if (SIG) v = sigf(v);
                C[ci] = v;
            }
        }
    }
}

// ---------------- LSTM pointwise ----------------
__global__ void lstm_kernel(const float* __restrict__ c0) {
    int idx = blockIdx.x * blockDim.x + threadIdx.x;
    if (idx >= B_ * C_) return;
    int b = idx / C_, j = idx % C_;
    const float* gr = g_gates + (size_t)b * 2048;
    float ig = gr[j], fg = gr[512 + j], gg = gr[1024 + j], og = gr[1536 + j];
    float c = sigf(fg) * c0[idx] + sigf(ig) * tanhf(gg);
    g_c[idx] = c;
    g_h[idx] = sigf(og) * tanhf(c);
}

// ---------------- head activations ----------------
__global__ void head_act_kernel() {
    int b = blockIdx.x;
    int lane = threadIdx.x;   // 32 threads
    for (int hd = 0; hd < 7; ++hd) {
        const float* p = g_pall + (size_t)b * 560 + hd * 70;
        float ssq = 0.f;
        for (int j = lane; j < 64; j += 32) {
            float kv = tanhf(p[j]);
            g_k[((size_t)hd * B_ + b) * 64 + j] = kv;
            ssq += kv * kv;
        }
#pragma unroll
        for (int o = 16; o; o >>= 1) ssq += __shfl_xor_sync(0xffffffffu, ssq, o);
        if (lane == 0) {
            int hb = hd * B_ + b;
            g_knorm[hb] = sqrtf(ssq);
            g_beta[hb] = softplusf(p[64]);
            g_gate[hb] = sigf(p[65]);
            float s0 = p[66], s1 = p[67], s2 = p[68];
            float mx = fmaxf(s0, fmaxf(s1, s2));
            float e0 = expf(s0 - mx), e1 = expf(s1 - mx), e2 = expf(s2 - mx);
            float inv = 1.f / (e0 + e1 + e2);
            g_s[hb * 3 + 0] = e0 * inv; g_s[hb * 3 + 1] = e1 * inv; g_s[hb * 3 + 2] = e2 * inv;
            g_gamma[hb] = 1.f + softplusf(p[69]);
        }
    }
    for (int wh = 0; wh < 3; ++wh) {
        const float* ea = g_eaall + (size_t)b * 512 + wh * 128;
        for (int j = lane; j < 64; j += 32) {
            g_e[((size_t)wh * B_ + b) * 64 + j] = sigf(ea[j]);
            g_a[((size_t)wh * B_ + b) * 64 + j] = tanhf(ea[64 + j]);
        }
    }
    // scalars a5.k6 and |a5|^2
    {
        const float* ea2 = g_eaall + (size_t)b * 512 + 2 * 128;
        const float* p6  = g_pall + (size_t)b * 560 + 6 * 70;
        float pak = 0.f, paa = 0.f;
        for (int j = lane; j < 64; j += 32) {
            float a5v = tanhf(ea2[64 + j]);
            float k6v = tanhf(p6[j]);
            pak += a5v * k6v; paa += a5v * a5v;
        }
#pragma unroll
        for (int o = 16; o; o >>= 1) {
            pak += __shfl_xor_sync(0xffffffffu, pak, o);
            paa += __shfl_xor_sync(0xffffffffu, paa, o);
        }
        if (lane == 0) { g_ak[b] = pak; g_aa[b] = paa; }
    }
}

// =================== big memory passes: 8 lanes/row, depth-2 prefetch ===================
#define PASS_PRE()                                                         \
    int b = blockIdx.y, chunk = blockIdx.x, tid = threadIdx.x;             \
    int lane = tid & 31, warp = tid >> 5, c = lane & 7, rg = lane >> 3;    \
    int col0 = c * 8;                                                      \
    size_t rowBase = (size_t)b * N_ + (size_t)chunk * 256;

__device__ __forceinline__ void reads_epilogue(px2* acc, float (*sred)[64],
                                               int lane, int warp, int c, int tid,
                                               int b, int chunk, int slot) {
    float va[8];
#pragma unroll
    for (int i = 0; i < 4; ++i) { float2 f = up(acc[i]); va[2 * i] = f.x; va[2 * i + 1] = f.y; }
#pragma unroll
    for (int t = 0; t < 8; ++t) {
        va[t] += __shfl_xor_sync(0xffffffffu, va[t], 8);
        va[t] += __shfl_xor_sync(0xffffffffu, va[t], 16);
    }
    if (lane < 8) {
#pragma unroll
        for (int t = 0; t < 8; ++t) sred[warp][c * 8 + t] = va[t];
    }
    __syncthreads();
    if (tid < 64) {
        float s = 0.f;
#pragma unroll
        for (int wv = 0; wv < 8; ++wv) s += sred[wv][tid];
        g_rpart[(size_t)slot * B_ * 16 * 64 + ((size_t)b * 16 + chunk) * 64 + tid] = s;
    }
    __syncthreads();
}

// ---- Pass A: dot0, dot1, nrm0 on mem0 ----
__global__ __launch_bounds__(256, 2) void passA_kernel(const float* __restrict__ mem0) {
    __shared__ float s_k0[64], s_k1[64];
    PASS_PRE();
    if (tid < 64) {
        s_k0[tid] = g_k[((size_t)0 * B_ + b) * 64 + tid];
        s_k1[tid] = g_k[((size_t)1 * B_ + b) * 64 + tid];
    }
    __syncthreads();
    px2 k0[4], k1[4];
#pragma unroll
    for (int i = 0; i < 4; ++i) {
        int col = col0 + 2 * i;
        k0[i] = pk(s_k0[col], s_k0[col + 1]);
        k1[i] = pk(s_k1[col], s_k1[col + 1]);
    }
    float4 bufA[3], bufB[3];
#define ISS_A(j) { size_t n = rowBase + (j) * 32 + warp * 4 + rg;                        \
        const float* p = mem0 + n * 64 + col0;                                           \
        bufA[(j) % 3] = *(const float4*)p; bufB[(j) % 3] = *(const float4*)(p + 4); }
    ISS_A(0); ISS_A(1);
#pragma unroll
    for (int it = 0; it < 8; ++it) {
        if (it + 2 < 8) ISS_A(it + 2);
        size_t n = rowBase + it * 32 + warp * 4 + rg;
        float4 A = bufA[it % 3], Bv = bufB[it % 3];
        px2 v[4] = { pk(A.x, A.y), pk(A.z, A.w), pk(Bv.x, Bv.y), pk(Bv.z, Bv.w) };
        px2 d0 = pk(0.f, 0.f), d1 = pk(0.f, 0.f), nr = pk(0.f, 0.f);
#pragma unroll
        for (int i = 0; i < 4; ++i) {
            d0 = fma2(v[i], k0[i], d0);
            d1 = fma2(v[i], k1[i], d1);
            nr = fma2(v[i], v[i], nr);
        }
        float2 f0 = up(d0), f1 = up(d1), fn = up(nr);
        float s0 = f0.x + f0.y, s1 = f1.x + f1.y, sn = fn.x + fn.y;
#pragma unroll
        for (int o = 1; o <= 4; o <<= 1) {
            s0 += __shfl_xor_sync(0xffffffffu, s0, o);
            s1 += __shfl_xor_sync(0xffffffffu, s1, o);
            sn += __shfl_xor_sync(0xffffffffu, sn, o);
        }
        if (c == 0) { g_dot0[n] = s0; g_dot1[n] = s1; g_nrm[n] = sn; }
    }
}

// ---- Pass B: reads0 (w0, mem0); m1 in regs; dot2, dot3, nrm1 ----
__global__ __launch_bounds__(256, 2) void passB_kernel(const float* __restrict__ mem0) {
    __shared__ float s_k2[64], s_k3[64], s_e1[64], s_a1[64];
    __shared__ float sred[8][64];
    PASS_PRE();
    if (tid < 64) {
        s_k2[tid] = g_k[((size_t)2 * B_ + b) * 64 + tid];
        s_k3[tid] = g_k[((size_t)3 * B_ + b) * 64 + tid];
        s_e1[tid] = g_e[((size_t)0 * B_ + b) * 64 + tid];
        s_a1[tid] = g_a[((size_t)0 * B_ + b) * 64 + tid];
    }
    __syncthreads();
    px2 k2[4], k3[4], ne1[4], a1[4], acc[4];
#pragma unroll
    for (int i = 0; i < 4; ++i) {
        int col = col0 + 2 * i;
        k2[i] = pk(s_k2[col], s_k2[col + 1]);
        k3[i] = pk(s_k3[col], s_k3[col + 1]);
        ne1[i] = pk(-s_e1[col], -s_e1[col + 1]);
        a1[i]  = pk(s_a1[col], s_a1[col + 1]);
        acc[i] = pk(0.f, 0.f);
    }
    const float* wp0 = g_w + (size_t)0 * B_ * N_;
    const float* wp1 = g_w + (size_t)1 * B_ * N_;
    float4 bufA[3], bufB[3]; float bw0[3], bw1[3];
#define ISS_B(j) { size_t n = rowBase + (j) * 32 + warp * 4 + rg;                        \
        const float* p = mem0 + n * 64 + col0;                                           \
        bufA[(j) % 3] = *(const float4*)p; bufB[(j) % 3] = *(const float4*)(p + 4);      \
        bw0[(j) % 3] = wp0[n]; bw1[(j) % 3] = wp1[n]; }
    ISS_B(0); ISS_B(1);
#pragma unroll
    for (int it = 0; it < 8; ++it) {
        if (it + 2 < 8) ISS_B(it + 2);
        size_t n = rowBase + it * 32 + warp * 4 + rg;
        float4 A = bufA[it % 3], Bv = bufB[it % 3];
        float w0 = bw0[it % 3], w1 = bw1[it % 3];
        px2 v[4] = { pk(A.x, A.y), pk(A.z, A.w), pk(Bv.x, Bv.y), pk(Bv.z, Bv.w) };
        px2 w0p = pk(w0, w0), w1p = pk(w1, w1);
        px2 d2 = pk(0.f, 0.f), d3 = pk(0.f, 0.f), nr = pk(0.f, 0.f);
#pragma unroll
        for (int i = 0; i < 4; ++i) {
            acc[i] = fma2(w0p, v[i], acc[i]);                // reads0 on mem0
            px2 t = fma2(ne1[i], v[i], a1[i]);
            px2 m1 = fma2(w1p, t, v[i]);                     // m1 = mem1 (not stored)
            d2 = fma2(m1, k2[i], d2);
            d3 = fma2(m1, k3[i], d3);
            nr = fma2(m1, m1, nr);
        }
        float2 f0 = up(d2), f1 = up(d3), fn = up(nr);
        float s0 = f0.x + f0.y, s1 = f1.x + f1.y, sn = fn.x + fn.y;
#pragma unroll
        for (int o = 1; o <= 4; o <<= 1) {
            s0 += __shfl_xor_sync(0xffffffffu, s0, o);
            s1 += __shfl_xor_sync(0xffffffffu, s1, o);
            sn += __shfl_xor_sync(0xffffffffu, sn, o);
        }
        if (c == 0) { g_dot0[n] = s0; g_dot1[n] = s1; g_nrm[n] = sn; }
    }
    reads_epilogue(acc, sred, lane, warp, c, tid, b, chunk, 0);
}

// ---- Pass C: recompute m1, reads2, update -> write v2, dot4, dot5, nrm2 ----
__global__ __launch_bounds__(256, 2) void passC_kernel(const float* __restrict__ mem0) {
    __shared__ float s_k4[64], s_k5[64], s_e1[64], s_a1[64], s_e3[64], s_a3[64];
    __shared__ float sred[8][64];
    PASS_PRE();
    if (tid < 64) {
        s_k4[tid] = g_k[((size_t)4 * B_ + b) * 64 + tid];
        s_k5[tid] = g_k[((size_t)5 * B_ + b) * 64 + tid];
        s_e1[tid] = g_e[((size_t)0 * B_ + b) * 64 + tid];
        s_a1[tid] = g_a[((size_t)0 * B_ + b) * 64 + tid];
        s_e3[tid] = g_e[((size_t)1 * B_ + b) * 64 + tid];
        s_a3[tid] = g_a[((size_t)1 * B_ + b) * 64 + tid];
    }
    __syncthreads();
    px2 k4[4], k5[4], ne1[4], a1[4], ne3[4], a3[4], acc[4];
#pragma unroll
    for (int i = 0; i < 4; ++i) {
        int col = col0 + 2 * i;
        k4[i] = pk(s_k4[col], s_k4[col + 1]);
        k5[i] = pk(s_k5[col], s_k5[col + 1]);
        ne1[i] = pk(-s_e1[col], -s_e1[col + 1]);
        a1[i]  = pk(s_a1[col], s_a1[col + 1]);
        ne3[i] = pk(-s_e3[col], -s_e3[col + 1]);
        a3[i]  = pk(s_a3[col], s_a3[col + 1]);
        acc[i] = pk(0.f, 0.f);
    }
    const float* wp1 = g_w + (size_t)1 * B_ * N_;
    const float* wp2 = g_w + (size_t)2 * B_ * N_;
    const float* wp3 = g_w + (size_t)3 * B_ * N_;
    float4 bufA[3], bufB[3]; float bw1[3], bw2[3], bw3[3];
#define ISS_C(j) { size_t n = rowBase + (j) * 32 + warp * 4 + rg;                        \
        const float* p = mem0 + n * 64 + col0;                                           \
        bufA[(j) % 3] = *(const float4*)p; bufB[(j) % 3] = *(const float4*)(p + 4);      \
        bw1[(j) % 3] = wp1[n]; bw2[(j) % 3] = wp2[n]; bw3[(j) % 3] = wp3[n]; }
    ISS_C(0); ISS_C(1);
#pragma unroll
    for (int it = 0; it < 8; ++it) {
        if (it + 2 < 8) ISS_C(it + 2);
        size_t n = rowBase + it * 32 + warp * 4 + rg;
        float4 A = bufA[it % 3], Bv = bufB[it % 3];
        float w1 = bw1[it % 3], w2 = bw2[it % 3], w3 = bw3[it % 3];
        px2 v[4] = { pk(A.x, A.y), pk(A.z, A.w), pk(Bv.x, Bv.y), pk(Bv.z, Bv.w) };
        px2 w1p = pk(w1, w1), w2p = pk(w2, w2), w3p = pk(w3, w3);
        px2 d4 = pk(0.f, 0.f), d5 = pk(0.f, 0.f), nr = pk(0.f, 0.f);
#pragma unroll
        for (int i = 0; i < 4; ++i) {
            px2 t = fma2(ne1[i], v[i], a1[i]);
            px2 m1 = fma2(w1p, t, v[i]);
            acc[i] = fma2(w2p, m1, acc[i]);                 // reads2 on m1
            px2 t3 = fma2(ne3[i], m1, a3[i]);
            px2 m2 = fma2(w3p, t3, m1);
            v[i] = m2;
            d4 = fma2(m2, k4[i], d4);
            d5 = fma2(m2, k5[i], d5);
            nr = fma2(m2, m2, nr);
        }
        float* po = g_mem + n * 64 + col0;
        float2 f0 = up(v[0]), f1 = up(v[1]);
        *(float4*)po = make_float4(f0.x, f0.y, f1.x, f1.y);
        float2 f2 = up(v[2]), f3 = up(v[3]);
        *(float4*)(po + 4) = make_float4(f2.x, f2.y, f3.x, f3.y);
        float2 fd4 = up(d4), fd5 = up(d5), fn = up(nr);
        float s0 = fd4.x + fd4.y, s1 = fd5.x + fd5.y, sn = fn.x + fn.y;
#pragma unroll
        for (int o = 1; o <= 4; o <<= 1) {
            s0 += __shfl_xor_sync(0xffffffffu, s0, o);
            s1 += __shfl_xor_sync(0xffffffffu, s1, o);
            sn += __shfl_xor_sync(0xffffffffu, sn, o);
        }
        if (c == 0) { g_dot0[n] = s0; g_dot1[n] = s1; g_nrm[n] = sn; }
    }
    reads_epilogue(acc, sred, lane, warp, c, tid, b, chunk, 1);
}

// ---- Pass D: reads4 + algebraic reductions for head 6 on v2 (NO memory write) ----
__global__ __launch_bounds__(256, 2) void passD_kernel() {
    __shared__ float s_k6[64], s_e5[64], s_a5[64];
    __shared__ float sred[8][64];
    PASS_PRE();
    if (tid < 64) {
        s_k6[tid] = g_k[((size_t)6 * B_ + b) * 64 + tid];
        s_e5[tid] = g_e[((size_t)2 * B_ + b) * 64 + tid];
        s_a5[tid] = g_a[((size_t)2 * B_ + b) * 64 + tid];
    }
    __syncthreads();
    px2 k6[4], ek[4], e5[4], es[4], a5[4], ea[4], acc[4];
#pragma unroll
    for (int i = 0; i < 4; ++i) {
        int col = col0 + 2 * i;
        float e0v = s_e5[col], e1v = s_e5[col + 1];
        float k0v = s_k6[col], k1v = s_k6[col + 1];
        float a0v = s_a5[col], a1v = s_a5[col + 1];
        k6[i] = pk(k0v, k1v);
        e5[i] = pk(e0v, e1v);
        ek[i] = pk(e0v * k0v, e1v * k1v);
        es[i] = pk(e0v * e0v, e1v * e1v);
        a5[i] = pk(a0v, a1v);
        ea[i] = pk(e0v * a0v, e1v * a1v);
        acc[i] = pk(0.f, 0.f);
    }
    const float* wp4 = g_w + (size_t)4 * B_ * N_;
    float4 bufA[3], bufB[3]; float bw4[3];
#define ISS_D(j) { size_t n = rowBase + (j) * 32 + warp * 4 + rg;                        \
        const float* p = g_mem + n * 64 + col0;                                          \
        bufA[(j) % 3] = *(const float4*)p; bufB[(j) % 3] = *(const float4*)(p + 4);      \
        bw4[(j) % 3] = wp4[n]; }
    ISS_D(0); ISS_D(1);
    px2 pz = pk(0.f, 0.f);
#pragma unroll
    for (int it = 0; it < 8; ++it) {
        if (it + 2 < 8) ISS_D(it + 2);
        size_t n = rowBase + it * 32 + warp * 4 + rg;
        float4 A = bufA[it % 3], Bv = bufB[it % 3];
        float w4 = bw4[it % 3];
        px2 v[4] = { pk(A.x, A.y), pk(A.z, A.w), pk(Bv.x, Bv.y), pk(Bv.z, Bv.w) };
        px2 w4p = pk(w4, w4);
        px2 d6a = pz, d6b = pz, q1 = pz, q2 = pz, p1 = pz, p2 = pz;
#pragma unroll
        for (int i = 0; i < 4; ++i) {
            acc[i] = fma2(w4p, v[i], acc[i]);               // reads4 on m2
            px2 vsq = fma2(v[i], v[i], pz);
            d6a = fma2(v[i], k6[i], d6a);
            d6b = fma2(v[i], ek[i], d6b);
            q1  = fma2(vsq, e5[i], q1);
            q2  = fma2(vsq, es[i], q2);
            p1  = fma2(v[i], a5[i], p1);
            p2  = fma2(v[i], ea[i], p2);
        }
        float2 f;
        f = up(d6a); float r0 = f.x + f.y;
        f = up(d6b); float r1v = f.x + f.y;
        f = up(q1);  float r2v = f.x + f.y;
        f = up(q2);  float r3v = f.x + f.y;
        f = up(p1);  float r4v = f.x + f.y;
        f = up(p2);  float r5v = f.x + f.y;
#pragma unroll
        for (int o = 1; o <= 4; o <<= 1) {
            r0  += __shfl_xor_sync(0xffffffffu, r0, o);
            r1v += __shfl_xor_sync(0xffffffffu, r1v, o);
            r2v += __shfl_xor_sync(0xffffffffu, r2v, o);
            r3v += __shfl_xor_sync(0xffffffffu, r3v, o);
            r4v += __shfl_xor_sync(0xffffffffu, r4v, o);
            r5v += __shfl_xor_sync(0xffffffffu, r5v, o);
        }
        if (c == 0) {
            g_dot0[n] = r0; g_dot1[n] = r1v;
            g_r1[n] = r2v; g_r2[n] = r3v; g_r3[n] = r4v; g_r4[n] = r5v;
        }
    }
    reads_epilogue(acc, sred, lane, warp, c, tid, b, chunk, 2);
}

// ---- Pass E: Sa = colsum(w6, v2), Sb = colsum(w6*w5, v2) ----
__global__ __launch_bounds__(256, 2) void passE_kernel() {
    __shared__ float sredA[8][64];
    __shared__ float sredB[8][64];
    PASS_PRE();
    px2 accA[4], accB[4];
#pragma unroll
    for (int i = 0; i < 4; ++i) { accA[i] = pk(0.f, 0.f); accB[i] = pk(0.f, 0.f); }
    const float* wp5 = g_w + (size_t)5 * B_ * N_;
    const float* wp6 = g_w + (size_t)6 * B_ * N_;
    float4 bufA[3], bufB[3]; float bw5[3], bw6[3];
#define ISS_E(j) { size_t n = rowBase + (j) * 32 + warp * 4 + rg;                        \
        const float* p = g_mem + n * 64 + col0;                                          \
        bufA[(j) % 3] = *(const float4*)p; bufB[(j) % 3] = *(const float4*)(p + 4);      \
        bw5[(j) % 3] = wp5[n]; bw6[(j) % 3] = wp6[n]; }
    ISS_E(0); ISS_E(1);
#pragma unroll
    for (int it = 0; it < 8; ++it) {
        if (it + 2 < 8) ISS_E(it + 2);
        float4 A = bufA[it % 3], Bv = bufB[it % 3];
        float w6 = bw6[it % 3], w65 = bw6[it % 3] * bw5[it % 3];
        px2 v[4] = { pk(A.x, A.y), pk(A.z, A.w), pk(Bv.x, Bv.y), pk(Bv.z, Bv.w) };
        px2 w6p = pk(w6, w6), w65p = pk(w65, w65);
#pragma unroll
        for (int i = 0; i < 4; ++i) {
            accA[i] = fma2(w6p, v[i], accA[i]);
            accB[i] = fma2(w65p, v[i], accB[i]);
        }
    }
    reads_epilogue(accA, sredA, lane, warp, c, tid, b, chunk, 3);
    reads_epilogue(accB, sredB, lane, warp, c, tid, b, chunk, 4);
}

// ---------------- finalize helpers ----------------
__device__ __forceinline__ float block_reduce_max(float v, float* sbuf) {
#pragma unroll
    for (int o = 16; o; o >>= 1) v = fmaxf(v, __shfl_xor_sync(0xffffffffu, v, o));
    int lane = threadIdx.x & 31, w = threadIdx.x >> 5;
    if (lane == 0) sbuf[w] = v;
    __syncthreads();
    if (threadIdx.x < 32) {
        float vv = (threadIdx.x < 8) ? sbuf[threadIdx.x] : -3.4e38f;
#pragma unroll
        for (int o = 4; o; o >>= 1) vv = fmaxf(vv, __shfl_xor_sync(0xffffffffu, vv, o));
        if (threadIdx.x == 0) sbuf[0] = vv;
    }
    __syncthreads();
    v = sbuf[0];
    __syncthreads();
    return v;
}
__device__ __forceinline__ float block_reduce_sum(float v, float* sbuf) {
#pragma unroll
    for (int o = 16; o; o >>= 1) v += __shfl_xor_sync(0xffffffffu, v, o);
    int lane = threadIdx.x & 31, w = threadIdx.x >> 5;
    if (lane == 0) sbuf[w] = v;
    __syncthreads();
    if (threadIdx.x < 32) {
        float vv = (threadIdx.x < 8) ? sbuf[threadIdx.x] : 0.f;
#pragma unroll
        for (int o = 4; o; o >>= 1) vv += __shfl_xor_sync(0xffffffffu, vv, o);
        if (threadIdx.x == 0) sbuf[0] = vv;
    }
    __syncthreads();
    v = sbuf[0];
    __syncthreads();
    return v;
}

// softmax/interp/shift/sharpen from per-element score sc[] -> w_hd
__device__ __forceinline__ void fin_core(float* sc, int hd, int b, float gate,
                                         float s0, float s1, float s2, float gamma,
                                         const float* pw, float* sbuf, float* swg) {
    int tid = threadIdx.x;
    float lmax = -3.4e38f;
#pragma unroll
    for (int t = 0; t < 16; ++t) lmax = fmaxf(lmax, sc[t]);
    float bmax = block_reduce_max(lmax, sbuf);
    float lsum = 0.f;
#pragma unroll
    for (int t = 0; t < 16; ++t) { float e = __expf(sc[t] - bmax); sc[t] = e; lsum += e; }
    float bsum = block_reduce_sum(lsum, sbuf);
    float inv = 1.f / bsum;
#pragma unroll
    for (int t = 0; t < 16; ++t) {
        int idx = tid + t * 256;
        swg[idx] = gate * sc[t] * inv + (1.f - gate) * pw[idx];
    }
    __syncthreads();
    float wp[16];
    float lps = 0.f;
#pragma unroll
    for (int t = 0; t < 16; ++t) {
        int idx = tid + t * 256;
        float ws = s0 * swg[(idx + N_ - 1) & (N_ - 1)] + s1 * swg[idx]
                 + s2 * swg[(idx + 1) & (N_ - 1)];
        float p = __powf(ws, gamma);
        wp[t] = p; lps += p;
    }
    float psum = block_reduce_sum(lps, sbuf);
    float invp = 1.f / (psum + EPSV);
    float* wout = g_w + (size_t)hd * B_ * N_ + (size_t)b * N_;
#pragma unroll
    for (int t = 0; t < 16; ++t) {
        int idx = tid + t * 256;
        wout[idx] = wp[t] * invp;
    }
}

__global__ void fin_kernel(int head0, const float* __restrict__ prevW) {
    __shared__ float swg[N_];
    __shared__ float sbuf[8];
    int b = blockIdx.x;
    int hh = blockIdx.y;
    int hd = head0 + hh;
    int tid = threadIdx.x;
    const float* dot = hh ? g_dot1 : g_dot0;
    int hb = hd * B_ + b;
    float knorm = g_knorm[hb], beta = g_beta[hb], gate = g_gate[hb], gamma = g_gamma[hb];
    float s0 = g_s[hb * 3 + 0], s1 = g_s[hb * 3 + 1], s2 = g_s[hb * 3 + 2];
    const float* pw = prevW + ((size_t)hd * B_ + b) * N_;
    const size_t base = (size_t)b * N_;
    float sc[16];
#pragma unroll
    for (int t = 0; t < 16; ++t) {
        int idx = tid + t * 256;
        float d = dot[base + idx];
        float nr = g_nrm[base + idx];
        sc[t] = beta * d / (sqrtf(nr) * knorm + EPSV);
    }
    fin_core(sc, hd, b, gate, s0, s1, s2, gamma, pw, sbuf, swg);
}

// fin for head 6: assemble dot6/nrm3 from pass-D reductions + w5; also T[b] = sum w6 w5
__global__ void fin6_kernel(const float* __restrict__ prevW) {
    __shared__ float swg[N_];
    __shared__ float sbuf[8];
    int b = blockIdx.x;
    int tid = threadIdx.x;
    const int hd = 6;
    int hb = hd * B_ + b;
    float knorm = g_knorm[hb], beta = g_beta[hb], gate = g_gate[hb], gamma = g_gamma[hb];
    float s0 = g_s[hb * 3 + 0], s1 = g_s[hb * 3 + 1], s2 = g_s[hb * 3 + 2];
    float ak = g_ak[b], aa = g_aa[b];
    const float* pw = prevW + ((size_t)hd * B_ + b) * N_;
    const float* wp5 = g_w + (size_t)5 * B_ * N_ + (size_t)b * N_;
    const size_t base = (size_t)b * N_;
    float sc[16];
#pragma unroll
    for (int t = 0; t < 16; ++t) {
        int idx = tid + t * 256;
        float w5 = wp5[idx];
        float d6 = g_dot0[base + idx] + w5 * (ak - g_dot1[base + idx]);
        float q0 = g_nrm[base + idx];
        float q1 = g_r1[base + idx], q2 = g_r2[base + idx];
        float p1 = g_r3[base + idx], p2 = g_r4[base + idx];
        float nrm3 = q0 + w5 * (-2.f * q1 + 2.f * p1) + w5 * w5 * (q2 - 2.f * p2 + aa);
        nrm3 = fmaxf(nrm3, 0.f);
        sc[t] = beta * d6 / (sqrtf(nrm3) * knorm + EPSV);
    }
    fin_core(sc, hd, b, gate, s0, s1, s2, gamma, pw, sbuf, swg);
    // T[b] = sum_n w6 w5
    const float* wout = g_w + (size_t)6 * B_ * N_ + base;
    float lt = 0.f;
#pragma unroll
    for (int t = 0; t < 16; ++t) {
        int idx = tid + t * 256;
        lt += wout[idx] * wp5[idx];
    }
    float T = block_reduce_sum(lt, sbuf);
    if (tid == 0) g_T[b] = T;
}

// ---------------- build state = [h | reads0 | reads2 | reads4 | reads6] ----------------
__global__ void build_state_kernel() {
    int b = blockIdx.x;
    for (int j = threadIdx.x; j < 768; j += blockDim.x) {
        float v;
        if (j < 512) v = g_h[(size_t)b * C_ + j];
        else {
            int ri = (j - 512) >> 6, m = (j - 512) & 63;
            if (ri < 3) {
                float s = 0.f;
                const float* rp = g_rpart + (size_t)ri * B_ * 16 * 64 + (size_t)b * 16 * 64 + m;
#pragma unroll
                for (int cc = 0; cc < 16; ++cc) s += rp[cc * 64];
                v = s;
            } else {
                float sa = 0.f, sb = 0.f;
                const float* rpa = g_rpart + (size_t)3 * B_ * 16 * 64 + (size_t)b * 16 * 64 + m;
                const float* rpb = g_rpart + (size_t)4 * B_ * 16 * 64 + (size_t)b * 16 * 64 + m;
#pragma unroll
                for (int cc = 0; cc < 16; ++cc) { sa += rpa[cc * 64]; sb += rpb[cc * 64]; }
                float e5 = g_e[((size_t)2 * B_ + b) * 64 + m];
                float a5 = g_a[((size_t)2 * B_ + b) * 64 + m];
                v = sa - e5 * sb + g_T[b] * a5;
            }
        }
        g_state[(size_t)b * 768 + j] = v;
    }
}

// ---------------- host ----------------
extern "C" void kernel_launch(void* const* d_in, const int* in_sizes, int n_in,
                              void* d_out, int out_size) {
    const float* in_data      = (const float*)d_in[0];
    const float* memory       = (const float*)d_in[1];
    const float* h0           = (const float*)d_in[2];
    const float* c0           = (const float*)d_in[3];
    const float* prev_weights = (const float*)d_in[4];
    const float* prev_reads   = (const float*)d_in[5];
    const float* W_ih         = (const float*)d_in[6];
    const float* b_ih         = (const float*)d_in[7];
    const float* W_hh         = (const float*)d_in[8];
    const float* b_hh         = (const float*)d_in[9];
    const float* W_out        = (const float*)d_in[10];
    const float* b_out        = (const float*)d_in[11];
    const float* W_addr       = (const float*)d_in[12];
    const float* b_addr       = (const float*)d_in[13];
    const float* W_ea         = (const float*)d_in[14];
    const float* b_ea         = (const float*)d_in[15];
    float* outp = (float*)d_out;

    float *p_x, *p_gates, *p_c, *p_pall, *p_ea, *p_state;
    cudaGetSymbolAddress((void**)&p_x,     g_x);
    cudaGetSymbolAddress((void**)&p_gates, g_gates);
    cudaGetSymbolAddress((void**)&p_c,     g_c);
    cudaGetSymbolAddress((void**)&p_pall,  g_pall);
    cudaGetSymbolAddress((void**)&p_ea,    g_eaall);
    cudaGetSymbolAddress((void**)&p_state, g_state);

    // controller
    build_x_kernel<<<(B_ * 320 + 255) / 256, 256>>>(in_data, prev_reads);
    sgemm_kernel<false, false><<<dim3(2048 / 64, B_ / 64), 256>>>(p_x, W_ih, b_ih, p_gates, 2048, 320);
    sgemm_kernel<true,  false><<<dim3(2048 / 64, B_ / 64), 256>>>(h0,  W_hh, b_hh, p_gates, 2048, 512);
    lstm_kernel<<<(B_ * C_ + 255) / 256, 256>>>(c0);

    // head parameters (head 7 is dead code)
    sgemm_kernel<false, false><<<dim3((560 + 63) / 64, B_ / 64), 256>>>(p_c, W_addr, b_addr, p_pall, 560, 512);
    sgemm_kernel<false, false><<<dim3(512 / 64, B_ / 64), 256>>>(p_c, W_ea, b_ea, p_ea, 512, 512);
    head_act_kernel<<<B_, 32>>>();

    dim3 pg(16, B_);
    passA_kernel<<<pg, 256>>>(memory);
    fin_kernel<<<dim3(B_, 2), 256>>>(0, prev_weights);
    passB_kernel<<<pg, 256>>>(memory);
    fin_kernel<<<dim3(B_, 2), 256>>>(2, prev_weights);
    passC_kernel<<<pg, 256>>>(memory);
    fin_kernel<<<dim3(B_, 2), 256>>>(4, prev_weights);
    passD_kernel<<<pg, 256>>>();
    fin6_kernel<<<B_, 256>>>(prev_weights);
    passE_kernel<<<pg, 256>>>();

    // output
    build_state_kernel<<<B_, 256>>>();
    sgemm_kernel<false, true><<<dim3(1, B_ / 64), 256>>>(p_state, W_out, b_out, outp, 64, 768);
}

// round 6
// speedup vs baseline: 1.3870x; 1.0261x over previous
#include <cuda_runtime.h>
#include <cstdint>

#define B_  256
#define N_  4096
#define M_  64
#define C_  512
#define EPSV 1e-8f
#define NPASSBLK 296
#define NPAIRS   4096

// ---------------- packed f32x2 helpers (sm_103a FFMA2) ----------------
struct px2 { unsigned long long u; };
__device__ __forceinline__ px2 pk(float x, float y) {
    px2 r; asm("mov.b64 %0,{%1,%2};" : "=l"(r.u) : "f"(x), "f"(y)); return r;
}
__device__ __forceinline__ float2 up(px2 a) {
    float2 f; asm("mov.b64 {%0,%1},%2;" : "=f"(f.x), "=f"(f.y) : "l"(a.u)); return f;
}
__device__ __forceinline__ px2 fma2(px2 a, px2 b, px2 c) {
    px2 r; asm("fma.rn.f32x2 %0,%1,%2,%3;" : "=l"(r.u) : "l"(a.u), "l"(b.u), "l"(c.u)); return r;
}

// ---------------- device scratch ----------------
__device__ __align__(16) float g_mem[(size_t)B_ * N_ * M_];      // v2 working memory (written once, pass C)
__device__ __align__(16) float g_x[B_ * 320];
__device__ __align__(16) float g_gates[B_ * 2048];
__device__ __align__(16) float g_c[B_ * C_];
__device__ __align__(16) float g_h[B_ * C_];
__device__ __align__(16) float g_pall[B_ * 560];
__device__ __align__(16) float g_eaall[B_ * 512];
__device__ __align__(16) float g_k[7 * B_ * M_];
__device__ float g_knorm[7 * B_];
__device__ float g_beta[7 * B_];
__device__ float g_gate[7 * B_];
__device__ float g_s[7 * B_ * 3];
__device__ float g_gamma[7 * B_];
__device__ __align__(16) float g_e[3 * B_ * M_];
__device__ __align__(16) float g_a[3 * B_ * M_];
__device__ __align__(16) float g_dot0[(size_t)B_ * N_];
__device__ __align__(16) float g_dot1[(size_t)B_ * N_];
__device__ __align__(16) float g_nrm[(size_t)B_ * N_];
__device__ __align__(16) float g_r1[(size_t)B_ * N_];
__device__ __align__(16) float g_r2[(size_t)B_ * N_];
__device__ __align__(16) float g_r3[(size_t)B_ * N_];
__device__ __align__(16) float g_r4[(size_t)B_ * N_];
__device__ __align__(16) float g_w[7 * (size_t)B_ * N_];         // per-head weights, slot = head index
__device__ __align__(16) float g_rpart[5 * B_ * 16 * M_];        // colsum partials: reads0,2,4, Sa, Sb
__device__ float g_ak[B_];    // a5 . k6
__device__ float g_aa[B_];    // |a5|^2
__device__ float g_T[B_];     // sum_n w6 w5
__device__ __align__(16) float g_state[B_ * 768];

// ---------------- helpers ----------------
__device__ __forceinline__ float sigf(float x) { return 1.f / (1.f + expf(-x)); }
__device__ __forceinline__ float softplusf(float x) { return x > 20.f ? x : log1pf(expf(x)); }

// ---------------- build x = [in_data | prev_reads 0..3] ----------------
__global__ void build_x_kernel(const float* __restrict__ in_data,
                               const float* __restrict__ prev_reads) {
    int idx = blockIdx.x * blockDim.x + threadIdx.x;
    if (idx >= B_ * 320) return;
    int b = idx / 320, j = idx % 320;
    float v;
    if (j < 64) v = in_data[b * 64 + j];
    else { int i = (j - 64) >> 6, m = (j - 64) & 63; v = prev_reads[((size_t)i * B_ + b) * 64 + m]; }
    g_x[idx] = v;
}

// ---------------- generic SGEMM ----------------
template<bool ACC, bool SIG>
__global__ void sgemm_kernel(const float* __restrict__ A, const float* __restrict__ Bw,
                             const float* __restrict__ bias, float* __restrict__ C,
                             int NN, int K) {
    __shared__ __align__(16) float As[16][64];
    __shared__ __align__(16) float Bs[16][64];
    int tid = threadIdx.x;
    int m0 = blockIdx.y * 64, n0 = blockIdx.x * 64;
    int ty = tid >> 4, tx = tid & 15;
    int la_r = tid >> 2;
    int la_k = (tid & 3) << 2;
    float acc[4][4];
#pragma unroll
    for (int i = 0; i < 4; i++)
#pragma unroll
        for (int j = 0; j < 4; j++) acc[i][j] = 0.f;

    for (int k0 = 0; k0 < K; k0 += 16) {
        float4 av = *(const float4*)(A + (size_t)(m0 + la_r) * K + k0 + la_k);
        float4 bv = make_float4(0.f, 0.f, 0.f, 0.f);
        int br = n0 + la_r;
        if (br < NN) bv = *(const float4*)(Bw + (size_t)br * K + k0 + la_k);
        __syncthreads();
        As[la_k + 0][la_r] = av.x; As[la_k + 1][la_r] = av.y;
        As[la_k + 2][la_r] = av.z; As[la_k + 3][la_r] = av.w;
        Bs[la_k + 0][la_r] = bv.x; Bs[la_k + 1][la_r] = bv.y;
        Bs[la_k + 2][la_r] = bv.z; Bs[la_k + 3][la_r] = bv.w;
        __syncthreads();
#pragma unroll
        for (int kk = 0; kk < 16; kk++) {
            float4 a = *(const float4*)&As[kk][ty << 2];
            float4 b = *(const float4*)&Bs[kk][tx << 2];
            acc[0][0] += a.x * b.x; acc[0][1] += a.x * b.y; acc[0][2] += a.x * b.z; acc[0][3] += a.x * b.w;
            acc[1][0] += a.y * b.x; acc[1][1] += a.y * b.y; acc[1][2] += a.y * b.z; acc[1][3] += a.y * b.w;
            acc[2][0] += a.z * b.x; acc[2][1] += a.z * b.y; acc[2][2] += a.z * b.z; acc[2][3] += a.z * b.w;
            acc[3][0] += a.w * b.x; acc[3][1] += a.w * b.y; acc[3][2] += a.w * b.z; acc[3][3] += a.w * b.w;
        }
    }
#pragma unroll
    for (int i = 0; i < 4; i++) {
        int m = m0 + (ty << 2) + i;
#pragma unroll
        for (int j = 0; j < 4; j++) {
            int n = n0 + (tx << 2) + j;
            if (n < NN) {
                float v = acc[i][j];
                if (bias) v += bias[n];
                size_t ci = (size_t)m * NN + n;
                if (ACC) v += C[ci];
                if (SIG) v = sigf(v);
                C[ci] = v;
            }
        }
    }
}

// ---------------- LSTM pointwise ----------------
__global__ void lstm_kernel(const float* __restrict__ c0) {
    int idx = blockIdx.x * blockDim.x + threadIdx.x;
    if (idx >= B_ * C_) return;
    int b = idx / C_, j = idx % C_;
    const float* gr = g_gates + (size_t)b * 2048;
    float ig = gr[j], fg = gr[512 + j], gg = gr[1024 + j], og = gr[1536 + j];
    float c = sigf(fg) * c0[idx] + sigf(ig) * tanhf(gg);
    g_c[idx] = c;
    g_h[idx] = sigf(og) * tanhf(c);
}

// ---------------- head activations ----------------
__global__ void head_act_kernel() {
    int b = blockIdx.x;
    int lane = threadIdx.x;   // 32 threads
    for (int hd = 0; hd < 7; ++hd) {
        const float* p = g_pall + (size_t)b * 560 + hd * 70;
        float ssq = 0.f;
        for (int j = lane; j < 64; j += 32) {
            float kv = tanhf(p[j]);
            g_k[((size_t)hd * B_ + b) * 64 + j] = kv;
            ssq += kv * kv;
        }
#pragma unroll
        for (int o = 16; o; o >>= 1) ssq += __shfl_xor_sync(0xffffffffu, ssq, o);
        if (lane == 0) {
            int hb = hd * B_ + b;
            g_knorm[hb] = sqrtf(ssq);
            g_beta[hb] = softplusf(p[64]);
            g_gate[hb] = sigf(p[65]);
            float s0 = p[66], s1 = p[67], s2 = p[68];
            float mx = fmaxf(s0, fmaxf(s1, s2));
            float e0 = expf(s0 - mx), e1 = expf(s1 - mx), e2 = expf(s2 - mx);
            float inv = 1.f / (e0 + e1 + e2);
            g_s[hb * 3 + 0] = e0 * inv; g_s[hb * 3 + 1] = e1 * inv; g_s[hb * 3 + 2] = e2 * inv;
            g_gamma[hb] = 1.f + softplusf(p[69]);
        }
    }
    for (int wh = 0; wh < 3; ++wh) {
        const float* ea = g_eaall + (size_t)b * 512 + wh * 128;
        for (int j = lane; j < 64; j += 32) {
            g_e[((size_t)wh * B_ + b) * 64 + j] = sigf(ea[j]);
            g_a[((size_t)wh * B_ + b) * 64 + j] = tanhf(ea[64 + j]);
        }
    }
    // scalars a5.k6 and |a5|^2
    {
        const float* ea2 = g_eaall + (size_t)b * 512 + 2 * 128;
        const float* p6  = g_pall + (size_t)b * 560 + 6 * 70;
        float pak = 0.f, paa = 0.f;
        for (int j = lane; j < 64; j += 32) {
            float a5v = tanhf(ea2[64 + j]);
            float k6v = tanhf(p6[j]);
            pak += a5v * k6v; paa += a5v * a5v;
        }
#pragma unroll
        for (int o = 16; o; o >>= 1) {
            pak += __shfl_xor_sync(0xffffffffu, pak, o);
            paa += __shfl_xor_sync(0xffffffffu, paa, o);
        }
        if (lane == 0) { g_ak[b] = pak; g_aa[b] = paa; }
    }
}

// =================== persistent grid-stride memory passes ===================
// Grid: NPASSBLK blocks × 256 threads. Each block owns a CONTIGUOUS range of
// pairs P (P = b*16 + chunk, rowBase = P*256) so loads stream linearly and the
// depth-2 prefetch pipeline crosses pair boundaries. Operands reloaded on b change.
// lane: c = lane&7 owns cols c*8..c*8+7; rg = lane>>3 row-in-group.

#define PASS_HEAD()                                                         \
    int tid = threadIdx.x, lane = tid & 31, warp = tid >> 5;                \
    int c = lane & 7, rg = lane >> 3, col0 = c * 8;                         \
    int p0 = (NPAIRS * blockIdx.x) / NPASSBLK;                              \
    int p1 = (NPAIRS * (blockIdx.x + 1)) / NPASSBLK;                        \
    int Lend = p1 * 8;

// load one 64-float operand row into 4 px2 regs (optionally negated)
#define LOADOP(dst, baseptr) {                                              \
    const float4* _q = (const float4*)((baseptr) + col0);                   \
    float4 _u0 = __ldg(_q), _u1 = __ldg(_q + 1);                            \
    dst[0] = pk(_u0.x, _u0.y); dst[1] = pk(_u0.z, _u0.w);                   \
    dst[2] = pk(_u1.x, _u1.y); dst[3] = pk(_u1.z, _u1.w); }
#define LOADOPN(dst, baseptr) {                                             \
    const float4* _q = (const float4*)((baseptr) + col0);                   \
    float4 _u0 = __ldg(_q), _u1 = __ldg(_q + 1);                            \
    dst[0] = pk(-_u0.x, -_u0.y); dst[1] = pk(-_u0.z, -_u0.w);               \
    dst[2] = pk(-_u1.x, -_u1.y); dst[3] = pk(-_u1.z, -_u1.w); }

__device__ __forceinline__ void reads_epilogue(px2* acc, float (*sred)[64],
                                               int lane, int warp, int c, int tid,
                                               int pair, int slot) {
    float va[8];
#pragma unroll
    for (int i = 0; i < 4; ++i) { float2 f = up(acc[i]); va[2 * i] = f.x; va[2 * i + 1] = f.y; }
#pragma unroll
    for (int t = 0; t < 8; ++t) {
        va[t] += __shfl_xor_sync(0xffffffffu, va[t], 8);
        va[t] += __shfl_xor_sync(0xffffffffu, va[t], 16);
    }
    if (lane < 8) {
#pragma unroll
        for (int t = 0; t < 8; ++t) sred[warp][c * 8 + t] = va[t];
    }
    __syncthreads();
    if (tid < 64) {
        float s = 0.f;
#pragma unroll
        for (int wv = 0; wv < 8; ++wv) s += sred[wv][tid];
        g_rpart[(size_t)slot * B_ * 16 * 64 + (size_t)pair * 64 + tid] = s;
    }
    __syncthreads();
}

// ---- Pass A: dot0, dot1, nrm0 on mem0 ----
__global__ __launch_bounds__(256, 2) void passA_kernel(const float* __restrict__ mem0) {
    PASS_HEAD();
    float4 bufA[4], bufB[4];
#define LD_A(L) { size_t n = (size_t)(L) * 32 + warp * 4 + rg;              \
        const float4* p = (const float4*)(mem0 + n * 64 + col0);            \
        bufA[(L) & 3] = __ldcs(p); bufB[(L) & 3] = __ldcs(p + 1); }
    LD_A(p0 * 8); LD_A(p0 * 8 + 1);
    px2 k0[4], k1[4];
    int bcur = -1;
    for (int p = p0; p < p1; ++p) {
        int b = p >> 4;
        if (b != bcur) {
            bcur = b;
            LOADOP(k0, g_k + ((size_t)0 * B_ + b) * 64);
            LOADOP(k1, g_k + ((size_t)1 * B_ + b) * 64);
        }
#pragma unroll
        for (int it = 0; it < 8; ++it) {
            int L = p * 8 + it;
            if (L + 2 < Lend) LD_A(L + 2);
            size_t n = (size_t)L * 32 + warp * 4 + rg;
            float4 A = bufA[it & 3], Bv = bufB[it & 3];
            px2 v[4] = { pk(A.x, A.y), pk(A.z, A.w), pk(Bv.x, Bv.y), pk(Bv.z, Bv.w) };
            px2 d0 = pk(0.f, 0.f), d1 = pk(0.f, 0.f), nr = pk(0.f, 0.f);
#pragma unroll
            for (int i = 0; i < 4; ++i) {
                d0 = fma2(v[i], k0[i], d0);
                d1 = fma2(v[i], k1[i], d1);
                nr = fma2(v[i], v[i], nr);
            }
            float2 f0 = up(d0), f1 = up(d1), fn = up(nr);
            float s0 = f0.x + f0.y, s1 = f1.x + f1.y, sn = fn.x + fn.y;
#pragma unroll
            for (int o = 1; o <= 4; o <<= 1) {
                s0 += __shfl_xor_sync(0xffffffffu, s0, o);
                s1 += __shfl_xor_sync(0xffffffffu, s1, o);
                sn += __shfl_xor_sync(0xffffffffu, sn, o);
            }
            if (c == 0) { g_dot0[n] = s0; g_dot1[n] = s1; g_nrm[n] = sn; }
        }
    }
}

// ---- Pass B: reads0 (w0, mem0); m1 in regs; dot2, dot3, nrm1 ----
__global__ __launch_bounds__(256, 2) void passB_kernel(const float* __restrict__ mem0) {
    __shared__ float sred[8][64];
    PASS_HEAD();
    const float* wp0 = g_w + (size_t)0 * B_ * N_;
    const float* wp1 = g_w + (size_t)1 * B_ * N_;
    float4 bufA[4], bufB[4]; float bw0[4], bw1[4];
#define LD_B(L) { size_t n = (size_t)(L) * 32 + warp * 4 + rg;              \
        const float4* p = (const float4*)(mem0 + n * 64 + col0);            \
        bufA[(L) & 3] = __ldcs(p); bufB[(L) & 3] = __ldcs(p + 1);           \
        bw0[(L) & 3] = __ldg(wp0 + n); bw1[(L) & 3] = __ldg(wp1 + n); }
    LD_B(p0 * 8); LD_B(p0 * 8 + 1);
    px2 k2[4], k3[4], ne1[4], a1[4];
    int bcur = -1;
    for (int p = p0; p < p1; ++p) {
        int b = p >> 4;
        if (b != bcur) {
            bcur = b;
            LOADOP(k2, g_k + ((size_t)2 * B_ + b) * 64);
            LOADOP(k3, g_k + ((size_t)3 * B_ + b) * 64);
            LOADOPN(ne1, g_e + ((size_t)0 * B_ + b) * 64);
            LOADOP(a1, g_a + ((size_t)0 * B_ + b) * 64);
        }
        px2 acc[4] = { pk(0.f,0.f), pk(0.f,0.f), pk(0.f,0.f), pk(0.f,0.f) };
#pragma unroll
        for (int it = 0; it < 8; ++it) {
            int L = p * 8 + it;
            if (L + 2 < Lend) LD_B(L + 2);
            size_t n = (size_t)L * 32 + warp * 4 + rg;
            float4 A = bufA[it & 3], Bv = bufB[it & 3];
            float w0 = bw0[it & 3], w1 = bw1[it & 3];
            px2 v[4] = { pk(A.x, A.y), pk(A.z, A.w), pk(Bv.x, Bv.y), pk(Bv.z, Bv.w) };
            px2 w0p = pk(w0, w0), w1p = pk(w1, w1);
            px2 d2 = pk(0.f, 0.f), d3 = pk(0.f, 0.f), nr = pk(0.f, 0.f);
#pragma unroll
            for (int i = 0; i < 4; ++i) {
                acc[i] = fma2(w0p, v[i], acc[i]);                // reads0 on mem0
                px2 t = fma2(ne1[i], v[i], a1[i]);
                px2 m1 = fma2(w1p, t, v[i]);                     // m1 (not stored)
                d2 = fma2(m1, k2[i], d2);
                d3 = fma2(m1, k3[i], d3);
                nr = fma2(m1, m1, nr);
            }
            float2 f0 = up(d2), f1 = up(d3), fn = up(nr);
            float s0 = f0.x + f0.y, s1 = f1.x + f1.y, sn = fn.x + fn.y;
#pragma unroll
            for (int o = 1; o <= 4; o <<= 1) {
                s0 += __shfl_xor_sync(0xffffffffu, s0, o);
                s1 += __shfl_xor_sync(0xffffffffu, s1, o);
                sn += __shfl_xor_sync(0xffffffffu, sn, o);
            }
            if (c == 0) { g_dot0[n] = s0; g_dot1[n] = s1; g_nrm[n] = sn; }
        }
        reads_epilogue(acc, sred, lane, warp, c, tid, p, 0);
    }
}

// ---- Pass C: recompute m1, reads2, update -> write v2, dot4, dot5, nrm2 ----
__global__ __launch_bounds__(256, 2) void passC_kernel(const float* __restrict__ mem0) {
    __shared__ float sred[8][64];
    PASS_HEAD();
    const float* wp1 = g_w + (size_t)1 * B_ * N_;
    const float* wp2 = g_w + (size_t)2 * B_ * N_;
    const float* wp3 = g_w + (size_t)3 * B_ * N_;
    float4 bufA[4], bufB[4]; float bw1[4], bw2[4], bw3[4];
#define LD_C(L) { size_t n = (size_t)(L) * 32 + warp * 4 + rg;              \
        const float4* p = (const float4*)(mem0 + n * 64 + col0);            \
        bufA[(L) & 3] = __ldcs(p); bufB[(L) & 3] = __ldcs(p + 1);           \
        bw1[(L) & 3] = __ldg(wp1 + n); bw2[(L) & 3] = __ldg(wp2 + n);       \
        bw3[(L) & 3] = __ldg(wp3 + n); }
    LD_C(p0 * 8); LD_C(p0 * 8 + 1);
    px2 k4[4], k5[4], ne1[4], a1[4], ne3[4], a3[4];
    int bcur = -1;
    for (int p = p0; p < p1; ++p) {
        int b = p >> 4;
        if (b != bcur) {
            bcur = b;
            LOADOP(k4, g_k + ((size_t)4 * B_ + b) * 64);
            LOADOP(k5, g_k + ((size_t)5 * B_ + b) * 64);
            LOADOPN(ne1, g_e + ((size_t)0 * B_ + b) * 64);
            LOADOP(a1, g_a + ((size_t)0 * B_ + b) * 64);
            LOADOPN(ne3, g_e + ((size_t)1 * B_ + b) * 64);
            LOADOP(a3, g_a + ((size_t)1 * B_ + b) * 64);
        }
        px2 acc[4] = { pk(0.f,0.f), pk(0.f,0.f), pk(0.f,0.f), pk(0.f,0.f) };
#pragma unroll
        for (int it = 0; it < 8; ++it) {
            int L = p * 8 + it;
            if (L + 2 < Lend) LD_C(L + 2);
            size_t n = (size_t)L * 32 + warp * 4 + rg;
            float4 A = bufA[it & 3], Bv = bufB[it & 3];
            float w1 = bw1[it & 3], w2 = bw2[it & 3], w3 = bw3[it & 3];
            px2 v[4] = { pk(A.x, A.y), pk(A.z, A.w), pk(Bv.x, Bv.y), pk(Bv.z, Bv.w) };
            px2 w1p = pk(w1, w1), w2p = pk(w2, w2), w3p = pk(w3, w3);
            px2 d4 = pk(0.f, 0.f), d5 = pk(0.f, 0.f), nr = pk(0.f, 0.f);
#pragma unroll
            for (int i = 0; i < 4; ++i) {
                px2 t = fma2(ne1[i], v[i], a1[i]);
                px2 m1 = fma2(w1p, t, v[i]);
                acc[i] = fma2(w2p, m1, acc[i]);                 // reads2 on m1
                px2 t3 = fma2(ne3[i], m1, a3[i]);
                px2 m2 = fma2(w3p, t3, m1);
                v[i] = m2;
                d4 = fma2(m2, k4[i], d4);
                d5 = fma2(m2, k5[i], d5);
                nr = fma2(m2, m2, nr);
            }
            float* po = g_mem + n * 64 + col0;
            float2 f0 = up(v[0]), f1 = up(v[1]);
            __stcs((float4*)po, make_float4(f0.x, f0.y, f1.x, f1.y));
            float2 f2 = up(v[2]), f3 = up(v[3]);
            __stcs((float4*)po + 1, make_float4(f2.x, f2.y, f3.x, f3.y));
            float2 fd4 = up(d4), fd5 = up(d5), fn = up(nr);
            float s0 = fd4.x + fd4.y, s1 = fd5.x + fd5.y, sn = fn.x + fn.y;
#pragma unroll
            for (int o = 1; o <= 4; o <<= 1) {
                s0 += __shfl_xor_sync(0xffffffffu, s0, o);
                s1 += __shfl_xor_sync(0xffffffffu, s1, o);
                sn += __shfl_xor_sync(0xffffffffu, sn, o);
            }
            if (c == 0) { g_dot0[n] = s0; g_dot1[n] = s1; g_nrm[n] = sn; }
        }
        reads_epilogue(acc, sred, lane, warp, c, tid, p, 1);
    }
}

// ---- Pass D: reads4 + algebraic reductions for head 6 on v2 (NO memory write) ----
__global__ __launch_bounds__(256, 2) void passD_kernel() {
    __shared__ float sred[8][64];
    PASS_HEAD();
    const float* wp4 = g_w + (size_t)4 * B_ * N_;
    float4 bufA[4], bufB[4]; float bw4[4];
#define LD_D(L) { size_t n = (size_t)(L) * 32 + warp * 4 + rg;              \
        const float4* p = (const float4*)(g_mem + n * 64 + col0);           \
        bufA[(L) & 3] = __ldcs(p); bufB[(L) & 3] = __ldcs(p + 1);           \
        bw4[(L) & 3] = __ldg(wp4 + n); }
    LD_D(p0 * 8); LD_D(p0 * 8 + 1);
    px2 k6[4], ek[4], e5[4], es[4], a5[4], ea[4];
    int bcur = -1;
    px2 pz = pk(0.f, 0.f);
    for (int p = p0; p < p1; ++p) {
        int b = p >> 4;
        if (b != bcur) {
            bcur = b;
            float kk[8], ee[8], av[8];
            const float4* qk = (const float4*)(g_k + ((size_t)6 * B_ + b) * 64 + col0);
            const float4* qe = (const float4*)(g_e + ((size_t)2 * B_ + b) * 64 + col0);
            const float4* qa = (const float4*)(g_a + ((size_t)2 * B_ + b) * 64 + col0);
            *(float4*)&kk[0] = __ldg(qk); *(float4*)&kk[4] = __ldg(qk + 1);
            *(float4*)&ee[0] = __ldg(qe); *(float4*)&ee[4] = __ldg(qe + 1);
            *(float4*)&av[0] = __ldg(qa); *(float4*)&av[4] = __ldg(qa + 1);
#pragma unroll
            for (int i = 0; i < 4; ++i) {
                float k0v = kk[2*i], k1v = kk[2*i+1];
                float e0v = ee[2*i], e1v = ee[2*i+1];
                float a0v = av[2*i], a1v = av[2*i+1];
                k6[i] = pk(k0v, k1v);
                e5[i] = pk(e0v, e1v);
                ek[i] = pk(e0v * k0v, e1v * k1v);
                es[i] = pk(e0v * e0v, e1v * e1v);
                a5[i] = pk(a0v, a1v);
                ea[i] = pk(e0v * a0v, e1v * a1v);
            }
        }
        px2 acc[4] = { pz, pz, pz, pz };
#pragma unroll
        for (int it = 0; it < 8; ++it) {
            int L = p * 8 + it;
            if (L + 2 < Lend) LD_D(L + 2);
            size_t n = (size_t)L * 32 + warp * 4 + rg;
            float4 A = bufA[it & 3], Bv = bufB[it & 3];
            float w4 = bw4[it & 3];
            px2 v[4] = { pk(A.x, A.y), pk(A.z, A.w), pk(Bv.x, Bv.y), pk(Bv.z, Bv.w) };
            px2 w4p = pk(w4, w4);
            px2 d6a = pz, d6b = pz, q1 = pz, q2 = pz, p1v = pz, p2v = pz;
#pragma unroll
            for (int i = 0; i < 4; ++i) {
                acc[i] = fma2(w4p, v[i], acc[i]);               // reads4 on m2
                px2 vsq = fma2(v[i], v[i], pz);
                d6a = fma2(v[i], k6[i], d6a);
                d6b = fma2(v[i], ek[i], d6b);
                q1  = fma2(vsq, e5[i], q1);
                q2  = fma2(vsq, es[i], q2);
                p1v = fma2(v[i], a5[i], p1v);
                p2v = fma2(v[i], ea[i], p2v);
            }
            float2 f;
            f = up(d6a); float r0 = f.x + f.y;
            f = up(d6b); float r1v = f.x + f.y;
            f = up(q1);  float r2v = f.x + f.y;
            f = up(q2);  float r3v = f.x + f.y;
            f = up(p1v); float r4v = f.x + f.y;
            f = up(p2v); float r5v = f.x + f.y;
#pragma unroll
            for (int o = 1; o <= 4; o <<= 1) {
                r0  += __shfl_xor_sync(0xffffffffu, r0, o);
                r1v += __shfl_xor_sync(0xffffffffu, r1v, o);
                r2v += __shfl_xor_sync(0xffffffffu, r2v, o);
                r3v += __shfl_xor_sync(0xffffffffu, r3v, o);
                r4v += __shfl_xor_sync(0xffffffffu, r4v, o);
                r5v += __shfl_xor_sync(0xffffffffu, r5v, o);
            }
            if (c == 0) {
                g_dot0[n] = r0; g_dot1[n] = r1v;
                g_r1[n] = r2v; g_r2[n] = r3v; g_r3[n] = r4v; g_r4[n] = r5v;
            }
        }
        reads_epilogue(acc, sred, lane, warp, c, tid, p, 2);
    }
}

// ---- Pass E: Sa = colsum(w6, v2), Sb = colsum(w6*w5, v2) ----
__global__ __launch_bounds__(256, 2) void passE_kernel() {
    __shared__ float sredA[8][64];
    __shared__ float sredB[8][64];
    PASS_HEAD();
    const float* wp5 = g_w + (size_t)5 * B_ * N_;
    const float* wp6 = g_w + (size_t)6 * B_ * N_;
    float4 bufA[4], bufB[4]; float bw5[4], bw6[4];
#define LD_E(L) { size_t n = (size_t)(L) * 32 + warp * 4 + rg;              \
        const float4* p = (const float4*)(g_mem + n * 64 + col0);           \
        bufA[(L) & 3] = __ldcs(p); bufB[(L) & 3] = __ldcs(p + 1);           \
        bw5[(L) & 3] = __ldg(wp5 + n); bw6[(L) & 3] = __ldg(wp6 + n); }
    LD_E(p0 * 8); LD_E(p0 * 8 + 1);
    for (int p = p0; p < p1; ++p) {
        px2 accA[4], accB[4];
#pragma unroll
        for (int i = 0; i < 4; ++i) { accA[i] = pk(0.f, 0.f); accB[i] = pk(0.f, 0.f); }
#pragma unroll
        for (int it = 0; it < 8; ++it) {
            int L = p * 8 + it;
            if (L + 2 < Lend) LD_E(L + 2);
            float4 A = bufA[it & 3], Bv = bufB[it & 3];
            float w6 = bw6[it & 3], w65 = bw6[it & 3] * bw5[it & 3];
            px2 v[4] = { pk(A.x, A.y), pk(A.z, A.w), pk(Bv.x, Bv.y), pk(Bv.z, Bv.w) };
            px2 w6p = pk(w6, w6), w65p = pk(w65, w65);
#pragma unroll
            for (int i = 0; i < 4; ++i) {
                accA[i] = fma2(w6p, v[i], accA[i]);
                accB[i] = fma2(w65p, v[i], accB[i]);
            }
        }
        reads_epilogue(accA, sredA, lane, warp, c, tid, p, 3);
        reads_epilogue(accB, sredB, lane, warp, c, tid, p, 4);
    }
}

// ---------------- finalize helpers ----------------
__device__ __forceinline__ float block_reduce_max(float v, float* sbuf) {
#pragma unroll
    for (int o = 16; o; o >>= 1) v = fmaxf(v, __shfl_xor_sync(0xffffffffu, v, o));
    int lane = threadIdx.x & 31, w = threadIdx.x >> 5;
    if (lane == 0) sbuf[w] = v;
    __syncthreads();
    if (threadIdx.x < 32) {
        float vv = (threadIdx.x < 8) ? sbuf[threadIdx.x] : -3.4e38f;
#pragma unroll
        for (int o = 4; o; o >>= 1) vv = fmaxf(vv, __shfl_xor_sync(0xffffffffu, vv, o));
        if (threadIdx.x == 0) sbuf[0] = vv;
    }
    __syncthreads();
    v = sbuf[0];
    __syncthreads();
    return v;
}
__device__ __forceinline__ float block_reduce_sum(float v, float* sbuf) {
#pragma unroll
    for (int o = 16; o; o >>= 1) v += __shfl_xor_sync(0xffffffffu, v, o);
    int lane = threadIdx.x & 31, w = threadIdx.x >> 5;
    if (lane == 0) sbuf[w] = v;
    __syncthreads();
    if (threadIdx.x < 32) {
        float vv = (threadIdx.x < 8) ? sbuf[threadIdx.x] : 0.f;
#pragma unroll
        for (int o = 4; o; o >>= 1) vv += __shfl_xor_sync(0xffffffffu, vv, o);
        if (threadIdx.x == 0) sbuf[0] = vv;
    }
    __syncthreads();
    v = sbuf[0];
    __syncthreads();
    return v;
}

// softmax/interp/shift/sharpen from per-element score sc[] -> w_hd
__device__ __forceinline__ void fin_core(float* sc, int hd, int b, float gate,
                                         float s0, float s1, float s2, float gamma,
                                         const float* pw, float* sbuf, float* swg) {
    int tid = threadIdx.x;
    float lmax = -3.4e38f;
#pragma unroll
    for (int t = 0; t < 16; ++t) lmax = fmaxf(lmax, sc[t]);
    float bmax = block_reduce_max(lmax, sbuf);
    float lsum = 0.f;
#pragma unroll
    for (int t = 0; t < 16; ++t) { float e = __expf(sc[t] - bmax); sc[t] = e; lsum += e; }
    float bsum = block_reduce_sum(lsum, sbuf);
    float inv = 1.f / bsum;
#pragma unroll
    for (int t = 0; t < 16; ++t) {
        int idx = tid + t * 256;
        swg[idx] = gate * sc[t] * inv + (1.f - gate) * pw[idx];
    }
    __syncthreads();
    float wp[16];
    float lps = 0.f;
#pragma unroll
    for (int t = 0; t < 16; ++t) {
        int idx = tid + t * 256;
        float ws = s0 * swg[(idx + N_ - 1) & (N_ - 1)] + s1 * swg[idx]
                 + s2 * swg[(idx + 1) & (N_ - 1)];
        float p = __powf(ws, gamma);
        wp[t] = p; lps += p;
    }
    float psum = block_reduce_sum(lps, sbuf);
    float invp = 1.f / (psum + EPSV);
    float* wout = g_w + (size_t)hd * B_ * N_ + (size_t)b * N_;
#pragma unroll
    for (int t = 0; t < 16; ++t) {
        int idx = tid + t * 256;
        wout[idx] = wp[t] * invp;
    }
}

__global__ void fin_kernel(int head0, const float* __restrict__ prevW) {
    __shared__ float swg[N_];
    __shared__ float sbuf[8];
    int b = blockIdx.x;
    int hh = blockIdx.y;
    int hd = head0 + hh;
    int tid = threadIdx.x;
    const float* dot = hh ? g_dot1 : g_dot0;
    int hb = hd * B_ + b;
    float knorm = g_knorm[hb], beta = g_beta[hb], gate = g_gate[hb], gamma = g_gamma[hb];
    float s0 = g_s[hb * 3 + 0], s1 = g_s[hb * 3 + 1], s2 = g_s[hb * 3 + 2];
    const float* pw = prevW + ((size_t)hd * B_ + b) * N_;
    const size_t base = (size_t)b * N_;
    float sc[16];
#pragma unroll
    for (int t = 0; t < 16; ++t) {
        int idx = tid + t * 256;
        float d = dot[base + idx];
        float nr = g_nrm[base + idx];
        sc[t] = beta * d / (sqrtf(nr) * knorm + EPSV);
    }
    fin_core(sc, hd, b, gate, s0, s1, s2, gamma, pw, sbuf, swg);
}

// fin for head 6: assemble dot6/nrm3 from pass-D reductions + w5; also T[b] = sum w6 w5
__global__ void fin6_kernel(const float* __restrict__ prevW) {
    __shared__ float swg[N_];
    __shared__ float sbuf[8];
    int b = blockIdx.x;
    int tid = threadIdx.x;
    const int hd = 6;
    int hb = hd * B_ + b;
    float knorm = g_knorm[hb], beta = g_beta[hb], gate = g_gate[hb], gamma = g_gamma[hb];
    float s0 = g_s[hb * 3 + 0], s1 = g_s[hb * 3 + 1], s2 = g_s[hb * 3 + 2];
    float ak = g_ak[b], aa = g_aa[b];
    const float* pw = prevW + ((size_t)hd * B_ + b) * N_;
    const float* wp5 = g_w + (size_t)5 * B_ * N_ + (size_t)b * N_;
    const size_t base = (size_t)b * N_;
    float sc[16];
#pragma unroll
    for (int t = 0; t < 16; ++t) {
        int idx = tid + t * 256;
        float w5 = wp5[idx];
        float d6 = g_dot0[base + idx] + w5 * (ak - g_dot1[base + idx]);
        float q0 = g_nrm[base + idx];
        float q1 = g_r1[base + idx], q2 = g_r2[base + idx];
        float p1 = g_r3[base + idx], p2 = g_r4[base + idx];
        float nrm3 = q0 + w5 * (-2.f * q1 + 2.f * p1) + w5 * w5 * (q2 - 2.f * p2 + aa);
        nrm3 = fmaxf(nrm3, 0.f);
        sc[t] = beta * d6 / (sqrtf(nrm3) * knorm + EPSV);
    }
    fin_core(sc, hd, b, gate, s0, s1, s2, gamma, pw, sbuf, swg);
    // T[b] = sum_n w6 w5
    const float* wout = g_w + (size_t)6 * B_ * N_ + base;
    float lt = 0.f;
#pragma unroll
    for (int t = 0; t < 16; ++t) {
        int idx = tid + t * 256;
        lt += wout[idx] * wp5[idx];
    }
    float T = block_reduce_sum(lt, sbuf);
    if (tid == 0) g_T[b] = T;
}

// ---------------- build state = [h | reads0 | reads2 | reads4 | reads6] ----------------
__global__ void build_state_kernel() {
    int b = blockIdx.x;
    for (int j = threadIdx.x; j < 768; j += blockDim.x) {
        float v;
        if (j < 512) v = g_h[(size_t)b * C_ + j];
        else {
            int ri = (j - 512) >> 6, m = (j - 512) & 63;
            if (ri < 3) {
                float s = 0.f;
                const float* rp = g_rpart + (size_t)ri * B_ * 16 * 64 + (size_t)b * 16 * 64 + m;
#pragma unroll
                for (int cc = 0; cc < 16; ++cc) s += rp[cc * 64];
                v = s;
            } else {
                float sa = 0.f, sb = 0.f;
                const float* rpa = g_rpart + (size_t)3 * B_ * 16 * 64 + (size_t)b * 16 * 64 + m;
                const float* rpb = g_rpart + (size_t)4 * B_ * 16 * 64 + (size_t)b * 16 * 64 + m;
#pragma unroll
                for (int cc = 0; cc < 16; ++cc) { sa += rpa[cc * 64]; sb += rpb[cc * 64]; }
                float e5 = g_e[((size_t)2 * B_ + b) * 64 + m];
                float a5 = g_a[((size_t)2 * B_ + b) * 64 + m];
                v = sa - e5 * sb + g_T[b] * a5;
            }
        }
        g_state[(size_t)b * 768 + j] = v;
    }
}

// ---------------- host ----------------
extern "C" void kernel_launch(void* const* d_in, const int* in_sizes, int n_in,
                              void* d_out, int out_size) {
    const float* in_data      = (const float*)d_in[0];
    const float* memory       = (const float*)d_in[1];
    const float* h0           = (const float*)d_in[2];
    const float* c0           = (const float*)d_in[3];
    const float* prev_weights = (const float*)d_in[4];
    const float* prev_reads   = (const float*)d_in[5];
    const float* W_ih         = (const float*)d_in[6];
    const float* b_ih         = (const float*)d_in[7];
    const float* W_hh         = (const float*)d_in[8];
    const float* b_hh         = (const float*)d_in[9];
    const float* W_out        = (const float*)d_in[10];
    const float* b_out        = (const float*)d_in[11];
    const float* W_addr       = (const float*)d_in[12];
    const float* b_addr       = (const float*)d_in[13];
    const float* W_ea         = (const float*)d_in[14];
    const float* b_ea         = (const float*)d_in[15];
    float* outp = (float*)d_out;

    float *p_x, *p_gates, *p_c, *p_pall, *p_ea, *p_state;
    cudaGetSymbolAddress((void**)&p_x,     g_x);
    cudaGetSymbolAddress((void**)&p_gates, g_gates);
    cudaGetSymbolAddress((void**)&p_c,     g_c);
    cudaGetSymbolAddress((void**)&p_pall,  g_pall);
    cudaGetSymbolAddress((void**)&p_ea,    g_eaall);
    cudaGetSymbolAddress((void**)&p_state, g_state);

    // controller
    build_x_kernel<<<(B_ * 320 + 255) / 256, 256>>>(in_data, prev_reads);
    sgemm_kernel<false, false><<<dim3(2048 / 64, B_ / 64), 256>>>(p_x, W_ih, b_ih, p_gates, 2048, 320);
    sgemm_kernel<true,  false><<<dim3(2048 / 64, B_ / 64), 256>>>(h0,  W_hh, b_hh, p_gates, 2048, 512);
    lstm_kernel<<<(B_ * C_ + 255) / 256, 256>>>(c0);

    // head parameters (head 7 is dead code)
    sgemm_kernel<false, false><<<dim3((560 + 63) / 64, B_ / 64), 256>>>(p_c, W_addr, b_addr, p_pall, 560, 512);
    sgemm_kernel<false, false><<<dim3(512 / 64, B_ / 64), 256>>>(p_c, W_ea, b_ea, p_ea, 512, 512);
    head_act_kernel<<<B_, 32>>>();

    passA_kernel<<<NPASSBLK, 256>>>(memory);
    fin_kernel<<<dim3(B_, 2), 256>>>(0, prev_weights);
    passB_kernel<<<NPASSBLK, 256>>>(memory);
    fin_kernel<<<dim3(B_, 2), 256>>>(2, prev_weights);
    passC_kernel<<<NPASSBLK, 256>>>(memory);
    fin_kernel<<<dim3(B_, 2), 256>>>(4, prev_weights);
    passD_kernel<<<NPASSBLK, 256>>>();
    fin6_kernel<<<B_, 256>>>(prev_weights);
    passE_kernel<<<NPASSBLK, 256>>>();

    // output
    build_state_kernel<<<B_, 256>>>();
    sgemm_kernel<false, true><<<dim3(1, B_ / 64), 256>>>(p_state, W_out, b_out, outp, 64, 768);
}

// round 7
// speedup vs baseline: 1.4336x; 1.0336x over previous
#include <cuda_runtime.h>
#include <cstdint>

#define B_  256
#define N_  4096
#define M_  64
#define C_  512
#define EPSV 1e-8f
#define NPASSBLK 296
#define NPAIRS   4096

// ---------------- packed f32x2 helpers (sm_103a FFMA2) ----------------
struct px2 { unsigned long long u; };
__device__ __forceinline__ px2 pk(float x, float y) {
    px2 r; asm("mov.b64 %0,{%1,%2};" : "=l"(r.u) : "f"(x), "f"(y)); return r;
}
__device__ __forceinline__ float2 up(px2 a) {
    float2 f; asm("mov.b64 {%0,%1},%2;" : "=f"(f.x), "=f"(f.y) : "l"(a.u)); return f;
}
__device__ __forceinline__ px2 fma2(px2 a, px2 b, px2 c) {
    px2 r; asm("fma.rn.f32x2 %0,%1,%2,%3;" : "=l"(r.u) : "l"(a.u), "l"(b.u), "l"(c.u)); return r;
}

// ---------------- device scratch ----------------
__device__ __align__(16) float g_mem[(size_t)B_ * N_ * M_];      // v2 working memory (written once, pass C)
__device__ __align__(16) float g_x[B_ * 320];
__device__ __align__(16) float g_gates[B_ * 2048];
__device__ __align__(16) float g_c[B_ * C_];
__device__ __align__(16) float g_h[B_ * C_];
__device__ __align__(16) float g_pall[B_ * 560];
__device__ __align__(16) float g_eaall[B_ * 512];
__device__ __align__(16) float g_k[7 * B_ * M_];
__device__ float g_knorm[7 * B_];
__device__ float g_beta[7 * B_];
__device__ float g_gate[7 * B_];
__device__ float g_s[7 * B_ * 3];
__device__ float g_gamma[7 * B_];
__device__ __align__(16) float g_e[3 * B_ * M_];
__device__ __align__(16) float g_a[3 * B_ * M_];
__device__ __align__(16) float g_dot0[(size_t)B_ * N_];
__device__ __align__(16) float g_dot1[(size_t)B_ * N_];
__device__ __align__(16) float g_nrm[(size_t)B_ * N_];
__device__ __align__(16) float g_r1[(size_t)B_ * N_];
__device__ __align__(16) float g_r2[(size_t)B_ * N_];
__device__ __align__(16) float g_r3[(size_t)B_ * N_];
__device__ __align__(16) float g_r4[(size_t)B_ * N_];
__device__ __align__(16) float g_r5[(size_t)B_ * N_];
__device__ __align__(16) float g_r6[(size_t)B_ * N_];
__device__ __align__(16) float g_r7[(size_t)B_ * N_];
__device__ __align__(16) float g_r8[(size_t)B_ * N_];
__device__ __align__(16) float g_w[7 * (size_t)B_ * N_];         // per-head weights, slot = head index
__device__ __align__(16) float g_rpart[5 * B_ * 16 * M_];        // colsum partials: reads0,2,4, Sa, Sb
__device__ float g_ak[B_];    // a5 . k6
__device__ float g_aa[B_];    // |a5|^2
__device__ float g_A2[B_];    // a1 . k2
__device__ float g_A3[B_];    // a1 . k3
__device__ float g_Aaa[B_];   // |a1|^2
__device__ float g_T[B_];     // sum_n w6 w5
__device__ __align__(16) float g_state[B_ * 768];

// ---------------- helpers ----------------
__device__ __forceinline__ float sigf(float x) { return 1.f / (1.f + expf(-x)); }
__device__ __forceinline__ float softplusf(float x) { return x > 20.f ? x : log1pf(expf(x)); }

// ---------------- build x = [in_data | prev_reads 0..3] ----------------
__global__ void build_x_kernel(const float* __restrict__ in_data,
                               const float* __restrict__ prev_reads) {
    int idx = blockIdx.x * blockDim.x + threadIdx.x;
    if (idx >= B_ * 320) return;
    int b = idx / 320, j = idx % 320;
    float v;
    if (j < 64) v = in_data[b * 64 + j];
    else { int i = (j - 64) >> 6, m = (j - 64) & 63; v = prev_reads[((size_t)i * B_ + b) * 64 + m]; }
    g_x[idx] = v;
}

// ---------------- fused gates GEMM: gates = x Wih^T + h0 Whh^T + bih + bhh ----------------
__global__ void gates_gemm_kernel(const float* __restrict__ h0,
                                  const float* __restrict__ Wih, const float* __restrict__ bih,
                                  const float* __restrict__ Whh, const float* __restrict__ bhh) {
    __shared__ __align__(16) float As[16][64];
    __shared__ __align__(16) float Bs[16][64];
    int tid = threadIdx.x;
    int m0 = blockIdx.y * 64, n0 = blockIdx.x * 64;
    int ty = tid >> 4, tx = tid & 15;
    int la_r = tid >> 2;
    int la_k = (tid & 3) << 2;
    float acc[4][4];
#pragma unroll
    for (int i = 0; i < 4; i++)
#pragma unroll
        for (int j = 0; j < 4; j++) acc[i][j] = 0.f;

    for (int pass = 0; pass < 2; ++pass) {
        const float* A = pass ? h0 : g_x;
        const float* Bw = pass ? Whh : Wih;
        int K = pass ? 512 : 320;
        for (int k0 = 0; k0 < K; k0 += 16) {
            float4 av = *(const float4*)(A + (size_t)(m0 + la_r) * K + k0 + la_k);
            float4 bv = *(const float4*)(Bw + (size_t)(n0 + la_r) * K + k0 + la_k);
            __syncthreads();
            As[la_k + 0][la_r] = av.x; As[la_k + 1][la_r] = av.y;
            As[la_k + 2][la_r] = av.z; As[la_k + 3][la_r] = av.w;
            Bs[la_k + 0][la_r] = bv.x; Bs[la_k + 1][la_r] = bv.y;
            Bs[la_k + 2][la_r] = bv.z; Bs[la_k + 3][la_r] = bv.w;
            __syncthreads();
#pragma unroll
            for (int kk = 0; kk < 16; kk++) {
                float4 a = *(const float4*)&As[kk][ty << 2];
                float4 b = *(const float4*)&Bs[kk][tx << 2];
                acc[0][0] += a.x * b.x; acc[0][1] += a.x * b.y; acc[0][2] += a.x * b.z; acc[0][3] += a.x * b.w;
                acc[1][0] += a.y * b.x; acc[1][1] += a.y * b.y; acc[1][2] += a.y * b.z; acc[1][3] += a.y * b.w;
                acc[2][0] += a.z * b.x; acc[2][1] += a.z * b.y; acc[2][2] += a.z * b.z; acc[2][3] += a.z * b.w;
                acc[3][0] += a.w * b.x; acc[3][1] += a.w * b.y; acc[3][2] += a.w * b.z; acc[3][3] += a.w * b.w;
            }
        }
    }
#pragma unroll
    for (int i = 0; i < 4; i++) {
        int m = m0 + (ty << 2) + i;
#pragma unroll
        for (int j = 0; j < 4; j++) {
            int n = n0 + (tx << 2) + j;
            g_gates[(size_t)m * 2048 + n] = acc[i][j] + bih[n] + bhh[n];
        }
    }
}

// ---------------- generic SGEMM ----------------
template<bool SIG>
__global__ void sgemm_kernel(const float* __restrict__ A, const float* __restrict__ Bw,
                             const float* __restrict__ bias, float* __restrict__ C,
                             int NN, int K) {
    __shared__ __align__(16) float As[16][64];
    __shared__ __align__(16) float Bs[16][64];
    int tid = threadIdx.x;
    int m0 = blockIdx.y * 64, n0 = blockIdx.x * 64;
    int ty = tid >> 4, tx = tid & 15;
    int la_r = tid >> 2;
    int la_k = (tid & 3) << 2;
    float acc[4][4];
#pragma unroll
    for (int i = 0; i < 4; i++)
#pragma unroll
        for (int j = 0; j < 4; j++) acc[i][j] = 0.f;

    for (int k0 = 0; k0 < K; k0 += 16) {
        float4 av = *(const float4*)(A + (size_t)(m0 + la_r) * K + k0 + la_k);
        float4 bv = make_float4(0.f, 0.f, 0.f, 0.f);
        int br = n0 + la_r;
        if (br < NN) bv = *(const float4*)(Bw + (size_t)br * K + k0 + la_k);
        __syncthreads();
        As[la_k + 0][la_r] = av.x; As[la_k + 1][la_r] = av.y;
        As[la_k + 2][la_r] = av.z; As[la_k + 3][la_r] = av.w;
        Bs[la_k + 0][la_r] = bv.x; Bs[la_k + 1][la_r] = bv.y;
        Bs[la_k + 2][la_r] = bv.z; Bs[la_k + 3][la_r] = bv.w;
        __syncthreads();
#pragma unroll
        for (int kk = 0; kk < 16; kk++) {
            float4 a = *(const float4*)&As[kk][ty << 2];
            float4 b = *(const float4*)&Bs[kk][tx << 2];
            acc[0][0] += a.x * b.x; acc[0][1] += a.x * b.y; acc[0][2] += a.x * b.z; acc[0][3] += a.x * b.w;
            acc[1][0] += a.y * b.x; acc[1][1] += a.y * b.y; acc[1][2] += a.y * b.z; acc[1][3] += a.y * b.w;
            acc[2][0] += a.z * b.x; acc[2][1] += a.z * b.y; acc[2][2] += a.z * b.z; acc[2][3] += a.z * b.w;
            acc[3][0] += a.w * b.x; acc[3][1] += a.w * b.y; acc[3][2] += a.w * b.z; acc[3][3] += a.w * b.w;
        }
    }
#pragma unroll
    for (int i = 0; i < 4; i++) {
        int m = m0 + (ty << 2) + i;
#pragma unroll
        for (int j = 0; j < 4; j++) {
            int n = n0 + (tx << 2) + j;
            if (n < NN) {
                float v = acc[i][j] + bias[n];
                if (SIG) v = sigf(v);
                C[(size_t)m * NN + n] = v;
            }
        }
    }
}

// ---------------- LSTM pointwise ----------------
__global__ void lstm_kernel(const float* __restrict__ c0) {
    int idx = blockIdx.x * blockDim.x + threadIdx.x;
    if (idx >= B_ * C_) return;
    int b = idx / C_, j = idx % C_;
    const float* gr = g_gates + (size_t)b * 2048;
    float ig = gr[j], fg = gr[512 + j], gg = gr[1024 + j], og = gr[1536 + j];
    float c = sigf(fg) * c0[idx] + sigf(ig) * tanhf(gg);
    g_c[idx] = c;
    g_h[idx] = sigf(og) * tanhf(c);
}

// ---------------- head activations ----------------
__global__ void head_act_kernel() {
    int b = blockIdx.x;
    int lane = threadIdx.x;   // 32 threads
    for (int hd = 0; hd < 7; ++hd) {
        const float* p = g_pall + (size_t)b * 560 + hd * 70;
        float ssq = 0.f;
        for (int j = lane; j < 64; j += 32) {
            float kv = tanhf(p[j]);
            g_k[((size_t)hd * B_ + b) * 64 + j] = kv;
            ssq += kv * kv;
        }
#pragma unroll
        for (int o = 16; o; o >>= 1) ssq += __shfl_xor_sync(0xffffffffu, ssq, o);
        if (lane == 0) {
            int hb = hd * B_ + b;
            g_knorm[hb] = sqrtf(ssq);
            g_beta[hb] = softplusf(p[64]);
            g_gate[hb] = sigf(p[65]);
            float s0 = p[66], s1 = p[67], s2 = p[68];
            float mx = fmaxf(s0, fmaxf(s1, s2));
            float e0 = expf(s0 - mx), e1 = expf(s1 - mx), e2 = expf(s2 - mx);
            float inv = 1.f / (e0 + e1 + e2);
            g_s[hb * 3 + 0] = e0 * inv; g_s[hb * 3 + 1] = e1 * inv; g_s[hb * 3 + 2] = e2 * inv;
            g_gamma[hb] = 1.f + softplusf(p[69]);
        }
    }
    for (int wh = 0; wh < 3; ++wh) {
        const float* ea = g_eaall + (size_t)b * 512 + wh * 128;
        for (int j = lane; j < 64; j += 32) {
            g_e[((size_t)wh * B_ + b) * 64 + j] = sigf(ea[j]);
            g_a[((size_t)wh * B_ + b) * 64 + j] = tanhf(ea[64 + j]);
        }
    }
    // scalars: a5.k6, |a5|^2, a1.k2, a1.k3, |a1|^2
    {
        const float* ea2 = g_eaall + (size_t)b * 512 + 2 * 128;
        const float* ea0 = g_eaall + (size_t)b * 512 + 0 * 128;
        const float* p6  = g_pall + (size_t)b * 560 + 6 * 70;
        const float* p2  = g_pall + (size_t)b * 560 + 2 * 70;
        const float* p3  = g_pall + (size_t)b * 560 + 3 * 70;
        float pak = 0.f, paa = 0.f, pa2 = 0.f, pa3 = 0.f, p11 = 0.f;
        for (int j = lane; j < 64; j += 32) {
            float a5v = tanhf(ea2[64 + j]);
            float k6v = tanhf(p6[j]);
            float a1v = tanhf(ea0[64 + j]);
            float k2v = tanhf(p2[j]);
            float k3v = tanhf(p3[j]);
            pak += a5v * k6v; paa += a5v * a5v;
            pa2 += a1v * k2v; pa3 += a1v * k3v; p11 += a1v * a1v;
        }
#pragma unroll
        for (int o = 16; o; o >>= 1) {
            pak += __shfl_xor_sync(0xffffffffu, pak, o);
            paa += __shfl_xor_sync(0xffffffffu, paa, o);
            pa2 += __shfl_xor_sync(0xffffffffu, pa2, o);
            pa3 += __shfl_xor_sync(0xffffffffu, pa3, o);
            p11 += __shfl_xor_sync(0xffffffffu, p11, o);
        }
        if (lane == 0) {
            g_ak[b] = pak; g_aa[b] = paa;
            g_A2[b] = pa2; g_A3[b] = pa3; g_Aaa[b] = p11;
        }
    }
}

// =================== persistent grid-stride memory passes ===================
#define PASS_HEAD()                                                         \
    int tid = threadIdx.x, lane = tid & 31, warp = tid >> 5;                \
    int c = lane & 7, rg = lane >> 3, col0 = c * 8;                         \
    int p0 = (NPAIRS * blockIdx.x) / NPASSBLK;                              \
    int p1 = (NPAIRS * (blockIdx.x + 1)) / NPASSBLK;                        \
    int Lend = p1 * 8;

#define LOADOP(dst, baseptr) {                                              \
    const float4* _q = (const float4*)((baseptr) + col0);                   \
    float4 _u0 = __ldg(_q), _u1 = __ldg(_q + 1);                            \
    dst[0] = pk(_u0.x, _u0.y); dst[1] = pk(_u0.z, _u0.w);                   \
    dst[2] = pk(_u1.x, _u1.y); dst[3] = pk(_u1.z, _u1.w); }
#define LOADOPN(dst, baseptr) {                                             \
    const float4* _q = (const float4*)((baseptr) + col0);                   \
    float4 _u0 = __ldg(_q), _u1 = __ldg(_q + 1);                            \
    dst[0] = pk(-_u0.x, -_u0.y); dst[1] = pk(-_u0.z, -_u0.w);               \
    dst[2] = pk(-_u1.x, -_u1.y); dst[3] = pk(-_u1.z, -_u1.w); }

__device__ __forceinline__ void reads_epilogue(px2* acc, float (*sred)[64],
                                               int lane, int warp, int c, int tid,
                                               int pair, int slot) {
    float va[8];
#pragma unroll
    for (int i = 0; i < 4; ++i) { float2 f = up(acc[i]); va[2 * i] = f.x; va[2 * i + 1] = f.y; }
#pragma unroll
    for (int t = 0; t < 8; ++t) {
        va[t] += __shfl_xor_sync(0xffffffffu, va[t], 8);
        va[t] += __shfl_xor_sync(0xffffffffu, va[t], 16);
    }
    if (lane < 8) {
#pragma unroll
        for (int t = 0; t < 8; ++t) sred[warp][c * 8 + t] = va[t];
    }
    __syncthreads();
    if (tid < 64) {
        float s = 0.f;
#pragma unroll
        for (int wv = 0; wv < 8; ++wv) s += sred[wv][tid];
        g_rpart[(size_t)slot * B_ * 16 * 64 + (size_t)pair * 64 + tid] = s;
    }
    __syncthreads();
}

// ---- Pass A: 11 reductions on mem0 (heads 0-3 material) ----
// dot0,dot1,nrm0 + u2a,u2b,u3a,u3b (dot2/3 assembly) + v1..v4 (nrm1 assembly)
__global__ __launch_bounds__(256, 2) void passA_kernel(const float* __restrict__ mem0) {
    PASS_HEAD();
    float4 bufA[4], bufB[4];
#define LD_A(L) { size_t n = (size_t)(L) * 32 + warp * 4 + rg;              \
        const float4* p = (const float4*)(mem0 + n * 64 + col0);            \
        bufA[(L) & 3] = __ldcs(p); bufB[(L) & 3] = __ldcs(p + 1); }
    LD_A(p0 * 8); LD_A(p0 * 8 + 1); LD_A(p0 * 8 + 2);
    px2 k0[4], k1[4], k2[4], k3[4], e1[4], a1[4];
    int bcur = -1;
    px2 pz = pk(0.f, 0.f);
    for (int p = p0; p < p1; ++p) {
        int b = p >> 4;
        if (b != bcur) {
            bcur = b;
            LOADOP(k0, g_k + ((size_t)0 * B_ + b) * 64);
            LOADOP(k1, g_k + ((size_t)1 * B_ + b) * 64);
            LOADOP(k2, g_k + ((size_t)2 * B_ + b) * 64);
            LOADOP(k3, g_k + ((size_t)3 * B_ + b) * 64);
            LOADOP(e1, g_e + ((size_t)0 * B_ + b) * 64);
            LOADOP(a1, g_a + ((size_t)0 * B_ + b) * 64);
        }
#pragma unroll
        for (int it = 0; it < 8; ++it) {
            int L = p * 8 + it;
            if (L + 3 < Lend) LD_A(L + 3);
            size_t n = (size_t)L * 32 + warp * 4 + rg;
            float4 A = bufA[it & 3], Bv = bufB[it & 3];
            px2 v[4] = { pk(A.x, A.y), pk(A.z, A.w), pk(Bv.x, Bv.y), pk(Bv.z, Bv.w) };
            px2 d0 = pz, d1 = pz, nr = pz, u2a = pz, u2b = pz, u3a = pz, u3b = pz;
            px2 v1a = pz, v2a = pz, v3a = pz, v4a = pz;
#pragma unroll
            for (int i = 0; i < 4; ++i) {
                px2 ve = fma2(v[i], e1[i], pz);
                d0  = fma2(v[i], k0[i], d0);
                d1  = fma2(v[i], k1[i], d1);
                nr  = fma2(v[i], v[i], nr);
                u2a = fma2(v[i], k2[i], u2a);
                u3a = fma2(v[i], k3[i], u3a);
                u2b = fma2(ve, k2[i], u2b);
                u3b = fma2(ve, k3[i], u3b);
                v1a = fma2(v[i], a1[i], v1a);
                v3a = fma2(ve, a1[i], v3a);
                v2a = fma2(ve, v[i], v2a);
                v4a = fma2(ve, ve, v4a);
            }
            float s[11]; float2 f;
            f = up(d0);  s[0] = f.x + f.y;
            f = up(d1);  s[1] = f.x + f.y;
            f = up(nr);  s[2] = f.x + f.y;
            f = up(u2a); s[3] = f.x + f.y;
            f = up(u2b); s[4] = f.x + f.y;
            f = up(u3a); s[5] = f.x + f.y;
            f = up(u3b); s[6] = f.x + f.y;
            f = up(v1a); s[7] = f.x + f.y;
            f = up(v2a); s[8] = f.x + f.y;
            f = up(v3a); s[9] = f.x + f.y;
            f = up(v4a); s[10] = f.x + f.y;
#pragma unroll
            for (int o = 1; o <= 4; o <<= 1)
#pragma unroll
                for (int t = 0; t < 11; ++t) s[t] += __shfl_xor_sync(0xffffffffu, s[t], o);
            if (c == 0) {
                g_dot0[n] = s[0]; g_dot1[n] = s[1]; g_nrm[n] = s[2];
                g_r1[n] = s[3]; g_r2[n] = s[4]; g_r3[n] = s[5]; g_r4[n] = s[6];
                g_r5[n] = s[7]; g_r6[n] = s[8]; g_r7[n] = s[9]; g_r8[n] = s[10];
            }
        }
    }
}

// ---- Pass C: reads0 (w0,m0), m1 regs, reads2 (w2,m1), update -> write v2, dot4, dot5, nrm2 ----
__global__ __launch_bounds__(256, 2) void passC_kernel(const float* __restrict__ mem0) {
    __shared__ float sred[8][64];
    PASS_HEAD();
    const float* wp0 = g_w + (size_t)0 * B_ * N_;
    const float* wp1 = g_w + (size_t)1 * B_ * N_;
    const float* wp2 = g_w + (size_t)2 * B_ * N_;
    const float* wp3 = g_w + (size_t)3 * B_ * N_;
    float4 bufA[4], bufB[4];
#define LD_C(L) { size_t n = (size_t)(L) * 32 + warp * 4 + rg;              \
        const float4* p = (const float4*)(mem0 + n * 64 + col0);            \
        bufA[(L) & 3] = __ldcs(p); bufB[(L) & 3] = __ldcs(p + 1); }
    LD_C(p0 * 8); LD_C(p0 * 8 + 1);
    px2 k4[4], k5[4], ne1[4], a1[4], ne3[4], a3[4];
    int bcur = -1;
    px2 pz = pk(0.f, 0.f);
    for (int p = p0; p < p1; ++p) {
        int b = p >> 4;
        if (b != bcur) {
            bcur = b;
            LOADOP(k4, g_k + ((size_t)4 * B_ + b) * 64);
            LOADOP(k5, g_k + ((size_t)5 * B_ + b) * 64);
            LOADOPN(ne1, g_e + ((size_t)0 * B_ + b) * 64);
            LOADOP(a1, g_a + ((size_t)0 * B_ + b) * 64);
            LOADOPN(ne3, g_e + ((size_t)1 * B_ + b) * 64);
            LOADOP(a3, g_a + ((size_t)1 * B_ + b) * 64);
        }
        px2 acc0[4] = { pz, pz, pz, pz };
        px2 acc2[4] = { pz, pz, pz, pz };
#pragma unroll
        for (int it = 0; it < 8; ++it) {
            int L = p * 8 + it;
            if (L + 2 < Lend) LD_C(L + 2);
            size_t n = (size_t)L * 32 + warp * 4 + rg;
            float w0 = __ldg(wp0 + n), w1 = __ldg(wp1 + n);
            float w2 = __ldg(wp2 + n), w3 = __ldg(wp3 + n);
            float4 A = bufA[it & 3], Bv = bufB[it & 3];
            px2 v[4] = { pk(A.x, A.y), pk(A.z, A.w), pk(Bv.x, Bv.y), pk(Bv.z, Bv.w) };
            px2 w0p = pk(w0, w0), w1p = pk(w1, w1), w2p = pk(w2, w2), w3p = pk(w3, w3);
            px2 d4 = pz, d5 = pz, nr = pz;
#pragma unroll
            for (int i = 0; i < 4; ++i) {
                acc0[i] = fma2(w0p, v[i], acc0[i]);              // reads0 on m0
                px2 t = fma2(ne1[i], v[i], a1[i]);
                px2 m1 = fma2(w1p, t, v[i]);
                acc2[i] = fma2(w2p, m1, acc2[i]);                // reads2 on m1
                px2 t3 = fma2(ne3[i], m1, a3[i]);
                px2 m2 = fma2(w3p, t3, m1);
                v[i] = m2;
                d4 = fma2(m2, k4[i], d4);
                d5 = fma2(m2, k5[i], d5);
                nr = fma2(m2, m2, nr);
            }
            float* po = g_mem + n * 64 + col0;
            float2 f0 = up(v[0]), f1 = up(v[1]);
            __stcs((float4*)po, make_float4(f0.x, f0.y, f1.x, f1.y));
            float2 f2 = up(v[2]), f3 = up(v[3]);
            __stcs((float4*)po + 1, make_float4(f2.x, f2.y, f3.x, f3.y));
            float2 fd4 = up(d4), fd5 = up(d5), fn = up(nr);
            float s0 = fd4.x + fd4.y, s1 = fd5.x + fd5.y, sn = fn.x + fn.y;
#pragma unroll
            for (int o = 1; o <= 4; o <<= 1) {
                s0 += __shfl_xor_sync(0xffffffffu, s0, o);
                s1 += __shfl_xor_sync(0xffffffffu, s1, o);
                sn += __shfl_xor_sync(0xffffffffu, sn, o);
            }
            if (c == 0) { g_dot0[n] = s0; g_dot1[n] = s1; g_nrm[n] = sn; }
        }
        reads_epilogue(acc0, sred, lane, warp, c, tid, p, 0);
        reads_epilogue(acc2, sred, lane, warp, c, tid, p, 1);
    }
}

// ---- Pass D: reads4 + algebraic reductions for head 6 on v2 (NO memory write) ----
__global__ __launch_bounds__(256, 2) void passD_kernel() {
    __shared__ float sred[8][64];
    PASS_HEAD();
    const float* wp4 = g_w + (size_t)4 * B_ * N_;
    float4 bufA[4], bufB[4];
#define LD_D(L) { size_t n = (size_t)(L) * 32 + warp * 4 + rg;              \
        const float4* p = (const float4*)(g_mem + n * 64 + col0);           \
        bufA[(L) & 3] = __ldcs(p); bufB[(L) & 3] = __ldcs(p + 1); }
    LD_D(p0 * 8); LD_D(p0 * 8 + 1); LD_D(p0 * 8 + 2);
    px2 k6[4], ek[4], e5[4], es[4], a5[4], ea[4];
    int bcur = -1;
    px2 pz = pk(0.f, 0.f);
    for (int p = p0; p < p1; ++p) {
        int b = p >> 4;
        if (b != bcur) {
            bcur = b;
            float kk[8], ee[8], av[8];
            const float4* qk = (const float4*)(g_k + ((size_t)6 * B_ + b) * 64 + col0);
            const float4* qe = (const float4*)(g_e + ((size_t)2 * B_ + b) * 64 + col0);
            const float4* qa = (const float4*)(g_a + ((size_t)2 * B_ + b) * 64 + col0);
            *(float4*)&kk[0] = __ldg(qk); *(float4*)&kk[4] = __ldg(qk + 1);
            *(float4*)&ee[0] = __ldg(qe); *(float4*)&ee[4] = __ldg(qe + 1);
            *(float4*)&av[0] = __ldg(qa); *(float4*)&av[4] = __ldg(qa + 1);
#pragma unroll
            for (int i = 0; i < 4; ++i) {
                float k0v = kk[2*i], k1v = kk[2*i+1];
                float e0v = ee[2*i], e1v = ee[2*i+1];
                float a0v = av[2*i], a1v = av[2*i+1];
                k6[i] = pk(k0v, k1v);
                e5[i] = pk(e0v, e1v);
                ek[i] = pk(e0v * k0v, e1v * k1v);
                es[i] = pk(e0v * e0v, e1v * e1v);
                a5[i] = pk(a0v, a1v);
                ea[i] = pk(e0v * a0v, e1v * a1v);
            }
        }
        px2 acc[4] = { pz, pz, pz, pz };
#pragma unroll
        for (int it = 0; it < 8; ++it) {
            int L = p * 8 + it;
            if (L + 3 < Lend) LD_D(L + 3);
            size_t n = (size_t)L * 32 + warp * 4 + rg;
            float w4 = __ldg(wp4 + n);
            float4 A = bufA[it & 3], Bv = bufB[it & 3];
            px2 v[4] = { pk(A.x, A.y), pk(A.z, A.w), pk(Bv.x, Bv.y), pk(Bv.z, Bv.w) };
            px2 w4p = pk(w4, w4);
            px2 d6a = pz, d6b = pz, q1 = pz, q2 = pz, p1v = pz, p2v = pz;
#pragma unroll
            for (int i = 0; i < 4; ++i) {
                acc[i] = fma2(w4p, v[i], acc[i]);               // reads4 on m2
                px2 vsq = fma2(v[i], v[i], pz);
                d6a = fma2(v[i], k6[i], d6a);
                d6b = fma2(v[i], ek[i], d6b);
                q1  = fma2(vsq, e5[i], q1);
                q2  = fma2(vsq, es[i], q2);
                p1v = fma2(v[i], a5[i], p1v);
                p2v = fma2(v[i], ea[i], p2v);
            }
            float s[6]; float2 f;
            f = up(d6a); s[0] = f.x + f.y;
            f = up(d6b); s[1] = f.x + f.y;
            f = up(q1);  s[2] = f.x + f.y;
            f = up(q2);  s[3] = f.x + f.y;
            f = up(p1v); s[4] = f.x + f.y;
            f = up(p2v); s[5] = f.x + f.y;
#pragma unroll
            for (int o = 1; o <= 4; o <<= 1)
#pragma unroll
                for (int t = 0; t < 6; ++t) s[t] += __shfl_xor_sync(0xffffffffu, s[t], o);
            if (c == 0) {
                g_dot0[n] = s[0]; g_dot1[n] = s[1];
                g_r1[n] = s[2]; g_r2[n] = s[3]; g_r3[n] = s[4]; g_r4[n] = s[5];
            }
        }
        reads_epilogue(acc, sred, lane, warp, c, tid, p, 2);
    }
}

// ---- Pass E: Sa = colsum(w6, v2), Sb = colsum(w6*w5, v2) ----
__global__ __launch_bounds__(256, 2) void passE_kernel() {
    __shared__ float sredA[8][64];
    __shared__ float sredB[8][64];
    PASS_HEAD();
    const float* wp5 = g_w + (size_t)5 * B_ * N_;
    const float* wp6 = g_w + (size_t)6 * B_ * N_;
    float4 bufA[4], bufB[4];
#define LD_E(L) { size_t n = (size_t)(L) * 32 + warp * 4 + rg;              \
        const float4* p = (const float4*)(g_mem + n * 64 + col0);           \
        bufA[(L) & 3] = __ldcs(p); bufB[(L) & 3] = __ldcs(p + 1); }
    LD_E(p0 * 8); LD_E(p0 * 8 + 1); LD_E(p0 * 8 + 2);
    for (int p = p0; p < p1; ++p) {
        px2 accA[4], accB[4];
#pragma unroll
        for (int i = 0; i < 4; ++i) { accA[i] = pk(0.f, 0.f); accB[i] = pk(0.f, 0.f); }
#pragma unroll
        for (int it = 0; it < 8; ++it) {
            int L = p * 8 + it;
            if (L + 3 < Lend) LD_E(L + 3);
            size_t n = (size_t)L * 32 + warp * 4 + rg;
            float w5 = __ldg(wp5 + n), w6 = __ldg(wp6 + n);
            float4 A = bufA[it & 3], Bv = bufB[it & 3];
            px2 v[4] = { pk(A.x, A.y), pk(A.z, A.w), pk(Bv.x, Bv.y), pk(Bv.z, Bv.w) };
            px2 w6p = pk(w6, w6), w65p = pk(w6 * w5, w6 * w5);
#pragma unroll
            for (int i = 0; i < 4; ++i) {
                accA[i] = fma2(w6p, v[i], accA[i]);
                accB[i] = fma2(w65p, v[i], accB[i]);
            }
        }
        reads_epilogue(accA, sredA, lane, warp, c, tid, p, 3);
        reads_epilogue(accB, sredB, lane, warp, c, tid, p, 4);
    }
}

// ---------------- finalize helpers ----------------
__device__ __forceinline__ float block_reduce_max(float v, float* sbuf) {
#pragma unroll
    for (int o = 16; o; o >>= 1) v = fmaxf(v, __shfl_xor_sync(0xffffffffu, v, o));
    int lane = threadIdx.x & 31, w = threadIdx.x >> 5;
    if (lane == 0) sbuf[w] = v;
    __syncthreads();
    if (threadIdx.x < 32) {
        float vv = (threadIdx.x < 8) ? sbuf[threadIdx.x] : -3.4e38f;
#pragma unroll
        for (int o = 4; o; o >>= 1) vv = fmaxf(vv, __shfl_xor_sync(0xffffffffu, vv, o));
        if (threadIdx.x == 0) sbuf[0] = vv;
    }
    __syncthreads();
    v = sbuf[0];
    __syncthreads();
    return v;
}
__device__ __forceinline__ float block_reduce_sum(float v, float* sbuf) {
#pragma unroll
    for (int o = 16; o; o >>= 1) v += __shfl_xor_sync(0xffffffffu, v, o);
    int lane = threadIdx.x & 31, w = threadIdx.x >> 5;
    if (lane == 0) sbuf[w] = v;
    __syncthreads();
    if (threadIdx.x < 32) {
        float vv = (threadIdx.x < 8) ? sbuf[threadIdx.x] : 0.f;
#pragma unroll
        for (int o = 4; o; o >>= 1) vv += __shfl_xor_sync(0xffffffffu, vv, o);
        if (threadIdx.x == 0) sbuf[0] = vv;
    }
    __syncthreads();
    v = sbuf[0];
    __syncthreads();
    return v;
}

// softmax/interp/shift/sharpen from per-element score sc[] -> w_hd
__device__ __forceinline__ void fin_core(float* sc, int hd, int b, float gate,
                                         float s0, float s1, float s2, float gamma,
                                         const float* pw, float* sbuf, float* swg) {
    int tid = threadIdx.x;
    float lmax = -3.4e38f;
#pragma unroll
    for (int t = 0; t < 16; ++t) lmax = fmaxf(lmax, sc[t]);
    float bmax = block_reduce_max(lmax, sbuf);
    float lsum = 0.f;
#pragma unroll
    for (int t = 0; t < 16; ++t) { float e = __expf(sc[t] - bmax); sc[t] = e; lsum += e; }
    float bsum = block_reduce_sum(lsum, sbuf);
    float inv = 1.f / bsum;
#pragma unroll
    for (int t = 0; t < 16; ++t) {
        int idx = tid + t * 256;
        swg[idx] = gate * sc[t] * inv + (1.f - gate) * pw[idx];
    }
    __syncthreads();
    float wp[16];
    float lps = 0.f;
#pragma unroll
    for (int t = 0; t < 16; ++t) {
        int idx = tid + t * 256;
        float ws = s0 * swg[(idx + N_ - 1) & (N_ - 1)] + s1 * swg[idx]
                 + s2 * swg[(idx + 1) & (N_ - 1)];
        float p = __powf(ws, gamma);
        wp[t] = p; lps += p;
    }
    float psum = block_reduce_sum(lps, sbuf);
    float invp = 1.f / (psum + EPSV);
    float* wout = g_w + (size_t)hd * B_ * N_ + (size_t)b * N_;
#pragma unroll
    for (int t = 0; t < 16; ++t) {
        int idx = tid + t * 256;
        wout[idx] = wp[t] * invp;
    }
}

__global__ void fin_kernel(int head0, const float* __restrict__ prevW) {
    __shared__ float swg[N_];
    __shared__ float sbuf[8];
    int b = blockIdx.x;
    int hh = blockIdx.y;
    int hd = head0 + hh;
    int tid = threadIdx.x;
    const float* dot = hh ? g_dot1 : g_dot0;
    int hb = hd * B_ + b;
    float knorm = g_knorm[hb], beta = g_beta[hb], gate = g_gate[hb], gamma = g_gamma[hb];
    float s0 = g_s[hb * 3 + 0], s1 = g_s[hb * 3 + 1], s2 = g_s[hb * 3 + 2];
    const float* pw = prevW + ((size_t)hd * B_ + b) * N_;
    const size_t base = (size_t)b * N_;
    float sc[16];
#pragma unroll
    for (int t = 0; t < 16; ++t) {
        int idx = tid + t * 256;
        float d = dot[base + idx];
        float nr = g_nrm[base + idx];
        sc[t] = beta * d / (sqrtf(nr) * knorm + EPSV);
    }
    fin_core(sc, hd, b, gate, s0, s1, s2, gamma, pw, sbuf, swg);
}

// fin for heads 2,3: assemble dot/nrm from pass-A reductions + w1
__global__ void fin_asm_kernel(const float* __restrict__ prevW) {
    __shared__ float swg[N_];
    __shared__ float sbuf[8];
    int b = blockIdx.x;
    int hh = blockIdx.y;           // 0 -> head2, 1 -> head3
    int hd = 2 + hh;
    int tid = threadIdx.x;
    int hb = hd * B_ + b;
    float knorm = g_knorm[hb], beta = g_beta[hb], gate = g_gate[hb], gamma = g_gamma[hb];
    float s0 = g_s[hb * 3 + 0], s1 = g_s[hb * 3 + 1], s2 = g_s[hb * 3 + 2];
    float Ax = hh ? g_A3[b] : g_A2[b];
    float Aaa = g_Aaa[b];
    const float* ua = hh ? g_r3 : g_r1;
    const float* ub = hh ? g_r4 : g_r2;
    const float* pw = prevW + ((size_t)hd * B_ + b) * N_;
    const float* wp1 = g_w + (size_t)1 * B_ * N_ + (size_t)b * N_;
    const size_t base = (size_t)b * N_;
    float sc[16];
#pragma unroll
    for (int t = 0; t < 16; ++t) {
        int idx = tid + t * 256;
        float w1 = wp1[idx];
        float d = ua[base + idx] + w1 * (Ax - ub[base + idx]);
        float nrm1 = g_nrm[base + idx]
                   + 2.f * w1 * (g_r5[base + idx] - g_r6[base + idx])
                   + w1 * w1 * (Aaa - 2.f * g_r7[base + idx] + g_r8[base + idx]);
        nrm1 = fmaxf(nrm1, 0.f);
        sc[t] = beta * d / (sqrtf(nrm1) * knorm + EPSV);
    }
    fin_core(sc, hd, b, gate, s0, s1, s2, gamma, pw, sbuf, swg);
}

// fin for head 6: assemble dot6/nrm3 from pass-D reductions + w5; also T[b] = sum w6 w5
__global__ void fin6_kernel(const float* __restrict__ prevW) {
    __shared__ float swg[N_];
    __shared__ float sbuf[8];
    int b = blockIdx.x;
    int tid = threadIdx.x;
    const int hd = 6;
    int hb = hd * B_ + b;
    float knorm = g_knorm[hb], beta = g_beta[hb], gate = g_gate[hb], gamma = g_gamma[hb];
    float s0 = g_s[hb * 3 + 0], s1 = g_s[hb * 3 + 1], s2 = g_s[hb * 3 + 2];
    float ak = g_ak[b], aa = g_aa[b];
    const float* pw = prevW + ((size_t)hd * B_ + b) * N_;
    const float* wp5 = g_w + (size_t)5 * B_ * N_ + (size_t)b * N_;
    const size_t base = (size_t)b * N_;
    float sc[16];
#pragma unroll
    for (int t = 0; t < 16; ++t) {
        int idx = tid + t * 256;
        float w5 = wp5[idx];
        float d6 = g_dot0[base + idx] + w5 * (ak - g_dot1[base + idx]);
        float q0 = g_nrm[base + idx];
        float q1 = g_r1[base + idx], q2 = g_r2[base + idx];
        float p1 = g_r3[base + idx], p2 = g_r4[base + idx];
        float nrm3 = q0 + w5 * (-2.f * q1 + 2.f * p1) + w5 * w5 * (q2 - 2.f * p2 + aa);
        nrm3 = fmaxf(nrm3, 0.f);
        sc[t] = beta * d6 / (sqrtf(nrm3) * knorm + EPSV);
    }
    fin_core(sc, hd, b, gate, s0, s1, s2, gamma, pw, sbuf, swg);
    // T[b] = sum_n w6 w5
    const float* wout = g_w + (size_t)6 * B_ * N_ + base;
    float lt = 0.f;
#pragma unroll
    for (int t = 0; t < 16; ++t) {
        int idx = tid + t * 256;
        lt += wout[idx] * wp5[idx];
    }
    float T = block_reduce_sum(lt, sbuf);
    if (tid == 0) g_T[b] = T;
}

// ---------------- build state = [h | reads0 | reads2 | reads4 | reads6] ----------------
__global__ void build_state_kernel() {
    int b = blockIdx.x;
    for (int j = threadIdx.x; j < 768; j += blockDim.x) {
        float v;
        if (j < 512) v = g_h[(size_t)b * C_ + j];
        else {
            int ri = (j - 512) >> 6, m = (j - 512) & 63;
            if (ri < 3) {
                float s = 0.f;
                const float* rp = g_rpart + (size_t)ri * B_ * 16 * 64 + (size_t)b * 16 * 64 + m;
#pragma unroll
                for (int cc = 0; cc < 16; ++cc) s += rp[cc * 64];
                v = s;
            } else {
                float sa = 0.f, sb = 0.f;
                const float* rpa = g_rpart + (size_t)3 * B_ * 16 * 64 + (size_t)b * 16 * 64 + m;
                const float* rpb = g_rpart + (size_t)4 * B_ * 16 * 64 + (size_t)b * 16 * 64 + m;
#pragma unroll
                for (int cc = 0; cc < 16; ++cc) { sa += rpa[cc * 64]; sb += rpb[cc * 64]; }
                float e5 = g_e[((size_t)2 * B_ + b) * 64 + m];
                float a5 = g_a[((size_t)2 * B_ + b) * 64 + m];
                v = sa - e5 * sb + g_T[b] * a5;
            }
        }
        g_state[(size_t)b * 768 + j] = v;
    }
}

// ---------------- host ----------------
extern "C" void kernel_launch(void* const* d_in, const int* in_sizes, int n_in,
                              void* d_out, int out_size) {
    const float* in_data      = (const float*)d_in[0];
    const float* memory       = (const float*)d_in[1];
    const float* h0           = (const float*)d_in[2];
    const float* c0           = (const float*)d_in[3];
    const float* prev_weights = (const float*)d_in[4];
    const float* prev_reads   = (const float*)d_in[5];
    const float* W_ih         = (const float*)d_in[6];
    const float* b_ih         = (const float*)d_in[7];
    const float* W_hh         = (const float*)d_in[8];
    const float* b_hh         = (const float*)d_in[9];
    const float* W_out        = (const float*)d_in[10];
    const float* b_out        = (const float*)d_in[11];
    const float* W_addr       = (const float*)d_in[12];
    const float* b_addr       = (const float*)d_in[13];
    const float* W_ea         = (const float*)d_in[14];
    const float* b_ea         = (const float*)d_in[15];
    float* outp = (float*)d_out;

    float *p_c, *p_pall, *p_ea, *p_state;
    cudaGetSymbolAddress((void**)&p_c,     g_c);
    cudaGetSymbolAddress((void**)&p_pall,  g_pall);
    cudaGetSymbolAddress((void**)&p_ea,    g_eaall);
    cudaGetSymbolAddress((void**)&p_state, g_state);

    // controller
    build_x_kernel<<<(B_ * 320 + 255) / 256, 256>>>(in_data, prev_reads);
    gates_gemm_kernel<<<dim3(2048 / 64, B_ / 64), 256>>>(h0, W_ih, b_ih, W_hh, b_hh);
    lstm_kernel<<<(B_ * C_ + 255) / 256, 256>>>(c0);

    // head parameters (head 7 is dead code)
    sgemm_kernel<false><<<dim3((560 + 63) / 64, B_ / 64), 256>>>(p_c, W_addr, b_addr, p_pall, 560, 512);
    sgemm_kernel<false><<<dim3(512 / 64, B_ / 64), 256>>>(p_c, W_ea, b_ea, p_ea, 512, 512);
    head_act_kernel<<<B_, 32>>>();

    passA_kernel<<<NPASSBLK, 256>>>(memory);
    fin_kernel<<<dim3(B_, 2), 256>>>(0, prev_weights);     // heads 0,1 (direct)
    fin_asm_kernel<<<dim3(B_, 2), 256>>>(prev_weights);    // heads 2,3 (assembled from pass-A reductions)
    passC_kernel<<<NPASSBLK, 256>>>(memory);
    fin_kernel<<<dim3(B_, 2), 256>>>(4, prev_weights);     // heads 4,5 (direct on m2)
    passD_kernel<<<NPASSBLK, 256>>>();
    fin6_kernel<<<B_, 256>>>(prev_weights);                // head 6 (assembled)
    passE_kernel<<<NPASSBLK, 256>>>();

    // output
    build_state_kernel<<<B_, 256>>>();
    sgemm_kernel<true><<<dim3(1, B_ / 64), 256>>>(p_state, W_out, b_out, outp, 64, 768);
}

// round 8
// speedup vs baseline: 1.5667x; 1.0928x over previous
#include <cuda_runtime.h>
#include <cstdint>

#define B_  256
#define N_  4096
#define M_  64
#define C_  512
#define EPSV 1e-8f
#define NPASSBLK 296
#define NPAIRS   4096

// ---------------- packed f32x2 helpers (sm_103a FFMA2) ----------------
struct px2 { unsigned long long u; };
__device__ __forceinline__ px2 pk(float x, float y) {
    px2 r; asm("mov.b64 %0,{%1,%2};" : "=l"(r.u) : "f"(x), "f"(y)); return r;
}
__device__ __forceinline__ float2 up(px2 a) {
    float2 f; asm("mov.b64 {%0,%1},%2;" : "=f"(f.x), "=f"(f.y) : "l"(a.u)); return f;
}
__device__ __forceinline__ px2 fma2(px2 a, px2 b, px2 c) {
    px2 r; asm("fma.rn.f32x2 %0,%1,%2,%3;" : "=l"(r.u) : "l"(a.u), "l"(b.u), "l"(c.u)); return r;
}

// ---------------- device scratch ----------------
__device__ __align__(16) float g_mem[(size_t)B_ * N_ * M_];      // v2 working memory (written once, pass C)
__device__ __align__(16) float g_x[B_ * 320];
__device__ __align__(16) float g_gates[B_ * 2048];
__device__ __align__(16) float g_c[B_ * C_];
__device__ __align__(16) float g_h[B_ * C_];
__device__ __align__(16) float g_pe[B_ * 1072];                  // [0,560): addr params, [560,1072): ea params
__device__ __align__(16) float g_k[7 * B_ * M_];
__device__ float g_knorm[7 * B_];
__device__ float g_beta[7 * B_];
__device__ float g_gate[7 * B_];
__device__ float g_s[7 * B_ * 3];
__device__ float g_gamma[7 * B_];
__device__ __align__(16) float g_e[3 * B_ * M_];
__device__ __align__(16) float g_a[3 * B_ * M_];
__device__ __align__(16) float g_dot0[(size_t)B_ * N_];
__device__ __align__(16) float g_dot1[(size_t)B_ * N_];
__device__ __align__(16) float g_nrm[(size_t)B_ * N_];
__device__ __align__(16) float g_r1[(size_t)B_ * N_];
__device__ __align__(16) float g_r2[(size_t)B_ * N_];
__device__ __align__(16) float g_r3[(size_t)B_ * N_];
__device__ __align__(16) float g_r4[(size_t)B_ * N_];
__device__ __align__(16) float g_r5[(size_t)B_ * N_];
__device__ __align__(16) float g_r6[(size_t)B_ * N_];
__device__ __align__(16) float g_r7[(size_t)B_ * N_];
__device__ __align__(16) float g_r8[(size_t)B_ * N_];
__device__ __align__(16) float g_w[7 * (size_t)B_ * N_];         // per-head weights, slot = head index
__device__ __align__(16) float g_rpart[5 * B_ * 16 * M_];        // colsum partials: reads0,2,4, Sa, Sb
__device__ float g_ak[B_];    // a5 . k6
__device__ float g_aa[B_];    // |a5|^2
__device__ float g_A2[B_];    // a1 . k2
__device__ float g_A3[B_];    // a1 . k3
__device__ float g_Aaa[B_];   // |a1|^2
__device__ float g_T[B_];     // sum_n w6 w5
__device__ __align__(16) float g_state[B_ * 768];

// ---------------- helpers ----------------
__device__ __forceinline__ float sigf(float x) { return 1.f / (1.f + expf(-x)); }
__device__ __forceinline__ float softplusf(float x) { return x > 20.f ? x : log1pf(expf(x)); }

// ---------------- build x = [in_data | prev_reads 0..3] ----------------
__global__ void build_x_kernel(const float* __restrict__ in_data,
                               const float* __restrict__ prev_reads) {
    int idx = blockIdx.x * blockDim.x + threadIdx.x;
    if (idx >= B_ * 320) return;
    int b = idx / 320, j = idx % 320;
    float v;
    if (j < 64) v = in_data[b * 64 + j];
    else { int i = (j - 64) >> 6, m = (j - 64) & 63; v = prev_reads[((size_t)i * B_ + b) * 64 + m]; }
    g_x[idx] = v;
}

// =============== 32x64-tile SGEMMs (256 thr, 2x4 per thread) ===============
// shared loads: A tile 32x16 (thread: la_r=tid>>3, la_k=(tid&7)*2, float2)
//               B tile 64x16 (thread: lb_r=tid>>2, lb_k=(tid&3)*4, float4)

// fused gates GEMM: gates = x Wih^T + h0 Whh^T + bih + bhh   (N=2048)
__global__ void gates_gemm_kernel(const float* __restrict__ h0,
                                  const float* __restrict__ Wih, const float* __restrict__ bih,
                                  const float* __restrict__ Whh, const float* __restrict__ bhh) {
    __shared__ __align__(16) float As[16][32];
    __shared__ __align__(16) float Bs[16][64];
    int tid = threadIdx.x;
    int m0 = blockIdx.y * 32, n0 = blockIdx.x * 64;
    int la_r = tid >> 3, la_k = (tid & 7) * 2;
    int lb_r = tid >> 2, lb_k = (tid & 3) * 4;
    int ty = tid >> 4, tx = tid & 15;
    float acc[2][4] = {};
    for (int pass = 0; pass < 2; ++pass) {
        const float* A = pass ? h0 : g_x;
        const float* Bw = pass ? Whh : Wih;
        int K = pass ? 512 : 320;
        for (int k0 = 0; k0 < K; k0 += 16) {
            float2 av = *(const float2*)(A + (size_t)(m0 + la_r) * K + k0 + la_k);
            float4 bv = *(const float4*)(Bw + (size_t)(n0 + lb_r) * K + k0 + lb_k);
            __syncthreads();
            As[la_k][la_r] = av.x; As[la_k + 1][la_r] = av.y;
            Bs[lb_k + 0][lb_r] = bv.x; Bs[lb_k + 1][lb_r] = bv.y;
            Bs[lb_k + 2][lb_r] = bv.z; Bs[lb_k + 3][lb_r] = bv.w;
            __syncthreads();
#pragma unroll
            for (int kk = 0; kk < 16; kk++) {
                float2 a = *(const float2*)&As[kk][ty << 1];
                float4 b = *(const float4*)&Bs[kk][tx << 2];
                acc[0][0] += a.x * b.x; acc[0][1] += a.x * b.y; acc[0][2] += a.x * b.z; acc[0][3] += a.x * b.w;
                acc[1][0] += a.y * b.x; acc[1][1] += a.y * b.y; acc[1][2] += a.y * b.z; acc[1][3] += a.y * b.w;
            }
        }
    }
#pragma unroll
    for (int i = 0; i < 2; i++) {
        int m = m0 + (ty << 1) + i;
#pragma unroll
        for (int j = 0; j < 4; j++) {
            int n = n0 + (tx << 2) + j;
            g_gates[(size_t)m * 2048 + n] = acc[i][j] + bih[n] + bhh[n];
        }
    }
}

// fused head-param GEMM: g_pe = c @ [W_addr; W_ea]^T + [b_addr; b_ea]   (N=1072, K=512)
__global__ void headpe_gemm_kernel(const float* __restrict__ Wa, const float* __restrict__ ba,
                                   const float* __restrict__ We, const float* __restrict__ be) {
    __shared__ __align__(16) float As[16][32];
    __shared__ __align__(16) float Bs[16][64];
    const int NN = 1072, N1 = 560, K = 512;
    int tid = threadIdx.x;
    int m0 = blockIdx.y * 32, n0 = blockIdx.x * 64;
    int la_r = tid >> 3, la_k = (tid & 7) * 2;
    int lb_r = tid >> 2, lb_k = (tid & 3) * 4;
    int ty = tid >> 4, tx = tid & 15;
    int brow = n0 + lb_r;
    const float* browp = (brow < N1) ? (Wa + (size_t)brow * K)
                                     : (We + (size_t)(brow - N1) * K);
    float acc[2][4] = {};
    for (int k0 = 0; k0 < K; k0 += 16) {
        float2 av = *(const float2*)(g_c + (size_t)(m0 + la_r) * K + k0 + la_k);
        float4 bv = make_float4(0.f, 0.f, 0.f, 0.f);
        if (brow < NN) bv = *(const float4*)(browp + k0 + lb_k);
        __syncthreads();
        As[la_k][la_r] = av.x; As[la_k + 1][la_r] = av.y;
        Bs[lb_k + 0][lb_r] = bv.x; Bs[lb_k + 1][lb_r] = bv.y;
        Bs[lb_k + 2][lb_r] = bv.z; Bs[lb_k + 3][lb_r] = bv.w;
        __syncthreads();
#pragma unroll
        for (int kk = 0; kk < 16; kk++) {
            float2 a = *(const float2*)&As[kk][ty << 1];
            float4 b = *(const float4*)&Bs[kk][tx << 2];
            acc[0][0] += a.x * b.x; acc[0][1] += a.x * b.y; acc[0][2] += a.x * b.z; acc[0][3] += a.x * b.w;
            acc[1][0] += a.y * b.x; acc[1][1] += a.y * b.y; acc[1][2] += a.y * b.z; acc[1][3] += a.y * b.w;
        }
    }
#pragma unroll
    for (int i = 0; i < 2; i++) {
        int m = m0 + (ty << 1) + i;
#pragma unroll
        for (int j = 0; j < 4; j++) {
            int n = n0 + (tx << 2) + j;
            if (n < NN) {
                float bias = (n < N1) ? ba[n] : be[n - N1];
                g_pe[(size_t)m * 1072 + n] = acc[i][j] + bias;
            }
        }
    }
}

// output GEMM: out = sigmoid(state @ W_out^T + b_out)   (N=64, K=768)
__global__ void out_gemm_kernel(const float* __restrict__ Wo, const float* __restrict__ bo,
                                float* __restrict__ C) {
    __shared__ __align__(16) float As[16][32];
    __shared__ __align__(16) float Bs[16][64];
    const int NN = 64, K = 768;
    int tid = threadIdx.x;
    int m0 = blockIdx.y * 32, n0 = 0;
    int la_r = tid >> 3, la_k = (tid & 7) * 2;
    int lb_r = tid >> 2, lb_k = (tid & 3) * 4;
    int ty = tid >> 4, tx = tid & 15;
    float acc[2][4] = {};
    for (int k0 = 0; k0 < K; k0 += 16) {
        float2 av = *(const float2*)(g_state + (size_t)(m0 + la_r) * K + k0 + la_k);
        float4 bv = *(const float4*)(Wo + (size_t)(n0 + lb_r) * K + k0 + lb_k);
        __syncthreads();
        As[la_k][la_r] = av.x; As[la_k + 1][la_r] = av.y;
        Bs[lb_k + 0][lb_r] = bv.x; Bs[lb_k + 1][lb_r] = bv.y;
        Bs[lb_k + 2][lb_r] = bv.z; Bs[lb_k + 3][lb_r] = bv.w;
        __syncthreads();
#pragma unroll
        for (int kk = 0; kk < 16; kk++) {
            float2 a = *(const float2*)&As[kk][ty << 1];
            float4 b = *(const float4*)&Bs[kk][tx << 2];
            acc[0][0] += a.x * b.x; acc[0][1] += a.x * b.y; acc[0][2] += a.x * b.z; acc[0][3] += a.x * b.w;
            acc[1][0] += a.y * b.x; acc[1][1] += a.y * b.y; acc[1][2] += a.y * b.z; acc[1][3] += a.y * b.w;
        }
    }
#pragma unroll
    for (int i = 0; i < 2; i++) {
        int m = m0 + (ty << 1) + i;
#pragma unroll
        for (int j = 0; j < 4; j++) {
            int n = n0 + (tx << 2) + j;
            C[(size_t)m * NN + n] = sigf(acc[i][j] + bo[n]);
        }
    }
}

// ---------------- LSTM pointwise ----------------
__global__ void lstm_kernel(const float* __restrict__ c0) {
    int idx = blockIdx.x * blockDim.x + threadIdx.x;
    if (idx >= B_ * C_) return;
    int b = idx / C_, j = idx % C_;
    const float* gr = g_gates + (size_t)b * 2048;
    float ig = gr[j], fg = gr[512 + j], gg = gr[1024 + j], og = gr[1536 + j];
    float c = sigf(fg) * c0[idx] + sigf(ig) * tanhf(gg);
    g_c[idx] = c;
    g_h[idx] = sigf(og) * tanhf(c);
}

// ---------------- head activations ----------------
__global__ void head_act_kernel() {
    int b = blockIdx.x;
    int lane = threadIdx.x;   // 32 threads
    for (int hd = 0; hd < 7; ++hd) {
        const float* p = g_pe + (size_t)b * 1072 + hd * 70;
        float ssq = 0.f;
        for (int j = lane; j < 64; j += 32) {
            float kv = tanhf(p[j]);
            g_k[((size_t)hd * B_ + b) * 64 + j] = kv;
            ssq += kv * kv;
        }
#pragma unroll
        for (int o = 16; o; o >>= 1) ssq += __shfl_xor_sync(0xffffffffu, ssq, o);
        if (lane == 0) {
            int hb = hd * B_ + b;
            g_knorm[hb] = sqrtf(ssq);
            g_beta[hb] = softplusf(p[64]);
            g_gate[hb] = sigf(p[65]);
            float s0 = p[66], s1 = p[67], s2 = p[68];
            float mx = fmaxf(s0, fmaxf(s1, s2));
            float e0 = expf(s0 - mx), e1 = expf(s1 - mx), e2 = expf(s2 - mx);
            float inv = 1.f / (e0 + e1 + e2);
            g_s[hb * 3 + 0] = e0 * inv; g_s[hb * 3 + 1] = e1 * inv; g_s[hb * 3 + 2] = e2 * inv;
            g_gamma[hb] = 1.f + softplusf(p[69]);
        }
    }
    for (int wh = 0; wh < 3; ++wh) {
        const float* ea = g_pe + (size_t)b * 1072 + 560 + wh * 128;
        for (int j = lane; j < 64; j += 32) {
            g_e[((size_t)wh * B_ + b) * 64 + j] = sigf(ea[j]);
            g_a[((size_t)wh * B_ + b) * 64 + j] = tanhf(ea[64 + j]);
        }
    }
    // scalars: a5.k6, |a5|^2, a1.k2, a1.k3, |a1|^2
    {
        const float* ea2 = g_pe + (size_t)b * 1072 + 560 + 2 * 128;
        const float* ea0 = g_pe + (size_t)b * 1072 + 560 + 0 * 128;
        const float* p6  = g_pe + (size_t)b * 1072 + 6 * 70;
        const float* p2  = g_pe + (size_t)b * 1072 + 2 * 70;
        const float* p3  = g_pe + (size_t)b * 1072 + 3 * 70;
        float pak = 0.f, paa = 0.f, pa2 = 0.f, pa3 = 0.f, p11 = 0.f;
        for (int j = lane; j < 64; j += 32) {
            float a5v = tanhf(ea2[64 + j]);
            float k6v = tanhf(p6[j]);
            float a1v = tanhf(ea0[64 + j]);
            float k2v = tanhf(p2[j]);
            float k3v = tanhf(p3[j]);
            pak += a5v * k6v; paa += a5v * a5v;
            pa2 += a1v * k2v; pa3 += a1v * k3v; p11 += a1v * a1v;
        }
#pragma unroll
        for (int o = 16; o; o >>= 1) {
            pak += __shfl_xor_sync(0xffffffffu, pak, o);
            paa += __shfl_xor_sync(0xffffffffu, paa, o);
            pa2 += __shfl_xor_sync(0xffffffffu, pa2, o);
            pa3 += __shfl_xor_sync(0xffffffffu, pa3, o);
            p11 += __shfl_xor_sync(0xffffffffu, p11, o);
        }
        if (lane == 0) {
            g_ak[b] = pak; g_aa[b] = paa;
            g_A2[b] = pa2; g_A3[b] = pa3; g_Aaa[b] = p11;
        }
    }
}

// =================== persistent grid-stride memory passes ===================
#define PASS_HEAD()                                                         \
    int tid = threadIdx.x, lane = tid & 31, warp = tid >> 5;                \
    int c = lane & 7, rg = lane >> 3, col0 = c * 8;                         \
    int p0 = (NPAIRS * blockIdx.x) / NPASSBLK;                              \
    int p1 = (NPAIRS * (blockIdx.x + 1)) / NPASSBLK;                        \
    int Lend = p1 * 8;

#define LOADOP(dst, baseptr) {                                              \
    const float4* _q = (const float4*)((baseptr) + col0);                   \
    float4 _u0 = __ldg(_q), _u1 = __ldg(_q + 1);                            \
    dst[0] = pk(_u0.x, _u0.y); dst[1] = pk(_u0.z, _u0.w);                   \
    dst[2] = pk(_u1.x, _u1.y); dst[3] = pk(_u1.z, _u1.w); }
#define LOADOPN(dst, baseptr) {                                             \
    const float4* _q = (const float4*)((baseptr) + col0);                   \
    float4 _u0 = __ldg(_q), _u1 = __ldg(_q + 1);                            \
    dst[0] = pk(-_u0.x, -_u0.y); dst[1] = pk(-_u0.z, -_u0.w);               \
    dst[2] = pk(-_u1.x, -_u1.y); dst[3] = pk(-_u1.z, -_u1.w); }

__device__ __forceinline__ void reads_epilogue(px2* acc, float (*sred)[64],
                                               int lane, int warp, int c, int tid,
                                               int pair, int slot) {
    float va[8];
#pragma unroll
    for (int i = 0; i < 4; ++i) { float2 f = up(acc[i]); va[2 * i] = f.x; va[2 * i + 1] = f.y; }
#pragma unroll
    for (int t = 0; t < 8; ++t) {
        va[t] += __shfl_xor_sync(0xffffffffu, va[t], 8);
        va[t] += __shfl_xor_sync(0xffffffffu, va[t], 16);
    }
    if (lane < 8) {
#pragma unroll
        for (int t = 0; t < 8; ++t) sred[warp][c * 8 + t] = va[t];
    }
    __syncthreads();
    if (tid < 64) {
        float s = 0.f;
#pragma unroll
        for (int wv = 0; wv < 8; ++wv) s += sred[wv][tid];
        g_rpart[(size_t)slot * B_ * 16 * 64 + (size_t)pair * 64 + tid] = s;
    }
    __syncthreads();
}

// ---- Pass A: 11 reductions on mem0 (heads 0-3 material) ----
__global__ __launch_bounds__(256, 2) void passA_kernel(const float* __restrict__ mem0) {
    PASS_HEAD();
    float4 bufA[4], bufB[4];
#define LD_A(L) { size_t n = (size_t)(L) * 32 + warp * 4 + rg;              \
        const float4* p = (const float4*)(mem0 + n * 64 + col0);            \
        bufA[(L) & 3] = __ldcs(p); bufB[(L) & 3] = __ldcs(p + 1); }
    LD_A(p0 * 8); LD_A(p0 * 8 + 1); LD_A(p0 * 8 + 2);
    px2 k0[4], k1[4], k2[4], k3[4], e1[4], a1[4];
    int bcur = -1;
    px2 pz = pk(0.f, 0.f);
    for (int p = p0; p < p1; ++p) {
        int b = p >> 4;
        if (b != bcur) {
            bcur = b;
            LOADOP(k0, g_k + ((size_t)0 * B_ + b) * 64);
            LOADOP(k1, g_k + ((size_t)1 * B_ + b) * 64);
            LOADOP(k2, g_k + ((size_t)2 * B_ + b) * 64);
            LOADOP(k3, g_k + ((size_t)3 * B_ + b) * 64);
            LOADOP(e1, g_e + ((size_t)0 * B_ + b) * 64);
            LOADOP(a1, g_a + ((size_t)0 * B_ + b) * 64);
        }
#pragma unroll
        for (int it = 0; it < 8; ++it) {
            int L = p * 8 + it;
            if (L + 3 < Lend) LD_A(L + 3);
            size_t n = (size_t)L * 32 + warp * 4 + rg;
            float4 A = bufA[it & 3], Bv = bufB[it & 3];
            px2 v[4] = { pk(A.x, A.y), pk(A.z, A.w), pk(Bv.x, Bv.y), pk(Bv.z, Bv.w) };
            px2 d0 = pz, d1 = pz, nr = pz, u2a = pz, u2b = pz, u3a = pz, u3b = pz;
            px2 v1a = pz, v2a = pz, v3a = pz, v4a = pz;
#pragma unroll
            for (int i = 0; i < 4; ++i) {
                px2 ve = fma2(v[i], e1[i], pz);
                d0  = fma2(v[i], k0[i], d0);
                d1  = fma2(v[i], k1[i], d1);
                nr  = fma2(v[i], v[i], nr);
                u2a = fma2(v[i], k2[i], u2a);
                u3a = fma2(v[i], k3[i], u3a);
                u2b = fma2(ve, k2[i], u2b);
                u3b = fma2(ve, k3[i], u3b);
                v1a = fma2(v[i], a1[i], v1a);
                v3a = fma2(ve, a1[i], v3a);
                v2a = fma2(ve, v[i], v2a);
                v4a = fma2(ve, ve, v4a);
            }
            float s[11]; float2 f;
            f = up(d0);  s[0] = f.x + f.y;
            f = up(d1);  s[1] = f.x + f.y;
            f = up(nr);  s[2] = f.x + f.y;
            f = up(u2a); s[3] = f.x + f.y;
            f = up(u2b); s[4] = f.x + f.y;
            f = up(u3a); s[5] = f.x + f.y;
            f = up(u3b); s[6] = f.x + f.y;
            f = up(v1a); s[7] = f.x + f.y;
            f = up(v2a); s[8] = f.x + f.y;
            f = up(v3a); s[9] = f.x + f.y;
            f = up(v4a); s[10] = f.x + f.y;
#pragma unroll
            for (int o = 1; o <= 4; o <<= 1)
#pragma unroll
                for (int t = 0; t < 11; ++t) s[t] += __shfl_xor_sync(0xffffffffu, s[t], o);
            if (c == 0) {
                g_dot0[n] = s[0]; g_dot1[n] = s[1]; g_nrm[n] = s[2];
                g_r1[n] = s[3]; g_r2[n] = s[4]; g_r3[n] = s[5]; g_r4[n] = s[6];
                g_r5[n] = s[7]; g_r6[n] = s[8]; g_r7[n] = s[9]; g_r8[n] = s[10];
            }
        }
    }
}

// ---- Pass C: reads0 (w0,m0), m1 regs, reads2 (w2,m1), update -> write v2, dot4, dot5, nrm2 ----
__global__ __launch_bounds__(256, 2) void passC_kernel(const float* __restrict__ mem0) {
    __shared__ float sred[8][64];
    PASS_HEAD();
    const float* wp0 = g_w + (size_t)0 * B_ * N_;
    const float* wp1 = g_w + (size_t)1 * B_ * N_;
    const float* wp2 = g_w + (size_t)2 * B_ * N_;
    const float* wp3 = g_w + (size_t)3 * B_ * N_;
    float4 bufA[4], bufB[4];
#define LD_C(L) { size_t n = (size_t)(L) * 32 + warp * 4 + rg;              \
        const float4* p = (const float4*)(mem0 + n * 64 + col0);            \
        bufA[(L) & 3] = __ldcs(p); bufB[(L) & 3] = __ldcs(p + 1); }
    LD_C(p0 * 8); LD_C(p0 * 8 + 1);
    px2 k4[4], k5[4], ne1[4], a1[4], ne3[4], a3[4];
    int bcur = -1;
    px2 pz = pk(0.f, 0.f);
    for (int p = p0; p < p1; ++p) {
        int b = p >> 4;
        if (b != bcur) {
            bcur = b;
            LOADOP(k4, g_k + ((size_t)4 * B_ + b) * 64);
            LOADOP(k5, g_k + ((size_t)5 * B_ + b) * 64);
            LOADOPN(ne1, g_e + ((size_t)0 * B_ + b) * 64);
            LOADOP(a1, g_a + ((size_t)0 * B_ + b) * 64);
            LOADOPN(ne3, g_e + ((size_t)1 * B_ + b) * 64);
            LOADOP(a3, g_a + ((size_t)1 * B_ + b) * 64);
        }
        px2 acc0[4] = { pz, pz, pz, pz };
        px2 acc2[4] = { pz, pz, pz, pz };
#pragma unroll
        for (int it = 0; it < 8; ++it) {
            int L = p * 8 + it;
            if (L + 2 < Lend) LD_C(L + 2);
            size_t n = (size_t)L * 32 + warp * 4 + rg;
            float w0 = __ldg(wp0 + n), w1 = __ldg(wp1 + n);
            float w2 = __ldg(wp2 + n), w3 = __ldg(wp3 + n);
            float4 A = bufA[it & 3], Bv = bufB[it & 3];
            px2 v[4] = { pk(A.x, A.y), pk(A.z, A.w), pk(Bv.x, Bv.y), pk(Bv.z, Bv.w) };
            px2 w0p = pk(w0, w0), w1p = pk(w1, w1), w2p = pk(w2, w2), w3p = pk(w3, w3);
            px2 d4 = pz, d5 = pz, nr = pz;
#pragma unroll
            for (int i = 0; i < 4; ++i) {
                acc0[i] = fma2(w0p, v[i], acc0[i]);              // reads0 on m0
                px2 t = fma2(ne1[i], v[i], a1[i]);
                px2 m1 = fma2(w1p, t, v[i]);
                acc2[i] = fma2(w2p, m1, acc2[i]);                // reads2 on m1
                px2 t3 = fma2(ne3[i], m1, a3[i]);
                px2 m2 = fma2(w3p, t3, m1);
                v[i] = m2;
                d4 = fma2(m2, k4[i], d4);
                d5 = fma2(m2, k5[i], d5);
                nr = fma2(m2, m2, nr);
            }
            float* po = g_mem + n * 64 + col0;
            float2 f0 = up(v[0]), f1 = up(v[1]);
            __stcs((float4*)po, make_float4(f0.x, f0.y, f1.x, f1.y));
            float2 f2 = up(v[2]), f3 = up(v[3]);
            __stcs((float4*)po + 1, make_float4(f2.x, f2.y, f3.x, f3.y));
            float2 fd4 = up(d4), fd5 = up(d5), fn = up(nr);
            float s0 = fd4.x + fd4.y, s1 = fd5.x + fd5.y, sn = fn.x + fn.y;
#pragma unroll
            for (int o = 1; o <= 4; o <<= 1) {
                s0 += __shfl_xor_sync(0xffffffffu, s0, o);
                s1 += __shfl_xor_sync(0xffffffffu, s1, o);
                sn += __shfl_xor_sync(0xffffffffu, sn, o);
            }
            if (c == 0) { g_dot0[n] = s0; g_dot1[n] = s1; g_nrm[n] = sn; }
        }
        reads_epilogue(acc0, sred, lane, warp, c, tid, p, 0);
        reads_epilogue(acc2, sred, lane, warp, c, tid, p, 1);
    }
}

// ---- Pass D: reads4 + algebraic reductions for head 6 on v2 (NO memory write) ----
__global__ __launch_bounds__(256, 2) void passD_kernel() {
    __shared__ float sred[8][64];
    PASS_HEAD();
    const float* wp4 = g_w + (size_t)4 * B_ * N_;
    float4 bufA[4], bufB[4];
#define LD_D(L) { size_t n = (size_t)(L) * 32 + warp * 4 + rg;              \
        const float4* p = (const float4*)(g_mem + n * 64 + col0);           \
        bufA[(L) & 3] = __ldcs(p); bufB[(L) & 3] = __ldcs(p + 1); }
    LD_D(p0 * 8); LD_D(p0 * 8 + 1); LD_D(p0 * 8 + 2);
    px2 k6[4], ek[4], e5[4], es[4], a5[4], ea[4];
    int bcur = -1;
    px2 pz = pk(0.f, 0.f);
    for (int p = p0; p < p1; ++p) {
        int b = p >> 4;
        if (b != bcur) {
            bcur = b;
            float kk[8], ee[8], av[8];
            const float4* qk = (const float4*)(g_k + ((size_t)6 * B_ + b) * 64 + col0);
            const float4* qe = (const float4*)(g_e + ((size_t)2 * B_ + b) * 64 + col0);
            const float4* qa = (const float4*)(g_a + ((size_t)2 * B_ + b) * 64 + col0);
            *(float4*)&kk[0] = __ldg(qk); *(float4*)&kk[4] = __ldg(qk + 1);
            *(float4*)&ee[0] = __ldg(qe); *(float4*)&ee[4] = __ldg(qe + 1);
            *(float4*)&av[0] = __ldg(qa); *(float4*)&av[4] = __ldg(qa + 1);
#pragma unroll
            for (int i = 0; i < 4; ++i) {
                float k0v = kk[2*i], k1v = kk[2*i+1];
                float e0v = ee[2*i], e1v = ee[2*i+1];
                float a0v = av[2*i], a1v = av[2*i+1];
                k6[i] = pk(k0v, k1v);
                e5[i] = pk(e0v, e1v);
                ek[i] = pk(e0v * k0v, e1v * k1v);
                es[i] = pk(e0v * e0v, e1v * e1v);
                a5[i] = pk(a0v, a1v);
                ea[i] = pk(e0v * a0v, e1v * a1v);
            }
        }
        px2 acc[4] = { pz, pz, pz, pz };
#pragma unroll
        for (int it = 0; it < 8; ++it) {
            int L = p * 8 + it;
            if (L + 3 < Lend) LD_D(L + 3);
            size_t n = (size_t)L * 32 + warp * 4 + rg;
            float w4 = __ldg(wp4 + n);
            float4 A = bufA[it & 3], Bv = bufB[it & 3];
            px2 v[4] = { pk(A.x, A.y), pk(A.z, A.w), pk(Bv.x, Bv.y), pk(Bv.z, Bv.w) };
            px2 w4p = pk(w4, w4);
            px2 d6a = pz, d6b = pz, q1 = pz, q2 = pz, p1v = pz, p2v = pz;
#pragma unroll
            for (int i = 0; i < 4; ++i) {
                acc[i] = fma2(w4p, v[i], acc[i]);               // reads4 on m2
                px2 vsq = fma2(v[i], v[i], pz);
                d6a = fma2(v[i], k6[i], d6a);
                d6b = fma2(v[i], ek[i], d6b);
                q1  = fma2(vsq, e5[i], q1);
                q2  = fma2(vsq, es[i], q2);
                p1v = fma2(v[i], a5[i], p1v);
                p2v = fma2(v[i], ea[i], p2v);
            }
            float s[6]; float2 f;
            f = up(d6a); s[0] = f.x + f.y;
            f = up(d6b); s[1] = f.x + f.y;
            f = up(q1);  s[2] = f.x + f.y;
            f = up(q2);  s[3] = f.x + f.y;
            f = up(p1v); s[4] = f.x + f.y;
            f = up(p2v); s[5] = f.x + f.y;
#pragma unroll
            for (int o = 1; o <= 4; o <<= 1)
#pragma unroll
                for (int t = 0; t < 6; ++t) s[t] += __shfl_xor_sync(0xffffffffu, s[t], o);
            if (c == 0) {
                g_dot0[n] = s[0]; g_dot1[n] = s[1];
                g_r1[n] = s[2]; g_r2[n] = s[3]; g_r3[n] = s[4]; g_r4[n] = s[5];
            }
        }
        reads_epilogue(acc, sred, lane, warp, c, tid, p, 2);
    }
}

// ---- Pass E: Sa = colsum(w6, v2), Sb = colsum(w6*w5, v2) ----
__global__ __launch_bounds__(256, 2) void passE_kernel() {
    __shared__ float sredA[8][64];
    __shared__ float sredB[8][64];
    PASS_HEAD();
    const float* wp5 = g_w + (size_t)5 * B_ * N_;
    const float* wp6 = g_w + (size_t)6 * B_ * N_;
    float4 bufA[4], bufB[4];
#define LD_E(L) { size_t n = (size_t)(L) * 32 + warp * 4 + rg;              \
        const float4* p = (const float4*)(g_mem + n * 64 + col0);           \
        bufA[(L) & 3] = __ldcs(p); bufB[(L) & 3] = __ldcs(p + 1); }
    LD_E(p0 * 8); LD_E(p0 * 8 + 1); LD_E(p0 * 8 + 2);
    for (int p = p0; p < p1; ++p) {
        px2 accA[4], accB[4];
#pragma unroll
        for (int i = 0; i < 4; ++i) { accA[i] = pk(0.f, 0.f); accB[i] = pk(0.f, 0.f); }
#pragma unroll
        for (int it = 0; it < 8; ++it) {
            int L = p * 8 + it;
            if (L + 3 < Lend) LD_E(L + 3);
            size_t n = (size_t)L * 32 + warp * 4 + rg;
            float w5 = __ldg(wp5 + n), w6 = __ldg(wp6 + n);
            float4 A = bufA[it & 3], Bv = bufB[it & 3];
            px2 v[4] = { pk(A.x, A.y), pk(A.z, A.w), pk(Bv.x, Bv.y), pk(Bv.z, Bv.w) };
            px2 w6p = pk(w6, w6), w65p = pk(w6 * w5, w6 * w5);
#pragma unroll
            for (int i = 0; i < 4; ++i) {
                accA[i] = fma2(w6p, v[i], accA[i]);
                accB[i] = fma2(w65p, v[i], accB[i]);
            }
        }
        reads_epilogue(accA, sredA, lane, warp, c, tid, p, 3);
        reads_epilogue(accB, sredB, lane, warp, c, tid, p, 4);
    }
}

// ---------------- finalize helpers ----------------
__device__ __forceinline__ float block_reduce_max(float v, float* sbuf) {
#pragma unroll
    for (int o = 16; o; o >>= 1) v = fmaxf(v, __shfl_xor_sync(0xffffffffu, v, o));
    int lane = threadIdx.x & 31, w = threadIdx.x >> 5;
    if (lane == 0) sbuf[w] = v;
    __syncthreads();
    if (threadIdx.x < 32) {
        float vv = (threadIdx.x < 8) ? sbuf[threadIdx.x] : -3.4e38f;
#pragma unroll
        for (int o = 4; o; o >>= 1) vv = fmaxf(vv, __shfl_xor_sync(0xffffffffu, vv, o));
        if (threadIdx.x == 0) sbuf[0] = vv;
    }
    __syncthreads();
    v = sbuf[0];
    __syncthreads();
    return v;
}
__device__ __forceinline__ float block_reduce_sum(float v, float* sbuf) {
#pragma unroll
    for (int o = 16; o; o >>= 1) v += __shfl_xor_sync(0xffffffffu, v, o);
    int lane = threadIdx.x & 31, w = threadIdx.x >> 5;
    if (lane == 0) sbuf[w] = v;
    __syncthreads();
    if (threadIdx.x < 32) {
        float vv = (threadIdx.x < 8) ? sbuf[threadIdx.x] : 0.f;
#pragma unroll
        for (int o = 4; o; o >>= 1) vv += __shfl_xor_sync(0xffffffffu, vv, o);
        if (threadIdx.x == 0) sbuf[0] = vv;
    }
    __syncthreads();
    v = sbuf[0];
    __syncthreads();
    return v;
}

// softmax/interp/shift/sharpen from per-element score sc[] -> w_hd
__device__ __forceinline__ void fin_core(float* sc, int hd, int b, float gate,
                                         float s0, float s1, float s2, float gamma,
                                         const float* pw, float* sbuf, float* swg) {
    int tid = threadIdx.x;
    float lmax = -3.4e38f;
#pragma unroll
    for (int t = 0; t < 16; ++t) lmax = fmaxf(lmax, sc[t]);
    float bmax = block_reduce_max(lmax, sbuf);
    float lsum = 0.f;
#pragma unroll
    for (int t = 0; t < 16; ++t) { float e = __expf(sc[t] - bmax); sc[t] = e; lsum += e; }
    float bsum = block_reduce_sum(lsum, sbuf);
    float inv = 1.f / bsum;
#pragma unroll
    for (int t = 0; t < 16; ++t) {
        int idx = tid + t * 256;
        swg[idx] = gate * sc[t] * inv + (1.f - gate) * pw[idx];
    }
    __syncthreads();
    float wp[16];
    float lps = 0.f;
#pragma unroll
    for (int t = 0; t < 16; ++t) {
        int idx = tid + t * 256;
        float ws = s0 * swg[(idx + N_ - 1) & (N_ - 1)] + s1 * swg[idx]
                 + s2 * swg[(idx + 1) & (N_ - 1)];
        float p = __powf(ws, gamma);
        wp[t] = p; lps += p;
    }
    float psum = block_reduce_sum(lps, sbuf);
    float invp = 1.f / (psum + EPSV);
    float* wout = g_w + (size_t)hd * B_ * N_ + (size_t)b * N_;
#pragma unroll
    for (int t = 0; t < 16; ++t) {
        int idx = tid + t * 256;
        wout[idx] = wp[t] * invp;
    }
}

// fin for heads 0-3 after pass A: 0,1 direct; 2,3 assembled from pass-A reductions
__global__ void finA_kernel(const float* __restrict__ prevW) {
    __shared__ float swg[N_];
    __shared__ float sbuf[8];
    int b = blockIdx.x;
    int hd = blockIdx.y;          // 0..3
    int tid = threadIdx.x;
    int hb = hd * B_ + b;
    float knorm = g_knorm[hb], beta = g_beta[hb], gate = g_gate[hb], gamma = g_gamma[hb];
    float s0 = g_s[hb * 3 + 0], s1 = g_s[hb * 3 + 1], s2 = g_s[hb * 3 + 2];
    const float* pw = prevW + ((size_t)hd * B_ + b) * N_;
    const size_t base = (size_t)b * N_;
    float sc[16];
    if (hd < 2) {
        const float* dot = hd ? g_dot1 : g_dot0;
#pragma unroll
        for (int t = 0; t < 16; ++t) {
            int idx = tid + t * 256;
            float d = dot[base + idx];
            float nr = g_nrm[base + idx];
            sc[t] = beta * d / (sqrtf(nr) * knorm + EPSV);
        }
    } else {
        int hh = hd - 2;
        float Ax = hh ? g_A3[b] : g_A2[b];
        float Aaa = g_Aaa[b];
        const float* ua = hh ? g_r3 : g_r1;
        const float* ub = hh ? g_r4 : g_r2;
        const float* wp1 = g_w + (size_t)1 * B_ * N_ + base;
#pragma unroll
        for (int t = 0; t < 16; ++t) {
            int idx = tid + t * 256;
            float w1 = wp1[idx];
            float d = ua[base + idx] + w1 * (Ax - ub[base + idx]);
            float nrm1 = g_nrm[base + idx]
                       + 2.f * w1 * (g_r5[base + idx] - g_r6[base + idx])
                       + w1 * w1 * (Aaa - 2.f * g_r7[base + idx] + g_r8[base + idx]);
            nrm1 = fmaxf(nrm1, 0.f);
            sc[t] = beta * d / (sqrtf(nrm1) * knorm + EPSV);
        }
    }
    fin_core(sc, hd, b, gate, s0, s1, s2, gamma, pw, sbuf, swg);
}

__global__ void fin_kernel(int head0, const float* __restrict__ prevW) {
    __shared__ float swg[N_];
    __shared__ float sbuf[8];
    int b = blockIdx.x;
    int hh = blockIdx.y;
    int hd = head0 + hh;
    int tid = threadIdx.x;
    const float* dot = hh ? g_dot1 : g_dot0;
    int hb = hd * B_ + b;
    float knorm = g_knorm[hb], beta = g_beta[hb], gate = g_gate[hb], gamma = g_gamma[hb];
    float s0 = g_s[hb * 3 + 0], s1 = g_s[hb * 3 + 1], s2 = g_s[hb * 3 + 2];
    const float* pw = prevW + ((size_t)hd * B_ + b) * N_;
    const size_t base = (size_t)b * N_;
    float sc[16];
#pragma unroll
    for (int t = 0; t < 16; ++t) {
        int idx = tid + t * 256;
        float d = dot[base + idx];
        float nr = g_nrm[base + idx];
        sc[t] = beta * d / (sqrtf(nr) * knorm + EPSV);
    }
    fin_core(sc, hd, b, gate, s0, s1, s2, gamma, pw, sbuf, swg);
}

// fin for head 6: assemble dot6/nrm3 from pass-D reductions + w5; also T[b] = sum w6 w5
__global__ void fin6_kernel(const float* __restrict__ prevW) {
    __shared__ float swg[N_];
    __shared__ float sbuf[8];
    int b = blockIdx.x;
    int tid = threadIdx.x;
    const int hd = 6;
    int hb = hd * B_ + b;
    float knorm = g_knorm[hb], beta = g_beta[hb], gate = g_gate[hb], gamma = g_gamma[hb];
    float s0 = g_s[hb * 3 + 0], s1 = g_s[hb * 3 + 1], s2 = g_s[hb * 3 + 2];
    float ak = g_ak[b], aa = g_aa[b];
    const float* pw = prevW + ((size_t)hd * B_ + b) * N_;
    const float* wp5 = g_w + (size_t)5 * B_ * N_ + (size_t)b * N_;
    const size_t base = (size_t)b * N_;
    float sc[16];
#pragma unroll
    for (int t = 0; t < 16; ++t) {
        int idx = tid + t * 256;
        float w5 = wp5[idx];
        float d6 = g_dot0[base + idx] + w5 * (ak - g_dot1[base + idx]);
        float q0 = g_nrm[base + idx];
        float q1 = g_r1[base + idx], q2 = g_r2[base + idx];
        float p1 = g_r3[base + idx], p2 = g_r4[base + idx];
        float nrm3 = q0 + w5 * (-2.f * q1 + 2.f * p1) + w5 * w5 * (q2 - 2.f * p2 + aa);
        nrm3 = fmaxf(nrm3, 0.f);
        sc[t] = beta * d6 / (sqrtf(nrm3) * knorm + EPSV);
    }
    fin_core(sc, hd, b, gate, s0, s1, s2, gamma, pw, sbuf, swg);
    // T[b] = sum_n w6 w5
    const float* wout = g_w + (size_t)6 * B_ * N_ + base;
    float lt = 0.f;
#pragma unroll
    for (int t = 0; t < 16; ++t) {
        int idx = tid + t * 256;
        lt += wout[idx] * wp5[idx];
    }
    float T = block_reduce_sum(lt, sbuf);
    if (tid == 0) g_T[b] = T;
}

// ---------------- build state = [h | reads0 | reads2 | reads4 | reads6] ----------------
__global__ void build_state_kernel() {
    int b = blockIdx.x;
    for (int j = threadIdx.x; j < 768; j += blockDim.x) {
        float v;
        if (j < 512) v = g_h[(size_t)b * C_ + j];
        else {
            int ri = (j - 512) >> 6, m = (j - 512) & 63;
            if (ri < 3) {
                float s = 0.f;
                const float* rp = g_rpart + (size_t)ri * B_ * 16 * 64 + (size_t)b * 16 * 64 + m;
#pragma unroll
                for (int cc = 0; cc < 16; ++cc) s += rp[cc * 64];
                v = s;
            } else {
                float sa = 0.f, sb = 0.f;
                const float* rpa = g_rpart + (size_t)3 * B_ * 16 * 64 + (size_t)b * 16 * 64 + m;
                const float* rpb = g_rpart + (size_t)4 * B_ * 16 * 64 + (size_t)b * 16 * 64 + m;
#pragma unroll
                for (int cc = 0; cc < 16; ++cc) { sa += rpa[cc * 64]; sb += rpb[cc * 64]; }
                float e5 = g_e[((size_t)2 * B_ + b) * 64 + m];
                float a5 = g_a[((size_t)2 * B_ + b) * 64 + m];
                v = sa - e5 * sb + g_T[b] * a5;
            }
        }
        g_state[(size_t)b * 768 + j] = v;
    }
}

// ---------------- host ----------------
extern "C" void kernel_launch(void* const* d_in, const int* in_sizes, int n_in,
                              void* d_out, int out_size) {
    const float* in_data      = (const float*)d_in[0];
    const float* memory       = (const float*)d_in[1];
    const float* h0           = (const float*)d_in[2];
    const float* c0           = (const float*)d_in[3];
    const float* prev_weights = (const float*)d_in[4];
    const float* prev_reads   = (const float*)d_in[5];
    const float* W_ih         = (const float*)d_in[6];
    const float* b_ih         = (const float*)d_in[7];
    const float* W_hh         = (const float*)d_in[8];
    const float* b_hh         = (const float*)d_in[9];
    const float* W_out        = (const float*)d_in[10];
    const float* b_out        = (const float*)d_in[11];
    const float* W_addr       = (const float*)d_in[12];
    const float* b_addr       = (const float*)d_in[13];
    const float* W_ea         = (const float*)d_in[14];
    const float* b_ea         = (const float*)d_in[15];
    float* outp = (float*)d_out;

    // controller
    build_x_kernel<<<(B_ * 320 + 255) / 256, 256>>>(in_data, prev_reads);
    gates_gemm_kernel<<<dim3(2048 / 64, B_ / 32), 256>>>(h0, W_ih, b_ih, W_hh, b_hh);
    lstm_kernel<<<(B_ * C_ + 255) / 256, 256>>>(c0);

    // head parameters (addr + ea fused; head 7 is dead code)
    headpe_gemm_kernel<<<dim3((1072 + 63) / 64, B_ / 32), 256>>>(W_addr, b_addr, W_ea, b_ea);
    head_act_kernel<<<B_, 32>>>();

    passA_kernel<<<NPASSBLK, 256>>>(memory);
    finA_kernel<<<dim3(B_, 4), 256>>>(prev_weights);       // heads 0-3
    passC_kernel<<<NPASSBLK, 256>>>(memory);
    fin_kernel<<<dim3(B_, 2), 256>>>(4, prev_weights);     // heads 4,5 (direct on m2)
    passD_kernel<<<NPASSBLK, 256>>>();
    fin6_kernel<<<B_, 256>>>(prev_weights);                // head 6 (assembled)
    passE_kernel<<<NPASSBLK, 256>>>();

    // output
    build_state_kernel<<<B_, 256>>>();
    out_gemm_kernel<<<dim3(1, B_ / 32), 256>>>(W_out, b_out, outp);
}

// round 9
// speedup vs baseline: 1.5994x; 1.0209x over previous
#include <cuda_runtime.h>
#include <cstdint>

#define B_  256
#define N_  4096
#define M_  64
#define C_  512
#define EPSV 1e-8f
#define NPASSBLK 296
#define NPAIRS   4096
#define RBN ((size_t)B_ * N_)

// ---------------- packed f32x2 helpers (sm_103a FFMA2) ----------------
struct px2 { unsigned long long u; };
__device__ __forceinline__ px2 pk(float x, float y) {
    px2 r; asm("mov.b64 %0,{%1,%2};" : "=l"(r.u) : "f"(x), "f"(y)); return r;
}
__device__ __forceinline__ float2 up(px2 a) {
    float2 f; asm("mov.b64 {%0,%1},%2;" : "=f"(f.x), "=f"(f.y) : "l"(a.u)); return f;
}
__device__ __forceinline__ px2 fma2(px2 a, px2 b, px2 c) {
    px2 r; asm("fma.rn.f32x2 %0,%1,%2,%3;" : "=l"(r.u) : "l"(a.u), "l"(b.u), "l"(c.u)); return r;
}

// ---------------- device scratch ----------------
__device__ __align__(16) float g_mem[(size_t)B_ * N_ * M_];      // v2 working memory (written once, pass C)
__device__ __align__(16) float g_x[B_ * 320];
__device__ __align__(16) float g_gates[B_ * 2048];
__device__ __align__(16) float g_c[B_ * C_];
__device__ __align__(16) float g_h[B_ * C_];
__device__ __align__(16) float g_pe[B_ * 1072];                  // [0,560): addr params, [560,1072): ea params
__device__ __align__(16) float g_k[7 * B_ * M_];
__device__ float g_knorm[7 * B_];
__device__ float g_beta[7 * B_];
__device__ float g_gate[7 * B_];
__device__ float g_s[7 * B_ * 3];
__device__ float g_gamma[7 * B_];
__device__ __align__(16) float g_e[3 * B_ * M_];
__device__ __align__(16) float g_a[3 * B_ * M_];
__device__ __align__(16) float g_red[11 * RBN];                  // reduction slots
__device__ __align__(16) float g_w[7 * RBN];                     // per-head weights, slot = head index
__device__ __align__(16) float g_rpart[5 * B_ * 16 * M_];        // colsum partials: reads0,2,4, Sa, Sb
__device__ float g_ak[B_];    // a5 . k6
__device__ float g_aa[B_];    // |a5|^2
__device__ float g_A2[B_];    // a1 . k2
__device__ float g_A3[B_];    // a1 . k3
__device__ float g_Aaa[B_];   // |a1|^2
__device__ float g_T[B_];     // sum_n w6 w5
__device__ __align__(16) float g_state[B_ * 768];

#define RED(i) (g_red + (size_t)(i) * RBN)

// ---------------- helpers ----------------
__device__ __forceinline__ float sigf(float x) { return 1.f / (1.f + expf(-x)); }
__device__ __forceinline__ float softplusf(float x) { return x > 20.f ? x : log1pf(expf(x)); }

// ---------------- build x = [in_data | prev_reads 0..3] ----------------
__global__ void build_x_kernel(const float* __restrict__ in_data,
                               const float* __restrict__ prev_reads) {
    int idx = blockIdx.x * blockDim.x + threadIdx.x;
    if (idx >= B_ * 320) return;
    int b = idx / 320, j = idx % 320;
    float v;
    if (j < 64) v = in_data[b * 64 + j];
    else { int i = (j - 64) >> 6, m = (j - 64) & 63; v = prev_reads[((size_t)i * B_ + b) * 64 + m]; }
    g_x[idx] = v;
}

// fused gates GEMM: gates = x Wih^T + h0 Whh^T + bih + bhh   (N=2048)
__global__ void gates_gemm_kernel(const float* __restrict__ h0,
                                  const float* __restrict__ Wih, const float* __restrict__ bih,
                                  const float* __restrict__ Whh, const float* __restrict__ bhh) {
    __shared__ __align__(16) float As[16][32];
    __shared__ __align__(16) float Bs[16][64];
    int tid = threadIdx.x;
    int m0 = blockIdx.y * 32, n0 = blockIdx.x * 64;
    int la_r = tid >> 3, la_k = (tid & 7) * 2;
    int lb_r = tid >> 2, lb_k = (tid & 3) * 4;
    int ty = tid >> 4, tx = tid & 15;
    float acc[2][4] = {};
    for (int pass = 0; pass < 2; ++pass) {
        const float* A = pass ? h0 : g_x;
        const float* Bw = pass ? Whh : Wih;
        int K = pass ? 512 : 320;
        for (int k0 = 0; k0 < K; k0 += 16) {
            float2 av = *(const float2*)(A + (size_t)(m0 + la_r) * K + k0 + la_k);
            float4 bv = *(const float4*)(Bw + (size_t)(n0 + lb_r) * K + k0 + lb_k);
            __syncthreads();
            As[la_k][la_r] = av.x; As[la_k + 1][la_r] = av.y;
            Bs[lb_k + 0][lb_r] = bv.x; Bs[lb_k + 1][lb_r] = bv.y;
            Bs[lb_k + 2][lb_r] = bv.z; Bs[lb_k + 3][lb_r] = bv.w;
            __syncthreads();
#pragma unroll
            for (int kk = 0; kk < 16; kk++) {
                float2 a = *(const float2*)&As[kk][ty << 1];
                float4 b = *(const float4*)&Bs[kk][tx << 2];
                acc[0][0] += a.x * b.x; acc[0][1] += a.x * b.y; acc[0][2] += a.x * b.z; acc[0][3] += a.x * b.w;
                acc[1][0] += a.y * b.x; acc[1][1] += a.y * b.y; acc[1][2] += a.y * b.z; acc[1][3] += a.y * b.w;
            }
        }
    }
#pragma unroll
    for (int i = 0; i < 2; i++) {
        int m = m0 + (ty << 1) + i;
#pragma unroll
        for (int j = 0; j < 4; j++) {
            int n = n0 + (tx << 2) + j;
            g_gates[(size_t)m * 2048 + n] = acc[i][j] + bih[n] + bhh[n];
        }
    }
}

// fused head-param GEMM (32x32 tiles): g_pe = c @ [W_addr; W_ea]^T + bias  (N=1072, K=512)
__global__ void headpe_gemm_kernel(const float* __restrict__ Wa, const float* __restrict__ ba,
                                   const float* __restrict__ We, const float* __restrict__ be) {
    __shared__ __align__(16) float As[16][32];
    __shared__ __align__(16) float Bs[16][32];
    const int NN = 1072, N1 = 560, K = 512;
    int tid = threadIdx.x;
    int m0 = blockIdx.y * 32, n0 = blockIdx.x * 32;
    int l_r = tid >> 3, l_k = (tid & 7) * 2;
    int ty = tid >> 4, tx = tid & 15;
    int brow = n0 + l_r;
    const float* browp = (brow < N1) ? (Wa + (size_t)brow * K)
                                     : (We + (size_t)(brow - N1) * K);
    float acc[2][2] = {};
    for (int k0 = 0; k0 < K; k0 += 16) {
        float2 av = *(const float2*)(g_c + (size_t)(m0 + l_r) * K + k0 + l_k);
        float2 bv = make_float2(0.f, 0.f);
        if (brow < NN) bv = *(const float2*)(browp + k0 + l_k);
        __syncthreads();
        As[l_k][l_r] = av.x; As[l_k + 1][l_r] = av.y;
        Bs[l_k][l_r] = bv.x; Bs[l_k + 1][l_r] = bv.y;
        __syncthreads();
#pragma unroll
        for (int kk = 0; kk < 16; kk++) {
            float2 a = *(const float2*)&As[kk][ty << 1];
            float2 b = *(const float2*)&Bs[kk][tx << 1];
            acc[0][0] += a.x * b.x; acc[0][1] += a.x * b.y;
            acc[1][0] += a.y * b.x; acc[1][1] += a.y * b.y;
        }
    }
#pragma unroll
    for (int i = 0; i < 2; i++) {
        int m = m0 + (ty << 1) + i;
#pragma unroll
        for (int j = 0; j < 2; j++) {
            int n = n0 + (tx << 1) + j;
            if (n < NN) {
                float bias = (n < N1) ? ba[n] : be[n - N1];
                g_pe[(size_t)m * 1072 + n] = acc[i][j] + bias;
            }
        }
    }
}

// output GEMM: out = sigmoid(state @ W_out^T + b_out)   (N=64, K=768)
__global__ void out_gemm_kernel(const float* __restrict__ Wo, const float* __restrict__ bo,
                                float* __restrict__ C) {
    __shared__ __align__(16) float As[16][32];
    __shared__ __align__(16) float Bs[16][64];
    const int NN = 64, K = 768;
    int tid = threadIdx.x;
    int m0 = blockIdx.y * 32, n0 = 0;
    int la_r = tid >> 3, la_k = (tid & 7) * 2;
    int lb_r = tid >> 2, lb_k = (tid & 3) * 4;
    int ty = tid >> 4, tx = tid & 15;
    float acc[2][4] = {};
    for (int k0 = 0; k0 < K; k0 += 16) {
        float2 av = *(const float2*)(g_state + (size_t)(m0 + la_r) * K + k0 + la_k);
        float4 bv = *(const float4*)(Wo + (size_t)(n0 + lb_r) * K + k0 + lb_k);
        __syncthreads();
        As[la_k][la_r] = av.x; As[la_k + 1][la_r] = av.y;
        Bs[lb_k + 0][lb_r] = bv.x; Bs[lb_k + 1][lb_r] = bv.y;
        Bs[lb_k + 2][lb_r] = bv.z; Bs[lb_k + 3][lb_r] = bv.w;
        __syncthreads();
#pragma unroll
        for (int kk = 0; kk < 16; kk++) {
            float2 a = *(const float2*)&As[kk][ty << 1];
            float4 b = *(const float4*)&Bs[kk][tx << 2];
            acc[0][0] += a.x * b.x; acc[0][1] += a.x * b.y; acc[0][2] += a.x * b.z; acc[0][3] += a.x * b.w;
            acc[1][0] += a.y * b.x; acc[1][1] += a.y * b.y; acc[1][2] += a.y * b.z; acc[1][3] += a.y * b.w;
        }
    }
#pragma unroll
    for (int i = 0; i < 2; i++) {
        int m = m0 + (ty << 1) + i;
#pragma unroll
        for (int j = 0; j < 4; j++) {
            int n = n0 + (tx << 2) + j;
            C[(size_t)m * NN + n] = sigf(acc[i][j] + bo[n]);
        }
    }
}

// ---------------- LSTM pointwise ----------------
__global__ void lstm_kernel(const float* __restrict__ c0) {
    int idx = blockIdx.x * blockDim.x + threadIdx.x;
    if (idx >= B_ * C_) return;
    int b = idx / C_, j = idx % C_;
    const float* gr = g_gates + (size_t)b * 2048;
    float ig = gr[j], fg = gr[512 + j], gg = gr[1024 + j], og = gr[1536 + j];
    float c = sigf(fg) * c0[idx] + sigf(ig) * tanhf(gg);
    g_c[idx] = c;
    g_h[idx] = sigf(og) * tanhf(c);
}

// ---------------- head activations ----------------
__global__ void head_act_kernel() {
    int b = blockIdx.x;
    int lane = threadIdx.x;   // 32 threads
    for (int hd = 0; hd < 7; ++hd) {
        const float* p = g_pe + (size_t)b * 1072 + hd * 70;
        float ssq = 0.f;
        for (int j = lane; j < 64; j += 32) {
            float kv = tanhf(p[j]);
            g_k[((size_t)hd * B_ + b) * 64 + j] = kv;
            ssq += kv * kv;
        }
#pragma unroll
        for (int o = 16; o; o >>= 1) ssq += __shfl_xor_sync(0xffffffffu, ssq, o);
        if (lane == 0) {
            int hb = hd * B_ + b;
            g_knorm[hb] = sqrtf(ssq);
            g_beta[hb] = softplusf(p[64]);
            g_gate[hb] = sigf(p[65]);
            float s0 = p[66], s1 = p[67], s2 = p[68];
            float mx = fmaxf(s0, fmaxf(s1, s2));
            float e0 = expf(s0 - mx), e1 = expf(s1 - mx), e2 = expf(s2 - mx);
            float inv = 1.f / (e0 + e1 + e2);
            g_s[hb * 3 + 0] = e0 * inv; g_s[hb * 3 + 1] = e1 * inv; g_s[hb * 3 + 2] = e2 * inv;
            g_gamma[hb] = 1.f + softplusf(p[69]);
        }
    }
    for (int wh = 0; wh < 3; ++wh) {
        const float* ea = g_pe + (size_t)b * 1072 + 560 + wh * 128;
        for (int j = lane; j < 64; j += 32) {
            g_e[((size_t)wh * B_ + b) * 64 + j] = sigf(ea[j]);
            g_a[((size_t)wh * B_ + b) * 64 + j] = tanhf(ea[64 + j]);
        }
    }
    // scalars: a5.k6, |a5|^2, a1.k2, a1.k3, |a1|^2
    {
        const float* ea2 = g_pe + (size_t)b * 1072 + 560 + 2 * 128;
        const float* ea0 = g_pe + (size_t)b * 1072 + 560 + 0 * 128;
        const float* p6  = g_pe + (size_t)b * 1072 + 6 * 70;
        const float* p2  = g_pe + (size_t)b * 1072 + 2 * 70;
        const float* p3  = g_pe + (size_t)b * 1072 + 3 * 70;
        float pak = 0.f, paa = 0.f, pa2 = 0.f, pa3 = 0.f, p11 = 0.f;
        for (int j = lane; j < 64; j += 32) {
            float a5v = tanhf(ea2[64 + j]);
            float k6v = tanhf(p6[j]);
            float a1v = tanhf(ea0[64 + j]);
            float k2v = tanhf(p2[j]);
            float k3v = tanhf(p3[j]);
            pak += a5v * k6v; paa += a5v * a5v;
            pa2 += a1v * k2v; pa3 += a1v * k3v; p11 += a1v * a1v;
        }
#pragma unroll
        for (int o = 16; o; o >>= 1) {
            pak += __shfl_xor_sync(0xffffffffu, pak, o);
            paa += __shfl_xor_sync(0xffffffffu, paa, o);
            pa2 += __shfl_xor_sync(0xffffffffu, pa2, o);
            pa3 += __shfl_xor_sync(0xffffffffu, pa3, o);
            p11 += __shfl_xor_sync(0xffffffffu, p11, o);
        }
        if (lane == 0) {
            g_ak[b] = pak; g_aa[b] = paa;
            g_A2[b] = pa2; g_A3[b] = pa3; g_Aaa[b] = p11;
        }
    }
}

// =================== persistent grid-stride memory passes ===================
#define PASS_HEAD()                                                         \
    int tid = threadIdx.x, lane = tid & 31, warp = tid >> 5;                \
    int c = lane & 7, rg = lane >> 3, col0 = c * 8;                         \
    int p0 = (NPAIRS * blockIdx.x) / NPASSBLK;                              \
    int p1 = (NPAIRS * (blockIdx.x + 1)) / NPASSBLK;                        \
    int Lend = p1 * 8;

#define LOADOP(dst, baseptr) {                                              \
    const float4* _q = (const float4*)((baseptr) + col0);                   \
    float4 _u0 = __ldg(_q), _u1 = __ldg(_q + 1);                            \
    dst[0] = pk(_u0.x, _u0.y); dst[1] = pk(_u0.z, _u0.w);                   \
    dst[2] = pk(_u1.x, _u1.y); dst[3] = pk(_u1.z, _u1.w); }
#define LOADOPN(dst, baseptr) {                                             \
    const float4* _q = (const float4*)((baseptr) + col0);                   \
    float4 _u0 = __ldg(_q), _u1 = __ldg(_q + 1);                            \
    dst[0] = pk(-_u0.x, -_u0.y); dst[1] = pk(-_u0.z, -_u0.w);               \
    dst[2] = pk(-_u1.x, -_u1.y); dst[3] = pk(-_u1.z, -_u1.w); }

__device__ __forceinline__ void reads_epilogue(px2* acc, float (*sred)[64],
                                               int lane, int warp, int c, int tid,
                                               int pair, int slot) {
    float va[8];
#pragma unroll
    for (int i = 0; i < 4; ++i) { float2 f = up(acc[i]); va[2 * i] = f.x; va[2 * i + 1] = f.y; }
#pragma unroll
    for (int t = 0; t < 8; ++t) {
        va[t] += __shfl_xor_sync(0xffffffffu, va[t], 8);
        va[t] += __shfl_xor_sync(0xffffffffu, va[t], 16);
    }
    if (lane < 8) {
#pragma unroll
        for (int t = 0; t < 8; ++t) sred[warp][c * 8 + t] = va[t];
    }
    __syncthreads();
    if (tid < 64) {
        float s = 0.f;
#pragma unroll
        for (int wv = 0; wv < 8; ++wv) s += sred[wv][tid];
        g_rpart[(size_t)slot * B_ * 16 * 64 + (size_t)pair * 64 + tid] = s;
    }
    __syncthreads();
}

// ---- Pass A: 11 reductions on mem0 (heads 0-3 material), reduce-scatter ----
// slots: 0:dot0 1:dot1 2:nrm0 3:u2a 4:u2b 5:u3a 6:u3b 7:v1a 8:v2a 9:v3a 10:v4a
__global__ __launch_bounds__(256, 2) void passA_kernel(const float* __restrict__ mem0) {
    PASS_HEAD();
    float4 bufA[4], bufB[4];
#define LD_A(L) { size_t n = (size_t)(L) * 32 + warp * 4 + rg;              \
        const float4* p = (const float4*)(mem0 + n * 64 + col0);            \
        bufA[(L) & 3] = __ldcs(p); bufB[(L) & 3] = __ldcs(p + 1); }
    LD_A(p0 * 8); LD_A(p0 * 8 + 1); LD_A(p0 * 8 + 2);
    px2 k0[4], k1[4], k2[4], k3[4], e1[4], a1[4];
    int bcur = -1;
    px2 pz = pk(0.f, 0.f);
    bool oddc = (c & 1), bit1 = (c & 2);
    int sbase = (c == 0) ? 0 : (c == 1) ? 6 : (c == 2) ? 3 : 9;
    for (int p = p0; p < p1; ++p) {
        int b = p >> 4;
        if (b != bcur) {
            bcur = b;
            LOADOP(k0, g_k + ((size_t)0 * B_ + b) * 64);
            LOADOP(k1, g_k + ((size_t)1 * B_ + b) * 64);
            LOADOP(k2, g_k + ((size_t)2 * B_ + b) * 64);
            LOADOP(k3, g_k + ((size_t)3 * B_ + b) * 64);
            LOADOP(e1, g_e + ((size_t)0 * B_ + b) * 64);
            LOADOP(a1, g_a + ((size_t)0 * B_ + b) * 64);
        }
#pragma unroll
        for (int it = 0; it < 8; ++it) {
            int L = p * 8 + it;
            if (L + 3 < Lend) LD_A(L + 3);
            size_t n = (size_t)L * 32 + warp * 4 + rg;
            float4 A = bufA[it & 3], Bv = bufB[it & 3];
            px2 v[4] = { pk(A.x, A.y), pk(A.z, A.w), pk(Bv.x, Bv.y), pk(Bv.z, Bv.w) };
            px2 d0 = pz, d1 = pz, nr = pz, u2a = pz, u2b = pz, u3a = pz, u3b = pz;
            px2 v1a = pz, v2a = pz, v3a = pz, v4a = pz;
#pragma unroll
            for (int i = 0; i < 4; ++i) {
                px2 ve = fma2(v[i], e1[i], pz);
                d0  = fma2(v[i], k0[i], d0);
                d1  = fma2(v[i], k1[i], d1);
                nr  = fma2(v[i], v[i], nr);
                u2a = fma2(v[i], k2[i], u2a);
                u3a = fma2(v[i], k3[i], u3a);
                u2b = fma2(ve, k2[i], u2b);
                u3b = fma2(ve, k3[i], u3b);
                v1a = fma2(v[i], a1[i], v1a);
                v3a = fma2(ve, a1[i], v3a);
                v2a = fma2(ve, v[i], v2a);
                v4a = fma2(ve, ve, v4a);
            }
            float s[11]; float2 f;
            f = up(d0);  s[0] = f.x + f.y;
            f = up(d1);  s[1] = f.x + f.y;
            f = up(nr);  s[2] = f.x + f.y;
            f = up(u2a); s[3] = f.x + f.y;
            f = up(u2b); s[4] = f.x + f.y;
            f = up(u3a); s[5] = f.x + f.y;
            f = up(u3b); s[6] = f.x + f.y;
            f = up(v1a); s[7] = f.x + f.y;
            f = up(v2a); s[8] = f.x + f.y;
            f = up(v3a); s[9] = f.x + f.y;
            f = up(v4a); s[10] = f.x + f.y;
            // reduce-scatter over 8 lanes (c bits)
#pragma unroll
            for (int t = 0; t < 11; ++t) s[t] += __shfl_xor_sync(0xffffffffu, s[t], 1);
            float kk[6];
            kk[0] = oddc ? s[6]  : s[0];
            kk[1] = oddc ? s[7]  : s[1];
            kk[2] = oddc ? s[8]  : s[2];
            kk[3] = oddc ? s[9]  : s[3];
            kk[4] = oddc ? s[10] : s[4];
            kk[5] = oddc ? s[10] : s[5];
#pragma unroll
            for (int t = 0; t < 6; ++t) kk[t] += __shfl_xor_sync(0xffffffffu, kk[t], 2);
            float m0v = bit1 ? kk[3] : kk[0];
            float m1v = bit1 ? kk[4] : kk[1];
            float m2v = bit1 ? kk[5] : kk[2];
            m0v += __shfl_xor_sync(0xffffffffu, m0v, 4);
            m1v += __shfl_xor_sync(0xffffffffu, m1v, 4);
            m2v += __shfl_xor_sync(0xffffffffu, m2v, 4);
            // classes: c0:{0,1,2} c1:{6,7,8} c2:{3,4,5} c3:{9,10}
            if (c < 4) {
                g_red[(size_t)sbase * RBN + n] = m0v;
                g_red[(size_t)(sbase + 1) * RBN + n] = m1v;
                if (c < 3) g_red[(size_t)(sbase + 2) * RBN + n] = m2v;
            }
        }
    }
}

// ---- Pass C: reads0 (w0,m0), m1 regs, reads2 (w2,m1), update -> write v2, dot4, dot5, nrm2 ----
// slots: 0:dot4 1:dot5 2:nrm2
__global__ __launch_bounds__(256, 2) void passC_kernel(const float* __restrict__ mem0) {
    __shared__ float sred[8][64];
    PASS_HEAD();
    const float* wp0 = g_w + 0 * RBN;
    const float* wp1 = g_w + 1 * RBN;
    const float* wp2 = g_w + 2 * RBN;
    const float* wp3 = g_w + 3 * RBN;
    float4 bufA[4], bufB[4];
#define LD_C(L) { size_t n = (size_t)(L) * 32 + warp * 4 + rg;              \
        const float4* p = (const float4*)(mem0 + n * 64 + col0);            \
        bufA[(L) & 3] = __ldcs(p); bufB[(L) & 3] = __ldcs(p + 1); }
    LD_C(p0 * 8); LD_C(p0 * 8 + 1);
    px2 k4[4], k5[4], ne1[4], a1[4], ne3[4], a3[4];
    int bcur = -1;
    px2 pz = pk(0.f, 0.f);
    for (int p = p0; p < p1; ++p) {
        int b = p >> 4;
        if (b != bcur) {
            bcur = b;
            LOADOP(k4, g_k + ((size_t)4 * B_ + b) * 64);
            LOADOP(k5, g_k + ((size_t)5 * B_ + b) * 64);
            LOADOPN(ne1, g_e + ((size_t)0 * B_ + b) * 64);
            LOADOP(a1, g_a + ((size_t)0 * B_ + b) * 64);
            LOADOPN(ne3, g_e + ((size_t)1 * B_ + b) * 64);
            LOADOP(a3, g_a + ((size_t)1 * B_ + b) * 64);
        }
        px2 acc0[4] = { pz, pz, pz, pz };
        px2 acc2[4] = { pz, pz, pz, pz };
#pragma unroll
        for (int it = 0; it < 8; ++it) {
            int L = p * 8 + it;
            if (L + 2 < Lend) LD_C(L + 2);
            size_t n = (size_t)L * 32 + warp * 4 + rg;
            float w0 = __ldg(wp0 + n), w1 = __ldg(wp1 + n);
            float w2 = __ldg(wp2 + n), w3 = __ldg(wp3 + n);
            float4 A = bufA[it & 3], Bv = bufB[it & 3];
            px2 v[4] = { pk(A.x, A.y), pk(A.z, A.w), pk(Bv.x, Bv.y), pk(Bv.z, Bv.w) };
            px2 w0p = pk(w0, w0), w1p = pk(w1, w1), w2p = pk(w2, w2), w3p = pk(w3, w3);
            px2 d4 = pz, d5 = pz, nr = pz;
#pragma unroll
            for (int i = 0; i < 4; ++i) {
                acc0[i] = fma2(w0p, v[i], acc0[i]);              // reads0 on m0
                px2 t = fma2(ne1[i], v[i], a1[i]);
                px2 m1 = fma2(w1p, t, v[i]);
                acc2[i] = fma2(w2p, m1, acc2[i]);                // reads2 on m1
                px2 t3 = fma2(ne3[i], m1, a3[i]);
                px2 m2 = fma2(w3p, t3, m1);
                v[i] = m2;
                d4 = fma2(m2, k4[i], d4);
                d5 = fma2(m2, k5[i], d5);
                nr = fma2(m2, m2, nr);
            }
            float* po = g_mem + n * 64 + col0;
            float2 f0 = up(v[0]), f1 = up(v[1]);
            __stcs((float4*)po, make_float4(f0.x, f0.y, f1.x, f1.y));
            float2 f2 = up(v[2]), f3 = up(v[3]);
            __stcs((float4*)po + 1, make_float4(f2.x, f2.y, f3.x, f3.y));
            float2 fd4 = up(d4), fd5 = up(d5), fn = up(nr);
            float s0 = fd4.x + fd4.y, s1 = fd5.x + fd5.y, sn = fn.x + fn.y;
#pragma unroll
            for (int o = 1; o <= 4; o <<= 1) {
                s0 += __shfl_xor_sync(0xffffffffu, s0, o);
                s1 += __shfl_xor_sync(0xffffffffu, s1, o);
                sn += __shfl_xor_sync(0xffffffffu, sn, o);
            }
            // lane-distributed store: lane c stores slot c (c<3)
            float outv = (c == 0) ? s0 : (c == 1) ? s1 : sn;
            if (c < 3) g_red[(size_t)c * RBN + n] = outv;
        }
        reads_epilogue(acc0, sred, lane, warp, c, tid, p, 0);
        reads_epilogue(acc2, sred, lane, warp, c, tid, p, 1);
    }
}

// ---- Pass D: reads4 + algebraic reductions for head 6 on v2 (NO memory write) ----
// values: 0:d6a 1:d6b 2:q1 3:q2 4:p1 5:p2 -> slots {0,1,3,4,5,6} (slot2 = nrm2 preserved)
__global__ __launch_bounds__(256, 2) void passD_kernel() {
    __shared__ float sred[8][64];
    PASS_HEAD();
    const float* wp4 = g_w + 4 * RBN;
    float4 bufA[4], bufB[4];
#define LD_D(L) { size_t n = (size_t)(L) * 32 + warp * 4 + rg;              \
        const float4* p = (const float4*)(g_mem + n * 64 + col0);           \
        bufA[(L) & 3] = __ldcs(p); bufB[(L) & 3] = __ldcs(p + 1); }
    LD_D(p0 * 8); LD_D(p0 * 8 + 1); LD_D(p0 * 8 + 2);
    px2 k6[4], ek[4], e5[4], es[4], a5[4], ea[4];
    int bcur = -1;
    px2 pz = pk(0.f, 0.f);
    bool oddc = (c & 1), bit1 = (c & 2);
    // classes: c0:{v0,v1}->slots{0,1}; c1:{v3,v4}->slots{4,5}; c2:{v2}->slot{3}; c3:{v5}->slot{6}
    int slotA = (c == 0) ? 0 : (c == 1) ? 4 : (c == 2) ? 3 : 6;
    int slotB = (c == 0) ? 1 : 5;
    for (int p = p0; p < p1; ++p) {
        int b = p >> 4;
        if (b != bcur) {
            bcur = b;
            float kk[8], ee[8], av[8];
            const float4* qk = (const float4*)(g_k + ((size_t)6 * B_ + b) * 64 + col0);
            const float4* qe = (const float4*)(g_e + ((size_t)2 * B_ + b) * 64 + col0);
            const float4* qa = (const float4*)(g_a + ((size_t)2 * B_ + b) * 64 + col0);
            *(float4*)&kk[0] = __ldg(qk); *(float4*)&kk[4] = __ldg(qk + 1);
            *(float4*)&ee[0] = __ldg(qe); *(float4*)&ee[4] = __ldg(qe + 1);
            *(float4*)&av[0] = __ldg(qa); *(float4*)&av[4] = __ldg(qa + 1);
#pragma unroll
            for (int i = 0; i < 4; ++i) {
                float k0v = kk[2*i], k1v = kk[2*i+1];
                float e0v = ee[2*i], e1v = ee[2*i+1];
                float a0v = av[2*i], a1v = av[2*i+1];
                k6[i] = pk(k0v, k1v);
                e5[i] = pk(e0v, e1v);
                ek[i] = pk(e0v * k0v, e1v * k1v);
                es[i] = pk(e0v * e0v, e1v * e1v);
                a5[i] = pk(a0v, a1v);
                ea[i] = pk(e0v * a0v, e1v * a1v);
            }
        }
        px2 acc[4] = { pz, pz, pz, pz };
#pragma unroll
        for (int it = 0; it < 8; ++it) {
            int L = p * 8 + it;
            if (L + 3 < Lend) LD_D(L + 3);
            size_t n = (size_t)L * 32 + warp * 4 + rg;
            float w4 = __ldg(wp4 + n);
            float4 A = bufA[it & 3], Bv = bufB[it & 3];
            px2 v[4] = { pk(A.x, A.y), pk(A.z, A.w), pk(Bv.x, Bv.y), pk(Bv.z, Bv.w) };
            px2 w4p = pk(w4, w4);
            px2 d6a = pz, d6b = pz, q1 = pz, q2 = pz, p1v = pz, p2v = pz;
#pragma unroll
            for (int i = 0; i < 4; ++i) {
                acc[i] = fma2(w4p, v[i], acc[i]);               // reads4 on m2
                px2 vsq = fma2(v[i], v[i], pz);
                d6a = fma2(v[i], k6[i], d6a);
                d6b = fma2(v[i], ek[i], d6b);
                q1  = fma2(vsq, e5[i], q1);
                q2  = fma2(vsq, es[i], q2);
                p1v = fma2(v[i], a5[i], p1v);
                p2v = fma2(v[i], ea[i], p2v);
            }
            float s[6]; float2 f;
            f = up(d6a); s[0] = f.x + f.y;
            f = up(d6b); s[1] = f.x + f.y;
            f = up(q1);  s[2] = f.x + f.y;
            f = up(q2);  s[3] = f.x + f.y;
            f = up(p1v); s[4] = f.x + f.y;
            f = up(p2v); s[5] = f.x + f.y;
#pragma unroll
            for (int t = 0; t < 6; ++t) s[t] += __shfl_xor_sync(0xffffffffu, s[t], 1);
            float kk0 = oddc ? s[3] : s[0];
            float kk1 = oddc ? s[4] : s[1];
            float kk2 = oddc ? s[5] : s[2];
            kk0 += __shfl_xor_sync(0xffffffffu, kk0, 2);
            kk1 += __shfl_xor_sync(0xffffffffu, kk1, 2);
            kk2 += __shfl_xor_sync(0xffffffffu, kk2, 2);
            float m0v = bit1 ? kk2 : kk0;
            float m1v = bit1 ? kk2 : kk1;   // m1v only valid for c<2 classes
            m0v += __shfl_xor_sync(0xffffffffu, m0v, 4);
            m1v += __shfl_xor_sync(0xffffffffu, m1v, 4);
            if (c < 4) g_red[(size_t)slotA * RBN + n] = m0v;
            if (c < 2) g_red[(size_t)slotB * RBN + n] = m1v;
        }
        reads_epilogue(acc, sred, lane, warp, c, tid, p, 2);
    }
}

// ---- Pass E: Sa = colsum(w6, v2), Sb = colsum(w6*w5, v2) ----
__global__ __launch_bounds__(256, 2) void passE_kernel() {
    __shared__ float sredA[8][64];
    __shared__ float sredB[8][64];
    PASS_HEAD();
    const float* wp5 = g_w + 5 * RBN;
    const float* wp6 = g_w + 6 * RBN;
    float4 bufA[4], bufB[4];
#define LD_E(L) { size_t n = (size_t)(L) * 32 + warp * 4 + rg;              \
        const float4* p = (const float4*)(g_mem + n * 64 + col0);           \
        bufA[(L) & 3] = __ldcs(p); bufB[(L) & 3] = __ldcs(p + 1); }
    LD_E(p0 * 8); LD_E(p0 * 8 + 1); LD_E(p0 * 8 + 2);
    for (int p = p0; p < p1; ++p) {
        px2 accA[4], accB[4];
#pragma unroll
        for (int i = 0; i < 4; ++i) { accA[i] = pk(0.f, 0.f); accB[i] = pk(0.f, 0.f); }
#pragma unroll
        for (int it = 0; it < 8; ++it) {
            int L = p * 8 + it;
            if (L + 3 < Lend) LD_E(L + 3);
            size_t n = (size_t)L * 32 + warp * 4 + rg;
            float w5 = __ldg(wp5 + n), w6 = __ldg(wp6 + n);
            float4 A = bufA[it & 3], Bv = bufB[it & 3];
            px2 v[4] = { pk(A.x, A.y), pk(A.z, A.w), pk(Bv.x, Bv.y), pk(Bv.z, Bv.w) };
            px2 w6p = pk(w6, w6), w65p = pk(w6 * w5, w6 * w5);
#pragma unroll
            for (int i = 0; i < 4; ++i) {
                accA[i] = fma2(w6p, v[i], accA[i]);
                accB[i] = fma2(w65p, v[i], accB[i]);
            }
        }
        reads_epilogue(accA, sredA, lane, warp, c, tid, p, 3);
        reads_epilogue(accB, sredB, lane, warp, c, tid, p, 4);
    }
}

// ---------------- finalize helpers ----------------
__device__ __forceinline__ float block_reduce_max(float v, float* sbuf) {
#pragma unroll
    for (int o = 16; o; o >>= 1) v = fmaxf(v, __shfl_xor_sync(0xffffffffu, v, o));
    int lane = threadIdx.x & 31, w = threadIdx.x >> 5;
    if (lane == 0) sbuf[w] = v;
    __syncthreads();
    if (threadIdx.x < 32) {
        float vv = (threadIdx.x < 8) ? sbuf[threadIdx.x] : -3.4e38f;
#pragma unroll
        for (int o = 4; o; o >>= 1) vv = fmaxf(vv, __shfl_xor_sync(0xffffffffu, vv, o));
        if (threadIdx.x == 0) sbuf[0] = vv;
    }
    __syncthreads();
    v = sbuf[0];
    __syncthreads();
    return v;
}
__device__ __forceinline__ float block_reduce_sum(float v, float* sbuf) {
#pragma unroll
    for (int o = 16; o; o >>= 1) v += __shfl_xor_sync(0xffffffffu, v, o);
    int lane = threadIdx.x & 31, w = threadIdx.x >> 5;
    if (lane == 0) sbuf[w] = v;
    __syncthreads();
    if (threadIdx.x < 32) {
        float vv = (threadIdx.x < 8) ? sbuf[threadIdx.x] : 0.f;
#pragma unroll
        for (int o = 4; o; o >>= 1) vv += __shfl_xor_sync(0xffffffffu, vv, o);
        if (threadIdx.x == 0) sbuf[0] = vv;
    }
    __syncthreads();
    v = sbuf[0];
    __syncthreads();
    return v;
}

// softmax/interp/shift/sharpen from per-element score sc[] -> w_hd
__device__ __forceinline__ void fin_core(float* sc, int hd, int b, float gate,
                                         float s0, float s1, float s2, float gamma,
                                         const float* pw, float* sbuf, float* swg) {
    int tid = threadIdx.x;
    float lmax = -3.4e38f;
#pragma unroll
    for (int t = 0; t < 16; ++t) lmax = fmaxf(lmax, sc[t]);
    float bmax = block_reduce_max(lmax, sbuf);
    float lsum = 0.f;
#pragma unroll
    for (int t = 0; t < 16; ++t) { float e = __expf(sc[t] - bmax); sc[t] = e; lsum += e; }
    float bsum = block_reduce_sum(lsum, sbuf);
    float inv = 1.f / bsum;
#pragma unroll
    for (int t = 0; t < 16; ++t) {
        int idx = tid + t * 256;
        swg[idx] = gate * sc[t] * inv + (1.f - gate) * pw[idx];
    }
    __syncthreads();
    float wp[16];
    float lps = 0.f;
#pragma unroll
    for (int t = 0; t < 16; ++t) {
        int idx = tid + t * 256;
        float ws = s0 * swg[(idx + N_ - 1) & (N_ - 1)] + s1 * swg[idx]
                 + s2 * swg[(idx + 1) & (N_ - 1)];
        float p = __powf(ws, gamma);
        wp[t] = p; lps += p;
    }
    float psum = block_reduce_sum(lps, sbuf);
    float invp = 1.f / (psum + EPSV);
    float* wout = g_w + (size_t)hd * RBN + (size_t)b * N_;
#pragma unroll
    for (int t = 0; t < 16; ++t) {
        int idx = tid + t * 256;
        wout[idx] = wp[t] * invp;
    }
}

// fin for heads 0-3 after pass A: 0,1 direct; 2,3 assembled from pass-A reductions
__global__ void finA_kernel(const float* __restrict__ prevW) {
    __shared__ float swg[N_];
    __shared__ float sbuf[8];
    int b = blockIdx.x;
    int hd = blockIdx.y;          // 0..3
    int tid = threadIdx.x;
    int hb = hd * B_ + b;
    float knorm = g_knorm[hb], beta = g_beta[hb], gate = g_gate[hb], gamma = g_gamma[hb];
    float s0 = g_s[hb * 3 + 0], s1 = g_s[hb * 3 + 1], s2 = g_s[hb * 3 + 2];
    const float* pw = prevW + ((size_t)hd * B_ + b) * N_;
    const size_t base = (size_t)b * N_;
    float sc[16];
    if (hd < 2) {
        const float* dot = hd ? RED(1) : RED(0);
        const float* nrm = RED(2);
#pragma unroll
        for (int t = 0; t < 16; ++t) {
            int idx = tid + t * 256;
            float d = dot[base + idx];
            float nr = nrm[base + idx];
            sc[t] = beta * d / (sqrtf(nr) * knorm + EPSV);
        }
    } else {
        int hh = hd - 2;
        float Ax = hh ? g_A3[b] : g_A2[b];
        float Aaa = g_Aaa[b];
        const float* ua = hh ? RED(5) : RED(3);
        const float* ub = hh ? RED(6) : RED(4);
        const float* nrm = RED(2);
        const float* r5 = RED(7); const float* r6 = RED(8);
        const float* r7 = RED(9); const float* r8 = RED(10);
        const float* wp1 = g_w + 1 * RBN + base;
#pragma unroll
        for (int t = 0; t < 16; ++t) {
            int idx = tid + t * 256;
            float w1 = wp1[idx];
            float d = ua[base + idx] + w1 * (Ax - ub[base + idx]);
            float nrm1 = nrm[base + idx]
                       + 2.f * w1 * (r5[base + idx] - r6[base + idx])
                       + w1 * w1 * (Aaa - 2.f * r7[base + idx] + r8[base + idx]);
            nrm1 = fmaxf(nrm1, 0.f);
            sc[t] = beta * d / (sqrtf(nrm1) * knorm + EPSV);
        }
    }
    fin_core(sc, hd, b, gate, s0, s1, s2, gamma, pw, sbuf, swg);
}

__global__ void fin_kernel(int head0, const float* __restrict__ prevW) {
    __shared__ float swg[N_];
    __shared__ float sbuf[8];
    int b = blockIdx.x;
    int hh = blockIdx.y;
    int hd = head0 + hh;
    int tid = threadIdx.x;
    const float* dot = hh ? RED(1) : RED(0);
    const float* nrm = RED(2);
    int hb = hd * B_ + b;
    float knorm = g_knorm[hb], beta = g_beta[hb], gate = g_gate[hb], gamma = g_gamma[hb];
    float s0 = g_s[hb * 3 + 0], s1 = g_s[hb * 3 + 1], s2 = g_s[hb * 3 + 2];
    const float* pw = prevW + ((size_t)hd * B_ + b) * N_;
    const size_t base = (size_t)b * N_;
    float sc[16];
#pragma unroll
    for (int t = 0; t < 16; ++t) {
        int idx = tid + t * 256;
        float d = dot[base + idx];
        float nr = nrm[base + idx];
        sc[t] = beta * d / (sqrtf(nr) * knorm + EPSV);
    }
    fin_core(sc, hd, b, gate, s0, s1, s2, gamma, pw, sbuf, swg);
}

// fin for head 6: assemble dot6/nrm3 from pass-D reductions + w5; also T[b] = sum w6 w5
__global__ void fin6_kernel(const float* __restrict__ prevW) {
    __shared__ float swg[N_];
    __shared__ float sbuf[8];
    int b = blockIdx.x;
    int tid = threadIdx.x;
    const int hd = 6;
    int hb = hd * B_ + b;
    float knorm = g_knorm[hb], beta = g_beta[hb], gate = g_gate[hb], gamma = g_gamma[hb];
    float s0 = g_s[hb * 3 + 0], s1 = g_s[hb * 3 + 1], s2 = g_s[hb * 3 + 2];
    float ak = g_ak[b], aa = g_aa[b];
    const float* pw = prevW + ((size_t)hd * B_ + b) * N_;
    const float* wp5 = g_w + 5 * RBN + (size_t)b * N_;
    const size_t base = (size_t)b * N_;
    const float* d6ap = RED(0); const float* d6bp = RED(1);
    const float* q0p = RED(2);  const float* q1p = RED(3);
    const float* q2p = RED(4);  const float* p1p = RED(5);
    const float* p2p = RED(6);
    float sc[16];
#pragma unroll
    for (int t = 0; t < 16; ++t) {
        int idx = tid + t * 256;
        float w5 = wp5[idx];
        float d6 = d6ap[base + idx] + w5 * (ak - d6bp[base + idx]);
        float q0 = q0p[base + idx];
        float q1 = q1p[base + idx], q2 = q2p[base + idx];
        float p1 = p1p[base + idx], p2 = p2p[base + idx];
        float nrm3 = q0 + w5 * (-2.f * q1 + 2.f * p1) + w5 * w5 * (q2 - 2.f * p2 + aa);
        nrm3 = fmaxf(nrm3, 0.f);
        sc[t] = beta * d6 / (sqrtf(nrm3) * knorm + EPSV);
    }
    fin_core(sc, hd, b, gate, s0, s1, s2, gamma, pw, sbuf, swg);
    // T[b] = sum_n w6 w5
    const float* wout = g_w + 6 * RBN + base;
    float lt = 0.f;
#pragma unroll
    for (int t = 0; t < 16; ++t) {
        int idx = tid + t * 256;
        lt += wout[idx] * wp5[idx];
    }
    float T = block_reduce_sum(lt, sbuf);
    if (tid == 0) g_T[b] = T;
}

// ---------------- build state = [h | reads0 | reads2 | reads4 | reads6] ----------------
__global__ void build_state_kernel() {
    int b = blockIdx.x;
    for (int j = threadIdx.x; j < 768; j += blockDim.x) {
        float v;
        if (j < 512) v = g_h[(size_t)b * C_ + j];
        else {
            int ri = (j - 512) >> 6, m = (j - 512) & 63;
            if (ri < 3) {
                float s = 0.f;
                const float* rp = g_rpart + (size_t)ri * B_ * 16 * 64 + (size_t)b * 16 * 64 + m;
#pragma unroll
                for (int cc = 0; cc < 16; ++cc) s += rp[cc * 64];
                v = s;
            } else {
                float sa = 0.f, sb = 0.f;
                const float* rpa = g_rpart + (size_t)3 * B_ * 16 * 64 + (size_t)b * 16 * 64 + m;
                const float* rpb = g_rpart + (size_t)4 * B_ * 16 * 64 + (size_t)b * 16 * 64 + m;
#pragma unroll
                for (int cc = 0; cc < 16; ++cc) { sa += rpa[cc * 64]; sb += rpb[cc * 64]; }
                float e5 = g_e[((size_t)2 * B_ + b) * 64 + m];
                float a5 = g_a[((size_t)2 * B_ + b) * 64 + m];
                v = sa - e5 * sb + g_T[b] * a5;
            }
        }
        g_state[(size_t)b * 768 + j] = v;
    }
}

// ---------------- host ----------------
extern "C" void kernel_launch(void* const* d_in, const int* in_sizes, int n_in,
                              void* d_out, int out_size) {
    const float* in_data      = (const float*)d_in[0];
    const float* memory       = (const float*)d_in[1];
    const float* h0           = (const float*)d_in[2];
    const float* c0           = (const float*)d_in[3];
    const float* prev_weights = (const float*)d_in[4];
    const float* prev_reads   = (const float*)d_in[5];
    const float* W_ih         = (const float*)d_in[6];
    const float* b_ih         = (const float*)d_in[7];
    const float* W_hh         = (const float*)d_in[8];
    const float* b_hh         = (const float*)d_in[9];
    const float* W_out        = (const float*)d_in[10];
    const float* b_out        = (const float*)d_in[11];
    const float* W_addr       = (const float*)d_in[12];
    const float* b_addr       = (const float*)d_in[13];
    const float* W_ea         = (const float*)d_in[14];
    const float* b_ea         = (const float*)d_in[15];
    float* outp = (float*)d_out;

    // controller
    build_x_kernel<<<(B_ * 320 + 255) / 256, 256>>>(in_data, prev_reads);
    gates_gemm_kernel<<<dim3(2048 / 64, B_ / 32), 256>>>(h0, W_ih, b_ih, W_hh, b_hh);
    lstm_kernel<<<(B_ * C_ + 255) / 256, 256>>>(c0);

    // head parameters (addr + ea fused; head 7 is dead code)
    headpe_gemm_kernel<<<dim3((1072 + 31) / 32, B_ / 32), 256>>>(W_addr, b_addr, W_ea, b_ea);
    head_act_kernel<<<B_, 32>>>();

    passA_kernel<<<NPASSBLK, 256>>>(memory);
    finA_kernel<<<dim3(B_, 4), 256>>>(prev_weights);       // heads 0-3
    passC_kernel<<<NPASSBLK, 256>>>(memory);
    fin_kernel<<<dim3(B_, 2), 256>>>(4, prev_weights);     // heads 4,5 (direct on m2)
    passD_kernel<<<NPASSBLK, 256>>>();
    fin6_kernel<<<B_, 256>>>(prev_weights);                // head 6 (assembled)
    passE_kernel<<<NPASSBLK, 256>>>();

    // output
    build_state_kernel<<<B_, 256>>>();
    out_gemm_kernel<<<dim3(1, B_ / 32), 256>>>(W_out, b_out, outp);
}

// round 10
// speedup vs baseline: 1.7158x; 1.0728x over previous
#include <cuda_runtime.h>
#include <cstdint>

#define B_  256
#define N_  4096
#define M_  64
#define C_  512
#define EPSV 1e-8f
#define NPASSBLK 296
#define NPAIRS   4096
#define RBN ((size_t)B_ * N_)

// ---------------- packed f32x2 helpers (sm_103a FFMA2) ----------------
struct px2 { unsigned long long u; };
__device__ __forceinline__ px2 pk(float x, float y) {
    px2 r; asm("mov.b64 %0,{%1,%2};" : "=l"(r.u) : "f"(x), "f"(y)); return r;
}
__device__ __forceinline__ float2 up(px2 a) {
    float2 f; asm("mov.b64 {%0,%1},%2;" : "=f"(f.x), "=f"(f.y) : "l"(a.u)); return f;
}
__device__ __forceinline__ px2 fma2(px2 a, px2 b, px2 c) {
    px2 r; asm("fma.rn.f32x2 %0,%1,%2,%3;" : "=l"(r.u) : "l"(a.u), "l"(b.u), "l"(c.u)); return r;
}

// ---------------- device scratch ----------------
__device__ __align__(16) float g_mem[(size_t)B_ * N_ * M_];      // v2 working memory (written once, pass C)
__device__ __align__(16) float g_x[B_ * 320];
__device__ __align__(16) float g_gates[B_ * 2048];
__device__ __align__(16) float g_c[B_ * C_];
__device__ __align__(16) float g_h[B_ * C_];
__device__ __align__(16) float g_pe[B_ * 1072];                  // [0,560): addr params, [560,1072): ea params
__device__ __align__(16) float g_k[7 * B_ * M_];
__device__ float g_knorm[7 * B_];
__device__ float g_beta[7 * B_];
__device__ float g_gate[7 * B_];
__device__ float g_s[7 * B_ * 3];
__device__ float g_gamma[7 * B_];
__device__ __align__(16) float g_e[3 * B_ * M_];
__device__ __align__(16) float g_a[3 * B_ * M_];
__device__ __align__(16) float g_red[11 * RBN];                  // reduction slots
__device__ __align__(16) float g_w[7 * RBN];                     // per-head weights, slot = head index
__device__ __align__(16) float g_rpart[5 * B_ * 16 * M_];        // colsum partials: reads0,2,4, Sa, Sb
__device__ float g_ak[B_];    // a5 . k6
__device__ float g_aa[B_];    // |a5|^2
__device__ float g_A2[B_];    // a1 . k2
__device__ float g_A3[B_];    // a1 . k3
__device__ float g_Aaa[B_];   // |a1|^2
__device__ float g_T[B_];     // sum_n w6 w5
__device__ __align__(16) float g_state[B_ * 768];

#define RED(i) (g_red + (size_t)(i) * RBN)

// ---------------- helpers ----------------
__device__ __forceinline__ float sigf(float x) { return 1.f / (1.f + expf(-x)); }
__device__ __forceinline__ float softplusf(float x) { return x > 20.f ? x : log1pf(expf(x)); }

// ---------------- build x = [in_data | prev_reads 0..3] ----------------
__global__ void build_x_kernel(const float* __restrict__ in_data,
                               const float* __restrict__ prev_reads) {
    int idx = blockIdx.x * blockDim.x + threadIdx.x;
    if (idx >= B_ * 320) return;
    int b = idx / 320, j = idx % 320;
    float v;
    if (j < 64) v = in_data[b * 64 + j];
    else { int i = (j - 64) >> 6, m = (j - 64) & 63; v = prev_reads[((size_t)i * B_ + b) * 64 + m]; }
    g_x[idx] = v;
}

// fused gates GEMM (double-buffered): gates = x Wih^T + h0 Whh^T + bih + bhh   (N=2048)
__global__ void gates_gemm_kernel(const float* __restrict__ h0,
                                  const float* __restrict__ Wih, const float* __restrict__ bih,
                                  const float* __restrict__ Whh, const float* __restrict__ bhh) {
    __shared__ __align__(16) float As[16][32];
    __shared__ __align__(16) float Bs[16][64];
    int tid = threadIdx.x;
    int m0 = blockIdx.y * 32, n0 = blockIdx.x * 64;
    int la_r = tid >> 3, la_k = (tid & 7) * 2;
    int lb_r = tid >> 2, lb_k = (tid & 3) * 4;
    int ty = tid >> 4, tx = tid & 15;
    float acc[2][4] = {};
    for (int pass = 0; pass < 2; ++pass) {
        const float* A = pass ? h0 : g_x;
        const float* Bw = pass ? Whh : Wih;
        int K = pass ? 512 : 320;
        const float* ap = A + (size_t)(m0 + la_r) * K + la_k;
        const float* bp = Bw + (size_t)(n0 + lb_r) * K + lb_k;
        float2 av = *(const float2*)ap;
        float4 bv = *(const float4*)bp;
        for (int k0 = 0; k0 < K; k0 += 16) {
            __syncthreads();
            As[la_k][la_r] = av.x; As[la_k + 1][la_r] = av.y;
            Bs[lb_k + 0][lb_r] = bv.x; Bs[lb_k + 1][lb_r] = bv.y;
            Bs[lb_k + 2][lb_r] = bv.z; Bs[lb_k + 3][lb_r] = bv.w;
            if (k0 + 16 < K) {
                av = *(const float2*)(ap + k0 + 16);
                bv = *(const float4*)(bp + k0 + 16);
            }
            __syncthreads();
#pragma unroll
            for (int kk = 0; kk < 16; kk++) {
                float2 a = *(const float2*)&As[kk][ty << 1];
                float4 b = *(const float4*)&Bs[kk][tx << 2];
                acc[0][0] += a.x * b.x; acc[0][1] += a.x * b.y; acc[0][2] += a.x * b.z; acc[0][3] += a.x * b.w;
                acc[1][0] += a.y * b.x; acc[1][1] += a.y * b.y; acc[1][2] += a.y * b.z; acc[1][3] += a.y * b.w;
            }
        }
    }
#pragma unroll
    for (int i = 0; i < 2; i++) {
        int m = m0 + (ty << 1) + i;
#pragma unroll
        for (int j = 0; j < 4; j++) {
            int n = n0 + (tx << 2) + j;
            g_gates[(size_t)m * 2048 + n] = acc[i][j] + bih[n] + bhh[n];
        }
    }
}

// fused head-param GEMM (32x32 tiles, double-buffered): g_pe = c @ [W_addr; W_ea]^T + bias
__global__ void headpe_gemm_kernel(const float* __restrict__ Wa, const float* __restrict__ ba,
                                   const float* __restrict__ We, const float* __restrict__ be) {
    __shared__ __align__(16) float As[16][32];
    __shared__ __align__(16) float Bs[16][32];
    const int NN = 1072, N1 = 560, K = 512;
    int tid = threadIdx.x;
    int m0 = blockIdx.y * 32, n0 = blockIdx.x * 32;
    int l_r = tid >> 3, l_k = (tid & 7) * 2;
    int ty = tid >> 4, tx = tid & 15;
    int brow = n0 + l_r;
    const float* browp = (brow < N1) ? (Wa + (size_t)brow * K)
                                     : (We + (size_t)(brow - N1) * K);
    bool bok = (brow < NN);
    const float* ap = g_c + (size_t)(m0 + l_r) * K + l_k;
    float2 av = *(const float2*)ap;
    float2 bv = bok ? *(const float2*)(browp + l_k) : make_float2(0.f, 0.f);
    float acc[2][2] = {};
    for (int k0 = 0; k0 < K; k0 += 16) {
        __syncthreads();
        As[l_k][l_r] = av.x; As[l_k + 1][l_r] = av.y;
        Bs[l_k][l_r] = bv.x; Bs[l_k + 1][l_r] = bv.y;
        if (k0 + 16 < K) {
            av = *(const float2*)(ap + k0 + 16);
            bv = bok ? *(const float2*)(browp + l_k + k0 + 16) : make_float2(0.f, 0.f);
        }
        __syncthreads();
#pragma unroll
        for (int kk = 0; kk < 16; kk++) {
            float2 a = *(const float2*)&As[kk][ty << 1];
            float2 b = *(const float2*)&Bs[kk][tx << 1];
            acc[0][0] += a.x * b.x; acc[0][1] += a.x * b.y;
            acc[1][0] += a.y * b.x; acc[1][1] += a.y * b.y;
        }
    }
#pragma unroll
    for (int i = 0; i < 2; i++) {
        int m = m0 + (ty << 1) + i;
#pragma unroll
        for (int j = 0; j < 2; j++) {
            int n = n0 + (tx << 1) + j;
            if (n < NN) {
                float bias = (n < N1) ? ba[n] : be[n - N1];
                g_pe[(size_t)m * 1072 + n] = acc[i][j] + bias;
            }
        }
    }
}

// output GEMM (double-buffered): out = sigmoid(state @ W_out^T + b_out)   (N=64, K=768)
__global__ void out_gemm_kernel(const float* __restrict__ Wo, const float* __restrict__ bo,
                                float* __restrict__ C) {
    __shared__ __align__(16) float As[16][32];
    __shared__ __align__(16) float Bs[16][64];
    const int NN = 64, K = 768;
    int tid = threadIdx.x;
    int m0 = blockIdx.y * 32, n0 = 0;
    int la_r = tid >> 3, la_k = (tid & 7) * 2;
    int lb_r = tid >> 2, lb_k = (tid & 3) * 4;
    int ty = tid >> 4, tx = tid & 15;
    const float* ap = g_state + (size_t)(m0 + la_r) * K + la_k;
    const float* bp = Wo + (size_t)(n0 + lb_r) * K + lb_k;
    float2 av = *(const float2*)ap;
    float4 bv = *(const float4*)bp;
    float acc[2][4] = {};
    for (int k0 = 0; k0 < K; k0 += 16) {
        __syncthreads();
        As[la_k][la_r] = av.x; As[la_k + 1][la_r] = av.y;
        Bs[lb_k + 0][lb_r] = bv.x; Bs[lb_k + 1][lb_r] = bv.y;
        Bs[lb_k + 2][lb_r] = bv.z; Bs[lb_k + 3][lb_r] = bv.w;
        if (k0 + 16 < K) {
            av = *(const float2*)(ap + k0 + 16);
            bv = *(const float4*)(bp + k0 + 16);
        }
        __syncthreads();
#pragma unroll
        for (int kk = 0; kk < 16; kk++) {
            float2 a = *(const float2*)&As[kk][ty << 1];
            float4 b = *(const float4*)&Bs[kk][tx << 2];
            acc[0][0] += a.x * b.x; acc[0][1] += a.x * b.y; acc[0][2] += a.x * b.z; acc[0][3] += a.x * b.w;
            acc[1][0] += a.y * b.x; acc[1][1] += a.y * b.y; acc[1][2] += a.y * b.z; acc[1][3] += a.y * b.w;
        }
    }
#pragma unroll
    for (int i = 0; i < 2; i++) {
        int m = m0 + (ty << 1) + i;
#pragma unroll
        for (int j = 0; j < 4; j++) {
            int n = n0 + (tx << 2) + j;
            C[(size_t)m * NN + n] = sigf(acc[i][j] + bo[n]);
        }
    }
}

// ---------------- LSTM pointwise ----------------
__global__ void lstm_kernel(const float* __restrict__ c0) {
    int idx = blockIdx.x * blockDim.x + threadIdx.x;
    if (idx >= B_ * C_) return;
    int b = idx / C_, j = idx % C_;
    const float* gr = g_gates + (size_t)b * 2048;
    float ig = gr[j], fg = gr[512 + j], gg = gr[1024 + j], og = gr[1536 + j];
    float c = sigf(fg) * c0[idx] + sigf(ig) * tanhf(gg);
    g_c[idx] = c;
    g_h[idx] = sigf(og) * tanhf(c);
}

// ---------------- head activations (8 warps: warp hd handles head hd, warp 7 does e/a+scalars) ----
__global__ void head_act_kernel() {
    int b = blockIdx.x;
    int wid = threadIdx.x >> 5, lane = threadIdx.x & 31;
    if (wid < 7) {
        int hd = wid;
        const float* p = g_pe + (size_t)b * 1072 + hd * 70;
        float ssq = 0.f;
        for (int j = lane; j < 64; j += 32) {
            float kv = tanhf(p[j]);
            g_k[((size_t)hd * B_ + b) * 64 + j] = kv;
            ssq += kv * kv;
        }
#pragma unroll
        for (int o = 16; o; o >>= 1) ssq += __shfl_xor_sync(0xffffffffu, ssq, o);
        if (lane == 0) {
            int hb = hd * B_ + b;
            g_knorm[hb] = sqrtf(ssq);
            g_beta[hb] = softplusf(p[64]);
            g_gate[hb] = sigf(p[65]);
            float s0 = p[66], s1 = p[67], s2 = p[68];
            float mx = fmaxf(s0, fmaxf(s1, s2));
            float e0 = expf(s0 - mx), e1 = expf(s1 - mx), e2 = expf(s2 - mx);
            float inv = 1.f / (e0 + e1 + e2);
            g_s[hb * 3 + 0] = e0 * inv; g_s[hb * 3 + 1] = e1 * inv; g_s[hb * 3 + 2] = e2 * inv;
            g_gamma[hb] = 1.f + softplusf(p[69]);
        }
    } else {
        for (int wh = 0; wh < 3; ++wh) {
            const float* ea = g_pe + (size_t)b * 1072 + 560 + wh * 128;
            for (int j = lane; j < 64; j += 32) {
                g_e[((size_t)wh * B_ + b) * 64 + j] = sigf(ea[j]);
                g_a[((size_t)wh * B_ + b) * 64 + j] = tanhf(ea[64 + j]);
            }
        }
        // scalars: a5.k6, |a5|^2, a1.k2, a1.k3, |a1|^2
        const float* ea2 = g_pe + (size_t)b * 1072 + 560 + 2 * 128;
        const float* ea0 = g_pe + (size_t)b * 1072 + 560 + 0 * 128;
        const float* p6  = g_pe + (size_t)b * 1072 + 6 * 70;
        const float* p2  = g_pe + (size_t)b * 1072 + 2 * 70;
        const float* p3  = g_pe + (size_t)b * 1072 + 3 * 70;
        float pak = 0.f, paa = 0.f, pa2 = 0.f, pa3 = 0.f, p11 = 0.f;
        for (int j = lane; j < 64; j += 32) {
            float a5v = tanhf(ea2[64 + j]);
            float k6v = tanhf(p6[j]);
            float a1v = tanhf(ea0[64 + j]);
            float k2v = tanhf(p2[j]);
            float k3v = tanhf(p3[j]);
            pak += a5v * k6v; paa += a5v * a5v;
            pa2 += a1v * k2v; pa3 += a1v * k3v; p11 += a1v * a1v;
        }
#pragma unroll
        for (int o = 16; o; o >>= 1) {
            pak += __shfl_xor_sync(0xffffffffu, pak, o);
            paa += __shfl_xor_sync(0xffffffffu, paa, o);
            pa2 += __shfl_xor_sync(0xffffffffu, pa2, o);
            pa3 += __shfl_xor_sync(0xffffffffu, pa3, o);
            p11 += __shfl_xor_sync(0xffffffffu, p11, o);
        }
        if (lane == 0) {
            g_ak[b] = pak; g_aa[b] = paa;
            g_A2[b] = pa2; g_A3[b] = pa3; g_Aaa[b] = p11;
        }
    }
}

// =================== persistent grid-stride memory passes ===================
#define PASS_HEAD()                                                         \
    int tid = threadIdx.x, lane = tid & 31, warp = tid >> 5;                \
    int c = lane & 7, rg = lane >> 3, col0 = c * 8;                         \
    int p0 = (NPAIRS * blockIdx.x) / NPASSBLK;                              \
    int p1 = (NPAIRS * (blockIdx.x + 1)) / NPASSBLK;                        \
    int Lend = p1 * 8;

#define LOADOP(dst, baseptr) {                                              \
    const float4* _q = (const float4*)((baseptr) + col0);                   \
    float4 _u0 = __ldg(_q), _u1 = __ldg(_q + 1);                            \
    dst[0] = pk(_u0.x, _u0.y); dst[1] = pk(_u0.z, _u0.w);                   \
    dst[2] = pk(_u1.x, _u1.y); dst[3] = pk(_u1.z, _u1.w); }
#define LOADOPN(dst, baseptr) {                                             \
    const float4* _q = (const float4*)((baseptr) + col0);                   \
    float4 _u0 = __ldg(_q), _u1 = __ldg(_q + 1);                            \
    dst[0] = pk(-_u0.x, -_u0.y); dst[1] = pk(-_u0.z, -_u0.w);               \
    dst[2] = pk(-_u1.x, -_u1.y); dst[3] = pk(-_u1.z, -_u1.w); }

__device__ __forceinline__ void reads_epilogue(px2* acc, float (*sred)[64],
                                               int lane, int warp, int c, int tid,
                                               int pair, int slot) {
    float va[8];
#pragma unroll
    for (int i = 0; i < 4; ++i) { float2 f = up(acc[i]); va[2 * i] = f.x; va[2 * i + 1] = f.y; }
#pragma unroll
    for (int t = 0; t < 8; ++t) {
        va[t] += __shfl_xor_sync(0xffffffffu, va[t], 8);
        va[t] += __shfl_xor_sync(0xffffffffu, va[t], 16);
    }
    if (lane < 8) {
#pragma unroll
        for (int t = 0; t < 8; ++t) sred[warp][c * 8 + t] = va[t];
    }
    __syncthreads();
    if (tid < 64) {
        float s = 0.f;
#pragma unroll
        for (int wv = 0; wv < 8; ++wv) s += sred[wv][tid];
        g_rpart[(size_t)slot * B_ * 16 * 64 + (size_t)pair * 64 + tid] = s;
    }
    __syncthreads();
}

// ---- Pass A: 11 reductions on mem0 (heads 0-3 material), reduce-scatter ----
// slots: 0:dot0 1:dot1 2:nrm0 3:u2a 4:u2b 5:u3a 6:u3b 7:v1a 8:v2a 9:v3a 10:v4a
__global__ __launch_bounds__(256, 2) void passA_kernel(const float* __restrict__ mem0) {
    PASS_HEAD();
    float4 bufA[4], bufB[4];
#define LD_A(L) { size_t n = (size_t)(L) * 32 + warp * 4 + rg;              \
        const float4* p = (const float4*)(mem0 + n * 64 + col0);            \
        bufA[(L) & 3] = __ldcs(p); bufB[(L) & 3] = __ldcs(p + 1); }
    LD_A(p0 * 8); LD_A(p0 * 8 + 1); LD_A(p0 * 8 + 2);
    px2 k0[4], k1[4], k2[4], k3[4], e1[4], a1[4];
    int bcur = -1;
    px2 pz = pk(0.f, 0.f);
    bool oddc = (c & 1), bit1 = (c & 2);
    int sbase = (c == 0) ? 0 : (c == 1) ? 6 : (c == 2) ? 3 : 9;
    for (int p = p0; p < p1; ++p) {
        int b = p >> 4;
        if (b != bcur) {
            bcur = b;
            LOADOP(k0, g_k + ((size_t)0 * B_ + b) * 64);
            LOADOP(k1, g_k + ((size_t)1 * B_ + b) * 64);
            LOADOP(k2, g_k + ((size_t)2 * B_ + b) * 64);
            LOADOP(k3, g_k + ((size_t)3 * B_ + b) * 64);
            LOADOP(e1, g_e + ((size_t)0 * B_ + b) * 64);
            LOADOP(a1, g_a + ((size_t)0 * B_ + b) * 64);
        }
#pragma unroll
        for (int it = 0; it < 8; ++it) {
            int L = p * 8 + it;
            if (L + 3 < Lend) LD_A(L + 3);
            size_t n = (size_t)L * 32 + warp * 4 + rg;
            float4 A = bufA[it & 3], Bv = bufB[it & 3];
            px2 v[4] = { pk(A.x, A.y), pk(A.z, A.w), pk(Bv.x, Bv.y), pk(Bv.z, Bv.w) };
            px2 d0 = pz, d1 = pz, nr = pz, u2a = pz, u2b = pz, u3a = pz, u3b = pz;
            px2 v1a = pz, v2a = pz, v3a = pz, v4a = pz;
#pragma unroll
            for (int i = 0; i < 4; ++i) {
                px2 ve = fma2(v[i], e1[i], pz);
                d0  = fma2(v[i], k0[i], d0);
                d1  = fma2(v[i], k1[i], d1);
                nr  = fma2(v[i], v[i], nr);
                u2a = fma2(v[i], k2[i], u2a);
                u3a = fma2(v[i], k3[i], u3a);
                u2b = fma2(ve, k2[i], u2b);
                u3b = fma2(ve, k3[i], u3b);
                v1a = fma2(v[i], a1[i], v1a);
                v3a = fma2(ve, a1[i], v3a);
                v2a = fma2(ve, v[i], v2a);
                v4a = fma2(ve, ve, v4a);
            }
            float s[11]; float2 f;
            f = up(d0);  s[0] = f.x + f.y;
            f = up(d1);  s[1] = f.x + f.y;
            f = up(nr);  s[2] = f.x + f.y;
            f = up(u2a); s[3] = f.x + f.y;
            f = up(u2b); s[4] = f.x + f.y;
            f = up(u3a); s[5] = f.x + f.y;
            f = up(u3b); s[6] = f.x + f.y;
            f = up(v1a); s[7] = f.x + f.y;
            f = up(v2a); s[8] = f.x + f.y;
            f = up(v3a); s[9] = f.x + f.y;
            f = up(v4a); s[10] = f.x + f.y;
            // reduce-scatter over 8 lanes (c bits)
#pragma unroll
            for (int t = 0; t < 11; ++t) s[t] += __shfl_xor_sync(0xffffffffu, s[t], 1);
            float kk[6];
            kk[0] = oddc ? s[6]  : s[0];
            kk[1] = oddc ? s[7]  : s[1];
            kk[2] = oddc ? s[8]  : s[2];
            kk[3] = oddc ? s[9]  : s[3];
            kk[4] = oddc ? s[10] : s[4];
            kk[5] = oddc ? s[10] : s[5];
#pragma unroll
            for (int t = 0; t < 6; ++t) kk[t] += __shfl_xor_sync(0xffffffffu, kk[t], 2);
            float m0v = bit1 ? kk[3] : kk[0];
            float m1v = bit1 ? kk[4] : kk[1];
            float m2v = bit1 ? kk[5] : kk[2];
            m0v += __shfl_xor_sync(0xffffffffu, m0v, 4);
            m1v += __shfl_xor_sync(0xffffffffu, m1v, 4);
            m2v += __shfl_xor_sync(0xffffffffu, m2v, 4);
            // classes: c0:{0,1,2} c1:{6,7,8} c2:{3,4,5} c3:{9,10}
            if (c < 4) {
                g_red[(size_t)sbase * RBN + n] = m0v;
                g_red[(size_t)(sbase + 1) * RBN + n] = m1v;
                if (c < 3) g_red[(size_t)(sbase + 2) * RBN + n] = m2v;
            }
        }
    }
}

// ---- Pass C: reads0 (w0,m0), m1 regs, reads2 (w2,m1), update -> write v2, dot4, dot5, nrm2 ----
// slots: 0:dot4 1:dot5 2:nrm2
__global__ __launch_bounds__(256, 2) void passC_kernel(const float* __restrict__ mem0) {
    __shared__ float sred[8][64];
    PASS_HEAD();
    const float* wp0 = g_w + 0 * RBN;
    const float* wp1 = g_w + 1 * RBN;
    const float* wp2 = g_w + 2 * RBN;
    const float* wp3 = g_w + 3 * RBN;
    float4 bufA[4], bufB[4];
#define LD_C(L) { size_t n = (size_t)(L) * 32 + warp * 4 + rg;              \
        const float4* p = (const float4*)(mem0 + n * 64 + col0);            \
        bufA[(L) & 3] = __ldcs(p); bufB[(L) & 3] = __ldcs(p + 1); }
    LD_C(p0 * 8); LD_C(p0 * 8 + 1);
    px2 k4[4], k5[4], ne1[4], a1[4], ne3[4], a3[4];
    int bcur = -1;
    px2 pz = pk(0.f, 0.f);
    for (int p = p0; p < p1; ++p) {
        int b = p >> 4;
        if (b != bcur) {
            bcur = b;
            LOADOP(k4, g_k + ((size_t)4 * B_ + b) * 64);
            LOADOP(k5, g_k + ((size_t)5 * B_ + b) * 64);
            LOADOPN(ne1, g_e + ((size_t)0 * B_ + b) * 64);
            LOADOP(a1, g_a + ((size_t)0 * B_ + b) * 64);
            LOADOPN(ne3, g_e + ((size_t)1 * B_ + b) * 64);
            LOADOP(a3, g_a + ((size_t)1 * B_ + b) * 64);
        }
        px2 acc0[4] = { pz, pz, pz, pz };
        px2 acc2[4] = { pz, pz, pz, pz };
#pragma unroll
        for (int it = 0; it < 8; ++it) {
            int L = p * 8 + it;
            if (L + 2 < Lend) LD_C(L + 2);
            size_t n = (size_t)L * 32 + warp * 4 + rg;
            float w0 = __ldg(wp0 + n), w1 = __ldg(wp1 + n);
            float w2 = __ldg(wp2 + n), w3 = __ldg(wp3 + n);
            float4 A = bufA[it & 3], Bv = bufB[it & 3];
            px2 v[4] = { pk(A.x, A.y), pk(A.z, A.w), pk(Bv.x, Bv.y), pk(Bv.z, Bv.w) };
            px2 w0p = pk(w0, w0), w1p = pk(w1, w1), w2p = pk(w2, w2), w3p = pk(w3, w3);
            px2 d4 = pz, d5 = pz, nr = pz;
#pragma unroll
            for (int i = 0; i < 4; ++i) {
                acc0[i] = fma2(w0p, v[i], acc0[i]);              // reads0 on m0
                px2 t = fma2(ne1[i], v[i], a1[i]);
                px2 m1 = fma2(w1p, t, v[i]);
                acc2[i] = fma2(w2p, m1, acc2[i]);                // reads2 on m1
                px2 t3 = fma2(ne3[i], m1, a3[i]);
                px2 m2 = fma2(w3p, t3, m1);
                v[i] = m2;
                d4 = fma2(m2, k4[i], d4);
                d5 = fma2(m2, k5[i], d5);
                nr = fma2(m2, m2, nr);
            }
            float* po = g_mem + n * 64 + col0;
            float2 f0 = up(v[0]), f1 = up(v[1]);
            __stcs((float4*)po, make_float4(f0.x, f0.y, f1.x, f1.y));
            float2 f2 = up(v[2]), f3 = up(v[3]);
            __stcs((float4*)po + 1, make_float4(f2.x, f2.y, f3.x, f3.y));
            float2 fd4 = up(d4), fd5 = up(d5), fn = up(nr);
            float s0 = fd4.x + fd4.y, s1 = fd5.x + fd5.y, sn = fn.x + fn.y;
#pragma unroll
            for (int o = 1; o <= 4; o <<= 1) {
                s0 += __shfl_xor_sync(0xffffffffu, s0, o);
                s1 += __shfl_xor_sync(0xffffffffu, s1, o);
                sn += __shfl_xor_sync(0xffffffffu, sn, o);
            }
            // lane-distributed store: lane c stores slot c (c<3)
            float outv = (c == 0) ? s0 : (c == 1) ? s1 : sn;
            if (c < 3) g_red[(size_t)c * RBN + n] = outv;
        }
        reads_epilogue(acc0, sred, lane, warp, c, tid, p, 0);
        reads_epilogue(acc2, sred, lane, warp, c, tid, p, 1);
    }
}

// ---- Pass D: reads4 + algebraic reductions for head 6 on v2 (NO memory write) ----
// values: 0:d6a 1:d6b 2:q1 3:q2 4:p1 5:p2 -> slots {0,1,3,4,5,6} (slot2 = nrm2 preserved)
__global__ __launch_bounds__(256, 2) void passD_kernel() {
    __shared__ float sred[8][64];
    PASS_HEAD();
    const float* wp4 = g_w + 4 * RBN;
    float4 bufA[4], bufB[4];
#define LD_D(L) { size_t n = (size_t)(L) * 32 + warp * 4 + rg;              \
        const float4* p = (const float4*)(g_mem + n * 64 + col0);           \
        bufA[(L) & 3] = __ldcs(p); bufB[(L) & 3] = __ldcs(p + 1); }
    LD_D(p0 * 8); LD_D(p0 * 8 + 1); LD_D(p0 * 8 + 2);
    px2 k6[4], ek[4], e5[4], es[4], a5[4], ea[4];
    int bcur = -1;
    px2 pz = pk(0.f, 0.f);
    bool oddc = (c & 1), bit1 = (c & 2);
    // classes: c0:{v0,v1}->slots{0,1}; c1:{v3,v4}->slots{4,5}; c2:{v2}->slot{3}; c3:{v5}->slot{6}
    int slotA = (c == 0) ? 0 : (c == 1) ? 4 : (c == 2) ? 3 : 6;
    int slotB = (c == 0) ? 1 : 5;
    for (int p = p0; p < p1; ++p) {
        int b = p >> 4;
        if (b != bcur) {
            bcur = b;
            float kk[8], ee[8], av[8];
            const float4* qk = (const float4*)(g_k + ((size_t)6 * B_ + b) * 64 + col0);
            const float4* qe = (const float4*)(g_e + ((size_t)2 * B_ + b) * 64 + col0);
            const float4* qa = (const float4*)(g_a + ((size_t)2 * B_ + b) * 64 + col0);
            *(float4*)&kk[0] = __ldg(qk); *(float4*)&kk[4] = __ldg(qk + 1);
            *(float4*)&ee[0] = __ldg(qe); *(float4*)&ee[4] = __ldg(qe + 1);
            *(float4*)&av[0] = __ldg(qa); *(float4*)&av[4] = __ldg(qa + 1);
#pragma unroll
            for (int i = 0; i < 4; ++i) {
                float k0v = kk[2*i], k1v = kk[2*i+1];
                float e0v = ee[2*i], e1v = ee[2*i+1];
                float a0v = av[2*i], a1v = av[2*i+1];
                k6[i] = pk(k0v, k1v);
                e5[i] = pk(e0v, e1v);
                ek[i] = pk(e0v * k0v, e1v * k1v);
                es[i] = pk(e0v * e0v, e1v * e1v);
                a5[i] = pk(a0v, a1v);
                ea[i] = pk(e0v * a0v, e1v * a1v);
            }
        }
        px2 acc[4] = { pz, pz, pz, pz };
#pragma unroll
        for (int it = 0; it < 8; ++it) {
            int L = p * 8 + it;
            if (L + 3 < Lend) LD_D(L + 3);
            size_t n = (size_t)L * 32 + warp * 4 + rg;
            float w4 = __ldg(wp4 + n);
            float4 A = bufA[it & 3], Bv = bufB[it & 3];
            px2 v[4] = { pk(A.x, A.y), pk(A.z, A.w), pk(Bv.x, Bv.y), pk(Bv.z, Bv.w) };
            px2 w4p = pk(w4, w4);
            px2 d6a = pz, d6b = pz, q1 = pz, q2 = pz, p1v = pz, p2v = pz;
#pragma unroll
            for (int i = 0; i < 4; ++i) {
                acc[i] = fma2(w4p, v[i], acc[i]);               // reads4 on m2
                px2 vsq = fma2(v[i], v[i], pz);
                d6a = fma2(v[i], k6[i], d6a);
                d6b = fma2(v[i], ek[i], d6b);
                q1  = fma2(vsq, e5[i], q1);
                q2  = fma2(vsq, es[i], q2);
                p1v = fma2(v[i], a5[i], p1v);
                p2v = fma2(v[i], ea[i], p2v);
            }
            float s[6]; float2 f;
            f = up(d6a); s[0] = f.x + f.y;
            f = up(d6b); s[1] = f.x + f.y;
            f = up(q1);  s[2] = f.x + f.y;
            f = up(q2);  s[3] = f.x + f.y;
            f = up(p1v); s[4] = f.x + f.y;
            f = up(p2v); s[5] = f.x + f.y;
#pragma unroll
            for (int t = 0; t < 6; ++t) s[t] += __shfl_xor_sync(0xffffffffu, s[t], 1);
            float kk0 = oddc ? s[3] : s[0];
            float kk1 = oddc ? s[4] : s[1];
            float kk2 = oddc ? s[5] : s[2];
            kk0 += __shfl_xor_sync(0xffffffffu, kk0, 2);
            kk1 += __shfl_xor_sync(0xffffffffu, kk1, 2);
            kk2 += __shfl_xor_sync(0xffffffffu, kk2, 2);
            float m0v = bit1 ? kk2 : kk0;
            float m1v = bit1 ? kk2 : kk1;   // m1v only valid for c<2 classes
            m0v += __shfl_xor_sync(0xffffffffu, m0v, 4);
            m1v += __shfl_xor_sync(0xffffffffu, m1v, 4);
            if (c < 4) g_red[(size_t)slotA * RBN + n] = m0v;
            if (c < 2) g_red[(size_t)slotB * RBN + n] = m1v;
        }
        reads_epilogue(acc, sred, lane, warp, c, tid, p, 2);
    }
}

// ---- Pass E: Sa = colsum(w6, v2), Sb = colsum(w6*w5, v2) ----
__global__ __launch_bounds__(256, 2) void passE_kernel() {
    __shared__ float sredA[8][64];
    __shared__ float sredB[8][64];
    PASS_HEAD();
    const float* wp5 = g_w + 5 * RBN;
    const float* wp6 = g_w + 6 * RBN;
    float4 bufA[4], bufB[4];
#define LD_E(L) { size_t n = (size_t)(L) * 32 + warp * 4 + rg;              \
        const float4* p = (const float4*)(g_mem + n * 64 + col0);           \
        bufA[(L) & 3] = __ldcs(p); bufB[(L) & 3] = __ldcs(p + 1); }
    LD_E(p0 * 8); LD_E(p0 * 8 + 1); LD_E(p0 * 8 + 2);
    for (int p = p0; p < p1; ++p) {
        px2 accA[4], accB[4];
#pragma unroll
        for (int i = 0; i < 4; ++i) { accA[i] = pk(0.f, 0.f); accB[i] = pk(0.f, 0.f); }
#pragma unroll
        for (int it = 0; it < 8; ++it) {
            int L = p * 8 + it;
            if (L + 3 < Lend) LD_E(L + 3);
            size_t n = (size_t)L * 32 + warp * 4 + rg;
            float w5 = __ldg(wp5 + n), w6 = __ldg(wp6 + n);
            float4 A = bufA[it & 3], Bv = bufB[it & 3];
            px2 v[4] = { pk(A.x, A.y), pk(A.z, A.w), pk(Bv.x, Bv.y), pk(Bv.z, Bv.w) };
            px2 w6p = pk(w6, w6), w65p = pk(w6 * w5, w6 * w5);
#pragma unroll
            for (int i = 0; i < 4; ++i) {
                accA[i] = fma2(w6p, v[i], accA[i]);
                accB[i] = fma2(w65p, v[i], accB[i]);
            }
        }
        reads_epilogue(accA, sredA, lane, warp, c, tid, p, 3);
        reads_epilogue(accB, sredB, lane, warp, c, tid, p, 4);
    }
}

// ---------------- finalize helpers ----------------
__device__ __forceinline__ float block_reduce_max(float v, float* sbuf) {
#pragma unroll
    for (int o = 16; o; o >>= 1) v = fmaxf(v, __shfl_xor_sync(0xffffffffu, v, o));
    int lane = threadIdx.x & 31, w = threadIdx.x >> 5;
    if (lane == 0) sbuf[w] = v;
    __syncthreads();
    if (threadIdx.x < 32) {
        float vv = (threadIdx.x < 8) ? sbuf[threadIdx.x] : -3.4e38f;
#pragma unroll
        for (int o = 4; o; o >>= 1) vv = fmaxf(vv, __shfl_xor_sync(0xffffffffu, vv, o));
        if (threadIdx.x == 0) sbuf[0] = vv;
    }
    __syncthreads();
    v = sbuf[0];
    __syncthreads();
    return v;
}
__device__ __forceinline__ float block_reduce_sum(float v, float* sbuf) {
#pragma unroll
    for (int o = 16; o; o >>= 1) v += __shfl_xor_sync(0xffffffffu, v, o);
    int lane = threadIdx.x & 31, w = threadIdx.x >> 5;
    if (lane == 0) sbuf[w] = v;
    __syncthreads();
    if (threadIdx.x < 32) {
        float vv = (threadIdx.x < 8) ? sbuf[threadIdx.x] : 0.f;
#pragma unroll
        for (int o = 4; o; o >>= 1) vv += __shfl_xor_sync(0xffffffffu, vv, o);
        if (threadIdx.x == 0) sbuf[0] = vv;
    }
    __syncthreads();
    v = sbuf[0];
    __syncthreads();
    return v;
}

// softmax/interp/shift/sharpen from per-element score sc[] -> w_hd
__device__ __forceinline__ void fin_core(float* sc, int hd, int b, float gate,
                                         float s0, float s1, float s2, float gamma,
                                         const float* pw, float* sbuf, float* swg) {
    int tid = threadIdx.x;
    float lmax = -3.4e38f;
#pragma unroll
    for (int t = 0; t < 16; ++t) lmax = fmaxf(lmax, sc[t]);
    float bmax = block_reduce_max(lmax, sbuf);
    float lsum = 0.f;
#pragma unroll
    for (int t = 0; t < 16; ++t) { float e = __expf(sc[t] - bmax); sc[t] = e; lsum += e; }
    float bsum = block_reduce_sum(lsum, sbuf);
    float inv = 1.f / bsum;
#pragma unroll
    for (int t = 0; t < 16; ++t) {
        int idx = tid + t * 256;
        swg[idx] = gate * sc[t] * inv + (1.f - gate) * pw[idx];
    }
    __syncthreads();
    float wp[16];
    float lps = 0.f;
#pragma unroll
    for (int t = 0; t < 16; ++t) {
        int idx = tid + t * 256;
        float ws = s0 * swg[(idx + N_ - 1) & (N_ - 1)] + s1 * swg[idx]
                 + s2 * swg[(idx + 1) & (N_ - 1)];
        float p = __powf(ws, gamma);
        wp[t] = p; lps += p;
    }
    float psum = block_reduce_sum(lps, sbuf);
    float invp = 1.f / (psum + EPSV);
    float* wout = g_w + (size_t)hd * RBN + (size_t)b * N_;
#pragma unroll
    for (int t = 0; t < 16; ++t) {
        int idx = tid + t * 256;
        wout[idx] = wp[t] * invp;
    }
}

// fin for heads 0-3 after pass A: 0,1 direct; 2,3 assembled from pass-A reductions
__global__ void finA_kernel(const float* __restrict__ prevW) {
    __shared__ float swg[N_];
    __shared__ float sbuf[8];
    int b = blockIdx.x;
    int hd = blockIdx.y;          // 0..3
    int tid = threadIdx.x;
    int hb = hd * B_ + b;
    float knorm = g_knorm[hb], beta = g_beta[hb], gate = g_gate[hb], gamma = g_gamma[hb];
    float s0 = g_s[hb * 3 + 0], s1 = g_s[hb * 3 + 1], s2 = g_s[hb * 3 + 2];
    const float* pw = prevW + ((size_t)hd * B_ + b) * N_;
    const size_t base = (size_t)b * N_;
    float sc[16];
    if (hd < 2) {
        const float* dot = hd ? RED(1) : RED(0);
        const float* nrm = RED(2);
#pragma unroll
        for (int t = 0; t < 16; ++t) {
            int idx = tid + t * 256;
            float d = dot[base + idx];
            float nr = nrm[base + idx];
            sc[t] = beta * d / (sqrtf(nr) * knorm + EPSV);
        }
    } else {
        int hh = hd - 2;
        float Ax = hh ? g_A3[b] : g_A2[b];
        float Aaa = g_Aaa[b];
        const float* ua = hh ? RED(5) : RED(3);
        const float* ub = hh ? RED(6) : RED(4);
        const float* nrm = RED(2);
        const float* r5 = RED(7); const float* r6 = RED(8);
        const float* r7 = RED(9); const float* r8 = RED(10);
        const float* wp1 = g_w + 1 * RBN + base;
#pragma unroll
        for (int t = 0; t < 16; ++t) {
            int idx = tid + t * 256;
            float w1 = wp1[idx];
            float d = ua[base + idx] + w1 * (Ax - ub[base + idx]);
            float nrm1 = nrm[base + idx]
                       + 2.f * w1 * (r5[base + idx] - r6[base + idx])
                       + w1 * w1 * (Aaa - 2.f * r7[base + idx] + r8[base + idx]);
            nrm1 = fmaxf(nrm1, 0.f);
            sc[t] = beta * d / (sqrtf(nrm1) * knorm + EPSV);
        }
    }
    fin_core(sc, hd, b, gate, s0, s1, s2, gamma, pw, sbuf, swg);
}

__global__ void fin_kernel(int head0, const float* __restrict__ prevW) {
    __shared__ float swg[N_];
    __shared__ float sbuf[8];
    int b = blockIdx.x;
    int hh = blockIdx.y;
    int hd = head0 + hh;
    int tid = threadIdx.x;
    const float* dot = hh ? RED(1) : RED(0);
    const float* nrm = RED(2);
    int hb = hd * B_ + b;
    float knorm = g_knorm[hb], beta = g_beta[hb], gate = g_gate[hb], gamma = g_gamma[hb];
    float s0 = g_s[hb * 3 + 0], s1 = g_s[hb * 3 + 1], s2 = g_s[hb * 3 + 2];
    const float* pw = prevW + ((size_t)hd * B_ + b) * N_;
    const size_t base = (size_t)b * N_;
    float sc[16];
#pragma unroll
    for (int t = 0; t < 16; ++t) {
        int idx = tid + t * 256;
        float d = dot[base + idx];
        float nr = nrm[base + idx];
        sc[t] = beta * d / (sqrtf(nr) * knorm + EPSV);
    }
    fin_core(sc, hd, b, gate, s0, s1, s2, gamma, pw, sbuf, swg);
}

// fin for head 6: assemble dot6/nrm3 from pass-D reductions + w5; also T[b] = sum w6 w5
__global__ void fin6_kernel(const float* __restrict__ prevW) {
    __shared__ float swg[N_];
    __shared__ float sbuf[8];
    int b = blockIdx.x;
    int tid = threadIdx.x;
    const int hd = 6;
    int hb = hd * B_ + b;
    float knorm = g_knorm[hb], beta = g_beta[hb], gate = g_gate[hb], gamma = g_gamma[hb];
    float s0 = g_s[hb * 3 + 0], s1 = g_s[hb * 3 + 1], s2 = g_s[hb * 3 + 2];
    float ak = g_ak[b], aa = g_aa[b];
    const float* pw = prevW + ((size_t)hd * B_ + b) * N_;
    const float* wp5 = g_w + 5 * RBN + (size_t)b * N_;
    const size_t base = (size_t)b * N_;
    const float* d6ap = RED(0); const float* d6bp = RED(1);
    const float* q0p = RED(2);  const float* q1p = RED(3);
    const float* q2p = RED(4);  const float* p1p = RED(5);
    const float* p2p = RED(6);
    float sc[16];
#pragma unroll
    for (int t = 0; t < 16; ++t) {
        int idx = tid + t * 256;
        float w5 = wp5[idx];
        float d6 = d6ap[base + idx] + w5 * (ak - d6bp[base + idx]);
        float q0 = q0p[base + idx];
        float q1 = q1p[base + idx], q2 = q2p[base + idx];
        float p1 = p1p[base + idx], p2 = p2p[base + idx];
        float nrm3 = q0 + w5 * (-2.f * q1 + 2.f * p1) + w5 * w5 * (q2 - 2.f * p2 + aa);
        nrm3 = fmaxf(nrm3, 0.f);
        sc[t] = beta * d6 / (sqrtf(nrm3) * knorm + EPSV);
    }
    fin_core(sc, hd, b, gate, s0, s1, s2, gamma, pw, sbuf, swg);
    // T[b] = sum_n w6 w5
    const float* wout = g_w + 6 * RBN + base;
    float lt = 0.f;
#pragma unroll
    for (int t = 0; t < 16; ++t) {
        int idx = tid + t * 256;
        lt += wout[idx] * wp5[idx];
    }
    float T = block_reduce_sum(lt, sbuf);
    if (tid == 0) g_T[b] = T;
}

// ---------------- build state = [h | reads0 | reads2 | reads4 | reads6] ----------------
__global__ void build_state_kernel() {
    int b = blockIdx.x;
    for (int j = threadIdx.x; j < 768; j += blockDim.x) {
        float v;
        if (j < 512) v = g_h[(size_t)b * C_ + j];
        else {
            int ri = (j - 512) >> 6, m = (j - 512) & 63;
            if (ri < 3) {
                float s = 0.f;
                const float* rp = g_rpart + (size_t)ri * B_ * 16 * 64 + (size_t)b * 16 * 64 + m;
#pragma unroll
                for (int cc = 0; cc < 16; ++cc) s += rp[cc * 64];
                v = s;
            } else {
                float sa = 0.f, sb = 0.f;
                const float* rpa = g_rpart + (size_t)3 * B_ * 16 * 64 + (size_t)b * 16 * 64 + m;
                const float* rpb = g_rpart + (size_t)4 * B_ * 16 * 64 + (size_t)b * 16 * 64 + m;
#pragma unroll
                for (int cc = 0; cc < 16; ++cc) { sa += rpa[cc * 64]; sb += rpb[cc * 64]; }
                float e5 = g_e[((size_t)2 * B_ + b) * 64 + m];
                float a5 = g_a[((size_t)2 * B_ + b) * 64 + m];
                v = sa - e5 * sb + g_T[b] * a5;
            }
        }
        g_state[(size_t)b * 768 + j] = v;
    }
}

// ---------------- host ----------------
extern "C" void kernel_launch(void* const* d_in, const int* in_sizes, int n_in,
                              void* d_out, int out_size) {
    const float* in_data      = (const float*)d_in[0];
    const float* memory       = (const float*)d_in[1];
    const float* h0           = (const float*)d_in[2];
    const float* c0           = (const float*)d_in[3];
    const float* prev_weights = (const float*)d_in[4];
    const float* prev_reads   = (const float*)d_in[5];
    const float* W_ih         = (const float*)d_in[6];
    const float* b_ih         = (const float*)d_in[7];
    const float* W_hh         = (const float*)d_in[8];
    const float* b_hh         = (const float*)d_in[9];
    const float* W_out        = (const float*)d_in[10];
    const float* b_out        = (const float*)d_in[11];
    const float* W_addr       = (const float*)d_in[12];
    const float* b_addr       = (const float*)d_in[13];
    const float* W_ea         = (const float*)d_in[14];
    const float* b_ea         = (const float*)d_in[15];
    float* outp = (float*)d_out;

    // controller
    build_x_kernel<<<(B_ * 320 + 255) / 256, 256>>>(in_data, prev_reads);
    gates_gemm_kernel<<<dim3(2048 / 64, B_ / 32), 256>>>(h0, W_ih, b_ih, W_hh, b_hh);
    lstm_kernel<<<(B_ * C_ + 255) / 256, 256>>>(c0);

    // head parameters (addr + ea fused; head 7 is dead code)
    headpe_gemm_kernel<<<dim3((1072 + 31) / 32, B_ / 32), 256>>>(W_addr, b_addr, W_ea, b_ea);
    head_act_kernel<<<B_, 256>>>();

    passA_kernel<<<NPASSBLK, 256>>>(memory);
    finA_kernel<<<dim3(B_, 4), 256>>>(prev_weights);       // heads 0-3
    passC_kernel<<<NPASSBLK, 256>>>(memory);
    fin_kernel<<<dim3(B_, 2), 256>>>(4, prev_weights);     // heads 4,5 (direct on m2)
    passD_kernel<<<NPASSBLK, 256>>>();
    fin6_kernel<<<B_, 256>>>(prev_weights);                // head 6 (assembled)
    passE_kernel<<<NPASSBLK, 256>>>();

    // output
    build_state_kernel<<<B_, 256>>>();
    out_gemm_kernel<<<dim3(1, B_ / 32), 256>>>(W_out, b_out, outp);
}

// round 11
// speedup vs baseline: 1.8038x; 1.0513x over previous
#include <cuda_runtime.h>
#include <cstdint>

#define B_  256
#define N_  4096
#define M_  64
#define C_  512
#define EPSV 1e-8f
#define NPASSBLK 296
#define NPAIRS   4096
#define RBN ((size_t)B_ * N_)
#define PEB ((size_t)B_ * 1072)
#define GTB ((size_t)B_ * 2048)
#define OTB ((size_t)B_ * 64)

// ---------------- packed f32x2 helpers (sm_103a FFMA2) ----------------
struct px2 { unsigned long long u; };
__device__ __forceinline__ px2 pk(float x, float y) {
    px2 r; asm("mov.b64 %0,{%1,%2};" : "=l"(r.u) : "f"(x), "f"(y)); return r;
}
__device__ __forceinline__ float2 up(px2 a) {
    float2 f; asm("mov.b64 {%0,%1},%2;" : "=f"(f.x), "=f"(f.y) : "l"(a.u)); return f;
}
__device__ __forceinline__ px2 fma2(px2 a, px2 b, px2 c) {
    px2 r; asm("fma.rn.f32x2 %0,%1,%2,%3;" : "=l"(r.u) : "l"(a.u), "l"(b.u), "l"(c.u)); return r;
}

// ---------------- device scratch ----------------
__device__ __align__(16) float g_mem[(size_t)B_ * N_ * M_];      // v2 working memory (written once, pass C)
__device__ __align__(16) float g_x[B_ * 320];
__device__ __align__(16) float g_gates4[4 * GTB];
__device__ __align__(16) float g_c[B_ * C_];
__device__ __align__(16) float g_h[B_ * C_];
__device__ __align__(16) float g_pe4[4 * PEB];
__device__ __align__(16) float g_out4[4 * OTB];
__device__ __align__(16) float g_k[7 * B_ * M_];
__device__ float g_knorm[7 * B_];
__device__ float g_beta[7 * B_];
__device__ float g_gate[7 * B_];
__device__ float g_s[7 * B_ * 3];
__device__ float g_gamma[7 * B_];
__device__ __align__(16) float g_e[3 * B_ * M_];
__device__ __align__(16) float g_a[3 * B_ * M_];
__device__ __align__(16) float g_red[11 * RBN];                  // reduction slots
__device__ __align__(16) float g_w[7 * RBN];                     // per-head weights, slot = head index
__device__ __align__(16) float g_rpart[5 * B_ * 16 * M_];        // colsum partials: reads0,2,4, Sa, Sb
__device__ float g_ak[B_];    // a5 . k6
__device__ float g_aa[B_];    // |a5|^2
__device__ float g_A2[B_];    // a1 . k2
__device__ float g_A3[B_];    // a1 . k3
__device__ float g_Aaa[B_];   // |a1|^2
__device__ float g_T[B_];     // sum_n w6 w5
__device__ __align__(16) float g_state[B_ * 768];

#define RED(i) (g_red + (size_t)(i) * RBN)

// ---------------- helpers ----------------
__device__ __forceinline__ float sigf(float x) { return 1.f / (1.f + expf(-x)); }
__device__ __forceinline__ float softplusf(float x) { return x > 20.f ? x : log1pf(expf(x)); }

// ---------------- build x = [in_data | prev_reads 0..3] ----------------
__global__ void build_x_kernel(const float* __restrict__ in_data,
                               const float* __restrict__ prev_reads) {
    int idx = blockIdx.x * blockDim.x + threadIdx.x;
    if (idx >= B_ * 320) return;
    int b = idx / 320, j = idx % 320;
    float v;
    if (j < 64) v = in_data[b * 64 + j];
    else { int i = (j - 64) >> 6, m = (j - 64) & 63; v = prev_reads[((size_t)i * B_ + b) * 64 + m]; }
    g_x[idx] = v;
}

// gates GEMM, split-K over 4 chunks: partials -> g_gates4[z]
__global__ void gates_gemm_kernel(const float* __restrict__ h0,
                                  const float* __restrict__ Wih,
                                  const float* __restrict__ Whh) {
    __shared__ __align__(16) float As[16][32];
    __shared__ __align__(16) float Bs[16][64];
    int tid = threadIdx.x;
    int z = blockIdx.z;
    const float* A = (z < 2) ? g_x : h0;
    const float* Bw = (z < 2) ? Wih : Whh;
    int K = (z < 2) ? 320 : 512;
    int kbeg = (z == 0) ? 0 : (z == 1) ? 160 : (z == 2) ? 0 : 256;
    int kend = (z == 0) ? 160 : (z == 1) ? 320 : (z == 2) ? 256 : 512;
    int m0 = blockIdx.y * 32, n0 = blockIdx.x * 64;
    int la_r = tid >> 3, la_k = (tid & 7) * 2;
    int lb_r = tid >> 2, lb_k = (tid & 3) * 4;
    int ty = tid >> 4, tx = tid & 15;
    float acc[2][4] = {};
    const float* ap = A + (size_t)(m0 + la_r) * K + la_k;
    const float* bp = Bw + (size_t)(n0 + lb_r) * K + lb_k;
    float2 av = *(const float2*)(ap + kbeg);
    float4 bv = *(const float4*)(bp + kbeg);
    for (int k0 = kbeg; k0 < kend; k0 += 16) {
        __syncthreads();
        As[la_k][la_r] = av.x; As[la_k + 1][la_r] = av.y;
        Bs[lb_k + 0][lb_r] = bv.x; Bs[lb_k + 1][lb_r] = bv.y;
        Bs[lb_k + 2][lb_r] = bv.z; Bs[lb_k + 3][lb_r] = bv.w;
        if (k0 + 16 < kend) {
            av = *(const float2*)(ap + k0 + 16);
            bv = *(const float4*)(bp + k0 + 16);
        }
        __syncthreads();
#pragma unroll
        for (int kk = 0; kk < 16; kk++) {
            float2 a = *(const float2*)&As[kk][ty << 1];
            float4 b = *(const float4*)&Bs[kk][tx << 2];
            acc[0][0] += a.x * b.x; acc[0][1] += a.x * b.y; acc[0][2] += a.x * b.z; acc[0][3] += a.x * b.w;
            acc[1][0] += a.y * b.x; acc[1][1] += a.y * b.y; acc[1][2] += a.y * b.z; acc[1][3] += a.y * b.w;
        }
    }
    float* outp = g_gates4 + (size_t)z * GTB;
#pragma unroll
    for (int i = 0; i < 2; i++) {
        int m = m0 + (ty << 1) + i;
#pragma unroll
        for (int j = 0; j < 4; j++) {
            int n = n0 + (tx << 2) + j;
            outp[(size_t)m * 2048 + n] = acc[i][j];
        }
    }
}

// head-param GEMM, split-K 4 x 128: partials -> g_pe4[z]  (N=1072)
__global__ void headpe_gemm_kernel(const float* __restrict__ Wa,
                                   const float* __restrict__ We) {
    __shared__ __align__(16) float As[16][32];
    __shared__ __align__(16) float Bs[16][32];
    const int NN = 1072, N1 = 560, K = 512;
    int tid = threadIdx.x;
    int z = blockIdx.z;
    int kbeg = z * 128, kend = kbeg + 128;
    int m0 = blockIdx.y * 32, n0 = blockIdx.x * 32;
    int l_r = tid >> 3, l_k = (tid & 7) * 2;
    int ty = tid >> 4, tx = tid & 15;
    int brow = n0 + l_r;
    const float* browp = (brow < N1) ? (Wa + (size_t)brow * K)
                                     : (We + (size_t)(brow - N1) * K);
    bool bok = (brow < NN);
    const float* ap = g_c + (size_t)(m0 + l_r) * K + l_k;
    float2 av = *(const float2*)(ap + kbeg);
    float2 bv = bok ? *(const float2*)(browp + l_k + kbeg) : make_float2(0.f, 0.f);
    float acc[2][2] = {};
    for (int k0 = kbeg; k0 < kend; k0 += 16) {
        __syncthreads();
        As[l_k][l_r] = av.x; As[l_k + 1][l_r] = av.y;
        Bs[l_k][l_r] = bv.x; Bs[l_k + 1][l_r] = bv.y;
        if (k0 + 16 < kend) {
            av = *(const float2*)(ap + k0 + 16);
            bv = bok ? *(const float2*)(browp + l_k + k0 + 16) : make_float2(0.f, 0.f);
        }
        __syncthreads();
#pragma unroll
        for (int kk = 0; kk < 16; kk++) {
            float2 a = *(const float2*)&As[kk][ty << 1];
            float2 b = *(const float2*)&Bs[kk][tx << 1];
            acc[0][0] += a.x * b.x; acc[0][1] += a.x * b.y;
            acc[1][0] += a.y * b.x; acc[1][1] += a.y * b.y;
        }
    }
    float* outp = g_pe4 + (size_t)z * PEB;
#pragma unroll
    for (int i = 0; i < 2; i++) {
        int m = m0 + (ty << 1) + i;
#pragma unroll
        for (int j = 0; j < 2; j++) {
            int n = n0 + (tx << 1) + j;
            if (n < NN) outp[(size_t)m * 1072 + n] = acc[i][j];
        }
    }
}

// output GEMM, split-K 4 x 192: partials -> g_out4[z]   (N=64, K=768)
__global__ void out_gemm_kernel(const float* __restrict__ Wo) {
    __shared__ __align__(16) float As[16][32];
    __shared__ __align__(16) float Bs[16][64];
    const int NN = 64, K = 768;
    int tid = threadIdx.x;
    int z = blockIdx.z;
    int kbeg = z * 192, kend = kbeg + 192;
    int m0 = blockIdx.y * 32, n0 = 0;
    int la_r = tid >> 3, la_k = (tid & 7) * 2;
    int lb_r = tid >> 2, lb_k = (tid & 3) * 4;
    int ty = tid >> 4, tx = tid & 15;
    const float* ap = g_state + (size_t)(m0 + la_r) * K + la_k;
    const float* bp = Wo + (size_t)(n0 + lb_r) * K + lb_k;
    float2 av = *(const float2*)(ap + kbeg);
    float4 bv = *(const float4*)(bp + kbeg);
    float acc[2][4] = {};
    for (int k0 = kbeg; k0 < kend; k0 += 16) {
        __syncthreads();
        As[la_k][la_r] = av.x; As[la_k + 1][la_r] = av.y;
        Bs[lb_k + 0][lb_r] = bv.x; Bs[lb_k + 1][lb_r] = bv.y;
        Bs[lb_k + 2][lb_r] = bv.z; Bs[lb_k + 3][lb_r] = bv.w;
        if (k0 + 16 < kend) {
            av = *(const float2*)(ap + k0 + 16);
            bv = *(const float4*)(bp + k0 + 16);
        }
        __syncthreads();
#pragma unroll
        for (int kk = 0; kk < 16; kk++) {
            float2 a = *(const float2*)&As[kk][ty << 1];
            float4 b = *(const float4*)&Bs[kk][tx << 2];
            acc[0][0] += a.x * b.x; acc[0][1] += a.x * b.y; acc[0][2] += a.x * b.z; acc[0][3] += a.x * b.w;
            acc[1][0] += a.y * b.x; acc[1][1] += a.y * b.y; acc[1][2] += a.y * b.z; acc[1][3] += a.y * b.w;
        }
    }
    float* outp = g_out4 + (size_t)z * OTB;
#pragma unroll
    for (int i = 0; i < 2; i++) {
        int m = m0 + (ty << 1) + i;
#pragma unroll
        for (int j = 0; j < 4; j++) {
            int n = n0 + (tx << 2) + j;
            outp[(size_t)m * NN + n] = acc[i][j];
        }
    }
}

// out finalize: sum split-K partials + bias, sigmoid
__global__ void out_fin_kernel(const float* __restrict__ bo, float* __restrict__ C) {
    int idx = blockIdx.x * 256 + threadIdx.x;
    if (idx >= B_ * 64) return;
    int n = idx & 63;
    float s = g_out4[idx] + g_out4[OTB + idx] + g_out4[2 * OTB + idx] + g_out4[3 * OTB + idx];
    C[idx] = sigf(s + bo[n]);
}

// ---------------- LSTM pointwise (sums gates split-K partials + biases) ----------------
__global__ void lstm_kernel(const float* __restrict__ c0,
                            const float* __restrict__ bih, const float* __restrict__ bhh) {
    int idx = blockIdx.x * blockDim.x + threadIdx.x;
    if (idx >= B_ * C_) return;
    int b = idx / C_, j = idx % C_;
    size_t base = (size_t)b * 2048;
    float g4[4];
#pragma unroll
    for (int gi = 0; gi < 4; ++gi) {
        size_t o = base + gi * 512 + j;
        g4[gi] = g_gates4[o] + g_gates4[GTB + o] + g_gates4[2 * GTB + o] + g_gates4[3 * GTB + o]
               + bih[gi * 512 + j] + bhh[gi * 512 + j];
    }
    float c = sigf(g4[1]) * c0[idx] + sigf(g4[0]) * tanhf(g4[2]);
    g_c[idx] = c;
    g_h[idx] = sigf(g4[3]) * tanhf(c);
}

// ---------------- head activations (stage pe = sum partials + bias into smem) ----------------
__global__ void head_act_kernel(const float* __restrict__ ba, const float* __restrict__ be) {
    __shared__ float spe[1072];
    int b = blockIdx.x;
    int tid = threadIdx.x;
    for (int j = tid; j < 1072; j += 256) {
        size_t o = (size_t)b * 1072 + j;
        float bias = (j < 560) ? ba[j] : be[j - 560];
        spe[j] = g_pe4[o] + g_pe4[PEB + o] + g_pe4[2 * PEB + o] + g_pe4[3 * PEB + o] + bias;
    }
    __syncthreads();
    int wid = tid >> 5, lane = tid & 31;
    if (wid < 7) {
        int hd = wid;
        const float* p = spe + hd * 70;
        float ssq = 0.f;
        for (int j = lane; j < 64; j += 32) {
            float kv = tanhf(p[j]);
            g_k[((size_t)hd * B_ + b) * 64 + j] = kv;
            ssq += kv * kv;
        }
#pragma unroll
        for (int o = 16; o; o >>= 1) ssq += __shfl_xor_sync(0xffffffffu, ssq, o);
        if (lane == 0) {
            int hb = hd * B_ + b;
            g_knorm[hb] = sqrtf(ssq);
            g_beta[hb] = softplusf(p[64]);
            g_gate[hb] = sigf(p[65]);
            float s0 = p[66], s1 = p[67], s2 = p[68];
            float mx = fmaxf(s0, fmaxf(s1, s2));
            float e0 = expf(s0 - mx), e1 = expf(s1 - mx), e2 = expf(s2 - mx);
            float inv = 1.f / (e0 + e1 + e2);
            g_s[hb * 3 + 0] = e0 * inv; g_s[hb * 3 + 1] = e1 * inv; g_s[hb * 3 + 2] = e2 * inv;
            g_gamma[hb] = 1.f + softplusf(p[69]);
        }
    } else {
        for (int wh = 0; wh < 3; ++wh) {
            const float* ea = spe + 560 + wh * 128;
            for (int j = lane; j < 64; j += 32) {
                g_e[((size_t)wh * B_ + b) * 64 + j] = sigf(ea[j]);
                g_a[((size_t)wh * B_ + b) * 64 + j] = tanhf(ea[64 + j]);
            }
        }
        const float* ea2 = spe + 560 + 2 * 128;
        const float* ea0 = spe + 560 + 0 * 128;
        const float* p6  = spe + 6 * 70;
        const float* p2  = spe + 2 * 70;
        const float* p3  = spe + 3 * 70;
        float pak = 0.f, paa = 0.f, pa2 = 0.f, pa3 = 0.f, p11 = 0.f;
        for (int j = lane; j < 64; j += 32) {
            float a5v = tanhf(ea2[64 + j]);
            float k6v = tanhf(p6[j]);
            float a1v = tanhf(ea0[64 + j]);
            float k2v = tanhf(p2[j]);
            float k3v = tanhf(p3[j]);
            pak += a5v * k6v; paa += a5v * a5v;
            pa2 += a1v * k2v; pa3 += a1v * k3v; p11 += a1v * a1v;
        }
#pragma unroll
        for (int o = 16; o; o >>= 1) {
            pak += __shfl_xor_sync(0xffffffffu, pak, o);
            paa += __shfl_xor_sync(0xffffffffu, paa, o);
            pa2 += __shfl_xor_sync(0xffffffffu, pa2, o);
            pa3 += __shfl_xor_sync(0xffffffffu, pa3, o);
            p11 += __shfl_xor_sync(0xffffffffu, p11, o);
        }
        if (lane == 0) {
            g_ak[b] = pak; g_aa[b] = paa;
            g_A2[b] = pa2; g_A3[b] = pa3; g_Aaa[b] = p11;
        }
    }
}

// =================== persistent grid-stride memory passes ===================
#define PASS_HEAD()                                                         \
    int tid = threadIdx.x, lane = tid & 31, warp = tid >> 5;                \
    int c = lane & 7, rg = lane >> 3, col0 = c * 8;                         \
    int p0 = (NPAIRS * blockIdx.x) / NPASSBLK;                              \
    int p1 = (NPAIRS * (blockIdx.x + 1)) / NPASSBLK;                        \
    int Lend = p1 * 8;

#define LOADOP(dst, baseptr) {                                              \
    const float4* _q = (const float4*)((baseptr) + col0);                   \
    float4 _u0 = __ldg(_q), _u1 = __ldg(_q + 1);                            \
    dst[0] = pk(_u0.x, _u0.y); dst[1] = pk(_u0.z, _u0.w);                   \
    dst[2] = pk(_u1.x, _u1.y); dst[3] = pk(_u1.z, _u1.w); }
#define LOADOPN(dst, baseptr) {                                             \
    const float4* _q = (const float4*)((baseptr) + col0);                   \
    float4 _u0 = __ldg(_q), _u1 = __ldg(_q + 1);                            \
    dst[0] = pk(-_u0.x, -_u0.y); dst[1] = pk(-_u0.z, -_u0.w);               \
    dst[2] = pk(-_u1.x, -_u1.y); dst[3] = pk(-_u1.z, -_u1.w); }

__device__ __forceinline__ void reads_epilogue(px2* acc, float (*sred)[64],
                                               int lane, int warp, int c, int tid,
                                               int pair, int slot) {
    float va[8];
#pragma unroll
    for (int i = 0; i < 4; ++i) { float2 f = up(acc[i]); va[2 * i] = f.x; va[2 * i + 1] = f.y; }
#pragma unroll
    for (int t = 0; t < 8; ++t) {
        va[t] += __shfl_xor_sync(0xffffffffu, va[t], 8);
        va[t] += __shfl_xor_sync(0xffffffffu, va[t], 16);
    }
    if (lane < 8) {
#pragma unroll
        for (int t = 0; t < 8; ++t) sred[warp][c * 8 + t] = va[t];
    }
    __syncthreads();
    if (tid < 64) {
        float s = 0.f;
#pragma unroll
        for (int wv = 0; wv < 8; ++wv) s += sred[wv][tid];
        g_rpart[(size_t)slot * B_ * 16 * 64 + (size_t)pair * 64 + tid] = s;
    }
    __syncthreads();
}

// ---- Pass A: 11 reductions on mem0 (heads 0-3 material), reduce-scatter ----
// slots: 0:dot0 1:dot1 2:nrm0 3:u2a 4:u2b 5:u3a 6:u3b 7:v1a 8:v2a 9:v3a 10:v4a
__global__ __launch_bounds__(256, 2) void passA_kernel(const float* __restrict__ mem0) {
    PASS_HEAD();
    float4 bufA[4], bufB[4];
#define LD_A(L) { size_t n = (size_t)(L) * 32 + warp * 4 + rg;              \
        const float4* p = (const float4*)(mem0 + n * 64 + col0);            \
        bufA[(L) & 3] = __ldcs(p); bufB[(L) & 3] = __ldcs(p + 1); }
    LD_A(p0 * 8); LD_A(p0 * 8 + 1); LD_A(p0 * 8 + 2);
    px2 k0[4], k1[4], k2[4], k3[4], e1[4], a1[4];
    int bcur = -1;
    px2 pz = pk(0.f, 0.f);
    bool oddc = (c & 1), bit1 = (c & 2);
    int sbase = (c == 0) ? 0 : (c == 1) ? 6 : (c == 2) ? 3 : 9;
    for (int p = p0; p < p1; ++p) {
        int b = p >> 4;
        if (b != bcur) {
            bcur = b;
            LOADOP(k0, g_k + ((size_t)0 * B_ + b) * 64);
            LOADOP(k1, g_k + ((size_t)1 * B_ + b) * 64);
            LOADOP(k2, g_k + ((size_t)2 * B_ + b) * 64);
            LOADOP(k3, g_k + ((size_t)3 * B_ + b) * 64);
            LOADOP(e1, g_e + ((size_t)0 * B_ + b) * 64);
            LOADOP(a1, g_a + ((size_t)0 * B_ + b) * 64);
        }
#pragma unroll
        for (int it = 0; it < 8; ++it) {
            int L = p * 8 + it;
            if (L + 3 < Lend) LD_A(L + 3);
            size_t n = (size_t)L * 32 + warp * 4 + rg;
            float4 A = bufA[it & 3], Bv = bufB[it & 3];
            px2 v[4] = { pk(A.x, A.y), pk(A.z, A.w), pk(Bv.x, Bv.y), pk(Bv.z, Bv.w) };
            px2 d0 = pz, d1 = pz, nr = pz, u2a = pz, u2b = pz, u3a = pz, u3b = pz;
            px2 v1a = pz, v2a = pz, v3a = pz, v4a = pz;
#pragma unroll
            for (int i = 0; i < 4; ++i) {
                px2 ve = fma2(v[i], e1[i], pz);
                d0  = fma2(v[i], k0[i], d0);
                d1  = fma2(v[i], k1[i], d1);
                nr  = fma2(v[i], v[i], nr);
                u2a = fma2(v[i], k2[i], u2a);
                u3a = fma2(v[i], k3[i], u3a);
                u2b = fma2(ve, k2[i], u2b);
                u3b = fma2(ve, k3[i], u3b);
                v1a = fma2(v[i], a1[i], v1a);
                v3a = fma2(ve, a1[i], v3a);
                v2a = fma2(ve, v[i], v2a);
                v4a = fma2(ve, ve, v4a);
            }
            float s[11]; float2 f;
            f = up(d0);  s[0] = f.x + f.y;
            f = up(d1);  s[1] = f.x + f.y;
            f = up(nr);  s[2] = f.x + f.y;
            f = up(u2a); s[3] = f.x + f.y;
            f = up(u2b); s[4] = f.x + f.y;
            f = up(u3a); s[5] = f.x + f.y;
            f = up(u3b); s[6] = f.x + f.y;
            f = up(v1a); s[7] = f.x + f.y;
            f = up(v2a); s[8] = f.x + f.y;
            f = up(v3a); s[9] = f.x + f.y;
            f = up(v4a); s[10] = f.x + f.y;
            // reduce-scatter over 8 lanes (c bits)
#pragma unroll
            for (int t = 0; t < 11; ++t) s[t] += __shfl_xor_sync(0xffffffffu, s[t], 1);
            float kk[6];
            kk[0] = oddc ? s[6]  : s[0];
            kk[1] = oddc ? s[7]  : s[1];
            kk[2] = oddc ? s[8]  : s[2];
            kk[3] = oddc ? s[9]  : s[3];
            kk[4] = oddc ? s[10] : s[4];
            kk[5] = oddc ? s[10] : s[5];
#pragma unroll
            for (int t = 0; t < 6; ++t) kk[t] += __shfl_xor_sync(0xffffffffu, kk[t], 2);
            float m0v = bit1 ? kk[3] : kk[0];
            float m1v = bit1 ? kk[4] : kk[1];
            float m2v = bit1 ? kk[5] : kk[2];
            m0v += __shfl_xor_sync(0xffffffffu, m0v, 4);
            m1v += __shfl_xor_sync(0xffffffffu, m1v, 4);
            m2v += __shfl_xor_sync(0xffffffffu, m2v, 4);
            // classes: c0:{0,1,2} c1:{6,7,8} c2:{3,4,5} c3:{9,10}
            if (c < 4) {
                g_red[(size_t)sbase * RBN + n] = m0v;
                g_red[(size_t)(sbase + 1) * RBN + n] = m1v;
                if (c < 3) g_red[(size_t)(sbase + 2) * RBN + n] = m2v;
            }
        }
    }
}

// ---- Pass C: reads0 (w0,m0), m1 regs, reads2 (w2,m1), update -> write v2, dot4, dot5, nrm2 ----
// slots: 0:dot4 1:dot5 2:nrm2
__global__ __launch_bounds__(256, 2) void passC_kernel(const float* __restrict__ mem0) {
    __shared__ float sred[8][64];
    PASS_HEAD();
    const float* wp0 = g_w + 0 * RBN;
    const float* wp1 = g_w + 1 * RBN;
    const float* wp2 = g_w + 2 * RBN;
    const float* wp3 = g_w + 3 * RBN;
    float4 bufA[4], bufB[4];
#define LD_C(L) { size_t n = (size_t)(L) * 32 + warp * 4 + rg;              \
        const float4* p = (const float4*)(mem0 + n * 64 + col0);            \
        bufA[(L) & 3] = __ldcs(p); bufB[(L) & 3] = __ldcs(p + 1); }
    LD_C(p0 * 8); LD_C(p0 * 8 + 1);
    px2 k4[4], k5[4], ne1[4], a1[4], ne3[4], a3[4];
    int bcur = -1;
    px2 pz = pk(0.f, 0.f);
    for (int p = p0; p < p1; ++p) {
        int b = p >> 4;
        if (b != bcur) {
            bcur = b;
            LOADOP(k4, g_k + ((size_t)4 * B_ + b) * 64);
            LOADOP(k5, g_k + ((size_t)5 * B_ + b) * 64);
            LOADOPN(ne1, g_e + ((size_t)0 * B_ + b) * 64);
            LOADOP(a1, g_a + ((size_t)0 * B_ + b) * 64);
            LOADOPN(ne3, g_e + ((size_t)1 * B_ + b) * 64);
            LOADOP(a3, g_a + ((size_t)1 * B_ + b) * 64);
        }
        px2 acc0[4] = { pz, pz, pz, pz };
        px2 acc2[4] = { pz, pz, pz, pz };
#pragma unroll
        for (int it = 0; it < 8; ++it) {
            int L = p * 8 + it;
            if (L + 2 < Lend) LD_C(L + 2);
            size_t n = (size_t)L * 32 + warp * 4 + rg;
            float w0 = __ldg(wp0 + n), w1 = __ldg(wp1 + n);
            float w2 = __ldg(wp2 + n), w3 = __ldg(wp3 + n);
            float4 A = bufA[it & 3], Bv = bufB[it & 3];
            px2 v[4] = { pk(A.x, A.y), pk(A.z, A.w), pk(Bv.x, Bv.y), pk(Bv.z, Bv.w) };
            px2 w0p = pk(w0, w0), w1p = pk(w1, w1), w2p = pk(w2, w2), w3p = pk(w3, w3);
            px2 d4 = pz, d5 = pz, nr = pz;
#pragma unroll
            for (int i = 0; i < 4; ++i) {
                acc0[i] = fma2(w0p, v[i], acc0[i]);              // reads0 on m0
                px2 t = fma2(ne1[i], v[i], a1[i]);
                px2 m1 = fma2(w1p, t, v[i]);
                acc2[i] = fma2(w2p, m1, acc2[i]);                // reads2 on m1
                px2 t3 = fma2(ne3[i], m1, a3[i]);
                px2 m2 = fma2(w3p, t3, m1);
                v[i] = m2;
                d4 = fma2(m2, k4[i], d4);
                d5 = fma2(m2, k5[i], d5);
                nr = fma2(m2, m2, nr);
            }
            float* po = g_mem + n * 64 + col0;
            float2 f0 = up(v[0]), f1 = up(v[1]);
            __stcs((float4*)po, make_float4(f0.x, f0.y, f1.x, f1.y));
            float2 f2 = up(v[2]), f3 = up(v[3]);
            __stcs((float4*)po + 1, make_float4(f2.x, f2.y, f3.x, f3.y));
            float2 fd4 = up(d4), fd5 = up(d5), fn = up(nr);
            float s0 = fd4.x + fd4.y, s1 = fd5.x + fd5.y, sn = fn.x + fn.y;
#pragma unroll
            for (int o = 1; o <= 4; o <<= 1) {
                s0 += __shfl_xor_sync(0xffffffffu, s0, o);
                s1 += __shfl_xor_sync(0xffffffffu, s1, o);
                sn += __shfl_xor_sync(0xffffffffu, sn, o);
            }
            // lane-distributed store: lane c stores slot c (c<3)
            float outv = (c == 0) ? s0 : (c == 1) ? s1 : sn;
            if (c < 3) g_red[(size_t)c * RBN + n] = outv;
        }
        reads_epilogue(acc0, sred, lane, warp, c, tid, p, 0);
        reads_epilogue(acc2, sred, lane, warp, c, tid, p, 1);
    }
}

// ---- Pass D: reads4 + algebraic reductions for head 6 on v2 (NO memory write) ----
// values: 0:d6a 1:d6b 2:q1 3:q2 4:p1 5:p2 -> slots {0,1,3,4,5,6} (slot2 = nrm2 preserved)
__global__ __launch_bounds__(256, 2) void passD_kernel() {
    __shared__ float sred[8][64];
    PASS_HEAD();
    const float* wp4 = g_w + 4 * RBN;
    float4 bufA[4], bufB[4];
#define LD_D(L) { size_t n = (size_t)(L) * 32 + warp * 4 + rg;              \
        const float4* p = (const float4*)(g_mem + n * 64 + col0);           \
        bufA[(L) & 3] = __ldcs(p); bufB[(L) & 3] = __ldcs(p + 1); }
    LD_D(p0 * 8); LD_D(p0 * 8 + 1); LD_D(p0 * 8 + 2);
    px2 k6[4], ek[4], e5[4], es[4], a5[4], ea[4];
    int bcur = -1;
    px2 pz = pk(0.f, 0.f);
    bool oddc = (c & 1), bit1 = (c & 2);
    // classes: c0:{v0,v1}->slots{0,1}; c1:{v3,v4}->slots{4,5}; c2:{v2}->slot{3}; c3:{v5}->slot{6}
    int slotA = (c == 0) ? 0 : (c == 1) ? 4 : (c == 2) ? 3 : 6;
    int slotB = (c == 0) ? 1 : 5;
    for (int p = p0; p < p1; ++p) {
        int b = p >> 4;
        if (b != bcur) {
            bcur = b;
            float kk[8], ee[8], av[8];
            const float4* qk = (const float4*)(g_k + ((size_t)6 * B_ + b) * 64 + col0);
            const float4* qe = (const float4*)(g_e + ((size_t)2 * B_ + b) * 64 + col0);
            const float4* qa = (const float4*)(g_a + ((size_t)2 * B_ + b) * 64 + col0);
            *(float4*)&kk[0] = __ldg(qk); *(float4*)&kk[4] = __ldg(qk + 1);
            *(float4*)&ee[0] = __ldg(qe); *(float4*)&ee[4] = __ldg(qe + 1);
            *(float4*)&av[0] = __ldg(qa); *(float4*)&av[4] = __ldg(qa + 1);
#pragma unroll
            for (int i = 0; i < 4; ++i) {
                float k0v = kk[2*i], k1v = kk[2*i+1];
                float e0v = ee[2*i], e1v = ee[2*i+1];
                float a0v = av[2*i], a1v = av[2*i+1];
                k6[i] = pk(k0v, k1v);
                e5[i] = pk(e0v, e1v);
                ek[i] = pk(e0v * k0v, e1v * k1v);
                es[i] = pk(e0v * e0v, e1v * e1v);
                a5[i] = pk(a0v, a1v);
                ea[i] = pk(e0v * a0v, e1v * a1v);
            }
        }
        px2 acc[4] = { pz, pz, pz, pz };
#pragma unroll
        for (int it = 0; it < 8; ++it) {
            int L = p * 8 + it;
            if (L + 3 < Lend) LD_D(L + 3);
            size_t n = (size_t)L * 32 + warp * 4 + rg;
            float w4 = __ldg(wp4 + n);
            float4 A = bufA[it & 3], Bv = bufB[it & 3];
            px2 v[4] = { pk(A.x, A.y), pk(A.z, A.w), pk(Bv.x, Bv.y), pk(Bv.z, Bv.w) };
            px2 w4p = pk(w4, w4);
            px2 d6a = pz, d6b = pz, q1 = pz, q2 = pz, p1v = pz, p2v = pz;
#pragma unroll
            for (int i = 0; i < 4; ++i) {
                acc[i] = fma2(w4p, v[i], acc[i]);               // reads4 on m2
                px2 vsq = fma2(v[i], v[i], pz);
                d6a = fma2(v[i], k6[i], d6a);
                d6b = fma2(v[i], ek[i], d6b);
                q1  = fma2(vsq, e5[i], q1);
                q2  = fma2(vsq, es[i], q2);
                p1v = fma2(v[i], a5[i], p1v);
                p2v = fma2(v[i], ea[i], p2v);
            }
            float s[6]; float2 f;
            f = up(d6a); s[0] = f.x + f.y;
            f = up(d6b); s[1] = f.x + f.y;
            f = up(q1);  s[2] = f.x + f.y;
            f = up(q2);  s[3] = f.x + f.y;
            f = up(p1v); s[4] = f.x + f.y;
            f = up(p2v); s[5] = f.x + f.y;
#pragma unroll
            for (int t = 0; t < 6; ++t) s[t] += __shfl_xor_sync(0xffffffffu, s[t], 1);
            float kk0 = oddc ? s[3] : s[0];
            float kk1 = oddc ? s[4] : s[1];
            float kk2 = oddc ? s[5] : s[2];
            kk0 += __shfl_xor_sync(0xffffffffu, kk0, 2);
            kk1 += __shfl_xor_sync(0xffffffffu, kk1, 2);
            kk2 += __shfl_xor_sync(0xffffffffu, kk2, 2);
            float m0v = bit1 ? kk2 : kk0;
            float m1v = bit1 ? kk2 : kk1;   // m1v only valid for c<2 classes
            m0v += __shfl_xor_sync(0xffffffffu, m0v, 4);
            m1v += __shfl_xor_sync(0xffffffffu, m1v, 4);
            if (c < 4) g_red[(size_t)slotA * RBN + n] = m0v;
            if (c < 2) g_red[(size_t)slotB * RBN + n] = m1v;
        }
        reads_epilogue(acc, sred, lane, warp, c, tid, p, 2);
    }
}

// ---- Pass E: Sa = colsum(w6, v2), Sb = colsum(w6*w5, v2) ----
__global__ __launch_bounds__(256, 2) void passE_kernel() {
    __shared__ float sredA[8][64];
    __shared__ float sredB[8][64];
    PASS_HEAD();
    const float* wp5 = g_w + 5 * RBN;
    const float* wp6 = g_w + 6 * RBN;
    float4 bufA[4], bufB[4];
#define LD_E(L) { size_t n = (size_t)(L) * 32 + warp * 4 + rg;              \
        const float4* p = (const float4*)(g_mem + n * 64 + col0);           \
        bufA[(L) & 3] = __ldcs(p); bufB[(L) & 3] = __ldcs(p + 1); }
    LD_E(p0 * 8); LD_E(p0 * 8 + 1); LD_E(p0 * 8 + 2);
    for (int p = p0; p < p1; ++p) {
        px2 accA[4], accB[4];
#pragma unroll
        for (int i = 0; i < 4; ++i) { accA[i] = pk(0.f, 0.f); accB[i] = pk(0.f, 0.f); }
#pragma unroll
        for (int it = 0; it < 8; ++it) {
            int L = p * 8 + it;
            if (L + 3 < Lend) LD_E(L + 3);
            size_t n = (size_t)L * 32 + warp * 4 + rg;
            float w5 = __ldg(wp5 + n), w6 = __ldg(wp6 + n);
            float4 A = bufA[it & 3], Bv = bufB[it & 3];
            px2 v[4] = { pk(A.x, A.y), pk(A.z, A.w), pk(Bv.x, Bv.y), pk(Bv.z, Bv.w) };
            px2 w6p = pk(w6, w6), w65p = pk(w6 * w5, w6 * w5);
#pragma unroll
            for (int i = 0; i < 4; ++i) {
                accA[i] = fma2(w6p, v[i], accA[i]);
                accB[i] = fma2(w65p, v[i], accB[i]);
            }
        }
        reads_epilogue(accA, sredA, lane, warp, c, tid, p, 3);
        reads_epilogue(accB, sredB, lane, warp, c, tid, p, 4);
    }
}

// ---------------- finalize helpers ----------------
__device__ __forceinline__ float block_reduce_max(float v, float* sbuf) {
#pragma unroll
    for (int o = 16; o; o >>= 1) v = fmaxf(v, __shfl_xor_sync(0xffffffffu, v, o));
    int lane = threadIdx.x & 31, w = threadIdx.x >> 5;
    if (lane == 0) sbuf[w] = v;
    __syncthreads();
    if (threadIdx.x < 32) {
        float vv = (threadIdx.x < 8) ? sbuf[threadIdx.x] : -3.4e38f;
#pragma unroll
        for (int o = 4; o; o >>= 1) vv = fmaxf(vv, __shfl_xor_sync(0xffffffffu, vv, o));
        if (threadIdx.x == 0) sbuf[0] = vv;
    }
    __syncthreads();
    v = sbuf[0];
    __syncthreads();
    return v;
}
__device__ __forceinline__ float block_reduce_sum(float v, float* sbuf) {
#pragma unroll
    for (int o = 16; o; o >>= 1) v += __shfl_xor_sync(0xffffffffu, v, o);
    int lane = threadIdx.x & 31, w = threadIdx.x >> 5;
    if (lane == 0) sbuf[w] = v;
    __syncthreads();
    if (threadIdx.x < 32) {
        float vv = (threadIdx.x < 8) ? sbuf[threadIdx.x] : 0.f;
#pragma unroll
        for (int o = 4; o; o >>= 1) vv += __shfl_xor_sync(0xffffffffu, vv, o);
        if (threadIdx.x == 0) sbuf[0] = vv;
    }
    __syncthreads();
    v = sbuf[0];
    __syncthreads();
    return v;
}

// softmax/interp/shift/sharpen from per-element score sc[] -> w_hd
__device__ __forceinline__ void fin_core(float* sc, int hd, int b, float gate,
                                         float s0, float s1, float s2, float gamma,
                                         const float* pw, float* sbuf, float* swg) {
    int tid = threadIdx.x;
    float lmax = -3.4e38f;
#pragma unroll
    for (int t = 0; t < 16; ++t) lmax = fmaxf(lmax, sc[t]);
    float bmax = block_reduce_max(lmax, sbuf);
    float lsum = 0.f;
#pragma unroll
    for (int t = 0; t < 16; ++t) { float e = __expf(sc[t] - bmax); sc[t] = e; lsum += e; }
    float bsum = block_reduce_sum(lsum, sbuf);
    float inv = 1.f / bsum;
#pragma unroll
    for (int t = 0; t < 16; ++t) {
        int idx = tid + t * 256;
        swg[idx] = gate * sc[t] * inv + (1.f - gate) * pw[idx];
    }
    __syncthreads();
    float wp[16];
    float lps = 0.f;
#pragma unroll
    for (int t = 0; t < 16; ++t) {
        int idx = tid + t * 256;
        float ws = s0 * swg[(idx + N_ - 1) & (N_ - 1)] + s1 * swg[idx]
                 + s2 * swg[(idx + 1) & (N_ - 1)];
        float p = __powf(ws, gamma);
        wp[t] = p; lps += p;
    }
    float psum = block_reduce_sum(lps, sbuf);
    float invp = 1.f / (psum + EPSV);
    float* wout = g_w + (size_t)hd * RBN + (size_t)b * N_;
#pragma unroll
    for (int t = 0; t < 16; ++t) {
        int idx = tid + t * 256;
        wout[idx] = wp[t] * invp;
    }
}

// fin for heads 0-3 after pass A: 0,1 direct; 2,3 assembled from pass-A reductions
__global__ void finA_kernel(const float* __restrict__ prevW) {
    __shared__ float swg[N_];
    __shared__ float sbuf[8];
    int b = blockIdx.x;
    int hd = blockIdx.y;          // 0..3
    int tid = threadIdx.x;
    int hb = hd * B_ + b;
    float knorm = g_knorm[hb], beta = g_beta[hb], gate = g_gate[hb], gamma = g_gamma[hb];
    float s0 = g_s[hb * 3 + 0], s1 = g_s[hb * 3 + 1], s2 = g_s[hb * 3 + 2];
    const float* pw = prevW + ((size_t)hd * B_ + b) * N_;
    const size_t base = (size_t)b * N_;
    float sc[16];
    if (hd < 2) {
        const float* dot = hd ? RED(1) : RED(0);
        const float* nrm = RED(2);
#pragma unroll
        for (int t = 0; t < 16; ++t) {
            int idx = tid + t * 256;
            float d = dot[base + idx];
            float nr = nrm[base + idx];
            sc[t] = beta * d / (sqrtf(nr) * knorm + EPSV);
        }
    } else {
        int hh = hd - 2;
        float Ax = hh ? g_A3[b] : g_A2[b];
        float Aaa = g_Aaa[b];
        const float* ua = hh ? RED(5) : RED(3);
        const float* ub = hh ? RED(6) : RED(4);
        const float* nrm = RED(2);
        const float* r5 = RED(7); const float* r6 = RED(8);
        const float* r7 = RED(9); const float* r8 = RED(10);
        const float* wp1 = g_w + 1 * RBN + base;
#pragma unroll
        for (int t = 0; t < 16; ++t) {
            int idx = tid + t * 256;
            float w1 = wp1[idx];
            float d = ua[base + idx] + w1 * (Ax - ub[base + idx]);
            float nrm1 = nrm[base + idx]
                       + 2.f * w1 * (r5[base + idx] - r6[base + idx])
                       + w1 * w1 * (Aaa - 2.f * r7[base + idx] + r8[base + idx]);
            nrm1 = fmaxf(nrm1, 0.f);
            sc[t] = beta * d / (sqrtf(nrm1) * knorm + EPSV);
        }
    }
    fin_core(sc, hd, b, gate, s0, s1, s2, gamma, pw, sbuf, swg);
}

__global__ void fin_kernel(int head0, const float* __restrict__ prevW) {
    __shared__ float swg[N_];
    __shared__ float sbuf[8];
    int b = blockIdx.x;
    int hh = blockIdx.y;
    int hd = head0 + hh;
    int tid = threadIdx.x;
    const float* dot = hh ? RED(1) : RED(0);
    const float* nrm = RED(2);
    int hb = hd * B_ + b;
    float knorm = g_knorm[hb], beta = g_beta[hb], gate = g_gate[hb], gamma = g_gamma[hb];
    float s0 = g_s[hb * 3 + 0], s1 = g_s[hb * 3 + 1], s2 = g_s[hb * 3 + 2];
    const float* pw = prevW + ((size_t)hd * B_ + b) * N_;
    const size_t base = (size_t)b * N_;
    float sc[16];
#pragma unroll
    for (int t = 0; t < 16; ++t) {
        int idx = tid + t * 256;
        float d = dot[base + idx];
        float nr = nrm[base + idx];
        sc[t] = beta * d / (sqrtf(nr) * knorm + EPSV);
    }
    fin_core(sc, hd, b, gate, s0, s1, s2, gamma, pw, sbuf, swg);
}

// fin for head 6: assemble dot6/nrm3 from pass-D reductions + w5; also T[b] = sum w6 w5
__global__ void fin6_kernel(const float* __restrict__ prevW) {
    __shared__ float swg[N_];
    __shared__ float sbuf[8];
    int b = blockIdx.x;
    int tid = threadIdx.x;
    const int hd = 6;
    int hb = hd * B_ + b;
    float knorm = g_knorm[hb], beta = g_beta[hb], gate = g_gate[hb], gamma = g_gamma[hb];
    float s0 = g_s[hb * 3 + 0], s1 = g_s[hb * 3 + 1], s2 = g_s[hb * 3 + 2];
    float ak = g_ak[b], aa = g_aa[b];
    const float* pw = prevW + ((size_t)hd * B_ + b) * N_;
    const float* wp5 = g_w + 5 * RBN + (size_t)b * N_;
    const size_t base = (size_t)b * N_;
    const float* d6ap = RED(0); const float* d6bp = RED(1);
    const float* q0p = RED(2);  const float* q1p = RED(3);
    const float* q2p = RED(4);  const float* p1p = RED(5);
    const float* p2p = RED(6);
    float sc[16];
#pragma unroll
    for (int t = 0; t < 16; ++t) {
        int idx = tid + t * 256;
        float w5 = wp5[idx];
        float d6 = d6ap[base + idx] + w5 * (ak - d6bp[base + idx]);
        float q0 = q0p[base + idx];
        float q1 = q1p[base + idx], q2 = q2p[base + idx];
        float p1 = p1p[base + idx], p2 = p2p[base + idx];
        float nrm3 = q0 + w5 * (-2.f * q1 + 2.f * p1) + w5 * w5 * (q2 - 2.f * p2 + aa);
        nrm3 = fmaxf(nrm3, 0.f);
        sc[t] = beta * d6 / (sqrtf(nrm3) * knorm + EPSV);
    }
    fin_core(sc, hd, b, gate, s0, s1, s2, gamma, pw, sbuf, swg);
    // T[b] = sum_n w6 w5
    const float* wout = g_w + 6 * RBN + base;
    float lt = 0.f;
#pragma unroll
    for (int t = 0; t < 16; ++t) {
        int idx = tid + t * 256;
        lt += wout[idx] * wp5[idx];
    }
    float T = block_reduce_sum(lt, sbuf);
    if (tid == 0) g_T[b] = T;
}

// ---------------- build state = [h | reads0 | reads2 | reads4 | reads6] ----------------
__global__ void build_state_kernel() {
    int b = blockIdx.x;
    for (int j = threadIdx.x; j < 768; j += blockDim.x) {
        float v;
        if (j < 512) v = g_h[(size_t)b * C_ + j];
        else {
            int ri = (j - 512) >> 6, m = (j - 512) & 63;
            if (ri < 3) {
                float s = 0.f;
                const float* rp = g_rpart + (size_t)ri * B_ * 16 * 64 + (size_t)b * 16 * 64 + m;
#pragma unroll
                for (int cc = 0; cc < 16; ++cc) s += rp[cc * 64];
                v = s;
            } else {
                float sa = 0.f, sb = 0.f;
                const float* rpa = g_rpart + (size_t)3 * B_ * 16 * 64 + (size_t)b * 16 * 64 + m;
                const float* rpb = g_rpart + (size_t)4 * B_ * 16 * 64 + (size_t)b * 16 * 64 + m;
#pragma unroll
                for (int cc = 0; cc < 16; ++cc) { sa += rpa[cc * 64]; sb += rpb[cc * 64]; }
                float e5 = g_e[((size_t)2 * B_ + b) * 64 + m];
                float a5 = g_a[((size_t)2 * B_ + b) * 64 + m];
                v = sa - e5 * sb + g_T[b] * a5;
            }
        }
        g_state[(size_t)b * 768 + j] = v;
    }
}

// ---------------- host ----------------
extern "C" void kernel_launch(void* const* d_in, const int* in_sizes, int n_in,
                              void* d_out, int out_size) {
    const float* in_data      = (const float*)d_in[0];
    const float* memory       = (const float*)d_in[1];
    const float* h0           = (const float*)d_in[2];
    const float* c0           = (const float*)d_in[3];
    const float* prev_weights = (const float*)d_in[4];
    const float* prev_reads   = (const float*)d_in[5];
    const float* W_ih         = (const float*)d_in[6];
    const float* b_ih         = (const float*)d_in[7];
    const float* W_hh         = (const float*)d_in[8];
    const float* b_hh         = (const float*)d_in[9];
    const float* W_out        = (const float*)d_in[10];
    const float* b_out        = (const float*)d_in[11];
    const float* W_addr       = (const float*)d_in[12];
    const float* b_addr       = (const float*)d_in[13];
    const float* W_ea         = (const float*)d_in[14];
    const float* b_ea         = (const float*)d_in[15];
    float* outp = (float*)d_out;

    // controller (split-K GEMMs)
    build_x_kernel<<<(B_ * 320 + 255) / 256, 256>>>(in_data, prev_reads);
    gates_gemm_kernel<<<dim3(2048 / 64, B_ / 32, 4), 256>>>(h0, W_ih, W_hh);
    lstm_kernel<<<(B_ * C_ + 255) / 256, 256>>>(c0, b_ih, b_hh);

    // head parameters (split-K; head 7 is dead code)
    headpe_gemm_kernel<<<dim3((1072 + 31) / 32, B_ / 32, 4), 256>>>(W_addr, W_ea);
    head_act_kernel<<<B_, 256>>>(b_addr, b_ea);

    passA_kernel<<<NPASSBLK, 256>>>(memory);
    finA_kernel<<<dim3(B_, 4), 256>>>(prev_weights);       // heads 0-3
    passC_kernel<<<NPASSBLK, 256>>>(memory);
    fin_kernel<<<dim3(B_, 2), 256>>>(4, prev_weights);     // heads 4,5 (direct on m2)
    passD_kernel<<<NPASSBLK, 256>>>();
    fin6_kernel<<<B_, 256>>>(prev_weights);                // head 6 (assembled)
    passE_kernel<<<NPASSBLK, 256>>>();

    // output
    build_state_kernel<<<B_, 256>>>();
    out_gemm_kernel<<<dim3(1, B_ / 32, 4), 256>>>(W_out);
    out_fin_kernel<<<(B_ * 64 + 255) / 256, 256>>>(b_out, outp);
}

// round 12
// speedup vs baseline: 1.8923x; 1.0491x over previous
#include <cuda_runtime.h>
#include <cstdint>

#define B_  256
#define N_  4096
#define M_  64
#define C_  512
#define EPSV 1e-8f
#define NPASSBLK 296
#define NPAIRS   4096
#define RBN ((size_t)B_ * N_)
#define PEN 874
#define PE1 490
#define PEB ((size_t)B_ * PEN)
#define GTB ((size_t)B_ * 2048)
#define OTB ((size_t)B_ * 64)

// ---------------- packed f32x2 helpers (sm_103a FFMA2) ----------------
struct px2 { unsigned long long u; };
__device__ __forceinline__ px2 pk(float x, float y) {
    px2 r; asm("mov.b64 %0,{%1,%2};" : "=l"(r.u) : "f"(x), "f"(y)); return r;
}
__device__ __forceinline__ float2 up(px2 a) {
    float2 f; asm("mov.b64 {%0,%1},%2;" : "=f"(f.x), "=f"(f.y) : "l"(a.u)); return f;
}
__device__ __forceinline__ px2 fma2(px2 a, px2 b, px2 c) {
    px2 r; asm("fma.rn.f32x2 %0,%1,%2,%3;" : "=l"(r.u) : "l"(a.u), "l"(b.u), "l"(c.u)); return r;
}

// ---------------- device scratch ----------------
__device__ __align__(16) float g_mem[(size_t)B_ * N_ * M_];      // v2 working memory (written once, pass C)
__device__ __align__(16) float g_x[B_ * 320];
__device__ __align__(16) float g_gates4[4 * GTB];
__device__ __align__(16) float g_c[B_ * C_];
__device__ __align__(16) float g_h[B_ * C_];
__device__ __align__(16) float g_pe8[8 * PEB];
__device__ __align__(16) float g_out4[4 * OTB];
__device__ __align__(16) float g_k[7 * B_ * M_];
__device__ float g_knorm[7 * B_];
__device__ float g_beta[7 * B_];
__device__ float g_gate[7 * B_];
__device__ float g_s[7 * B_ * 3];
__device__ float g_gamma[7 * B_];
__device__ __align__(16) float g_e[3 * B_ * M_];
__device__ __align__(16) float g_a[3 * B_ * M_];
__device__ __align__(16) float g_red[11 * RBN];                  // reduction slots
__device__ __align__(16) float g_w[7 * RBN];                     // per-head weights, slot = head index
__device__ __align__(16) float g_rpart[5 * B_ * 16 * M_];        // colsum partials: reads0,2,4, Sa, Sb
__device__ float g_ak[B_];    // a5 . k6
__device__ float g_aa[B_];    // |a5|^2
__device__ float g_A2[B_];    // a1 . k2
__device__ float g_A3[B_];    // a1 . k3
__device__ float g_Aaa[B_];   // |a1|^2
__device__ float g_T[B_];     // sum_n w6 w5
__device__ __align__(16) float g_state[B_ * 768];

#define RED(i) (g_red + (size_t)(i) * RBN)

// ---------------- helpers ----------------
__device__ __forceinline__ float sigf(float x) { return 1.f / (1.f + expf(-x)); }
__device__ __forceinline__ float softplusf(float x) { return x > 20.f ? x : log1pf(expf(x)); }

// ---------------- build x = [in_data | prev_reads 0..3] ----------------
__global__ void build_x_kernel(const float* __restrict__ in_data,
                               const float* __restrict__ prev_reads) {
    int idx = blockIdx.x * blockDim.x + threadIdx.x;
    if (idx >= B_ * 320) return;
    int b = idx / 320, j = idx % 320;
    float v;
    if (j < 64) v = in_data[b * 64 + j];
    else { int i = (j - 64) >> 6, m = (j - 64) & 63; v = prev_reads[((size_t)i * B_ + b) * 64 + m]; }
    g_x[idx] = v;
}

// gates GEMM, 64x64 tile / 4x4 microtile, split-K 4: partials -> g_gates4[z]
__global__ void gates_gemm_kernel(const float* __restrict__ h0,
                                  const float* __restrict__ Wih,
                                  const float* __restrict__ Whh) {
    __shared__ __align__(16) float As[16][64];
    __shared__ __align__(16) float Bs[16][64];
    int tid = threadIdx.x;
    int z = blockIdx.z;
    const float* A = (z < 2) ? g_x : h0;
    const float* Bw = (z < 2) ? Wih : Whh;
    int K = (z < 2) ? 320 : 512;
    int kbeg = (z == 0) ? 0 : (z == 1) ? 160 : (z == 2) ? 0 : 256;
    int kend = (z == 0) ? 160 : (z == 1) ? 320 : (z == 2) ? 256 : 512;
    int m0 = blockIdx.y * 64, n0 = blockIdx.x * 64;
    int l_r = tid >> 2, l_k = (tid & 3) * 4;
    int ty = tid >> 4, tx = tid & 15;
    float acc[4][4] = {};
    const float* ap = A + (size_t)(m0 + l_r) * K + l_k;
    const float* bp = Bw + (size_t)(n0 + l_r) * K + l_k;
    float4 av = *(const float4*)(ap + kbeg);
    float4 bv = *(const float4*)(bp + kbeg);
    for (int k0 = kbeg; k0 < kend; k0 += 16) {
        __syncthreads();
        As[l_k + 0][l_r] = av.x; As[l_k + 1][l_r] = av.y;
        As[l_k + 2][l_r] = av.z; As[l_k + 3][l_r] = av.w;
        Bs[l_k + 0][l_r] = bv.x; Bs[l_k + 1][l_r] = bv.y;
        Bs[l_k + 2][l_r] = bv.z; Bs[l_k + 3][l_r] = bv.w;
        if (k0 + 16 < kend) {
            av = *(const float4*)(ap + k0 + 16);
            bv = *(const float4*)(bp + k0 + 16);
        }
        __syncthreads();
#pragma unroll
        for (int kk = 0; kk < 16; kk++) {
            float4 a = *(const float4*)&As[kk][ty << 2];
            float4 b = *(const float4*)&Bs[kk][tx << 2];
            acc[0][0] += a.x * b.x; acc[0][1] += a.x * b.y; acc[0][2] += a.x * b.z; acc[0][3] += a.x * b.w;
            acc[1][0] += a.y * b.x; acc[1][1] += a.y * b.y; acc[1][2] += a.y * b.z; acc[1][3] += a.y * b.w;
            acc[2][0] += a.z * b.x; acc[2][1] += a.z * b.y; acc[2][2] += a.z * b.z; acc[2][3] += a.z * b.w;
            acc[3][0] += a.w * b.x; acc[3][1] += a.w * b.y; acc[3][2] += a.w * b.z; acc[3][3] += a.w * b.w;
        }
    }
    float* outp = g_gates4 + (size_t)z * GTB;
#pragma unroll
    for (int i = 0; i < 4; i++) {
        int m = m0 + (ty << 2) + i;
#pragma unroll
        for (int j = 0; j < 4; j++) {
            int n = n0 + (tx << 2) + j;
            outp[(size_t)m * 2048 + n] = acc[i][j];
        }
    }
}

// head-param GEMM, trimmed N=874 (addr heads 0-6, ea heads 0-2),
// 64x64 tile / 4x4 microtile, split-K 8 x 64: partials -> g_pe8[z]
__global__ void headpe_gemm_kernel(const float* __restrict__ Wa,
                                   const float* __restrict__ We) {
    __shared__ __align__(16) float As[16][64];
    __shared__ __align__(16) float Bs[16][64];
    const int K = 512;
    int tid = threadIdx.x;
    int z = blockIdx.z;
    int kbeg = z * 64, kend = kbeg + 64;
    int m0 = blockIdx.y * 64, n0 = blockIdx.x * 64;
    int l_r = tid >> 2, l_k = (tid & 3) * 4;
    int ty = tid >> 4, tx = tid & 15;
    int brow = n0 + l_r;
    const float* browp = (brow < PE1) ? (Wa + (size_t)brow * K)
                                      : (We + (size_t)(brow - PE1) * K);
    bool bok = (brow < PEN);
    const float* ap = g_c + (size_t)(m0 + l_r) * K + l_k;
    float4 av = *(const float4*)(ap + kbeg);
    float4 bv = bok ? *(const float4*)(browp + l_k + kbeg) : make_float4(0.f, 0.f, 0.f, 0.f);
    float acc[4][4] = {};
    for (int k0 = kbeg; k0 < kend; k0 += 16) {
        __syncthreads();
        As[l_k + 0][l_r] = av.x; As[l_k + 1][l_r] = av.y;
        As[l_k + 2][l_r] = av.z; As[l_k + 3][l_r] = av.w;
        Bs[l_k + 0][l_r] = bv.x; Bs[l_k + 1][l_r] = bv.y;
        Bs[l_k + 2][l_r] = bv.z; Bs[l_k + 3][l_r] = bv.w;
        if (k0 + 16 < kend) {
            av = *(const float4*)(ap + k0 + 16);
            bv = bok ? *(const float4*)(browp + l_k + k0 + 16) : make_float4(0.f, 0.f, 0.f, 0.f);
        }
        __syncthreads();
#pragma unroll
        for (int kk = 0; kk < 16; kk++) {
            float4 a = *(const float4*)&As[kk][ty << 2];
            float4 b = *(const float4*)&Bs[kk][tx << 2];
            acc[0][0] += a.x * b.x; acc[0][1] += a.x * b.y; acc[0][2] += a.x * b.z; acc[0][3] += a.x * b.w;
            acc[1][0] += a.y * b.x; acc[1][1] += a.y * b.y; acc[1][2] += a.y * b.z; acc[1][3] += a.y * b.w;
            acc[2][0] += a.z * b.x; acc[2][1] += a.z * b.y; acc[2][2] += a.z * b.z; acc[2][3] += a.z * b.w;
            acc[3][0] += a.w * b.x; acc[3][1] += a.w * b.y; acc[3][2] += a.w * b.z; acc[3][3] += a.w * b.w;
        }
    }
    float* outp = g_pe8 + (size_t)z * PEB;
#pragma unroll
    for (int i = 0; i < 4; i++) {
        int m = m0 + (ty << 2) + i;
#pragma unroll
        for (int j = 0; j < 4; j++) {
            int n = n0 + (tx << 2) + j;
            if (n < PEN) outp[(size_t)m * PEN + n] = acc[i][j];
        }
    }
}

// output GEMM, split-K 4 x 192: partials -> g_out4[z]   (N=64, K=768)
__global__ void out_gemm_kernel(const float* __restrict__ Wo) {
    __shared__ __align__(16) float As[16][32];
    __shared__ __align__(16) float Bs[16][64];
    const int NN = 64, K = 768;
    int tid = threadIdx.x;
    int z = blockIdx.z;
    int kbeg = z * 192, kend = kbeg + 192;
    int m0 = blockIdx.y * 32, n0 = 0;
    int la_r = tid >> 3, la_k = (tid & 7) * 2;
    int lb_r = tid >> 2, lb_k = (tid & 3) * 4;
    int ty = tid >> 4, tx = tid & 15;
    const float* ap = g_state + (size_t)(m0 + la_r) * K + la_k;
    const float* bp = Wo + (size_t)(n0 + lb_r) * K + lb_k;
    float2 av = *(const float2*)(ap + kbeg);
    float4 bv = *(const float4*)(bp + kbeg);
    float acc[2][4] = {};
    for (int k0 = kbeg; k0 < kend; k0 += 16) {
        __syncthreads();
        As[la_k][la_r] = av.x; As[la_k + 1][la_r] = av.y;
        Bs[lb_k + 0][lb_r] = bv.x; Bs[lb_k + 1][lb_r] = bv.y;
        Bs[lb_k + 2][lb_r] = bv.z; Bs[lb_k + 3][lb_r] = bv.w;
        if (k0 + 16 < kend) {
            av = *(const float2*)(ap + k0 + 16);
            bv = *(const float4*)(bp + k0 + 16);
        }
        __syncthreads();
#pragma unroll
        for (int kk = 0; kk < 16; kk++) {
            float2 a = *(const float2*)&As[kk][ty << 1];
            float4 b = *(const float4*)&Bs[kk][tx << 2];
            acc[0][0] += a.x * b.x; acc[0][1] += a.x * b.y; acc[0][2] += a.x * b.z; acc[0][3] += a.x * b.w;
            acc[1][0] += a.y * b.x; acc[1][1] += a.y * b.y; acc[1][2] += a.y * b.z; acc[1][3] += a.y * b.w;
        }
    }
    float* outp = g_out4 + (size_t)z * OTB;
#pragma unroll
    for (int i = 0; i < 2; i++) {
        int m = m0 + (ty << 1) + i;
#pragma unroll
        for (int j = 0; j < 4; j++) {
            int n = n0 + (tx << 2) + j;
            outp[(size_t)m * NN + n] = acc[i][j];
        }
    }
}

// out finalize: sum split-K partials + bias, sigmoid
__global__ void out_fin_kernel(const float* __restrict__ bo, float* __restrict__ C) {
    int idx = blockIdx.x * 256 + threadIdx.x;
    if (idx >= B_ * 64) return;
    int n = idx & 63;
    float s = g_out4[idx] + g_out4[OTB + idx] + g_out4[2 * OTB + idx] + g_out4[3 * OTB + idx];
    C[idx] = sigf(s + bo[n]);
}

// ---------------- LSTM pointwise (sums gates split-K partials + biases) ----------------
__global__ void lstm_kernel(const float* __restrict__ c0,
                            const float* __restrict__ bih, const float* __restrict__ bhh) {
    int idx = blockIdx.x * blockDim.x + threadIdx.x;
    if (idx >= B_ * C_) return;
    int b = idx / C_, j = idx % C_;
    size_t base = (size_t)b * 2048;
    float g4[4];
#pragma unroll
    for (int gi = 0; gi < 4; ++gi) {
        size_t o = base + gi * 512 + j;
        g4[gi] = g_gates4[o] + g_gates4[GTB + o] + g_gates4[2 * GTB + o] + g_gates4[3 * GTB + o]
               + bih[gi * 512 + j] + bhh[gi * 512 + j];
    }
    float c = sigf(g4[1]) * c0[idx] + sigf(g4[0]) * tanhf(g4[2]);
    g_c[idx] = c;
    g_h[idx] = sigf(g4[3]) * tanhf(c);
}

// ---------------- head activations (stage pe = sum 8 partials + bias into smem) ----------------
// trimmed layout: [0,490): addr heads 0..6 (70 each); [490,874): ea heads 0..2 (128 each)
__global__ void head_act_kernel(const float* __restrict__ ba, const float* __restrict__ be) {
    __shared__ float spe[PEN];
    int b = blockIdx.x;
    int tid = threadIdx.x;
    for (int j = tid; j < PEN; j += 256) {
        size_t o = (size_t)b * PEN + j;
        float bias = (j < PE1) ? ba[j] : be[j - PE1];
        float s = 0.f;
#pragma unroll
        for (int zz = 0; zz < 8; ++zz) s += g_pe8[(size_t)zz * PEB + o];
        spe[j] = s + bias;
    }
    __syncthreads();
    int wid = tid >> 5, lane = tid & 31;
    if (wid < 7) {
        int hd = wid;
        const float* p = spe + hd * 70;
        float ssq = 0.f;
        for (int j = lane; j < 64; j += 32) {
            float kv = tanhf(p[j]);
            g_k[((size_t)hd * B_ + b) * 64 + j] = kv;
            ssq += kv * kv;
        }
#pragma unroll
        for (int o = 16; o; o >>= 1) ssq += __shfl_xor_sync(0xffffffffu, ssq, o);
        if (lane == 0) {
            int hb = hd * B_ + b;
            g_knorm[hb] = sqrtf(ssq);
            g_beta[hb] = softplusf(p[64]);
            g_gate[hb] = sigf(p[65]);
            float s0 = p[66], s1 = p[67], s2 = p[68];
            float mx = fmaxf(s0, fmaxf(s1, s2));
            float e0 = expf(s0 - mx), e1 = expf(s1 - mx), e2 = expf(s2 - mx);
            float inv = 1.f / (e0 + e1 + e2);
            g_s[hb * 3 + 0] = e0 * inv; g_s[hb * 3 + 1] = e1 * inv; g_s[hb * 3 + 2] = e2 * inv;
            g_gamma[hb] = 1.f + softplusf(p[69]);
        }
    } else {
        for (int wh = 0; wh < 3; ++wh) {
            const float* ea = spe + PE1 + wh * 128;
            for (int j = lane; j < 64; j += 32) {
                g_e[((size_t)wh * B_ + b) * 64 + j] = sigf(ea[j]);
                g_a[((size_t)wh * B_ + b) * 64 + j] = tanhf(ea[64 + j]);
            }
        }
        const float* ea2 = spe + PE1 + 2 * 128;
        const float* ea0 = spe + PE1 + 0 * 128;
        const float* p6  = spe + 6 * 70;
        const float* p2  = spe + 2 * 70;
        const float* p3  = spe + 3 * 70;
        float pak = 0.f, paa = 0.f, pa2 = 0.f, pa3 = 0.f, p11 = 0.f;
        for (int j = lane; j < 64; j += 32) {
            float a5v = tanhf(ea2[64 + j]);
            float k6v = tanhf(p6[j]);
            float a1v = tanhf(ea0[64 + j]);
            float k2v = tanhf(p2[j]);
            float k3v = tanhf(p3[j]);
            pak += a5v * k6v; paa += a5v * a5v;
            pa2 += a1v * k2v; pa3 += a1v * k3v; p11 += a1v * a1v;
        }
#pragma unroll
        for (int o = 16; o; o >>= 1) {
            pak += __shfl_xor_sync(0xffffffffu, pak, o);
            paa += __shfl_xor_sync(0xffffffffu, paa, o);
            pa2 += __shfl_xor_sync(0xffffffffu, pa2, o);
            pa3 += __shfl_xor_sync(0xffffffffu, pa3, o);
            p11 += __shfl_xor_sync(0xffffffffu, p11, o);
        }
        if (lane == 0) {
            g_ak[b] = pak; g_aa[b] = paa;
            g_A2[b] = pa2; g_A3[b] = pa3; g_Aaa[b] = p11;
        }
    }
}

// =================== persistent grid-stride memory passes ===================
#define PASS_HEAD()                                                         \
    int tid = threadIdx.x, lane = tid & 31, warp = tid >> 5;                \
    int c = lane & 7, rg = lane >> 3, col0 = c * 8;                         \
    int p0 = (NPAIRS * blockIdx.x) / NPASSBLK;                              \
    int p1 = (NPAIRS * (blockIdx.x + 1)) / NPASSBLK;                        \
    int Lend = p1 * 8;

#define LOADOP(dst, baseptr) {                                              \
    const float4* _q = (const float4*)((baseptr) + col0);                   \
    float4 _u0 = __ldg(_q), _u1 = __ldg(_q + 1);                            \
    dst[0] = pk(_u0.x, _u0.y); dst[1] = pk(_u0.z, _u0.w);                   \
    dst[2] = pk(_u1.x, _u1.y); dst[3] = pk(_u1.z, _u1.w); }
#define LOADOPN(dst, baseptr) {                                             \
    const float4* _q = (const float4*)((baseptr) + col0);                   \
    float4 _u0 = __ldg(_q), _u1 = __ldg(_q + 1);                            \
    dst[0] = pk(-_u0.x, -_u0.y); dst[1] = pk(-_u0.z, -_u0.w);               \
    dst[2] = pk(-_u1.x, -_u1.y); dst[3] = pk(-_u1.z, -_u1.w); }

__device__ __forceinline__ void reads_epilogue(px2* acc, float (*sred)[64],
                                               int lane, int warp, int c, int tid,
                                               int pair, int slot) {
    float va[8];
#pragma unroll
    for (int i = 0; i < 4; ++i) { float2 f = up(acc[i]); va[2 * i] = f.x; va[2 * i + 1] = f.y; }
#pragma unroll
    for (int t = 0; t < 8; ++t) {
        va[t] += __shfl_xor_sync(0xffffffffu, va[t], 8);
        va[t] += __shfl_xor_sync(0xffffffffu, va[t], 16);
    }
    if (lane < 8) {
#pragma unroll
        for (int t = 0; t < 8; ++t) sred[warp][c * 8 + t] = va[t];
    }
    __syncthreads();
    if (tid < 64) {
        float s = 0.f;
#pragma unroll
        for (int wv = 0; wv < 8; ++wv) s += sred[wv][tid];
        g_rpart[(size_t)slot * B_ * 16 * 64 + (size_t)pair * 64 + tid] = s;
    }
    __syncthreads();
}

// ---- Pass A: 11 reductions on mem0 (heads 0-3 material), reduce-scatter ----
// slots: 0:dot0 1:dot1 2:nrm0 3:u2a 4:u2b 5:u3a 6:u3b 7:v1a 8:v2a 9:v3a 10:v4a
__global__ __launch_bounds__(256, 2) void passA_kernel(const float* __restrict__ mem0) {
    PASS_HEAD();
    float4 bufA[4], bufB[4];
#define LD_A(L) { size_t n = (size_t)(L) * 32 + warp * 4 + rg;              \
        const float4* p = (const float4*)(mem0 + n * 64 + col0);            \
        bufA[(L) & 3] = __ldcs(p); bufB[(L) & 3] = __ldcs(p + 1); }
    LD_A(p0 * 8); LD_A(p0 * 8 + 1); LD_A(p0 * 8 + 2);
    px2 k0[4], k1[4], k2[4], k3[4], e1[4], a1[4];
    int bcur = -1;
    px2 pz = pk(0.f, 0.f);
    bool oddc = (c & 1), bit1 = (c & 2);
    int sbase = (c == 0) ? 0 : (c == 1) ? 6 : (c == 2) ? 3 : 9;
    for (int p = p0; p < p1; ++p) {
        int b = p >> 4;
        if (b != bcur) {
            bcur = b;
            LOADOP(k0, g_k + ((size_t)0 * B_ + b) * 64);
            LOADOP(k1, g_k + ((size_t)1 * B_ + b) * 64);
            LOADOP(k2, g_k + ((size_t)2 * B_ + b) * 64);
            LOADOP(k3, g_k + ((size_t)3 * B_ + b) * 64);
            LOADOP(e1, g_e + ((size_t)0 * B_ + b) * 64);
            LOADOP(a1, g_a + ((size_t)0 * B_ + b) * 64);
        }
#pragma unroll
        for (int it = 0; it < 8; ++it) {
            int L = p * 8 + it;
            if (L + 3 < Lend) LD_A(L + 3);
            size_t n = (size_t)L * 32 + warp * 4 + rg;
            float4 A = bufA[it & 3], Bv = bufB[it & 3];
            px2 v[4] = { pk(A.x, A.y), pk(A.z, A.w), pk(Bv.x, Bv.y), pk(Bv.z, Bv.w) };
            px2 d0 = pz, d1 = pz, nr = pz, u2a = pz, u2b = pz, u3a = pz, u3b = pz;
            px2 v1a = pz, v2a = pz, v3a = pz, v4a = pz;
#pragma unroll
            for (int i = 0; i < 4; ++i) {
                px2 ve = fma2(v[i], e1[i], pz);
                d0  = fma2(v[i], k0[i], d0);
                d1  = fma2(v[i], k1[i], d1);
                nr  = fma2(v[i], v[i], nr);
                u2a = fma2(v[i], k2[i], u2a);
                u3a = fma2(v[i], k3[i], u3a);
                u2b = fma2(ve, k2[i], u2b);
                u3b = fma2(ve, k3[i], u3b);
                v1a = fma2(v[i], a1[i], v1a);
                v3a = fma2(ve, a1[i], v3a);
                v2a = fma2(ve, v[i], v2a);
                v4a = fma2(ve, ve, v4a);
            }
            float s[11]; float2 f;
            f = up(d0);  s[0] = f.x + f.y;
            f = up(d1);  s[1] = f.x + f.y;
            f = up(nr);  s[2] = f.x + f.y;
            f = up(u2a); s[3] = f.x + f.y;
            f = up(u2b); s[4] = f.x + f.y;
            f = up(u3a); s[5] = f.x + f.y;
            f = up(u3b); s[6] = f.x + f.y;
            f = up(v1a); s[7] = f.x + f.y;
            f = up(v2a); s[8] = f.x + f.y;
            f = up(v3a); s[9] = f.x + f.y;
            f = up(v4a); s[10] = f.x + f.y;
            // reduce-scatter over 8 lanes (c bits)
#pragma unroll
            for (int t = 0; t < 11; ++t) s[t] += __shfl_xor_sync(0xffffffffu, s[t], 1);
            float kk[6];
            kk[0] = oddc ? s[6]  : s[0];
            kk[1] = oddc ? s[7]  : s[1];
            kk[2] = oddc ? s[8]  : s[2];
            kk[3] = oddc ? s[9]  : s[3];
            kk[4] = oddc ? s[10] : s[4];
            kk[5] = oddc ? s[10] : s[5];
#pragma unroll
            for (int t = 0; t < 6; ++t) kk[t] += __shfl_xor_sync(0xffffffffu, kk[t], 2);
            float m0v = bit1 ? kk[3] : kk[0];
            float m1v = bit1 ? kk[4] : kk[1];
            float m2v = bit1 ? kk[5] : kk[2];
            m0v += __shfl_xor_sync(0xffffffffu, m0v, 4);
            m1v += __shfl_xor_sync(0xffffffffu, m1v, 4);
            m2v += __shfl_xor_sync(0xffffffffu, m2v, 4);
            // classes: c0:{0,1,2} c1:{6,7,8} c2:{3,4,5} c3:{9,10}
            if (c < 4) {
                g_red[(size_t)sbase * RBN + n] = m0v;
                g_red[(size_t)(sbase + 1) * RBN + n] = m1v;
                if (c < 3) g_red[(size_t)(sbase + 2) * RBN + n] = m2v;
            }
        }
    }
}

// ---- Pass C: reads0 (w0,m0), m1 regs, reads2 (w2,m1), update -> write v2, dot4, dot5, nrm2 ----
// slots: 0:dot4 1:dot5 2:nrm2
__global__ __launch_bounds__(256, 2) void passC_kernel(const float* __restrict__ mem0) {
    __shared__ float sred[8][64];
    PASS_HEAD();
    const float* wp0 = g_w + 0 * RBN;
    const float* wp1 = g_w + 1 * RBN;
    const float* wp2 = g_w + 2 * RBN;
    const float* wp3 = g_w + 3 * RBN;
    float4 bufA[4], bufB[4];
#define LD_C(L) { size_t n = (size_t)(L) * 32 + warp * 4 + rg;              \
        const float4* p = (const float4*)(mem0 + n * 64 + col0);            \
        bufA[(L) & 3] = __ldcs(p); bufB[(L) & 3] = __ldcs(p + 1); }
    LD_C(p0 * 8); LD_C(p0 * 8 + 1);
    px2 k4[4], k5[4], ne1[4], a1[4], ne3[4], a3[4];
    int bcur = -1;
    px2 pz = pk(0.f, 0.f);
    for (int p = p0; p < p1; ++p) {
        int b = p >> 4;
        if (b != bcur) {
            bcur = b;
            LOADOP(k4, g_k + ((size_t)4 * B_ + b) * 64);
            LOADOP(k5, g_k + ((size_t)5 * B_ + b) * 64);
            LOADOPN(ne1, g_e + ((size_t)0 * B_ + b) * 64);
            LOADOP(a1, g_a + ((size_t)0 * B_ + b) * 64);
            LOADOPN(ne3, g_e + ((size_t)1 * B_ + b) * 64);
            LOADOP(a3, g_a + ((size_t)1 * B_ + b) * 64);
        }
        px2 acc0[4] = { pz, pz, pz, pz };
        px2 acc2[4] = { pz, pz, pz, pz };
#pragma unroll
        for (int it = 0; it < 8; ++it) {
            int L = p * 8 + it;
            if (L + 2 < Lend) LD_C(L + 2);
            size_t n = (size_t)L * 32 + warp * 4 + rg;
            float w0 = __ldg(wp0 + n), w1 = __ldg(wp1 + n);
            float w2 = __ldg(wp2 + n), w3 = __ldg(wp3 + n);
            float4 A = bufA[it & 3], Bv = bufB[it & 3];
            px2 v[4] = { pk(A.x, A.y), pk(A.z, A.w), pk(Bv.x, Bv.y), pk(Bv.z, Bv.w) };
            px2 w0p = pk(w0, w0), w1p = pk(w1, w1), w2p = pk(w2, w2), w3p = pk(w3, w3);
            px2 d4 = pz, d5 = pz, nr = pz;
#pragma unroll
            for (int i = 0; i < 4; ++i) {
                acc0[i] = fma2(w0p, v[i], acc0[i]);              // reads0 on m0
                px2 t = fma2(ne1[i], v[i], a1[i]);
                px2 m1 = fma2(w1p, t, v[i]);
                acc2[i] = fma2(w2p, m1, acc2[i]);                // reads2 on m1
                px2 t3 = fma2(ne3[i], m1, a3[i]);
                px2 m2 = fma2(w3p, t3, m1);
                v[i] = m2;
                d4 = fma2(m2, k4[i], d4);
                d5 = fma2(m2, k5[i], d5);
                nr = fma2(m2, m2, nr);
            }
            float* po = g_mem + n * 64 + col0;
            float2 f0 = up(v[0]), f1 = up(v[1]);
            __stcs((float4*)po, make_float4(f0.x, f0.y, f1.x, f1.y));
            float2 f2 = up(v[2]), f3 = up(v[3]);
            __stcs((float4*)po + 1, make_float4(f2.x, f2.y, f3.x, f3.y));
            float2 fd4 = up(d4), fd5 = up(d5), fn = up(nr);
            float s0 = fd4.x + fd4.y, s1 = fd5.x + fd5.y, sn = fn.x + fn.y;
#pragma unroll
            for (int o = 1; o <= 4; o <<= 1) {
                s0 += __shfl_xor_sync(0xffffffffu, s0, o);
                s1 += __shfl_xor_sync(0xffffffffu, s1, o);
                sn += __shfl_xor_sync(0xffffffffu, sn, o);
            }
            // lane-distributed store: lane c stores slot c (c<3)
            float outv = (c == 0) ? s0 : (c == 1) ? s1 : sn;
            if (c < 3) g_red[(size_t)c * RBN + n] = outv;
        }
        reads_epilogue(acc0, sred, lane, warp, c, tid, p, 0);
        reads_epilogue(acc2, sred, lane, warp, c, tid, p, 1);
    }
}

// ---- Pass D: reads4 + algebraic reductions for head 6 on v2 (NO memory write) ----
// values: 0:d6a 1:d6b 2:q1 3:q2 4:p1 5:p2 -> slots {0,1,3,4,5,6} (slot2 = nrm2 preserved)
__global__ __launch_bounds__(256, 2) void passD_kernel() {
    __shared__ float sred[8][64];
    PASS_HEAD();
    const float* wp4 = g_w + 4 * RBN;
    float4 bufA[4], bufB[4];
#define LD_D(L) { size_t n = (size_t)(L) * 32 + warp * 4 + rg;              \
        const float4* p = (const float4*)(g_mem + n * 64 + col0);           \
        bufA[(L) & 3] = __ldcs(p); bufB[(L) & 3] = __ldcs(p + 1); }
    LD_D(p0 * 8); LD_D(p0 * 8 + 1); LD_D(p0 * 8 + 2);
    px2 k6[4], ek[4], e5[4], es[4], a5[4], ea[4];
    int bcur = -1;
    px2 pz = pk(0.f, 0.f);
    bool oddc = (c & 1), bit1 = (c & 2);
    // classes: c0:{v0,v1}->slots{0,1}; c1:{v3,v4}->slots{4,5}; c2:{v2}->slot{3}; c3:{v5}->slot{6}
    int slotA = (c == 0) ? 0 : (c == 1) ? 4 : (c == 2) ? 3 : 6;
    int slotB = (c == 0) ? 1 : 5;
    for (int p = p0; p < p1; ++p) {
        int b = p >> 4;
        if (b != bcur) {
            bcur = b;
            float kk[8], ee[8], av[8];
            const float4* qk = (const float4*)(g_k + ((size_t)6 * B_ + b) * 64 + col0);
            const float4* qe = (const float4*)(g_e + ((size_t)2 * B_ + b) * 64 + col0);
            const float4* qa = (const float4*)(g_a + ((size_t)2 * B_ + b) * 64 + col0);
            *(float4*)&kk[0] = __ldg(qk); *(float4*)&kk[4] = __ldg(qk + 1);
            *(float4*)&ee[0] = __ldg(qe); *(float4*)&ee[4] = __ldg(qe + 1);
            *(float4*)&av[0] = __ldg(qa); *(float4*)&av[4] = __ldg(qa + 1);
#pragma unroll
            for (int i = 0; i < 4; ++i) {
                float k0v = kk[2*i], k1v = kk[2*i+1];
                float e0v = ee[2*i], e1v = ee[2*i+1];
                float a0v = av[2*i], a1v = av[2*i+1];
                k6[i] = pk(k0v, k1v);
                e5[i] = pk(e0v, e1v);
                ek[i] = pk(e0v * k0v, e1v * k1v);
                es[i] = pk(e0v * e0v, e1v * e1v);
                a5[i] = pk(a0v, a1v);
                ea[i] = pk(e0v * a0v, e1v * a1v);
            }
        }
        px2 acc[4] = { pz, pz, pz, pz };
#pragma unroll
        for (int it = 0; it < 8; ++it) {
            int L = p * 8 + it;
            if (L + 3 < Lend) LD_D(L + 3);
            size_t n = (size_t)L * 32 + warp * 4 + rg;
            float w4 = __ldg(wp4 + n);
            float4 A = bufA[it & 3], Bv = bufB[it & 3];
            px2 v[4] = { pk(A.x, A.y), pk(A.z, A.w), pk(Bv.x, Bv.y), pk(Bv.z, Bv.w) };
            px2 w4p = pk(w4, w4);
            px2 d6a = pz, d6b = pz, q1 = pz, q2 = pz, p1v = pz, p2v = pz;
#pragma unroll
            for (int i = 0; i < 4; ++i) {
                acc[i] = fma2(w4p, v[i], acc[i]);               // reads4 on m2
                px2 vsq = fma2(v[i], v[i], pz);
                d6a = fma2(v[i], k6[i], d6a);
                d6b = fma2(v[i], ek[i], d6b);
                q1  = fma2(vsq, e5[i], q1);
                q2  = fma2(vsq, es[i], q2);
                p1v = fma2(v[i], a5[i], p1v);
                p2v = fma2(v[i], ea[i], p2v);
            }
            float s[6]; float2 f;
            f = up(d6a); s[0] = f.x + f.y;
            f = up(d6b); s[1] = f.x + f.y;
            f = up(q1);  s[2] = f.x + f.y;
            f = up(q2);  s[3] = f.x + f.y;
            f = up(p1v); s[4] = f.x + f.y;
            f = up(p2v); s[5] = f.x + f.y;
#pragma unroll
            for (int t = 0; t < 6; ++t) s[t] += __shfl_xor_sync(0xffffffffu, s[t], 1);
            float kk0 = oddc ? s[3] : s[0];
            float kk1 = oddc ? s[4] : s[1];
            float kk2 = oddc ? s[5] : s[2];
            kk0 += __shfl_xor_sync(0xffffffffu, kk0, 2);
            kk1 += __shfl_xor_sync(0xffffffffu, kk1, 2);
            kk2 += __shfl_xor_sync(0xffffffffu, kk2, 2);
            float m0v = bit1 ? kk2 : kk0;
            float m1v = bit1 ? kk2 : kk1;   // m1v only valid for c<2 classes
            m0v += __shfl_xor_sync(0xffffffffu, m0v, 4);
            m1v += __shfl_xor_sync(0xffffffffu, m1v, 4);
            if (c < 4) g_red[(size_t)slotA * RBN + n] = m0v;
            if (c < 2) g_red[(size_t)slotB * RBN + n] = m1v;
        }
        reads_epilogue(acc, sred, lane, warp, c, tid, p, 2);
    }
}

// ---- Pass E: Sa = colsum(w6, v2), Sb = colsum(w6*w5, v2) ----
__global__ __launch_bounds__(256, 2) void passE_kernel() {
    __shared__ float sredA[8][64];
    __shared__ float sredB[8][64];
    PASS_HEAD();
    const float* wp5 = g_w + 5 * RBN;
    const float* wp6 = g_w + 6 * RBN;
    float4 bufA[4], bufB[4];
#define LD_E(L) { size_t n = (size_t)(L) * 32 + warp * 4 + rg;              \
        const float4* p = (const float4*)(g_mem + n * 64 + col0);           \
        bufA[(L) & 3] = __ldcs(p); bufB[(L) & 3] = __ldcs(p + 1); }
    LD_E(p0 * 8); LD_E(p0 * 8 + 1); LD_E(p0 * 8 + 2);
    for (int p = p0; p < p1; ++p) {
        px2 accA[4], accB[4];
#pragma unroll
        for (int i = 0; i < 4; ++i) { accA[i] = pk(0.f, 0.f); accB[i] = pk(0.f, 0.f); }
#pragma unroll
        for (int it = 0; it < 8; ++it) {
            int L = p * 8 + it;
            if (L + 3 < Lend) LD_E(L + 3);
            size_t n = (size_t)L * 32 + warp * 4 + rg;
            float w5 = __ldg(wp5 + n), w6 = __ldg(wp6 + n);
            float4 A = bufA[it & 3], Bv = bufB[it & 3];
            px2 v[4] = { pk(A.x, A.y), pk(A.z, A.w), pk(Bv.x, Bv.y), pk(Bv.z, Bv.w) };
            px2 w6p = pk(w6, w6), w65p = pk(w6 * w5, w6 * w5);
#pragma unroll
            for (int i = 0; i < 4; ++i) {
                accA[i] = fma2(w6p, v[i], accA[i]);
                accB[i] = fma2(w65p, v[i], accB[i]);
            }
        }
        reads_epilogue(accA, sredA, lane, warp, c, tid, p, 3);
        reads_epilogue(accB, sredB, lane, warp, c, tid, p, 4);
    }
}

// ---------------- finalize helpers ----------------
__device__ __forceinline__ float block_reduce_max(float v, float* sbuf) {
#pragma unroll
    for (int o = 16; o; o >>= 1) v = fmaxf(v, __shfl_xor_sync(0xffffffffu, v, o));
    int lane = threadIdx.x & 31, w = threadIdx.x >> 5;
    if (lane == 0) sbuf[w] = v;
    __syncthreads();
    if (threadIdx.x < 32) {
        float vv = (threadIdx.x < 8) ? sbuf[threadIdx.x] : -3.4e38f;
#pragma unroll
        for (int o = 4; o; o >>= 1) vv = fmaxf(vv, __shfl_xor_sync(0xffffffffu, vv, o));
        if (threadIdx.x == 0) sbuf[0] = vv;
    }
    __syncthreads();
    v = sbuf[0];
    __syncthreads();
    return v;
}
__device__ __forceinline__ float block_reduce_sum(float v, float* sbuf) {
#pragma unroll
    for (int o = 16; o; o >>= 1) v += __shfl_xor_sync(0xffffffffu, v, o);
    int lane = threadIdx.x & 31, w = threadIdx.x >> 5;
    if (lane == 0) sbuf[w] = v;
    __syncthreads();
    if (threadIdx.x < 32) {
        float vv = (threadIdx.x < 8) ? sbuf[threadIdx.x] : 0.f;
#pragma unroll
        for (int o = 4; o; o >>= 1) vv += __shfl_xor_sync(0xffffffffu, vv, o);
        if (threadIdx.x == 0) sbuf[0] = vv;
    }
    __syncthreads();
    v = sbuf[0];
    __syncthreads();
    return v;
}

// softmax/interp/shift/sharpen from per-element score sc[] -> w_hd
__device__ __forceinline__ void fin_core(float* sc, int hd, int b, float gate,
                                         float s0, float s1, float s2, float gamma,
                                         const float* pw, float* sbuf, float* swg) {
    int tid = threadIdx.x;
    float lmax = -3.4e38f;
#pragma unroll
    for (int t = 0; t < 16; ++t) lmax = fmaxf(lmax, sc[t]);
    float bmax = block_reduce_max(lmax, sbuf);
    float lsum = 0.f;
#pragma unroll
    for (int t = 0; t < 16; ++t) { float e = __expf(sc[t] - bmax); sc[t] = e; lsum += e; }
    float bsum = block_reduce_sum(lsum, sbuf);
    float inv = 1.f / bsum;
#pragma unroll
    for (int t = 0; t < 16; ++t) {
        int idx = tid + t * 256;
        swg[idx] = gate * sc[t] * inv + (1.f - gate) * pw[idx];
    }
    __syncthreads();
    float wp[16];
    float lps = 0.f;
#pragma unroll
    for (int t = 0; t < 16; ++t) {
        int idx = tid + t * 256;
        float ws = s0 * swg[(idx + N_ - 1) & (N_ - 1)] + s1 * swg[idx]
                 + s2 * swg[(idx + 1) & (N_ - 1)];
        float p = __powf(ws, gamma);
        wp[t] = p; lps += p;
    }
    float psum = block_reduce_sum(lps, sbuf);
    float invp = 1.f / (psum + EPSV);
    float* wout = g_w + (size_t)hd * RBN + (size_t)b * N_;
#pragma unroll
    for (int t = 0; t < 16; ++t) {
        int idx = tid + t * 256;
        wout[idx] = wp[t] * invp;
    }
}

// fin for heads 0-3 after pass A: 0,1 direct; 2,3 assembled from pass-A reductions
__global__ void finA_kernel(const float* __restrict__ prevW) {
    __shared__ float swg[N_];
    __shared__ float sbuf[8];
    int b = blockIdx.x;
    int hd = blockIdx.y;          // 0..3
    int tid = threadIdx.x;
    int hb = hd * B_ + b;
    float knorm = g_knorm[hb], beta = g_beta[hb], gate = g_gate[hb], gamma = g_gamma[hb];
    float s0 = g_s[hb * 3 + 0], s1 = g_s[hb * 3 + 1], s2 = g_s[hb * 3 + 2];
    const float* pw = prevW + ((size_t)hd * B_ + b) * N_;
    const size_t base = (size_t)b * N_;
    float sc[16];
    if (hd < 2) {
        const float* dot = hd ? RED(1) : RED(0);
        const float* nrm = RED(2);
#pragma unroll
        for (int t = 0; t < 16; ++t) {
            int idx = tid + t * 256;
            float d = dot[base + idx];
            float nr = nrm[base + idx];
            sc[t] = beta * d / (sqrtf(nr) * knorm + EPSV);
        }
    } else {
        int hh = hd - 2;
        float Ax = hh ? g_A3[b] : g_A2[b];
        float Aaa = g_Aaa[b];
        const float* ua = hh ? RED(5) : RED(3);
        const float* ub = hh ? RED(6) : RED(4);
        const float* nrm = RED(2);
        const float* r5 = RED(7); const float* r6 = RED(8);
        const float* r7 = RED(9); const float* r8 = RED(10);
        const float* wp1 = g_w + 1 * RBN + base;
#pragma unroll
        for (int t = 0; t < 16; ++t) {
            int idx = tid + t * 256;
            float w1 = wp1[idx];
            float d = ua[base + idx] + w1 * (Ax - ub[base + idx]);
            float nrm1 = nrm[base + idx]
                       + 2.f * w1 * (r5[base + idx] - r6[base + idx])
                       + w1 * w1 * (Aaa - 2.f * r7[base + idx] + r8[base + idx]);
            nrm1 = fmaxf(nrm1, 0.f);
            sc[t] = beta * d / (sqrtf(nrm1) * knorm + EPSV);
        }
    }
    fin_core(sc, hd, b, gate, s0, s1, s2, gamma, pw, sbuf, swg);
}

__global__ void fin_kernel(int head0, const float* __restrict__ prevW) {
    __shared__ float swg[N_];
    __shared__ float sbuf[8];
    int b = blockIdx.x;
    int hh = blockIdx.y;
    int hd = head0 + hh;
    int tid = threadIdx.x;
    const float* dot = hh ? RED(1) : RED(0);
    const float* nrm = RED(2);
    int hb = hd * B_ + b;
    float knorm = g_knorm[hb], beta = g_beta[hb], gate = g_gate[hb], gamma = g_gamma[hb];
    float s0 = g_s[hb * 3 + 0], s1 = g_s[hb * 3 + 1], s2 = g_s[hb * 3 + 2];
    const float* pw = prevW + ((size_t)hd * B_ + b) * N_;
    const size_t base = (size_t)b * N_;
    float sc[16];
#pragma unroll
    for (int t = 0; t < 16; ++t) {
        int idx = tid + t * 256;
        float d = dot[base + idx];
        float nr = nrm[base + idx];
        sc[t] = beta * d / (sqrtf(nr) * knorm + EPSV);
    }
    fin_core(sc, hd, b, gate, s0, s1, s2, gamma, pw, sbuf, swg);
}

// fin for head 6: assemble dot6/nrm3 from pass-D reductions + w5; also T[b] = sum w6 w5
__global__ void fin6_kernel(const float* __restrict__ prevW) {
    __shared__ float swg[N_];
    __shared__ float sbuf[8];
    int b = blockIdx.x;
    int tid = threadIdx.x;
    const int hd = 6;
    int hb = hd * B_ + b;
    float knorm = g_knorm[hb], beta = g_beta[hb], gate = g_gate[hb], gamma = g_gamma[hb];
    float s0 = g_s[hb * 3 + 0], s1 = g_s[hb * 3 + 1], s2 = g_s[hb * 3 + 2];
    float ak = g_ak[b], aa = g_aa[b];
    const float* pw = prevW + ((size_t)hd * B_ + b) * N_;
    const float* wp5 = g_w + 5 * RBN + (size_t)b * N_;
    const size_t base = (size_t)b * N_;
    const float* d6ap = RED(0); const float* d6bp = RED(1);
    const float* q0p = RED(2);  const float* q1p = RED(3);
    const float* q2p = RED(4);  const float* p1p = RED(5);
    const float* p2p = RED(6);
    float sc[16];
#pragma unroll
    for (int t = 0; t < 16; ++t) {
        int idx = tid + t * 256;
        float w5 = wp5[idx];
        float d6 = d6ap[base + idx] + w5 * (ak - d6bp[base + idx]);
        float q0 = q0p[base + idx];
        float q1 = q1p[base + idx], q2 = q2p[base + idx];
        float p1 = p1p[base + idx], p2 = p2p[base + idx];
        float nrm3 = q0 + w5 * (-2.f * q1 + 2.f * p1) + w5 * w5 * (q2 - 2.f * p2 + aa);
        nrm3 = fmaxf(nrm3, 0.f);
        sc[t] = beta * d6 / (sqrtf(nrm3) * knorm + EPSV);
    }
    fin_core(sc, hd, b, gate, s0, s1, s2, gamma, pw, sbuf, swg);
    // T[b] = sum_n w6 w5
    const float* wout = g_w + 6 * RBN + base;
    float lt = 0.f;
#pragma unroll
    for (int t = 0; t < 16; ++t) {
        int idx = tid + t * 256;
        lt += wout[idx] * wp5[idx];
    }
    float T = block_reduce_sum(lt, sbuf);
    if (tid == 0) g_T[b] = T;
}

// ---------------- build state = [h | reads0 | reads2 | reads4 | reads6] ----------------
__global__ void build_state_kernel() {
    int b = blockIdx.x;
    for (int j = threadIdx.x; j < 768; j += blockDim.x) {
        float v;
        if (j < 512) v = g_h[(size_t)b * C_ + j];
        else {
            int ri = (j - 512) >> 6, m = (j - 512) & 63;
            if (ri < 3) {
                float s = 0.f;
                const float* rp = g_rpart + (size_t)ri * B_ * 16 * 64 + (size_t)b * 16 * 64 + m;
#pragma unroll
                for (int cc = 0; cc < 16; ++cc) s += rp[cc * 64];
                v = s;
            } else {
                float sa = 0.f, sb = 0.f;
                const float* rpa = g_rpart + (size_t)3 * B_ * 16 * 64 + (size_t)b * 16 * 64 + m;
                const float* rpb = g_rpart + (size_t)4 * B_ * 16 * 64 + (size_t)b * 16 * 64 + m;
#pragma unroll
                for (int cc = 0; cc < 16; ++cc) { sa += rpa[cc * 64]; sb += rpb[cc * 64]; }
                float e5 = g_e[((size_t)2 * B_ + b) * 64 + m];
                float a5 = g_a[((size_t)2 * B_ + b) * 64 + m];
                v = sa - e5 * sb + g_T[b] * a5;
            }
        }
        g_state[(size_t)b * 768 + j] = v;
    }
}

// ---------------- host ----------------
extern "C" void kernel_launch(void* const* d_in, const int* in_sizes, int n_in,
                              void* d_out, int out_size) {
    const float* in_data      = (const float*)d_in[0];
    const float* memory       = (const float*)d_in[1];
    const float* h0           = (const float*)d_in[2];
    const float* c0           = (const float*)d_in[3];
    const float* prev_weights = (const float*)d_in[4];
    const float* prev_reads   = (const float*)d_in[5];
    const float* W_ih         = (const float*)d_in[6];
    const float* b_ih         = (const float*)d_in[7];
    const float* W_hh         = (const float*)d_in[8];
    const float* b_hh         = (const float*)d_in[9];
    const float* W_out        = (const float*)d_in[10];
    const float* b_out        = (const float*)d_in[11];
    const float* W_addr       = (const float*)d_in[12];
    const float* b_addr       = (const float*)d_in[13];
    const float* W_ea         = (const float*)d_in[14];
    const float* b_ea         = (const float*)d_in[15];
    float* outp = (float*)d_out;

    // controller (split-K GEMMs)
    build_x_kernel<<<(B_ * 320 + 255) / 256, 256>>>(in_data, prev_reads);
    gates_gemm_kernel<<<dim3(2048 / 64, B_ / 64, 4), 256>>>(h0, W_ih, W_hh);
    lstm_kernel<<<(B_ * C_ + 255) / 256, 256>>>(c0, b_ih, b_hh);

    // head parameters (trimmed N=874: addr heads 0-6, ea heads 0-2; split-K 8)
    headpe_gemm_kernel<<<dim3((PEN + 63) / 64, B_ / 64, 8), 256>>>(W_addr, W_ea);
    head_act_kernel<<<B_, 256>>>(b_addr, b_ea);

    passA_kernel<<<NPASSBLK, 256>>>(memory);
    finA_kernel<<<dim3(B_, 4), 256>>>(prev_weights);       // heads 0-3
    passC_kernel<<<NPASSBLK, 256>>>(memory);
    fin_kernel<<<dim3(B_, 2), 256>>>(4, prev_weights);     // heads 4,5 (direct on m2)
    passD_kernel<<<NPASSBLK, 256>>>();
    fin6_kernel<<<B_, 256>>>(prev_weights);                // head 6 (assembled)
    passE_kernel<<<NPASSBLK, 256>>>();

    // output
    build_state_kernel<<<B_, 256>>>();
    out_gemm_kernel<<<dim3(1, B_ / 32, 4), 256>>>(W_out);
    out_fin_kernel<<<(B_ * 64 + 255) / 256, 256>>>(b_out, outp);
}